// round 1
// baseline (speedup 1.0000x reference)
#include <cuda_runtime.h>
#include <math.h>

// Problem constants
#define MTOT 4096      // B*S
#define SEQ  2048
#define HID  2048
#define NH   16
#define NKV  4
#define HD   128
#define QW   2048      // NH*HD
#define KVW  512       // NKV*HD

// Scratch (allocation-free rule: __device__ globals)
__device__ float g_Q[(size_t)MTOT * QW];    // 33.5 MB
__device__ float g_K[(size_t)MTOT * KVW];   // 8.4 MB
__device__ float g_V[(size_t)MTOT * KVW];   // 8.4 MB
__device__ float g_A[(size_t)MTOT * QW];    // 33.5 MB (attention output, pre O-proj)

// ---------------------------------------------------------------------------
// NT SGEMM: C[m][n] = sum_k A[m*K+k] * B[n*K+k]
// Tiles: BM=BN=128, BK=16, 256 threads, 8x8 per-thread register blocking.
// All dims here are multiples of the tile sizes (M=4096, N in {2048,512}, K=2048).
// ---------------------------------------------------------------------------
__global__ __launch_bounds__(256, 2)
void sgemm_nt(const float* __restrict__ A, const float* __restrict__ B,
              float* __restrict__ C, int M, int N, int K)
{
    __shared__ float As[16][128];
    __shared__ float Bs[16][128];

    const int t  = threadIdx.x;
    const int tx = t & 15;        // 0..15 -> N direction
    const int ty = t >> 4;        // 0..15 -> M direction
    const int bm = blockIdx.y * 128;
    const int bn = blockIdx.x * 128;

    const int lr = t >> 2;        // 0..63 (tile row for loads)
    const int lc = (t & 3) * 4;   // 0,4,8,12 (k offset for loads)

    const float* Ab = A + (size_t)bm * K;
    const float* Bb = B + (size_t)bn * K;

    float acc[8][8];
#pragma unroll
    for (int i = 0; i < 8; i++)
#pragma unroll
        for (int j = 0; j < 8; j++) acc[i][j] = 0.f;

    for (int k0 = 0; k0 < K; k0 += 16) {
        float4 a0 = *(const float4*)(Ab + (size_t)lr        * K + k0 + lc);
        float4 a1 = *(const float4*)(Ab + (size_t)(lr + 64) * K + k0 + lc);
        float4 b0 = *(const float4*)(Bb + (size_t)lr        * K + k0 + lc);
        float4 b1 = *(const float4*)(Bb + (size_t)(lr + 64) * K + k0 + lc);

        __syncthreads();
        As[lc + 0][lr] = a0.x; As[lc + 1][lr] = a0.y; As[lc + 2][lr] = a0.z; As[lc + 3][lr] = a0.w;
        As[lc + 0][lr + 64] = a1.x; As[lc + 1][lr + 64] = a1.y; As[lc + 2][lr + 64] = a1.z; As[lc + 3][lr + 64] = a1.w;
        Bs[lc + 0][lr] = b0.x; Bs[lc + 1][lr] = b0.y; Bs[lc + 2][lr] = b0.z; Bs[lc + 3][lr] = b0.w;
        Bs[lc + 0][lr + 64] = b1.x; Bs[lc + 1][lr + 64] = b1.y; Bs[lc + 2][lr + 64] = b1.z; Bs[lc + 3][lr + 64] = b1.w;
        __syncthreads();

#pragma unroll
        for (int kk = 0; kk < 16; kk++) {
            float av[8], bv[8];
            *(float4*)&av[0] = *(const float4*)&As[kk][ty * 8];
            *(float4*)&av[4] = *(const float4*)&As[kk][ty * 8 + 4];
            *(float4*)&bv[0] = *(const float4*)&Bs[kk][tx * 8];
            *(float4*)&bv[4] = *(const float4*)&Bs[kk][tx * 8 + 4];
#pragma unroll
            for (int i = 0; i < 8; i++)
#pragma unroll
                for (int j = 0; j < 8; j++)
                    acc[i][j] = fmaf(av[i], bv[j], acc[i][j]);
        }
    }

#pragma unroll
    for (int i = 0; i < 8; i++) {
        float* Crow = C + (size_t)(bm + ty * 8 + i) * N + bn + tx * 8;
        *(float4*)Crow       = *(float4*)&acc[i][0];
        *(float4*)(Crow + 4) = *(float4*)&acc[i][4];
    }
}

// ---------------------------------------------------------------------------
// RoPE applied in-place to Q (16 heads) and K (4 heads).
// One thread per rotation pair. q'[i] = q[i]*c - q[i+64]*s; q'[i+64] = q[i+64]*c + q[i]*s
// ---------------------------------------------------------------------------
__global__ void rope_kernel(float* __restrict__ Q, float* __restrict__ Kb,
                            const float* __restrict__ sinp, const float* __restrict__ cosp)
{
    const long long total = (long long)MTOT * (NH + NKV) * 64;
    long long idx = (long long)blockIdx.x * blockDim.x + threadIdx.x;
    if (idx >= total) return;
    int pi   = (int)(idx & 63);
    int head = (int)((idx >> 6) % (NH + NKV));
    int m    = (int)(idx / (64 * (NH + NKV)));
    int s    = m & (SEQ - 1);

    float* p;
    if (head < NH) p = Q  + (size_t)m * QW  + head * HD;
    else           p = Kb + (size_t)m * KVW + (head - NH) * HD;

    float c  = cosp[(size_t)s * HD + pi];
    float sn = sinp[(size_t)s * HD + pi];
    float x0 = p[pi];
    float x1 = p[pi + 64];
    p[pi]      = x0 * c - x1 * sn;
    p[pi + 64] = x1 * c + x0 * sn;
}

// ---------------------------------------------------------------------------
// Flash attention (fp32, softmax_scale=1.0, analytic causal mask).
// Block: 128 threads. BM=64 query rows, BN=64 key cols, D=128.
// Thread (ty=t/16, tx=t%16): S-frag rows ty*8..+7, cols tx*4..+3;
//                            O-frag rows ty*8..+7, cols tx*8..+7.
// ---------------------------------------------------------------------------
#define QSTRIDE 132
#define PSTRIDE 68

__global__ __launch_bounds__(128, 2)
void flash_attn(const float* __restrict__ Qg, const float* __restrict__ Kg,
                const float* __restrict__ Vg, float* __restrict__ Og)
{
    extern __shared__ float sm[];
    float* Qs = sm;                       // [64][132]
    float* Ks = sm + 64 * QSTRIDE;        // [64][132] (reused for V)
    float* Ps = sm + 2 * 64 * QSTRIDE;    // [64][68]

    const int qt = blockIdx.x;
    const int h  = blockIdx.y;
    const int b  = blockIdx.z;
    const int kvh = h >> 2;
    const int t  = threadIdx.x;
    const int tx = t & 15;
    const int ty = t >> 4;
    const int q0 = qt * 64;

    // Load Q tile [64][128]
    const float* Qbase = Qg + ((size_t)(b * SEQ + q0)) * QW + h * HD;
    for (int i = t; i < 64 * 32; i += 128) {
        int r = i >> 5, d4 = (i & 31) * 4;
        *(float4*)(Qs + r * QSTRIDE + d4) = *(const float4*)(Qbase + (size_t)r * QW + d4);
    }

    float o[8][8];
    float m_r[8], l_r[8];
#pragma unroll
    for (int i = 0; i < 8; i++) {
        m_r[i] = -1e30f; l_r[i] = 0.f;
#pragma unroll
        for (int j = 0; j < 8; j++) o[i][j] = 0.f;
    }

    for (int kt = 0; kt <= qt; kt++) {
        __syncthreads();  // Qs ready (iter 0) / prior PV reads of Ks(=V) done

        // Load K tile
        const float* Kbase = Kg + ((size_t)(b * SEQ + kt * 64)) * KVW + kvh * HD;
        for (int i = t; i < 64 * 32; i += 128) {
            int r = i >> 5, d4 = (i & 31) * 4;
            *(float4*)(Ks + r * QSTRIDE + d4) = *(const float4*)(Kbase + (size_t)r * KVW + d4);
        }
        __syncthreads();

        // S = Q K^T
        float s_acc[8][4];
#pragma unroll
        for (int i = 0; i < 8; i++)
#pragma unroll
            for (int j = 0; j < 4; j++) s_acc[i][j] = 0.f;

#pragma unroll 4
        for (int d4 = 0; d4 < 32; d4++) {
            float4 kf[4];
#pragma unroll
            for (int j = 0; j < 4; j++)
                kf[j] = *(const float4*)(Ks + (tx * 4 + j) * QSTRIDE + d4 * 4);
#pragma unroll
            for (int i = 0; i < 8; i++) {
                float4 qf = *(const float4*)(Qs + (ty * 8 + i) * QSTRIDE + d4 * 4);
#pragma unroll
                for (int j = 0; j < 4; j++) {
                    s_acc[i][j] = fmaf(qf.x, kf[j].x, s_acc[i][j]);
                    s_acc[i][j] = fmaf(qf.y, kf[j].y, s_acc[i][j]);
                    s_acc[i][j] = fmaf(qf.z, kf[j].z, s_acc[i][j]);
                    s_acc[i][j] = fmaf(qf.w, kf[j].w, s_acc[i][j]);
                }
            }
        }

        // Causal mask on the diagonal tile
        if (kt == qt) {
#pragma unroll
            for (int i = 0; i < 8; i++)
#pragma unroll
                for (int j = 0; j < 4; j++)
                    if (tx * 4 + j > ty * 8 + i) s_acc[i][j] = -1e30f;
        }

        // Row max (reduce across the 16 tx lanes; xor offsets < 16 stay in half-warp)
        float rmax[8];
#pragma unroll
        for (int i = 0; i < 8; i++) {
            float v = fmaxf(fmaxf(s_acc[i][0], s_acc[i][1]), fmaxf(s_acc[i][2], s_acc[i][3]));
#pragma unroll
            for (int off = 8; off >= 1; off >>= 1)
                v = fmaxf(v, __shfl_xor_sync(0xffffffffu, v, off));
            rmax[i] = v;
        }

        float alpha[8];
#pragma unroll
        for (int i = 0; i < 8; i++) {
            float mnew = fmaxf(m_r[i], rmax[i]);
            alpha[i] = __expf(m_r[i] - mnew);
            m_r[i] = mnew;
        }

        // P = exp(S - m), write to smem, row sums
        float rsum[8];
#pragma unroll
        for (int i = 0; i < 8; i++) {
            float s = 0.f;
#pragma unroll
            for (int j = 0; j < 4; j++) {
                float p = __expf(s_acc[i][j] - m_r[i]);
                Ps[(ty * 8 + i) * PSTRIDE + tx * 4 + j] = p;
                s += p;
            }
#pragma unroll
            for (int off = 8; off >= 1; off >>= 1)
                s += __shfl_xor_sync(0xffffffffu, s, off);
            rsum[i] = s;
        }
#pragma unroll
        for (int i = 0; i < 8; i++) l_r[i] = l_r[i] * alpha[i] + rsum[i];

        __syncthreads();  // S-phase reads of Ks done; Ps writes ordered

        // Load V tile into Ks
        const float* Vbase = Vg + ((size_t)(b * SEQ + kt * 64)) * KVW + kvh * HD;
        for (int i = t; i < 64 * 32; i += 128) {
            int r = i >> 5, d4 = (i & 31) * 4;
            *(float4*)(Ks + r * QSTRIDE + d4) = *(const float4*)(Vbase + (size_t)r * KVW + d4);
        }

        // Rescale O while V load is in flight
#pragma unroll
        for (int i = 0; i < 8; i++)
#pragma unroll
            for (int j = 0; j < 8; j++) o[i][j] *= alpha[i];

        __syncthreads();

        // O += P @ V
#pragma unroll 4
        for (int c = 0; c < 64; c++) {
            float4 v0 = *(const float4*)(Ks + c * QSTRIDE + tx * 8);
            float4 v1 = *(const float4*)(Ks + c * QSTRIDE + tx * 8 + 4);
#pragma unroll
            for (int i = 0; i < 8; i++) {
                float p = Ps[(ty * 8 + i) * PSTRIDE + c];
                o[i][0] = fmaf(p, v0.x, o[i][0]);
                o[i][1] = fmaf(p, v0.y, o[i][1]);
                o[i][2] = fmaf(p, v0.z, o[i][2]);
                o[i][3] = fmaf(p, v0.w, o[i][3]);
                o[i][4] = fmaf(p, v1.x, o[i][4]);
                o[i][5] = fmaf(p, v1.y, o[i][5]);
                o[i][6] = fmaf(p, v1.z, o[i][6]);
                o[i][7] = fmaf(p, v1.w, o[i][7]);
            }
        }
    }

    // Epilogue: normalize and write to attention buffer [b,s,h,d]
    float* Ob = Og + ((size_t)(b * SEQ + q0)) * QW + h * HD;
#pragma unroll
    for (int i = 0; i < 8; i++) {
        float inv = 1.f / l_r[i];
        float out[8];
#pragma unroll
        for (int j = 0; j < 8; j++) out[j] = o[i][j] * inv;
        float* row = Ob + (size_t)(ty * 8 + i) * QW + tx * 8;
        *(float4*)row       = *(float4*)&out[0];
        *(float4*)(row + 4) = *(float4*)&out[4];
    }
}

// ---------------------------------------------------------------------------
// Launcher
// Inputs: 0 hidden_states [2,2048,2048] f32, 1 attention_mask (unused),
//         2 q_w [2048,2048], 3 k_w [512,2048], 4 v_w [512,2048],
//         5 o_w [2048,2048], 6 sin [4096,128], 7 cos [4096,128]
// Output: [2,2048,2048] f32
// ---------------------------------------------------------------------------
extern "C" void kernel_launch(void* const* d_in, const int* in_sizes, int n_in,
                              void* d_out, int out_size)
{
    const float* x    = (const float*)d_in[0];
    const float* q_w  = (const float*)d_in[2];
    const float* k_w  = (const float*)d_in[3];
    const float* v_w  = (const float*)d_in[4];
    const float* o_w  = (const float*)d_in[5];
    const float* sinp = (const float*)d_in[6];
    const float* cosp = (const float*)d_in[7];
    float* out = (float*)d_out;

    float *Q, *K, *V, *A;
    cudaGetSymbolAddress((void**)&Q, g_Q);
    cudaGetSymbolAddress((void**)&K, g_K);
    cudaGetSymbolAddress((void**)&V, g_V);
    cudaGetSymbolAddress((void**)&A, g_A);

    // QKV projections
    sgemm_nt<<<dim3(QW / 128,  MTOT / 128), 256>>>(x, q_w, Q, MTOT, QW,  HID);
    sgemm_nt<<<dim3(KVW / 128, MTOT / 128), 256>>>(x, k_w, K, MTOT, KVW, HID);
    sgemm_nt<<<dim3(KVW / 128, MTOT / 128), 256>>>(x, v_w, V, MTOT, KVW, HID);

    // RoPE on Q and K
    {
        long long total = (long long)MTOT * (NH + NKV) * 64;
        int threads = 256;
        int blocks = (int)((total + threads - 1) / threads);
        rope_kernel<<<blocks, threads>>>(Q, K, sinp, cosp);
    }

    // Flash attention
    {
        size_t smem = (size_t)(2 * 64 * QSTRIDE + 64 * PSTRIDE) * sizeof(float); // ~85 KB
        cudaFuncSetAttribute(flash_attn, cudaFuncAttributeMaxDynamicSharedMemorySize, (int)smem);
        flash_attn<<<dim3(SEQ / 64, NH, 2), 128, smem>>>(Q, K, V, A);
    }

    // Output projection -> d_out
    sgemm_nt<<<dim3(HID / 128, MTOT / 128), 256>>>(A, o_w, out, MTOT, HID, HID);
}

// round 2
// speedup vs baseline: 1.1992x; 1.1992x over previous
#include <cuda_runtime.h>
#include <math.h>
#include <stdint.h>

// Problem constants
#define MTOT 4096      // B*S
#define SEQ  2048
#define HID  2048
#define NH   16
#define NKV  4
#define HD   128
#define QW   2048      // NH*HD
#define KVW  512       // NKV*HD

// Scratch (allocation-free rule: __device__ globals)
__device__ float g_Q[(size_t)MTOT * QW];    // 33.5 MB
__device__ float g_K[(size_t)MTOT * KVW];   // 8.4 MB
__device__ float g_V[(size_t)MTOT * KVW];   // 8.4 MB
__device__ float g_A[(size_t)MTOT * QW];    // 33.5 MB (attention output, pre O-proj)

// ---------------------------------------------------------------------------
// tf32 helpers
// ---------------------------------------------------------------------------
__device__ __forceinline__ float tf32_rn(float x) {
    uint32_t u;
    asm("cvt.rna.tf32.f32 %0, %1;" : "=r"(u) : "f"(x));
    return __uint_as_float(u);
}

__device__ __forceinline__ void mma8(float* c, const uint32_t* a, const uint32_t* b) {
    asm volatile(
        "mma.sync.aligned.m16n8k8.row.col.f32.tf32.tf32.f32 "
        "{%0,%1,%2,%3}, {%4,%5,%6,%7}, {%8,%9}, {%0,%1,%2,%3};"
        : "+f"(c[0]), "+f"(c[1]), "+f"(c[2]), "+f"(c[3])
        : "r"(a[0]), "r"(a[1]), "r"(a[2]), "r"(a[3]), "r"(b[0]), "r"(b[1]));
}

// ---------------------------------------------------------------------------
// NT GEMM on tensor cores (tf32, error-compensated split => ~fp32 accuracy):
//   C[m][n] = sum_k A[m*K+k] * B[n*K+k]
// Tiles: BM=BN=128, BK=32. 256 threads = 8 warps (2x4), warp tile 64x32.
// For each operand x = hi + lo (hi = round-to-tf32), accumulate
//   hi_a*hi_b + lo_a*hi_b + hi_a*lo_b  (lo*lo term ~2^-22, dropped).
// smem stride 36 floats => conflict-free frag loads.
// ---------------------------------------------------------------------------
#define GS 36          // smem row stride (floats)

__global__ __launch_bounds__(256)
void mma_gemm_nt(const float* __restrict__ A, const float* __restrict__ B,
                 float* __restrict__ C, int M, int N, int K)
{
    extern __shared__ float sm[];
    float* As = sm;                  // [128][36] hi
    float* Al = As + 128 * GS;       // [128][36] lo
    float* Bs = Al + 128 * GS;
    float* Bl = Bs + 128 * GS;

    const int t    = threadIdx.x;
    const int warp = t >> 5;
    const int lane = t & 31;
    const int wm   = warp >> 2;      // 0..1  (M)
    const int wn   = warp & 3;       // 0..3  (N)
    const int g    = lane >> 2;      // 0..7
    const int qd   = lane & 3;       // 0..3
    const int bm   = blockIdx.y * 128;
    const int bn   = blockIdx.x * 128;

    const int lrow = t >> 1;         // 0..127
    const int lkb  = (t & 1) * 16;   // 0 or 16

    const float* Ap = A + (size_t)(bm + lrow) * K + lkb;
    const float* Bp = B + (size_t)(bn + lrow) * K + lkb;

    float4 ra[4], rb[4];
#pragma unroll
    for (int i = 0; i < 4; i++) {
        ra[i] = *(const float4*)(Ap + i * 4);
        rb[i] = *(const float4*)(Bp + i * 4);
    }

    float acc[4][4][4];
#pragma unroll
    for (int mi = 0; mi < 4; mi++)
#pragma unroll
        for (int ni = 0; ni < 4; ni++)
#pragma unroll
            for (int r = 0; r < 4; r++) acc[mi][ni][r] = 0.f;

    for (int k0 = 0; k0 < K; k0 += 32) {
        __syncthreads();
        // split & store to smem
#pragma unroll
        for (int i = 0; i < 4; i++) {
            float4 x = ra[i], h, l;
            h.x = tf32_rn(x.x); l.x = x.x - h.x;
            h.y = tf32_rn(x.y); l.y = x.y - h.y;
            h.z = tf32_rn(x.z); l.z = x.z - h.z;
            h.w = tf32_rn(x.w); l.w = x.w - h.w;
            *(float4*)(As + lrow * GS + lkb + i * 4) = h;
            *(float4*)(Al + lrow * GS + lkb + i * 4) = l;
            x = rb[i];
            h.x = tf32_rn(x.x); l.x = x.x - h.x;
            h.y = tf32_rn(x.y); l.y = x.y - h.y;
            h.z = tf32_rn(x.z); l.z = x.z - h.z;
            h.w = tf32_rn(x.w); l.w = x.w - h.w;
            *(float4*)(Bs + lrow * GS + lkb + i * 4) = h;
            *(float4*)(Bl + lrow * GS + lkb + i * 4) = l;
        }
        __syncthreads();

        // prefetch next tile while computing this one
        if (k0 + 32 < K) {
            Ap += 32; Bp += 32;
#pragma unroll
            for (int i = 0; i < 4; i++) {
                ra[i] = *(const float4*)(Ap + i * 4);
                rb[i] = *(const float4*)(Bp + i * 4);
            }
        }

#pragma unroll
        for (int s = 0; s < 4; s++) {
            uint32_t afh[4][4], afl[4][4], bfh[4][2], bfl[4][2];
#pragma unroll
            for (int mi = 0; mi < 4; mi++) {
                int r0 = wm * 64 + mi * 16 + g;
                afh[mi][0] = __float_as_uint(As[r0 * GS + s * 8 + qd]);
                afh[mi][1] = __float_as_uint(As[(r0 + 8) * GS + s * 8 + qd]);
                afh[mi][2] = __float_as_uint(As[r0 * GS + s * 8 + qd + 4]);
                afh[mi][3] = __float_as_uint(As[(r0 + 8) * GS + s * 8 + qd + 4]);
                afl[mi][0] = __float_as_uint(Al[r0 * GS + s * 8 + qd]);
                afl[mi][1] = __float_as_uint(Al[(r0 + 8) * GS + s * 8 + qd]);
                afl[mi][2] = __float_as_uint(Al[r0 * GS + s * 8 + qd + 4]);
                afl[mi][3] = __float_as_uint(Al[(r0 + 8) * GS + s * 8 + qd + 4]);
            }
#pragma unroll
            for (int ni = 0; ni < 4; ni++) {
                int c0 = wn * 32 + ni * 8 + g;
                bfh[ni][0] = __float_as_uint(Bs[c0 * GS + s * 8 + qd]);
                bfh[ni][1] = __float_as_uint(Bs[c0 * GS + s * 8 + qd + 4]);
                bfl[ni][0] = __float_as_uint(Bl[c0 * GS + s * 8 + qd]);
                bfl[ni][1] = __float_as_uint(Bl[c0 * GS + s * 8 + qd + 4]);
            }
#pragma unroll
            for (int mi = 0; mi < 4; mi++)
#pragma unroll
                for (int ni = 0; ni < 4; ni++) {
                    mma8(acc[mi][ni], afh[mi], bfh[ni]);
                    mma8(acc[mi][ni], afl[mi], bfh[ni]);
                    mma8(acc[mi][ni], afh[mi], bfl[ni]);
                }
        }
    }

    // epilogue
#pragma unroll
    for (int mi = 0; mi < 4; mi++)
#pragma unroll
        for (int ni = 0; ni < 4; ni++) {
            float* Crow = C + (size_t)(bm + wm * 64 + mi * 16 + g) * N
                            + bn + wn * 32 + ni * 8 + qd * 2;
            float2 v0 = make_float2(acc[mi][ni][0], acc[mi][ni][1]);
            float2 v1 = make_float2(acc[mi][ni][2], acc[mi][ni][3]);
            *(float2*)Crow = v0;
            *(float2*)(Crow + (size_t)8 * N) = v1;
        }
}

// ---------------------------------------------------------------------------
// RoPE applied in-place to Q (16 heads) and K (4 heads).
// ---------------------------------------------------------------------------
__global__ void rope_kernel(float* __restrict__ Q, float* __restrict__ Kb,
                            const float* __restrict__ sinp, const float* __restrict__ cosp)
{
    const long long total = (long long)MTOT * (NH + NKV) * 64;
    long long idx = (long long)blockIdx.x * blockDim.x + threadIdx.x;
    if (idx >= total) return;
    int pi   = (int)(idx & 63);
    int head = (int)((idx >> 6) % (NH + NKV));
    int m    = (int)(idx / (64 * (NH + NKV)));
    int s    = m & (SEQ - 1);

    float* p;
    if (head < NH) p = Q  + (size_t)m * QW  + head * HD;
    else           p = Kb + (size_t)m * KVW + (head - NH) * HD;

    float c  = cosp[(size_t)s * HD + pi];
    float sn = sinp[(size_t)s * HD + pi];
    float x0 = p[pi];
    float x1 = p[pi + 64];
    p[pi]      = x0 * c - x1 * sn;
    p[pi + 64] = x1 * c + x0 * sn;
}

// ---------------------------------------------------------------------------
// Flash attention (fp32, softmax_scale=1.0, analytic causal mask).
// Block: 128 threads. BM=64 query rows, BN=64 key cols, D=128.
// ---------------------------------------------------------------------------
#define QSTRIDE 132
#define PSTRIDE 68

__global__ __launch_bounds__(128, 2)
void flash_attn(const float* __restrict__ Qg, const float* __restrict__ Kg,
                const float* __restrict__ Vg, float* __restrict__ Og)
{
    extern __shared__ float smf[];
    float* Qs = smf;                      // [64][132]
    float* Ks = smf + 64 * QSTRIDE;       // [64][132] (reused for V)
    float* Ps = smf + 2 * 64 * QSTRIDE;   // [64][68]

    const int qt = blockIdx.x;
    const int h  = blockIdx.y;
    const int b  = blockIdx.z;
    const int kvh = h >> 2;
    const int t  = threadIdx.x;
    const int tx = t & 15;
    const int ty = t >> 4;
    const int q0 = qt * 64;

    const float* Qbase = Qg + ((size_t)(b * SEQ + q0)) * QW + h * HD;
    for (int i = t; i < 64 * 32; i += 128) {
        int r = i >> 5, d4 = (i & 31) * 4;
        *(float4*)(Qs + r * QSTRIDE + d4) = *(const float4*)(Qbase + (size_t)r * QW + d4);
    }

    float o[8][8];
    float m_r[8], l_r[8];
#pragma unroll
    for (int i = 0; i < 8; i++) {
        m_r[i] = -1e30f; l_r[i] = 0.f;
#pragma unroll
        for (int j = 0; j < 8; j++) o[i][j] = 0.f;
    }

    for (int kt = 0; kt <= qt; kt++) {
        __syncthreads();

        const float* Kbase = Kg + ((size_t)(b * SEQ + kt * 64)) * KVW + kvh * HD;
        for (int i = t; i < 64 * 32; i += 128) {
            int r = i >> 5, d4 = (i & 31) * 4;
            *(float4*)(Ks + r * QSTRIDE + d4) = *(const float4*)(Kbase + (size_t)r * KVW + d4);
        }
        __syncthreads();

        float s_acc[8][4];
#pragma unroll
        for (int i = 0; i < 8; i++)
#pragma unroll
            for (int j = 0; j < 4; j++) s_acc[i][j] = 0.f;

#pragma unroll 4
        for (int d4 = 0; d4 < 32; d4++) {
            float4 kf[4];
#pragma unroll
            for (int j = 0; j < 4; j++)
                kf[j] = *(const float4*)(Ks + (tx * 4 + j) * QSTRIDE + d4 * 4);
#pragma unroll
            for (int i = 0; i < 8; i++) {
                float4 qf = *(const float4*)(Qs + (ty * 8 + i) * QSTRIDE + d4 * 4);
#pragma unroll
                for (int j = 0; j < 4; j++) {
                    s_acc[i][j] = fmaf(qf.x, kf[j].x, s_acc[i][j]);
                    s_acc[i][j] = fmaf(qf.y, kf[j].y, s_acc[i][j]);
                    s_acc[i][j] = fmaf(qf.z, kf[j].z, s_acc[i][j]);
                    s_acc[i][j] = fmaf(qf.w, kf[j].w, s_acc[i][j]);
                }
            }
        }

        if (kt == qt) {
#pragma unroll
            for (int i = 0; i < 8; i++)
#pragma unroll
                for (int j = 0; j < 4; j++)
                    if (tx * 4 + j > ty * 8 + i) s_acc[i][j] = -1e30f;
        }

        float rmax[8];
#pragma unroll
        for (int i = 0; i < 8; i++) {
            float v = fmaxf(fmaxf(s_acc[i][0], s_acc[i][1]), fmaxf(s_acc[i][2], s_acc[i][3]));
#pragma unroll
            for (int off = 8; off >= 1; off >>= 1)
                v = fmaxf(v, __shfl_xor_sync(0xffffffffu, v, off));
            rmax[i] = v;
        }

        float alpha[8];
#pragma unroll
        for (int i = 0; i < 8; i++) {
            float mnew = fmaxf(m_r[i], rmax[i]);
            alpha[i] = __expf(m_r[i] - mnew);
            m_r[i] = mnew;
        }

        float rsum[8];
#pragma unroll
        for (int i = 0; i < 8; i++) {
            float s = 0.f;
#pragma unroll
            for (int j = 0; j < 4; j++) {
                float p = __expf(s_acc[i][j] - m_r[i]);
                Ps[(ty * 8 + i) * PSTRIDE + tx * 4 + j] = p;
                s += p;
            }
#pragma unroll
            for (int off = 8; off >= 1; off >>= 1)
                s += __shfl_xor_sync(0xffffffffu, s, off);
            rsum[i] = s;
        }
#pragma unroll
        for (int i = 0; i < 8; i++) l_r[i] = l_r[i] * alpha[i] + rsum[i];

        __syncthreads();

        const float* Vbase = Vg + ((size_t)(b * SEQ + kt * 64)) * KVW + kvh * HD;
        for (int i = t; i < 64 * 32; i += 128) {
            int r = i >> 5, d4 = (i & 31) * 4;
            *(float4*)(Ks + r * QSTRIDE + d4) = *(const float4*)(Vbase + (size_t)r * KVW + d4);
        }

#pragma unroll
        for (int i = 0; i < 8; i++)
#pragma unroll
            for (int j = 0; j < 8; j++) o[i][j] *= alpha[i];

        __syncthreads();

#pragma unroll 4
        for (int c = 0; c < 64; c++) {
            float4 v0 = *(const float4*)(Ks + c * QSTRIDE + tx * 8);
            float4 v1 = *(const float4*)(Ks + c * QSTRIDE + tx * 8 + 4);
#pragma unroll
            for (int i = 0; i < 8; i++) {
                float p = Ps[(ty * 8 + i) * PSTRIDE + c];
                o[i][0] = fmaf(p, v0.x, o[i][0]);
                o[i][1] = fmaf(p, v0.y, o[i][1]);
                o[i][2] = fmaf(p, v0.z, o[i][2]);
                o[i][3] = fmaf(p, v0.w, o[i][3]);
                o[i][4] = fmaf(p, v1.x, o[i][4]);
                o[i][5] = fmaf(p, v1.y, o[i][5]);
                o[i][6] = fmaf(p, v1.z, o[i][6]);
                o[i][7] = fmaf(p, v1.w, o[i][7]);
            }
        }
    }

    float* Ob = Og + ((size_t)(b * SEQ + q0)) * QW + h * HD;
#pragma unroll
    for (int i = 0; i < 8; i++) {
        float inv = 1.f / l_r[i];
        float outv[8];
#pragma unroll
        for (int j = 0; j < 8; j++) outv[j] = o[i][j] * inv;
        float* row = Ob + (size_t)(ty * 8 + i) * QW + tx * 8;
        *(float4*)row       = *(float4*)&outv[0];
        *(float4*)(row + 4) = *(float4*)&outv[4];
    }
}

// ---------------------------------------------------------------------------
// Launcher
// Inputs: 0 hidden_states [2,2048,2048] f32, 1 attention_mask (unused),
//         2 q_w [2048,2048], 3 k_w [512,2048], 4 v_w [512,2048],
//         5 o_w [2048,2048], 6 sin [4096,128], 7 cos [4096,128]
// Output: [2,2048,2048] f32
// ---------------------------------------------------------------------------
extern "C" void kernel_launch(void* const* d_in, const int* in_sizes, int n_in,
                              void* d_out, int out_size)
{
    const float* x    = (const float*)d_in[0];
    const float* q_w  = (const float*)d_in[2];
    const float* k_w  = (const float*)d_in[3];
    const float* v_w  = (const float*)d_in[4];
    const float* o_w  = (const float*)d_in[5];
    const float* sinp = (const float*)d_in[6];
    const float* cosp = (const float*)d_in[7];
    float* out = (float*)d_out;

    float *Q, *K, *V, *A;
    cudaGetSymbolAddress((void**)&Q, g_Q);
    cudaGetSymbolAddress((void**)&K, g_K);
    cudaGetSymbolAddress((void**)&V, g_V);
    cudaGetSymbolAddress((void**)&A, g_A);

    size_t gsmem = (size_t)4 * 128 * GS * sizeof(float);   // 73.7 KB
    cudaFuncSetAttribute(mma_gemm_nt, cudaFuncAttributeMaxDynamicSharedMemorySize, (int)gsmem);

    // QKV projections (tensor cores)
    mma_gemm_nt<<<dim3(QW / 128,  MTOT / 128), 256, gsmem>>>(x, q_w, Q, MTOT, QW,  HID);
    mma_gemm_nt<<<dim3(KVW / 128, MTOT / 128), 256, gsmem>>>(x, k_w, K, MTOT, KVW, HID);
    mma_gemm_nt<<<dim3(KVW / 128, MTOT / 128), 256, gsmem>>>(x, v_w, V, MTOT, KVW, HID);

    // RoPE on Q and K
    {
        long long total = (long long)MTOT * (NH + NKV) * 64;
        int threads = 256;
        int blocks = (int)((total + threads - 1) / threads);
        rope_kernel<<<blocks, threads>>>(Q, K, sinp, cosp);
    }

    // Flash attention
    {
        size_t smem = (size_t)(2 * 64 * QSTRIDE + 64 * PSTRIDE) * sizeof(float); // ~85 KB
        cudaFuncSetAttribute(flash_attn, cudaFuncAttributeMaxDynamicSharedMemorySize, (int)smem);
        flash_attn<<<dim3(SEQ / 64, NH, 2), 128, smem>>>(Q, K, V, A);
    }

    // Output projection -> d_out (tensor cores)
    mma_gemm_nt<<<dim3(HID / 128, MTOT / 128), 256, gsmem>>>(A, o_w, out, MTOT, HID, HID);
}

// round 5
// speedup vs baseline: 2.3976x; 1.9994x over previous
#include <cuda_runtime.h>
#include <cuda_bf16.h>
#include <math.h>
#include <stdint.h>

// Problem constants
#define MTOT 4096      // B*S
#define SEQ  2048
#define HID  2048
#define NH   16
#define NKV  4
#define HD   128
#define QW   2048      // NH*HD
#define KVW  512       // NKV*HD

// Scratch (allocation-free rule: __device__ globals)
__device__ float g_Q[(size_t)MTOT * QW];
__device__ float g_K[(size_t)MTOT * KVW];
__device__ float g_V[(size_t)MTOT * KVW];
__device__ float g_A[(size_t)MTOT * QW];
__device__ __nv_bfloat16 g_Qh[(size_t)MTOT * QW];
__device__ __nv_bfloat16 g_Ql[(size_t)MTOT * QW];
__device__ __nv_bfloat16 g_Kh[(size_t)MTOT * KVW];
__device__ __nv_bfloat16 g_Kl[(size_t)MTOT * KVW];
__device__ __nv_bfloat16 g_Vh[(size_t)MTOT * KVW];
__device__ __nv_bfloat16 g_Vl[(size_t)MTOT * KVW];

// ---------------------------------------------------------------------------
// mma.sync helpers (bf16 m16n8k16, f32 accum) + ldmatrix
// ---------------------------------------------------------------------------
__device__ __forceinline__ void mma16816(float* c, const uint32_t* a, uint32_t b0, uint32_t b1) {
    asm volatile(
        "mma.sync.aligned.m16n8k16.row.col.f32.bf16.bf16.f32 "
        "{%0,%1,%2,%3}, {%4,%5,%6,%7}, {%8,%9}, {%0,%1,%2,%3};"
        : "+f"(c[0]), "+f"(c[1]), "+f"(c[2]), "+f"(c[3])
        : "r"(a[0]), "r"(a[1]), "r"(a[2]), "r"(a[3]), "r"(b0), "r"(b1));
}
__device__ __forceinline__ void ldm4(uint32_t* r, uint32_t a) {
    asm volatile("ldmatrix.sync.aligned.m8n8.x4.shared.b16 {%0,%1,%2,%3}, [%4];"
                 : "=r"(r[0]), "=r"(r[1]), "=r"(r[2]), "=r"(r[3]) : "r"(a));
}
__device__ __forceinline__ void ldm4t(uint32_t* r, uint32_t a) {
    asm volatile("ldmatrix.sync.aligned.m8n8.x4.trans.shared.b16 {%0,%1,%2,%3}, [%4];"
                 : "=r"(r[0]), "=r"(r[1]), "=r"(r[2]), "=r"(r[3]) : "r"(a));
}
__device__ __forceinline__ uint32_t smem_u32(const void* p) {
    uint32_t a;
    asm("{ .reg .u64 tmp; cvta.to.shared.u64 tmp, %1; cvt.u32.u64 %0, tmp; }"
        : "=r"(a) : "l"(p));
    return a;
}
// split fp32 pair -> bf16 hi pair + bf16 lo pair (packed)
__device__ __forceinline__ void split2(float a, float b, uint32_t& h, uint32_t& l) {
    __nv_bfloat162 hh = __floats2bfloat162_rn(a, b);
    float ra = a - __bfloat162float(hh.x);
    float rb = b - __bfloat162float(hh.y);
    __nv_bfloat162 ll = __floats2bfloat162_rn(ra, rb);
    h = *(uint32_t*)&hh;
    l = *(uint32_t*)&ll;
}

// ---------------------------------------------------------------------------
// NT GEMM, bf16-split on legacy tensor path:
//   C[m][n] = sum_k A[m*K+k] * B[n*K+k]    (fp32 in/out)
// BM=BN=128, BK=32, 256 threads = 8 warps (2x4), warp tile 64x32.
// acc += Ah*Bh + Al*Bh + Ah*Bl  (Al*Bl ~2^-18, dropped).
// smem rows padded to 80B -> conflict-free ldmatrix.
// ---------------------------------------------------------------------------
#define GROW 80                       // bytes per 32-elem bf16 row
#define GT   (128 * GROW)             // one tile (128 rows)
#define GEMM_SMEM (4 * GT)            // Ah, Al, Bh, Bl = 40960 B

__global__ __launch_bounds__(256)
void hmma_gemm_nt(const float* __restrict__ A, const float* __restrict__ B,
                  float* __restrict__ C, int M, int N, int K)
{
    extern __shared__ __align__(128) char smem[];
    const uint32_t sb   = smem_u32(smem);
    const uint32_t smAh = sb;
    const uint32_t smAl = sb + GT;
    const uint32_t smBh = sb + 2 * GT;
    const uint32_t smBl = sb + 3 * GT;

    const int t    = threadIdx.x;
    const int warp = t >> 5;
    const int lane = t & 31;
    const int wm   = warp >> 2;        // 0..1
    const int wn   = warp & 3;         // 0..3
    const int bm   = blockIdx.y * 128;
    const int bn   = blockIdx.x * 128;

    // per-thread load map: 4 float4 each for A and B
    const float* aptr[4];
    const float* bptr[4];
    int soff[4];
#pragma unroll
    for (int i = 0; i < 4; i++) {
        int f = i * 256 + t;
        int r = f >> 3, c = (f & 7) * 4;
        aptr[i] = A + (size_t)(bm + r) * K + c;
        bptr[i] = B + (size_t)(bn + r) * K + c;
        soff[i] = r * GROW + c * 2;
    }

    float4 ra[4], rb[4];
#pragma unroll
    for (int i = 0; i < 4; i++) { ra[i] = *(const float4*)aptr[i]; rb[i] = *(const float4*)bptr[i]; }

    float acc[4][4][4];
#pragma unroll
    for (int mi = 0; mi < 4; mi++)
#pragma unroll
        for (int ni = 0; ni < 4; ni++)
#pragma unroll
            for (int r = 0; r < 4; r++) acc[mi][ni][r] = 0.f;

    const int S = K / 32;
    for (int s = 0; s < S; s++) {
        __syncthreads();
#pragma unroll
        for (int i = 0; i < 4; i++) {
            uint32_t h0, l0, h1, l1;
            split2(ra[i].x, ra[i].y, h0, l0);
            split2(ra[i].z, ra[i].w, h1, l1);
            *(uint2*)(smem + (smAh - sb) + soff[i]) = make_uint2(h0, h1);
            *(uint2*)(smem + (smAl - sb) + soff[i]) = make_uint2(l0, l1);
            split2(rb[i].x, rb[i].y, h0, l0);
            split2(rb[i].z, rb[i].w, h1, l1);
            *(uint2*)(smem + (smBh - sb) + soff[i]) = make_uint2(h0, h1);
            *(uint2*)(smem + (smBl - sb) + soff[i]) = make_uint2(l0, l1);
        }
        __syncthreads();

        if (s + 1 < S) {
            int k0 = (s + 1) * 32;
#pragma unroll
            for (int i = 0; i < 4; i++) {
                ra[i] = *(const float4*)(aptr[i] + k0);
                rb[i] = *(const float4*)(bptr[i] + k0);
            }
        }

#pragma unroll
        for (int kk = 0; kk < 2; kk++) {           // k16 steps within BK=32
            const int chb = kk * 2;
            uint32_t bh[2][4], bl[2][4];
#pragma unroll
            for (int ng = 0; ng < 2; ng++) {
                int rr = wn * 32 + ng * 16 + (lane & 15);
                uint32_t ad = rr * GROW + (chb + (lane >> 4)) * 16;
                ldm4(bh[ng], smBh + ad);
                ldm4(bl[ng], smBl + ad);
            }
#pragma unroll
            for (int mt = 0; mt < 4; mt++) {
                uint32_t ah[4], al[4];
                int rr = wm * 64 + mt * 16 + (lane & 15);
                uint32_t ad = rr * GROW + (chb + (lane >> 4)) * 16;
                ldm4(ah, smAh + ad);
                ldm4(al, smAl + ad);
#pragma unroll
                for (int n8 = 0; n8 < 4; n8++) {
                    int ng = n8 >> 1, hf = n8 & 1;
                    // x4 regs: r0=(n0-7,k0-7) r1=(n8-15,k0-7) r2=(n0-7,k8-15) r3=(n8-15,k8-15)
                    // B operand = same n-half: {r[hf], r[hf+2]}
                    uint32_t b0 = bh[ng][hf], b1 = bh[ng][hf + 2];
                    mma16816(acc[mt][n8], ah, b0, b1);
                    mma16816(acc[mt][n8], al, b0, b1);
                    mma16816(acc[mt][n8], ah, bl[ng][hf], bl[ng][hf + 2]);
                }
            }
        }
    }

    // epilogue
    const int g   = lane >> 2;
    const int tig = lane & 3;
#pragma unroll
    for (int mt = 0; mt < 4; mt++)
#pragma unroll
        for (int n8 = 0; n8 < 4; n8++) {
            int row = bm + wm * 64 + mt * 16 + g;
            int col = bn + wn * 32 + n8 * 8 + tig * 2;
            *(float2*)(C + (size_t)row * N + col) = make_float2(acc[mt][n8][0], acc[mt][n8][1]);
            *(float2*)(C + (size_t)(row + 8) * N + col) = make_float2(acc[mt][n8][2], acc[mt][n8][3]);
        }
}

// ---------------------------------------------------------------------------
// RoPE + bf16 hi/lo conversion.
// hh 0..15: Q heads (rotate+split), 16..19: K heads (rotate+split),
// 20..23: V heads (split only).
// ---------------------------------------------------------------------------
__global__ void rope_convert(const float* __restrict__ Q, const float* __restrict__ K,
                             const float* __restrict__ V,
                             const float* __restrict__ sinp, const float* __restrict__ cosp,
                             __nv_bfloat16* __restrict__ Qh, __nv_bfloat16* __restrict__ Ql,
                             __nv_bfloat16* __restrict__ Kh, __nv_bfloat16* __restrict__ Kl,
                             __nv_bfloat16* __restrict__ Vh, __nv_bfloat16* __restrict__ Vl)
{
    const long long total = (long long)MTOT * 24 * 64;
    long long idx = (long long)blockIdx.x * blockDim.x + threadIdx.x;
    if (idx >= total) return;
    int pi = (int)(idx & 63);
    int hh = (int)((idx >> 6) % 24);
    int m  = (int)(idx / (64 * 24));
    int s  = m & (SEQ - 1);

    const float* p;
    __nv_bfloat16 *oh, *ol;
    bool rot = true;
    if (hh < 16) {
        size_t off = (size_t)m * QW + hh * HD;
        p = Q + off; oh = Qh + off; ol = Ql + off;
    } else if (hh < 20) {
        size_t off = (size_t)m * KVW + (hh - 16) * HD;
        p = K + off; oh = Kh + off; ol = Kl + off;
    } else {
        size_t off = (size_t)m * KVW + (hh - 20) * HD;
        p = V + off; oh = Vh + off; ol = Vl + off;
        rot = false;
    }

    float x0 = p[pi], x1 = p[pi + 64];
    if (rot) {
        float c  = cosp[(size_t)s * HD + pi];
        float sn = sinp[(size_t)s * HD + pi];
        float y0 = x0 * c - x1 * sn;
        float y1 = x1 * c + x0 * sn;
        x0 = y0; x1 = y1;
    }
    __nv_bfloat16 h0 = __float2bfloat16_rn(x0);
    __nv_bfloat16 h1 = __float2bfloat16_rn(x1);
    oh[pi]      = h0;
    oh[pi + 64] = h1;
    ol[pi]      = __float2bfloat16_rn(x0 - __bfloat162float(h0));
    ol[pi + 64] = __float2bfloat16_rn(x1 - __bfloat162float(h1));
}

// ---------------------------------------------------------------------------
// Flash attention on bf16 mma.sync (split precision QK and PV).
// 128 threads = 4 warps. BM=64 (16 rows/warp), BN=64 keys/iter, D=128.
// smem tiles: Qh, Ql (persistent), KVh, KVl (K then V per iter).
// 256B rows, 16-byte-chunk XOR swizzle -> conflict-free ldmatrix.
// ---------------------------------------------------------------------------
#define AT_TILE 16384                       // 64 rows * 256 B
#define AT_SMEM (4 * AT_TILE)               // 65536 B

__device__ __forceinline__ uint32_t swz256(int r, int ch) {
    return (uint32_t)(r * 256 + (((ch ^ (r & 7)) & 15) << 4));
}

__global__ __launch_bounds__(128)
void flash_attn_mma(const __nv_bfloat16* __restrict__ Qh, const __nv_bfloat16* __restrict__ Ql,
                    const __nv_bfloat16* __restrict__ Kh, const __nv_bfloat16* __restrict__ Kl,
                    const __nv_bfloat16* __restrict__ Vh, const __nv_bfloat16* __restrict__ Vl,
                    float* __restrict__ Og)
{
    extern __shared__ __align__(128) char smem[];
    const uint32_t sb    = smem_u32(smem);
    const uint32_t sQh   = sb;
    const uint32_t sQl   = sb + AT_TILE;
    const uint32_t sKVh  = sb + 2 * AT_TILE;
    const uint32_t sKVl  = sb + 3 * AT_TILE;

    const int qt  = blockIdx.x;
    const int h   = blockIdx.y;
    const int b   = blockIdx.z;
    const int kvh = h >> 2;
    const int t   = threadIdx.x;
    const int warp = t >> 5;
    const int lane = t & 31;
    const int g    = lane >> 2;
    const int tig  = lane & 3;
    const int q0   = qt * 64;

    // load persistent Q tiles (hi, lo)
    {
        const __nv_bfloat16* qbh = Qh + (size_t)(b * SEQ + q0) * QW + h * HD;
        const __nv_bfloat16* qbl = Ql + (size_t)(b * SEQ + q0) * QW + h * HD;
#pragma unroll
        for (int i = 0; i < 8; i++) {
            int f = i * 128 + t;
            int r = f >> 4, ch = f & 15;
            *(uint4*)(smem + (sQh - sb) + swz256(r, ch)) = *(const uint4*)(qbh + (size_t)r * QW + ch * 8);
            *(uint4*)(smem + (sQl - sb) + swz256(r, ch)) = *(const uint4*)(qbl + (size_t)r * QW + ch * 8);
        }
    }

    float o[16][4];
    float m0 = -1e30f, m1 = -1e30f, l0 = 0.f, l1 = 0.f;
#pragma unroll
    for (int i = 0; i < 16; i++)
#pragma unroll
        for (int j = 0; j < 4; j++) o[i][j] = 0.f;

    const int rl = warp * 16 + g;       // local row (lo), rh = rl + 8
    const int rh = rl + 8;

    for (int kt = 0; kt <= qt; kt++) {
        __syncthreads();   // prior PV reads done; Q load visible (iter 0)

        // load K tile
        {
            const __nv_bfloat16* kbh = Kh + (size_t)(b * SEQ + kt * 64) * KVW + kvh * HD;
            const __nv_bfloat16* kbl = Kl + (size_t)(b * SEQ + kt * 64) * KVW + kvh * HD;
#pragma unroll
            for (int i = 0; i < 8; i++) {
                int f = i * 128 + t;
                int r = f >> 4, ch = f & 15;
                *(uint4*)(smem + (sKVh - sb) + swz256(r, ch)) = *(const uint4*)(kbh + (size_t)r * KVW + ch * 8);
                *(uint4*)(smem + (sKVl - sb) + swz256(r, ch)) = *(const uint4*)(kbl + (size_t)r * KVW + ch * 8);
            }
        }
        __syncthreads();

        // S = Q K^T  (split: QhKh + QlKh + QhKl)
        float sacc[8][4];
#pragma unroll
        for (int i = 0; i < 8; i++)
#pragma unroll
            for (int j = 0; j < 4; j++) sacc[i][j] = 0.f;

#pragma unroll
        for (int ks = 0; ks < 8; ks++) {
            uint32_t qfh[4], qfl[4];
            {
                int rr = warp * 16 + (lane & 15);
                uint32_t ad = swz256(rr, ks * 2 + (lane >> 4));
                ldm4(qfh, sQh + ad);
                ldm4(qfl, sQl + ad);
            }
#pragma unroll
            for (int ng = 0; ng < 4; ng++) {
                uint32_t kfh[4], kfl[4];
                int rr = ng * 16 + (lane & 15);
                uint32_t ad = swz256(rr, ks * 2 + (lane >> 4));
                ldm4(kfh, sKVh + ad);
                ldm4(kfl, sKVl + ad);
#pragma unroll
                for (int hf = 0; hf < 2; hf++) {
                    int n8 = ng * 2 + hf;
                    // B operand = same n-half: {r[hf], r[hf+2]}
                    uint32_t b0 = kfh[hf], b1 = kfh[hf + 2];
                    mma16816(sacc[n8], qfh, b0, b1);
                    mma16816(sacc[n8], qfl, b0, b1);
                    mma16816(sacc[n8], qfh, kfl[hf], kfl[hf + 2]);
                }
            }
        }

        // causal mask (diagonal tile only)
        if (kt == qt) {
#pragma unroll
            for (int n8 = 0; n8 < 8; n8++) {
                int c0 = n8 * 8 + tig * 2, c1 = c0 + 1;
                if (c0 > rl) sacc[n8][0] = -1e30f;
                if (c1 > rl) sacc[n8][1] = -1e30f;
                if (c0 > rh) sacc[n8][2] = -1e30f;
                if (c1 > rh) sacc[n8][3] = -1e30f;
            }
        }

        // online softmax
        float mx0 = -1e30f, mx1 = -1e30f;
#pragma unroll
        for (int n8 = 0; n8 < 8; n8++) {
            mx0 = fmaxf(mx0, fmaxf(sacc[n8][0], sacc[n8][1]));
            mx1 = fmaxf(mx1, fmaxf(sacc[n8][2], sacc[n8][3]));
        }
        mx0 = fmaxf(mx0, __shfl_xor_sync(0xffffffffu, mx0, 1));
        mx0 = fmaxf(mx0, __shfl_xor_sync(0xffffffffu, mx0, 2));
        mx1 = fmaxf(mx1, __shfl_xor_sync(0xffffffffu, mx1, 1));
        mx1 = fmaxf(mx1, __shfl_xor_sync(0xffffffffu, mx1, 2));

        float mn0 = fmaxf(m0, mx0), mn1 = fmaxf(m1, mx1);
        float al0 = __expf(m0 - mn0), al1 = __expf(m1 - mn1);
        m0 = mn0; m1 = mn1;

        float s0 = 0.f, s1 = 0.f;
#pragma unroll
        for (int n8 = 0; n8 < 8; n8++) {
            float p0 = __expf(sacc[n8][0] - m0);
            float p1 = __expf(sacc[n8][1] - m0);
            float p2 = __expf(sacc[n8][2] - m1);
            float p3 = __expf(sacc[n8][3] - m1);
            sacc[n8][0] = p0; sacc[n8][1] = p1; sacc[n8][2] = p2; sacc[n8][3] = p3;
            s0 += p0 + p1; s1 += p2 + p3;
        }
        s0 += __shfl_xor_sync(0xffffffffu, s0, 1);
        s0 += __shfl_xor_sync(0xffffffffu, s0, 2);
        s1 += __shfl_xor_sync(0xffffffffu, s1, 1);
        s1 += __shfl_xor_sync(0xffffffffu, s1, 2);
        l0 = l0 * al0 + s0;
        l1 = l1 * al1 + s1;

        // rescale O
#pragma unroll
        for (int i = 0; i < 16; i++) {
            o[i][0] *= al0; o[i][1] *= al0;
            o[i][2] *= al1; o[i][3] *= al1;
        }

        // P -> bf16 A-fragments (hi/lo), registers only
        uint32_t ph[4][4], pl[4][4];
#pragma unroll
        for (int kk = 0; kk < 4; kk++) {
            split2(sacc[2 * kk][0],     sacc[2 * kk][1],     ph[kk][0], pl[kk][0]);
            split2(sacc[2 * kk][2],     sacc[2 * kk][3],     ph[kk][1], pl[kk][1]);
            split2(sacc[2 * kk + 1][0], sacc[2 * kk + 1][1], ph[kk][2], pl[kk][2]);
            split2(sacc[2 * kk + 1][2], sacc[2 * kk + 1][3], ph[kk][3], pl[kk][3]);
        }

        __syncthreads();   // all warps done reading K tile

        // load V tile into same buffers
        {
            const __nv_bfloat16* vbh = Vh + (size_t)(b * SEQ + kt * 64) * KVW + kvh * HD;
            const __nv_bfloat16* vbl = Vl + (size_t)(b * SEQ + kt * 64) * KVW + kvh * HD;
#pragma unroll
            for (int i = 0; i < 8; i++) {
                int f = i * 128 + t;
                int r = f >> 4, ch = f & 15;
                *(uint4*)(smem + (sKVh - sb) + swz256(r, ch)) = *(const uint4*)(vbh + (size_t)r * KVW + ch * 8);
                *(uint4*)(smem + (sKVl - sb) + swz256(r, ch)) = *(const uint4*)(vbl + (size_t)r * KVW + ch * 8);
            }
        }
        __syncthreads();

        // O += P V   (split: PhVh + PlVh + PhVl)
        // trans-ldmatrix regs: r0=(k0-7,d-half0) r1=(k8-15,d-half0)
        //                      r2=(k0-7,d-half1) r3=(k8-15,d-half1)
#pragma unroll
        for (int ng = 0; ng < 8; ng++) {       // d groups of 16
#pragma unroll
            for (int kk = 0; kk < 4; kk++) {   // key k16 steps
                uint32_t vfh[4], vfl[4];
                int rr = kk * 16 + (lane & 15);
                uint32_t ad = swz256(rr, ng * 2 + (lane >> 4));
                ldm4t(vfh, sKVh + ad);
                ldm4t(vfl, sKVl + ad);
#pragma unroll
                for (int hf = 0; hf < 2; hf++) {
                    int nt = ng * 2 + hf;
                    uint32_t b0 = vfh[hf * 2], b1 = vfh[hf * 2 + 1];
                    mma16816(o[nt], ph[kk], b0, b1);
                    mma16816(o[nt], pl[kk], b0, b1);
                    mma16816(o[nt], ph[kk], vfl[hf * 2], vfl[hf * 2 + 1]);
                }
            }
        }
    }

    // epilogue: normalize and write fp32
    float inv0 = 1.f / l0, inv1 = 1.f / l1;
    float* Ob = Og + (size_t)(b * SEQ + q0) * QW + h * HD;
#pragma unroll
    for (int nt = 0; nt < 16; nt++) {
        int col = nt * 8 + tig * 2;
        *(float2*)(Ob + (size_t)rl * QW + col) = make_float2(o[nt][0] * inv0, o[nt][1] * inv0);
        *(float2*)(Ob + (size_t)rh * QW + col) = make_float2(o[nt][2] * inv1, o[nt][3] * inv1);
    }
}

// ---------------------------------------------------------------------------
// Launcher
// Inputs: 0 hidden_states [2,2048,2048] f32, 1 attention_mask (unused),
//         2 q_w [2048,2048], 3 k_w [512,2048], 4 v_w [512,2048],
//         5 o_w [2048,2048], 6 sin [4096,128], 7 cos [4096,128]
// ---------------------------------------------------------------------------
extern "C" void kernel_launch(void* const* d_in, const int* in_sizes, int n_in,
                              void* d_out, int out_size)
{
    const float* x    = (const float*)d_in[0];
    const float* q_w  = (const float*)d_in[2];
    const float* k_w  = (const float*)d_in[3];
    const float* v_w  = (const float*)d_in[4];
    const float* o_w  = (const float*)d_in[5];
    const float* sinp = (const float*)d_in[6];
    const float* cosp = (const float*)d_in[7];
    float* out = (float*)d_out;

    float *Q, *K, *V, *A;
    cudaGetSymbolAddress((void**)&Q, g_Q);
    cudaGetSymbolAddress((void**)&K, g_K);
    cudaGetSymbolAddress((void**)&V, g_V);
    cudaGetSymbolAddress((void**)&A, g_A);
    __nv_bfloat16 *Qh, *Ql, *Kh, *Kl, *Vh, *Vl;
    cudaGetSymbolAddress((void**)&Qh, g_Qh);
    cudaGetSymbolAddress((void**)&Ql, g_Ql);
    cudaGetSymbolAddress((void**)&Kh, g_Kh);
    cudaGetSymbolAddress((void**)&Kl, g_Kl);
    cudaGetSymbolAddress((void**)&Vh, g_Vh);
    cudaGetSymbolAddress((void**)&Vl, g_Vl);

    // QKV projections
    hmma_gemm_nt<<<dim3(QW / 128,  MTOT / 128), 256, GEMM_SMEM>>>(x, q_w, Q, MTOT, QW,  HID);
    hmma_gemm_nt<<<dim3(KVW / 128, MTOT / 128), 256, GEMM_SMEM>>>(x, k_w, K, MTOT, KVW, HID);
    hmma_gemm_nt<<<dim3(KVW / 128, MTOT / 128), 256, GEMM_SMEM>>>(x, v_w, V, MTOT, KVW, HID);

    // RoPE + bf16 split conversion
    {
        long long total = (long long)MTOT * 24 * 64;
        int threads = 256;
        int blocks = (int)((total + threads - 1) / threads);
        rope_convert<<<blocks, threads>>>(Q, K, V, sinp, cosp, Qh, Ql, Kh, Kl, Vh, Vl);
    }

    // Flash attention (tensor cores)
    {
        cudaFuncSetAttribute(flash_attn_mma, cudaFuncAttributeMaxDynamicSharedMemorySize, AT_SMEM);
        flash_attn_mma<<<dim3(SEQ / 64, NH, 2), 128, AT_SMEM>>>(Qh, Ql, Kh, Kl, Vh, Vl, A);
    }

    // Output projection
    hmma_gemm_nt<<<dim3(HID / 128, MTOT / 128), 256, GEMM_SMEM>>>(A, o_w, out, MTOT, HID, HID);
}

// round 6
// speedup vs baseline: 2.6138x; 1.0902x over previous
#include <cuda_runtime.h>
#include <cuda_bf16.h>
#include <math.h>
#include <stdint.h>

// Problem constants
#define MTOT 4096      // B*S
#define SEQ  2048
#define HID  2048
#define NH   16
#define NKV  4
#define HD   128
#define QW   2048      // NH*HD
#define KVW  512       // NKV*HD
#define KVW2 1024      // fused K+V width

// Scratch (allocation-free rule: __device__ globals)
__device__ float g_Q[(size_t)MTOT * QW];        // Q proj out (fp32)
__device__ float g_KV[(size_t)MTOT * KVW2];     // fused K|V proj out (fp32)
// pre-split GEMM operands (bf16 hi/lo)
__device__ __nv_bfloat16 g_xh[(size_t)MTOT * HID];
__device__ __nv_bfloat16 g_xl[(size_t)MTOT * HID];
__device__ __nv_bfloat16 g_qwh[(size_t)QW * HID];
__device__ __nv_bfloat16 g_qwl[(size_t)QW * HID];
__device__ __nv_bfloat16 g_kvwh[(size_t)KVW2 * HID];
__device__ __nv_bfloat16 g_kvwl[(size_t)KVW2 * HID];
__device__ __nv_bfloat16 g_owh[(size_t)HID * QW];
__device__ __nv_bfloat16 g_owl[(size_t)HID * QW];
// attention operands/results (bf16 hi/lo)
__device__ __nv_bfloat16 g_Qh[(size_t)MTOT * QW];
__device__ __nv_bfloat16 g_Ql[(size_t)MTOT * QW];
__device__ __nv_bfloat16 g_Kh[(size_t)MTOT * KVW];
__device__ __nv_bfloat16 g_Kl[(size_t)MTOT * KVW];
__device__ __nv_bfloat16 g_Vh[(size_t)MTOT * KVW];
__device__ __nv_bfloat16 g_Vl[(size_t)MTOT * KVW];
__device__ __nv_bfloat16 g_Ah[(size_t)MTOT * QW];
__device__ __nv_bfloat16 g_Al[(size_t)MTOT * QW];

// ---------------------------------------------------------------------------
// helpers
// ---------------------------------------------------------------------------
__device__ __forceinline__ void mma16816(float* c, const uint32_t* a, uint32_t b0, uint32_t b1) {
    asm volatile(
        "mma.sync.aligned.m16n8k16.row.col.f32.bf16.bf16.f32 "
        "{%0,%1,%2,%3}, {%4,%5,%6,%7}, {%8,%9}, {%0,%1,%2,%3};"
        : "+f"(c[0]), "+f"(c[1]), "+f"(c[2]), "+f"(c[3])
        : "r"(a[0]), "r"(a[1]), "r"(a[2]), "r"(a[3]), "r"(b0), "r"(b1));
}
__device__ __forceinline__ void ldm4(uint32_t* r, uint32_t a) {
    asm volatile("ldmatrix.sync.aligned.m8n8.x4.shared.b16 {%0,%1,%2,%3}, [%4];"
                 : "=r"(r[0]), "=r"(r[1]), "=r"(r[2]), "=r"(r[3]) : "r"(a));
}
__device__ __forceinline__ void ldm4t(uint32_t* r, uint32_t a) {
    asm volatile("ldmatrix.sync.aligned.m8n8.x4.trans.shared.b16 {%0,%1,%2,%3}, [%4];"
                 : "=r"(r[0]), "=r"(r[1]), "=r"(r[2]), "=r"(r[3]) : "r"(a));
}
__device__ __forceinline__ uint32_t smem_u32(const void* p) {
    uint32_t a;
    asm("{ .reg .u64 tmp; cvta.to.shared.u64 tmp, %1; cvt.u32.u64 %0, tmp; }"
        : "=r"(a) : "l"(p));
    return a;
}
__device__ __forceinline__ void cpa16(uint32_t dst, const void* src) {
    asm volatile("cp.async.cg.shared.global [%0], [%1], 16;" :: "r"(dst), "l"(src));
}
#define CPA_COMMIT() asm volatile("cp.async.commit_group;" ::: "memory")
#define CPA_WAIT(n)  asm volatile("cp.async.wait_group %0;" :: "n"(n) : "memory")

// split fp32 pair -> packed bf16 hi pair + lo pair
__device__ __forceinline__ void split2(float a, float b, uint32_t& h, uint32_t& l) {
    __nv_bfloat162 hh = __floats2bfloat162_rn(a, b);
    float ra = a - __bfloat162float(hh.x);
    float rb = b - __bfloat162float(hh.y);
    __nv_bfloat162 ll = __floats2bfloat162_rn(ra, rb);
    h = *(uint32_t*)&hh;
    l = *(uint32_t*)&ll;
}

// ---------------------------------------------------------------------------
// fp32 -> bf16 hi/lo split (vectorized, grid-stride not needed: exact grids)
// ---------------------------------------------------------------------------
__global__ void split_f32(const float* __restrict__ in,
                          __nv_bfloat16* __restrict__ hi, __nv_bfloat16* __restrict__ lo,
                          int n4)
{
    int i = blockIdx.x * blockDim.x + threadIdx.x;
    if (i >= n4) return;
    float4 x = ((const float4*)in)[i];
    uint32_t h0, l0, h1, l1;
    split2(x.x, x.y, h0, l0);
    split2(x.z, x.w, h1, l1);
    ((uint2*)hi)[i] = make_uint2(h0, h1);
    ((uint2*)lo)[i] = make_uint2(l0, l1);
}

// ---------------------------------------------------------------------------
// NT GEMM on pre-split bf16 operands:
//   C[m][n] = sum_k (Ah+Al)[m][k] * (Bh+Bl)[n][k]   (3-term split)
// BM=BN=128, BK=32, 256 threads = 8 warps (2x4), warp tile 64x32.
// cp.async 2-stage pipeline; 80B-padded rows -> conflict-free ldmatrix.
// ---------------------------------------------------------------------------
#define GROW  80                      // bytes per 32-elem bf16 row
#define GT    (128 * GROW)            // 10240 B per tile
#define STG_B (4 * GT)                // Ah, Al, Bh, Bl per stage = 40960 B
#define GEMM_SMEM (2 * STG_B)         // 81920 B

__global__ __launch_bounds__(256)
void hmma_gemm_pre(const __nv_bfloat16* __restrict__ Ah, const __nv_bfloat16* __restrict__ Al,
                   const __nv_bfloat16* __restrict__ Bh, const __nv_bfloat16* __restrict__ Bl,
                   float* __restrict__ C, int M, int N, int K)
{
    extern __shared__ __align__(128) char smem[];
    const uint32_t sb = smem_u32(smem);

    const int t    = threadIdx.x;
    const int warp = t >> 5;
    const int lane = t & 31;
    const int wm   = warp >> 2;        // 0..1
    const int wn   = warp & 3;         // 0..3
    const int bm   = blockIdx.y * 128;
    const int bn   = blockIdx.x * 128;

    // cp.async load map: per tile, thread t covers chunks {t, t+256} (512 chunks/tile)
    const int r0c = t >> 2, ch0 = t & 3;            // chunk t     -> rows 0..63
    const int r1c = r0c + 64;                       // chunk t+256 -> rows 64..127
    const __nv_bfloat16* srcA[2] = { Ah, Al };
    const __nv_bfloat16* srcB[2] = { Bh, Bl };

    float acc[4][4][4];
#pragma unroll
    for (int mi = 0; mi < 4; mi++)
#pragma unroll
        for (int ni = 0; ni < 4; ni++)
#pragma unroll
            for (int r = 0; r < 4; r++) acc[mi][ni][r] = 0.f;

    const int S = K / 32;

    // issue one stage of cp.async loads
    auto issue = [&](int s, int buf) {
        const int k0 = s * 32;
        const uint32_t stg = sb + (uint32_t)buf * STG_B;
#pragma unroll
        for (int hl = 0; hl < 2; hl++) {
            // A tiles (hi at tile 0, lo at tile 1)
            uint32_t dA = stg + hl * GT;
            cpa16(dA + r0c * GROW + ch0 * 16, srcA[hl] + (size_t)(bm + r0c) * K + k0 + ch0 * 8);
            cpa16(dA + r1c * GROW + ch0 * 16, srcA[hl] + (size_t)(bm + r1c) * K + k0 + ch0 * 8);
            // B tiles (hi at tile 2, lo at tile 3)
            uint32_t dB = stg + (2 + hl) * GT;
            cpa16(dB + r0c * GROW + ch0 * 16, srcB[hl] + (size_t)(bn + r0c) * K + k0 + ch0 * 8);
            cpa16(dB + r1c * GROW + ch0 * 16, srcB[hl] + (size_t)(bn + r1c) * K + k0 + ch0 * 8);
        }
        CPA_COMMIT();
    };

    issue(0, 0);

    for (int s = 0; s < S; s++) {
        const int buf = s & 1;
        if (s + 1 < S) {
            issue(s + 1, buf ^ 1);
            CPA_WAIT(1);
        } else {
            CPA_WAIT(0);
        }
        __syncthreads();

        const uint32_t smAh = sb + (uint32_t)buf * STG_B;
        const uint32_t smAl = smAh + GT;
        const uint32_t smBh = smAh + 2 * GT;
        const uint32_t smBl = smAh + 3 * GT;

#pragma unroll
        for (int kk = 0; kk < 2; kk++) {           // k16 steps within BK=32
            const int chb = kk * 2;
            uint32_t bh[2][4], bl[2][4];
#pragma unroll
            for (int ng = 0; ng < 2; ng++) {
                int rr = wn * 32 + ng * 16 + (lane & 15);
                uint32_t ad = rr * GROW + (chb + (lane >> 4)) * 16;
                ldm4(bh[ng], smBh + ad);
                ldm4(bl[ng], smBl + ad);
            }
#pragma unroll
            for (int mt = 0; mt < 4; mt++) {
                uint32_t ah[4], al[4];
                int rr = wm * 64 + mt * 16 + (lane & 15);
                uint32_t ad = rr * GROW + (chb + (lane >> 4)) * 16;
                ldm4(ah, smAh + ad);
                ldm4(al, smAl + ad);
#pragma unroll
                for (int n8 = 0; n8 < 4; n8++) {
                    int ng = n8 >> 1, hf = n8 & 1;
                    // x4 regs: r0=(n0-7,k0-7) r1=(n8-15,k0-7) r2=(n0-7,k8-15) r3=(n8-15,k8-15)
                    uint32_t b0 = bh[ng][hf], b1 = bh[ng][hf + 2];
                    mma16816(acc[mt][n8], ah, b0, b1);
                    mma16816(acc[mt][n8], al, b0, b1);
                    mma16816(acc[mt][n8], ah, bl[ng][hf], bl[ng][hf + 2]);
                }
            }
        }
        __syncthreads();
    }

    // epilogue
    const int g   = lane >> 2;
    const int tig = lane & 3;
#pragma unroll
    for (int mt = 0; mt < 4; mt++)
#pragma unroll
        for (int n8 = 0; n8 < 4; n8++) {
            int row = bm + wm * 64 + mt * 16 + g;
            int col = bn + wn * 32 + n8 * 8 + tig * 2;
            *(float2*)(C + (size_t)row * N + col) = make_float2(acc[mt][n8][0], acc[mt][n8][1]);
            *(float2*)(C + (size_t)(row + 8) * N + col) = make_float2(acc[mt][n8][2], acc[mt][n8][3]);
        }
}

// ---------------------------------------------------------------------------
// RoPE + bf16 hi/lo conversion (Q from g_Q; K,V from fused g_KV).
// hh 0..15: Q heads (rotate), 16..19: K heads (rotate), 20..23: V heads.
// ---------------------------------------------------------------------------
__global__ void rope_convert(const float* __restrict__ Q, const float* __restrict__ KV,
                             const float* __restrict__ sinp, const float* __restrict__ cosp,
                             __nv_bfloat16* __restrict__ Qh, __nv_bfloat16* __restrict__ Ql,
                             __nv_bfloat16* __restrict__ Kh, __nv_bfloat16* __restrict__ Kl,
                             __nv_bfloat16* __restrict__ Vh, __nv_bfloat16* __restrict__ Vl)
{
    const long long total = (long long)MTOT * 24 * 64;
    long long idx = (long long)blockIdx.x * blockDim.x + threadIdx.x;
    if (idx >= total) return;
    int pi = (int)(idx & 63);
    int hh = (int)((idx >> 6) % 24);
    int m  = (int)(idx / (64 * 24));
    int s  = m & (SEQ - 1);

    const float* p;
    __nv_bfloat16 *oh, *ol;
    bool rot = true;
    if (hh < 16) {
        p  = Q + (size_t)m * QW + hh * HD;
        oh = Qh + (size_t)m * QW + hh * HD;
        ol = Ql + (size_t)m * QW + hh * HD;
    } else if (hh < 20) {
        p  = KV + (size_t)m * KVW2 + (hh - 16) * HD;
        oh = Kh + (size_t)m * KVW + (hh - 16) * HD;
        ol = Kl + (size_t)m * KVW + (hh - 16) * HD;
    } else {
        p  = KV + (size_t)m * KVW2 + 512 + (hh - 20) * HD;
        oh = Vh + (size_t)m * KVW + (hh - 20) * HD;
        ol = Vl + (size_t)m * KVW + (hh - 20) * HD;
        rot = false;
    }

    float x0 = p[pi], x1 = p[pi + 64];
    if (rot) {
        float c  = cosp[(size_t)s * HD + pi];
        float sn = sinp[(size_t)s * HD + pi];
        float y0 = x0 * c - x1 * sn;
        float y1 = x1 * c + x0 * sn;
        x0 = y0; x1 = y1;
    }
    __nv_bfloat16 h0 = __float2bfloat16_rn(x0);
    __nv_bfloat16 h1 = __float2bfloat16_rn(x1);
    oh[pi]      = h0;
    oh[pi + 64] = h1;
    ol[pi]      = __float2bfloat16_rn(x0 - __bfloat162float(h0));
    ol[pi + 64] = __float2bfloat16_rn(x1 - __bfloat162float(h1));
}

// ---------------------------------------------------------------------------
// Flash attention on bf16 mma.sync (split precision QK and PV).
// 128 threads = 4 warps. BM=64, BN=64 keys/iter, D=128.
// Epilogue writes bf16 hi/lo (feeds pre-split O-proj GEMM).
// ---------------------------------------------------------------------------
#define AT_TILE 16384                       // 64 rows * 256 B
#define AT_SMEM (4 * AT_TILE)               // 65536 B

__device__ __forceinline__ uint32_t swz256(int r, int ch) {
    return (uint32_t)(r * 256 + (((ch ^ (r & 7)) & 15) << 4));
}

__global__ __launch_bounds__(128)
void flash_attn_mma(const __nv_bfloat16* __restrict__ Qh, const __nv_bfloat16* __restrict__ Ql,
                    const __nv_bfloat16* __restrict__ Kh, const __nv_bfloat16* __restrict__ Kl,
                    const __nv_bfloat16* __restrict__ Vh, const __nv_bfloat16* __restrict__ Vl,
                    __nv_bfloat16* __restrict__ OAh, __nv_bfloat16* __restrict__ OAl)
{
    extern __shared__ __align__(128) char smem[];
    const uint32_t sb    = smem_u32(smem);
    const uint32_t sQh   = sb;
    const uint32_t sQl   = sb + AT_TILE;
    const uint32_t sKVh  = sb + 2 * AT_TILE;
    const uint32_t sKVl  = sb + 3 * AT_TILE;

    const int qt  = blockIdx.x;
    const int h   = blockIdx.y;
    const int b   = blockIdx.z;
    const int kvh = h >> 2;
    const int t   = threadIdx.x;
    const int warp = t >> 5;
    const int lane = t & 31;
    const int g    = lane >> 2;
    const int tig  = lane & 3;
    const int q0   = qt * 64;

    // load persistent Q tiles (hi, lo)
    {
        const __nv_bfloat16* qbh = Qh + (size_t)(b * SEQ + q0) * QW + h * HD;
        const __nv_bfloat16* qbl = Ql + (size_t)(b * SEQ + q0) * QW + h * HD;
#pragma unroll
        for (int i = 0; i < 8; i++) {
            int f = i * 128 + t;
            int r = f >> 4, ch = f & 15;
            *(uint4*)(smem + (sQh - sb) + swz256(r, ch)) = *(const uint4*)(qbh + (size_t)r * QW + ch * 8);
            *(uint4*)(smem + (sQl - sb) + swz256(r, ch)) = *(const uint4*)(qbl + (size_t)r * QW + ch * 8);
        }
    }

    float o[16][4];
    float m0 = -1e30f, m1 = -1e30f, l0 = 0.f, l1 = 0.f;
#pragma unroll
    for (int i = 0; i < 16; i++)
#pragma unroll
        for (int j = 0; j < 4; j++) o[i][j] = 0.f;

    const int rl = warp * 16 + g;
    const int rh = rl + 8;

    for (int kt = 0; kt <= qt; kt++) {
        __syncthreads();

        // load K tile
        {
            const __nv_bfloat16* kbh = Kh + (size_t)(b * SEQ + kt * 64) * KVW + kvh * HD;
            const __nv_bfloat16* kbl = Kl + (size_t)(b * SEQ + kt * 64) * KVW + kvh * HD;
#pragma unroll
            for (int i = 0; i < 8; i++) {
                int f = i * 128 + t;
                int r = f >> 4, ch = f & 15;
                *(uint4*)(smem + (sKVh - sb) + swz256(r, ch)) = *(const uint4*)(kbh + (size_t)r * KVW + ch * 8);
                *(uint4*)(smem + (sKVl - sb) + swz256(r, ch)) = *(const uint4*)(kbl + (size_t)r * KVW + ch * 8);
            }
        }
        __syncthreads();

        // S = Q K^T  (split: QhKh + QlKh + QhKl)
        float sacc[8][4];
#pragma unroll
        for (int i = 0; i < 8; i++)
#pragma unroll
            for (int j = 0; j < 4; j++) sacc[i][j] = 0.f;

#pragma unroll
        for (int ks = 0; ks < 8; ks++) {
            uint32_t qfh[4], qfl[4];
            {
                int rr = warp * 16 + (lane & 15);
                uint32_t ad = swz256(rr, ks * 2 + (lane >> 4));
                ldm4(qfh, sQh + ad);
                ldm4(qfl, sQl + ad);
            }
#pragma unroll
            for (int ng = 0; ng < 4; ng++) {
                uint32_t kfh[4], kfl[4];
                int rr = ng * 16 + (lane & 15);
                uint32_t ad = swz256(rr, ks * 2 + (lane >> 4));
                ldm4(kfh, sKVh + ad);
                ldm4(kfl, sKVl + ad);
#pragma unroll
                for (int hf = 0; hf < 2; hf++) {
                    int n8 = ng * 2 + hf;
                    uint32_t b0 = kfh[hf], b1 = kfh[hf + 2];
                    mma16816(sacc[n8], qfh, b0, b1);
                    mma16816(sacc[n8], qfl, b0, b1);
                    mma16816(sacc[n8], qfh, kfl[hf], kfl[hf + 2]);
                }
            }
        }

        // causal mask (diagonal tile only)
        if (kt == qt) {
#pragma unroll
            for (int n8 = 0; n8 < 8; n8++) {
                int c0 = n8 * 8 + tig * 2, c1 = c0 + 1;
                if (c0 > rl) sacc[n8][0] = -1e30f;
                if (c1 > rl) sacc[n8][1] = -1e30f;
                if (c0 > rh) sacc[n8][2] = -1e30f;
                if (c1 > rh) sacc[n8][3] = -1e30f;
            }
        }

        // online softmax
        float mx0 = -1e30f, mx1 = -1e30f;
#pragma unroll
        for (int n8 = 0; n8 < 8; n8++) {
            mx0 = fmaxf(mx0, fmaxf(sacc[n8][0], sacc[n8][1]));
            mx1 = fmaxf(mx1, fmaxf(sacc[n8][2], sacc[n8][3]));
        }
        mx0 = fmaxf(mx0, __shfl_xor_sync(0xffffffffu, mx0, 1));
        mx0 = fmaxf(mx0, __shfl_xor_sync(0xffffffffu, mx0, 2));
        mx1 = fmaxf(mx1, __shfl_xor_sync(0xffffffffu, mx1, 1));
        mx1 = fmaxf(mx1, __shfl_xor_sync(0xffffffffu, mx1, 2));

        float mn0 = fmaxf(m0, mx0), mn1 = fmaxf(m1, mx1);
        float al0 = __expf(m0 - mn0), al1 = __expf(m1 - mn1);
        m0 = mn0; m1 = mn1;

        float s0 = 0.f, s1 = 0.f;
#pragma unroll
        for (int n8 = 0; n8 < 8; n8++) {
            float p0 = __expf(sacc[n8][0] - m0);
            float p1 = __expf(sacc[n8][1] - m0);
            float p2 = __expf(sacc[n8][2] - m1);
            float p3 = __expf(sacc[n8][3] - m1);
            sacc[n8][0] = p0; sacc[n8][1] = p1; sacc[n8][2] = p2; sacc[n8][3] = p3;
            s0 += p0 + p1; s1 += p2 + p3;
        }
        s0 += __shfl_xor_sync(0xffffffffu, s0, 1);
        s0 += __shfl_xor_sync(0xffffffffu, s0, 2);
        s1 += __shfl_xor_sync(0xffffffffu, s1, 1);
        s1 += __shfl_xor_sync(0xffffffffu, s1, 2);
        l0 = l0 * al0 + s0;
        l1 = l1 * al1 + s1;

        // rescale O
#pragma unroll
        for (int i = 0; i < 16; i++) {
            o[i][0] *= al0; o[i][1] *= al0;
            o[i][2] *= al1; o[i][3] *= al1;
        }

        // P -> bf16 A-fragments (hi/lo), registers only
        uint32_t ph[4][4], pl[4][4];
#pragma unroll
        for (int kk = 0; kk < 4; kk++) {
            split2(sacc[2 * kk][0],     sacc[2 * kk][1],     ph[kk][0], pl[kk][0]);
            split2(sacc[2 * kk][2],     sacc[2 * kk][3],     ph[kk][1], pl[kk][1]);
            split2(sacc[2 * kk + 1][0], sacc[2 * kk + 1][1], ph[kk][2], pl[kk][2]);
            split2(sacc[2 * kk + 1][2], sacc[2 * kk + 1][3], ph[kk][3], pl[kk][3]);
        }

        __syncthreads();

        // load V tile into same buffers
        {
            const __nv_bfloat16* vbh = Vh + (size_t)(b * SEQ + kt * 64) * KVW + kvh * HD;
            const __nv_bfloat16* vbl = Vl + (size_t)(b * SEQ + kt * 64) * KVW + kvh * HD;
#pragma unroll
            for (int i = 0; i < 8; i++) {
                int f = i * 128 + t;
                int r = f >> 4, ch = f & 15;
                *(uint4*)(smem + (sKVh - sb) + swz256(r, ch)) = *(const uint4*)(vbh + (size_t)r * KVW + ch * 8);
                *(uint4*)(smem + (sKVl - sb) + swz256(r, ch)) = *(const uint4*)(vbl + (size_t)r * KVW + ch * 8);
            }
        }
        __syncthreads();

        // O += P V   (split: PhVh + PlVh + PhVl)
#pragma unroll
        for (int ng = 0; ng < 8; ng++) {
#pragma unroll
            for (int kk = 0; kk < 4; kk++) {
                uint32_t vfh[4], vfl[4];
                int rr = kk * 16 + (lane & 15);
                uint32_t ad = swz256(rr, ng * 2 + (lane >> 4));
                ldm4t(vfh, sKVh + ad);
                ldm4t(vfl, sKVl + ad);
#pragma unroll
                for (int hf = 0; hf < 2; hf++) {
                    int nt = ng * 2 + hf;
                    uint32_t b0 = vfh[hf * 2], b1 = vfh[hf * 2 + 1];
                    mma16816(o[nt], ph[kk], b0, b1);
                    mma16816(o[nt], pl[kk], b0, b1);
                    mma16816(o[nt], ph[kk], vfl[hf * 2], vfl[hf * 2 + 1]);
                }
            }
        }
    }

    // epilogue: normalize and write bf16 hi/lo (pre-split for O-proj)
    float inv0 = 1.f / l0, inv1 = 1.f / l1;
    __nv_bfloat16* Obh = OAh + (size_t)(b * SEQ + q0) * QW + h * HD;
    __nv_bfloat16* Obl = OAl + (size_t)(b * SEQ + q0) * QW + h * HD;
#pragma unroll
    for (int nt = 0; nt < 16; nt++) {
        int col = nt * 8 + tig * 2;
        uint32_t h0, l0r, h1, l1r;
        split2(o[nt][0] * inv0, o[nt][1] * inv0, h0, l0r);
        split2(o[nt][2] * inv1, o[nt][3] * inv1, h1, l1r);
        *(uint32_t*)(Obh + (size_t)rl * QW + col) = h0;
        *(uint32_t*)(Obl + (size_t)rl * QW + col) = l0r;
        *(uint32_t*)(Obh + (size_t)rh * QW + col) = h1;
        *(uint32_t*)(Obl + (size_t)rh * QW + col) = l1r;
    }
}

// ---------------------------------------------------------------------------
// Launcher
// Inputs: 0 hidden_states [2,2048,2048] f32, 1 attention_mask (unused),
//         2 q_w [2048,2048], 3 k_w [512,2048], 4 v_w [512,2048],
//         5 o_w [2048,2048], 6 sin [4096,128], 7 cos [4096,128]
// ---------------------------------------------------------------------------
extern "C" void kernel_launch(void* const* d_in, const int* in_sizes, int n_in,
                              void* d_out, int out_size)
{
    const float* x    = (const float*)d_in[0];
    const float* q_w  = (const float*)d_in[2];
    const float* k_w  = (const float*)d_in[3];
    const float* v_w  = (const float*)d_in[4];
    const float* o_w  = (const float*)d_in[5];
    const float* sinp = (const float*)d_in[6];
    const float* cosp = (const float*)d_in[7];
    float* out = (float*)d_out;

    float *Q, *KV;
    cudaGetSymbolAddress((void**)&Q, g_Q);
    cudaGetSymbolAddress((void**)&KV, g_KV);
    __nv_bfloat16 *xh, *xl, *qwh, *qwl, *kvwh, *kvwl, *owh, *owl;
    cudaGetSymbolAddress((void**)&xh, g_xh);
    cudaGetSymbolAddress((void**)&xl, g_xl);
    cudaGetSymbolAddress((void**)&qwh, g_qwh);
    cudaGetSymbolAddress((void**)&qwl, g_qwl);
    cudaGetSymbolAddress((void**)&kvwh, g_kvwh);
    cudaGetSymbolAddress((void**)&kvwl, g_kvwl);
    cudaGetSymbolAddress((void**)&owh, g_owh);
    cudaGetSymbolAddress((void**)&owl, g_owl);
    __nv_bfloat16 *Qh, *Ql, *Kh, *Kl, *Vh, *Vl, *Ah, *Al;
    cudaGetSymbolAddress((void**)&Qh, g_Qh);
    cudaGetSymbolAddress((void**)&Ql, g_Ql);
    cudaGetSymbolAddress((void**)&Kh, g_Kh);
    cudaGetSymbolAddress((void**)&Kl, g_Kl);
    cudaGetSymbolAddress((void**)&Vh, g_Vh);
    cudaGetSymbolAddress((void**)&Vl, g_Vl);
    cudaGetSymbolAddress((void**)&Ah, g_Ah);
    cudaGetSymbolAddress((void**)&Al, g_Al);

    // pre-split all GEMM operands (fp32 -> bf16 hi/lo)
    {
        const int T = 256;
        int n4;
        n4 = MTOT * HID / 4;  split_f32<<<(n4 + T - 1) / T, T>>>(x,   xh,   xl,   n4);
        n4 = QW * HID / 4;    split_f32<<<(n4 + T - 1) / T, T>>>(q_w, qwh,  qwl,  n4);
        n4 = KVW * HID / 4;   split_f32<<<(n4 + T - 1) / T, T>>>(k_w, kvwh, kvwl, n4);
        n4 = KVW * HID / 4;   split_f32<<<(n4 + T - 1) / T, T>>>(v_w, kvwh + (size_t)KVW * HID,
                                                                  kvwl + (size_t)KVW * HID, n4);
        n4 = HID * QW / 4;    split_f32<<<(n4 + T - 1) / T, T>>>(o_w, owh,  owl,  n4);
    }

    cudaFuncSetAttribute(hmma_gemm_pre, cudaFuncAttributeMaxDynamicSharedMemorySize, GEMM_SMEM);

    // Q and fused KV projections
    hmma_gemm_pre<<<dim3(QW / 128,   MTOT / 128), 256, GEMM_SMEM>>>(xh, xl, qwh,  qwl,  Q,  MTOT, QW,   HID);
    hmma_gemm_pre<<<dim3(KVW2 / 128, MTOT / 128), 256, GEMM_SMEM>>>(xh, xl, kvwh, kvwl, KV, MTOT, KVW2, HID);

    // RoPE + bf16 split conversion
    {
        long long total = (long long)MTOT * 24 * 64;
        int threads = 256;
        int blocks = (int)((total + threads - 1) / threads);
        rope_convert<<<blocks, threads>>>(Q, KV, sinp, cosp, Qh, Ql, Kh, Kl, Vh, Vl);
    }

    // Flash attention (tensor cores), emits pre-split bf16 A
    {
        cudaFuncSetAttribute(flash_attn_mma, cudaFuncAttributeMaxDynamicSharedMemorySize, AT_SMEM);
        flash_attn_mma<<<dim3(SEQ / 64, NH, 2), 128, AT_SMEM>>>(Qh, Ql, Kh, Kl, Vh, Vl, Ah, Al);
    }

    // Output projection
    hmma_gemm_pre<<<dim3(HID / 128, MTOT / 128), 256, GEMM_SMEM>>>(Ah, Al, owh, owl, out, MTOT, HID, HID);
}

// round 7
// speedup vs baseline: 2.7311x; 1.0449x over previous
#include <cuda_runtime.h>
#include <cuda_bf16.h>
#include <math.h>
#include <stdint.h>

// Problem constants
#define MTOT 4096      // B*S
#define SEQ  2048
#define HID  2048
#define NH   16
#define NKV  4
#define HD   128
#define QW   2048      // NH*HD
#define KVW  512       // NKV*HD
#define KVW2 1024      // fused K+V width

// Scratch (allocation-free rule: __device__ globals)
__device__ __nv_bfloat16 g_xh[(size_t)MTOT * HID];
__device__ __nv_bfloat16 g_xl[(size_t)MTOT * HID];
__device__ __nv_bfloat16 g_qwh[(size_t)QW * HID];
__device__ __nv_bfloat16 g_qwl[(size_t)QW * HID];
__device__ __nv_bfloat16 g_kvwh[(size_t)KVW2 * HID];
__device__ __nv_bfloat16 g_kvwl[(size_t)KVW2 * HID];
__device__ __nv_bfloat16 g_owh[(size_t)HID * QW];
__device__ __nv_bfloat16 g_owl[(size_t)HID * QW];
__device__ __nv_bfloat16 g_Qh[(size_t)MTOT * QW];
__device__ __nv_bfloat16 g_Ql[(size_t)MTOT * QW];
__device__ __nv_bfloat16 g_Kh[(size_t)MTOT * KVW];
__device__ __nv_bfloat16 g_Kl[(size_t)MTOT * KVW];
__device__ __nv_bfloat16 g_Vh[(size_t)MTOT * KVW];
__device__ __nv_bfloat16 g_Vl[(size_t)MTOT * KVW];
__device__ __nv_bfloat16 g_Ah[(size_t)MTOT * QW];
__device__ __nv_bfloat16 g_Al[(size_t)MTOT * QW];

// ---------------------------------------------------------------------------
// helpers
// ---------------------------------------------------------------------------
__device__ __forceinline__ void mma16816(float* c, const uint32_t* a, uint32_t b0, uint32_t b1) {
    asm volatile(
        "mma.sync.aligned.m16n8k16.row.col.f32.bf16.bf16.f32 "
        "{%0,%1,%2,%3}, {%4,%5,%6,%7}, {%8,%9}, {%0,%1,%2,%3};"
        : "+f"(c[0]), "+f"(c[1]), "+f"(c[2]), "+f"(c[3])
        : "r"(a[0]), "r"(a[1]), "r"(a[2]), "r"(a[3]), "r"(b0), "r"(b1));
}
__device__ __forceinline__ void ldm4(uint32_t* r, uint32_t a) {
    asm volatile("ldmatrix.sync.aligned.m8n8.x4.shared.b16 {%0,%1,%2,%3}, [%4];"
                 : "=r"(r[0]), "=r"(r[1]), "=r"(r[2]), "=r"(r[3]) : "r"(a));
}
__device__ __forceinline__ void ldm4t(uint32_t* r, uint32_t a) {
    asm volatile("ldmatrix.sync.aligned.m8n8.x4.trans.shared.b16 {%0,%1,%2,%3}, [%4];"
                 : "=r"(r[0]), "=r"(r[1]), "=r"(r[2]), "=r"(r[3]) : "r"(a));
}
__device__ __forceinline__ uint32_t smem_u32(const void* p) {
    uint32_t a;
    asm("{ .reg .u64 tmp; cvta.to.shared.u64 tmp, %1; cvt.u32.u64 %0, tmp; }"
        : "=r"(a) : "l"(p));
    return a;
}
__device__ __forceinline__ void cpa16(uint32_t dst, const void* src) {
    asm volatile("cp.async.cg.shared.global [%0], [%1], 16;" :: "r"(dst), "l"(src));
}
#define CPA_COMMIT() asm volatile("cp.async.commit_group;" ::: "memory")
#define CPA_WAIT(n)  asm volatile("cp.async.wait_group %0;" :: "n"(n) : "memory")

__device__ __forceinline__ void split2(float a, float b, uint32_t& h, uint32_t& l) {
    __nv_bfloat162 hh = __floats2bfloat162_rn(a, b);
    float ra = a - __bfloat162float(hh.x);
    float rb = b - __bfloat162float(hh.y);
    __nv_bfloat162 ll = __floats2bfloat162_rn(ra, rb);
    h = *(uint32_t*)&hh;
    l = *(uint32_t*)&ll;
}

// ---------------------------------------------------------------------------
// One fused split kernel for x, q_w, k_w, v_w, o_w (fp32 -> bf16 hi/lo)
// ---------------------------------------------------------------------------
#define N4_X   (MTOT * HID / 4)       // 2097152
#define N4_QW  (QW * HID / 4)         // 1048576
#define N4_KW  (KVW * HID / 4)        //  262144
#define N4_ALL (N4_X + N4_QW + 2 * N4_KW + N4_QW)

__global__ void split_all(const float* __restrict__ x, const float* __restrict__ qw,
                          const float* __restrict__ kw, const float* __restrict__ vw,
                          const float* __restrict__ ow,
                          __nv_bfloat16* __restrict__ xh, __nv_bfloat16* __restrict__ xl,
                          __nv_bfloat16* __restrict__ qwh, __nv_bfloat16* __restrict__ qwl,
                          __nv_bfloat16* __restrict__ kvwh, __nv_bfloat16* __restrict__ kvwl,
                          __nv_bfloat16* __restrict__ owh, __nv_bfloat16* __restrict__ owl)
{
    int i = blockIdx.x * blockDim.x + threadIdx.x;
    if (i >= N4_ALL) return;
    const float* src;
    __nv_bfloat16 *dh, *dl;
    int j = i;
    if (j < N4_X)                    { src = x;  dh = xh;  dl = xl; }
    else if ((j -= N4_X) < N4_QW)    { src = qw; dh = qwh; dl = qwl; }
    else if ((j -= N4_QW) < N4_KW)   { src = kw; dh = kvwh; dl = kvwl; }
    else if ((j -= N4_KW) < N4_KW)   { src = vw; dh = kvwh + (size_t)KVW * HID; dl = kvwl + (size_t)KVW * HID; }
    else                             { j -= N4_KW; src = ow; dh = owh; dl = owl; }
    float4 v = ((const float4*)src)[j];
    uint32_t h0, l0, h1, l1;
    split2(v.x, v.y, h0, l0);
    split2(v.z, v.w, h1, l1);
    ((uint2*)dh)[j] = make_uint2(h0, h1);
    ((uint2*)dl)[j] = make_uint2(l0, l1);
}

// ---------------------------------------------------------------------------
// NT GEMM on pre-split bf16 operands, 3-term split.
// MODE 0: write fp32 C.  MODE 1: Q epilogue (rope + split -> o1).
// MODE 2: KV epilogue (bx<4: rope K -> o1; bx>=4: V -> o2).
// ---------------------------------------------------------------------------
#define GROW  80
#define GT    (128 * GROW)            // 10240 B
#define STG_B (4 * GT)                // 40960 B
#define GEMM_SMEM (2 * STG_B)         // 81920 B

template<int MODE>
__global__ __launch_bounds__(256)
void hmma_gemm_pre(const __nv_bfloat16* __restrict__ Ah, const __nv_bfloat16* __restrict__ Al,
                   const __nv_bfloat16* __restrict__ Bh, const __nv_bfloat16* __restrict__ Bl,
                   float* __restrict__ C,
                   __nv_bfloat16* __restrict__ o1h, __nv_bfloat16* __restrict__ o1l,
                   __nv_bfloat16* __restrict__ o2h, __nv_bfloat16* __restrict__ o2l,
                   const float* __restrict__ sinp, const float* __restrict__ cosp,
                   int M, int N, int K)
{
    extern __shared__ __align__(128) char smem[];
    const uint32_t sb = smem_u32(smem);

    const int t    = threadIdx.x;
    const int warp = t >> 5;
    const int lane = t & 31;
    const int wm   = warp >> 2;
    const int wn   = warp & 3;
    const int bm   = blockIdx.y * 128;
    const int bn   = blockIdx.x * 128;

    const int r0c = t >> 2, ch0 = t & 3;
    const int r1c = r0c + 64;
    const __nv_bfloat16* srcA[2] = { Ah, Al };
    const __nv_bfloat16* srcB[2] = { Bh, Bl };

    float acc[4][4][4];
#pragma unroll
    for (int mi = 0; mi < 4; mi++)
#pragma unroll
        for (int ni = 0; ni < 4; ni++)
#pragma unroll
            for (int r = 0; r < 4; r++) acc[mi][ni][r] = 0.f;

    const int S = K / 32;

    auto issue = [&](int s, int buf) {
        const int k0 = s * 32;
        const uint32_t stg = sb + (uint32_t)buf * STG_B;
#pragma unroll
        for (int hl = 0; hl < 2; hl++) {
            uint32_t dA = stg + hl * GT;
            cpa16(dA + r0c * GROW + ch0 * 16, srcA[hl] + (size_t)(bm + r0c) * K + k0 + ch0 * 8);
            cpa16(dA + r1c * GROW + ch0 * 16, srcA[hl] + (size_t)(bm + r1c) * K + k0 + ch0 * 8);
            uint32_t dB = stg + (2 + hl) * GT;
            cpa16(dB + r0c * GROW + ch0 * 16, srcB[hl] + (size_t)(bn + r0c) * K + k0 + ch0 * 8);
            cpa16(dB + r1c * GROW + ch0 * 16, srcB[hl] + (size_t)(bn + r1c) * K + k0 + ch0 * 8);
        }
        CPA_COMMIT();
    };

    issue(0, 0);

    for (int s = 0; s < S; s++) {
        const int buf = s & 1;
        if (s + 1 < S) { issue(s + 1, buf ^ 1); CPA_WAIT(1); }
        else           { CPA_WAIT(0); }
        __syncthreads();

        const uint32_t smAh = sb + (uint32_t)buf * STG_B;
        const uint32_t smAl = smAh + GT;
        const uint32_t smBh = smAh + 2 * GT;
        const uint32_t smBl = smAh + 3 * GT;

#pragma unroll
        for (int kk = 0; kk < 2; kk++) {
            const int chb = kk * 2;
            uint32_t bh[2][4], bl[2][4];
#pragma unroll
            for (int ng = 0; ng < 2; ng++) {
                int rr = wn * 32 + ng * 16 + (lane & 15);
                uint32_t ad = rr * GROW + (chb + (lane >> 4)) * 16;
                ldm4(bh[ng], smBh + ad);
                ldm4(bl[ng], smBl + ad);
            }
#pragma unroll
            for (int mt = 0; mt < 4; mt++) {
                uint32_t ah[4], al[4];
                int rr = wm * 64 + mt * 16 + (lane & 15);
                uint32_t ad = rr * GROW + (chb + (lane >> 4)) * 16;
                ldm4(ah, smAh + ad);
                ldm4(al, smAl + ad);
#pragma unroll
                for (int n8 = 0; n8 < 4; n8++) {
                    int ng = n8 >> 1, hf = n8 & 1;
                    uint32_t b0 = bh[ng][hf], b1 = bh[ng][hf + 2];
                    mma16816(acc[mt][n8], ah, b0, b1);
                    mma16816(acc[mt][n8], al, b0, b1);
                    mma16816(acc[mt][n8], ah, bl[ng][hf], bl[ng][hf + 2]);
                }
            }
        }
        __syncthreads();
    }

    const int g   = lane >> 2;
    const int tig = lane & 3;

    if (MODE == 0) {
#pragma unroll
        for (int mt = 0; mt < 4; mt++)
#pragma unroll
            for (int n8 = 0; n8 < 4; n8++) {
                int row = bm + wm * 64 + mt * 16 + g;
                int col = bn + wn * 32 + n8 * 8 + tig * 2;
                *(float2*)(C + (size_t)row * N + col) = make_float2(acc[mt][n8][0], acc[mt][n8][1]);
                *(float2*)(C + (size_t)(row + 8) * N + col) = make_float2(acc[mt][n8][2], acc[mt][n8][3]);
            }
        return;
    }

    // MODE 1/2: stage acc -> smem, rope(optional) + bf16 split -> global
    float* stg = (float*)smem;   // [128][132]
#pragma unroll
    for (int mt = 0; mt < 4; mt++)
#pragma unroll
        for (int n8 = 0; n8 < 4; n8++) {
            int row = wm * 64 + mt * 16 + g;
            int col = wn * 32 + n8 * 8 + tig * 2;
            stg[row * 132 + col]     = acc[mt][n8][0];
            stg[row * 132 + col + 1] = acc[mt][n8][1];
            stg[(row + 8) * 132 + col]     = acc[mt][n8][2];
            stg[(row + 8) * 132 + col + 1] = acc[mt][n8][3];
        }
    __syncthreads();

    {
        const int r    = t >> 1;
        const int half = t & 1;
        const int gm   = bm + r;
        const int spos = gm & (SEQ - 1);
        const int pb   = half * 32;

        bool rot;
        __nv_bfloat16 *dh, *dl;
        if (MODE == 1) {
            rot = true;
            dh = o1h + (size_t)gm * QW + blockIdx.x * 128;
            dl = o1l + (size_t)gm * QW + blockIdx.x * 128;
        } else {
            int bx = blockIdx.x;
            if (bx < 4) {
                rot = true;
                dh = o1h + (size_t)gm * KVW + bx * 128;
                dl = o1l + (size_t)gm * KVW + bx * 128;
            } else {
                rot = false;
                dh = o2h + (size_t)gm * KVW + (bx - 4) * 128;
                dl = o2l + (size_t)gm * KVW + (bx - 4) * 128;
            }
        }

        uint32_t h0[16], l0[16], h1[16], l1[16];
#pragma unroll
        for (int j = 0; j < 16; j++) {
            int pi = pb + j * 2;
            float x0a = stg[r * 132 + pi],      x0b = stg[r * 132 + pi + 1];
            float x1a = stg[r * 132 + pi + 64], x1b = stg[r * 132 + pi + 65];
            float y0a, y0b, y1a, y1b;
            if (rot) {
                float ca = cosp[(size_t)spos * HD + pi],     cb = cosp[(size_t)spos * HD + pi + 1];
                float sa = sinp[(size_t)spos * HD + pi],     sbv = sinp[(size_t)spos * HD + pi + 1];
                y0a = x0a * ca - x1a * sa;  y1a = x1a * ca + x0a * sa;
                y0b = x0b * cb - x1b * sbv; y1b = x1b * cb + x0b * sbv;
            } else {
                y0a = x0a; y0b = x0b; y1a = x1a; y1b = x1b;
            }
            split2(y0a, y0b, h0[j], l0[j]);
            split2(y1a, y1b, h1[j], l1[j]);
        }
#pragma unroll
        for (int w = 0; w < 4; w++) {
            *(uint4*)(dh + pb + w * 8)      = ((uint4*)h0)[w];
            *(uint4*)(dh + 64 + pb + w * 8) = ((uint4*)h1)[w];
            *(uint4*)(dl + pb + w * 8)      = ((uint4*)l0)[w];
            *(uint4*)(dl + 64 + pb + w * 8) = ((uint4*)l1)[w];
        }
    }
}

// ---------------------------------------------------------------------------
// Flash attention, bf16 mma.sync, cp.async K/V pipeline, causal pair-balanced.
// 128 threads = 4 warps. BM=64, BN=64, D=128.
// smem: Qh,Ql + stage A{h,l} + stage B{h,l} = 6 x 16KB = 96KB.
// ---------------------------------------------------------------------------
#define AT_TILE 16384
#define AT_SMEM (6 * AT_TILE)               // 98304 B
#define NQT     (SEQ / 64)                  // 32

__device__ __forceinline__ uint32_t swz256(int r, int ch) {
    return (uint32_t)(r * 256 + (((ch ^ (r & 7)) & 15) << 4));
}

__global__ __launch_bounds__(128)
void flash_attn_mma(const __nv_bfloat16* __restrict__ Qh, const __nv_bfloat16* __restrict__ Ql,
                    const __nv_bfloat16* __restrict__ Kh, const __nv_bfloat16* __restrict__ Kl,
                    const __nv_bfloat16* __restrict__ Vh, const __nv_bfloat16* __restrict__ Vl,
                    __nv_bfloat16* __restrict__ OAh, __nv_bfloat16* __restrict__ OAl)
{
    extern __shared__ __align__(128) char smem[];
    const uint32_t sb  = smem_u32(smem);
    const uint32_t sQh = sb;
    const uint32_t sQl = sb + AT_TILE;
    const uint32_t sA  = sb + 2 * AT_TILE;   // K stage: {h, l}
    const uint32_t sB  = sb + 4 * AT_TILE;   // V stage: {h, l}

    const int h   = blockIdx.y;
    const int b   = blockIdx.z;
    const int kvh = h >> 2;
    const int t   = threadIdx.x;
    const int warp = t >> 5;
    const int lane = t & 31;
    const int g    = lane >> 2;
    const int tig  = lane & 3;

    const int rl = warp * 16 + g;
    const int rh = rl + 8;

    // cp.async tile loaders (64 rows x 128 cols bf16, hi+lo)
    auto load_kv = [&](const __nv_bfloat16* srch, const __nv_bfloat16* srcl,
                       uint32_t dst, int kt) {
        const __nv_bfloat16* bh = srch + (size_t)(b * SEQ + kt * 64) * KVW + kvh * HD;
        const __nv_bfloat16* bl = srcl + (size_t)(b * SEQ + kt * 64) * KVW + kvh * HD;
#pragma unroll
        for (int i = 0; i < 8; i++) {
            int f = i * 128 + t;
            int r = f >> 4, ch = f & 15;
            cpa16(dst + swz256(r, ch),           bh + (size_t)r * KVW + ch * 8);
            cpa16(dst + AT_TILE + swz256(r, ch), bl + (size_t)r * KVW + ch * 8);
        }
        CPA_COMMIT();
    };

    for (int sel = 0; sel < 2; sel++) {
        const int qt = sel ? (NQT - 1 - blockIdx.x) : blockIdx.x;
        const int q0 = qt * 64;

        // Q tiles (cp.async)
        {
            const __nv_bfloat16* qbh = Qh + (size_t)(b * SEQ + q0) * QW + h * HD;
            const __nv_bfloat16* qbl = Ql + (size_t)(b * SEQ + q0) * QW + h * HD;
#pragma unroll
            for (int i = 0; i < 8; i++) {
                int f = i * 128 + t;
                int r = f >> 4, ch = f & 15;
                cpa16(sQh + swz256(r, ch), qbh + (size_t)r * QW + ch * 8);
                cpa16(sQl + swz256(r, ch), qbl + (size_t)r * QW + ch * 8);
            }
            CPA_COMMIT();
        }
        load_kv(Kh, Kl, sA, 0);
        CPA_WAIT(0);
        __syncthreads();

        float o[16][4];
        float m0 = -1e30f, m1 = -1e30f, l0 = 0.f, l1 = 0.f;
#pragma unroll
        for (int i = 0; i < 16; i++)
#pragma unroll
            for (int j = 0; j < 4; j++) o[i][j] = 0.f;

        for (int kt = 0; kt <= qt; kt++) {
            // prefetch V(kt) into B while computing QK from A
            load_kv(Vh, Vl, sB, kt);

            // S = Q K^T  (QhKh + QlKh + QhKl)
            float sacc[8][4];
#pragma unroll
            for (int i = 0; i < 8; i++)
#pragma unroll
                for (int j = 0; j < 4; j++) sacc[i][j] = 0.f;

#pragma unroll
            for (int ks = 0; ks < 8; ks++) {
                uint32_t qfh[4], qfl[4];
                {
                    int rr = warp * 16 + (lane & 15);
                    uint32_t ad = swz256(rr, ks * 2 + (lane >> 4));
                    ldm4(qfh, sQh + ad);
                    ldm4(qfl, sQl + ad);
                }
#pragma unroll
                for (int ng = 0; ng < 4; ng++) {
                    uint32_t kfh[4], kfl[4];
                    int rr = ng * 16 + (lane & 15);
                    uint32_t ad = swz256(rr, ks * 2 + (lane >> 4));
                    ldm4(kfh, sA + ad);
                    ldm4(kfl, sA + AT_TILE + ad);
#pragma unroll
                    for (int hf = 0; hf < 2; hf++) {
                        int n8 = ng * 2 + hf;
                        uint32_t b0 = kfh[hf], b1 = kfh[hf + 2];
                        mma16816(sacc[n8], qfh, b0, b1);
                        mma16816(sacc[n8], qfl, b0, b1);
                        mma16816(sacc[n8], qfh, kfl[hf], kfl[hf + 2]);
                    }
                }
            }

            if (kt == qt) {
#pragma unroll
                for (int n8 = 0; n8 < 8; n8++) {
                    int c0 = n8 * 8 + tig * 2, c1 = c0 + 1;
                    if (c0 > rl) sacc[n8][0] = -1e30f;
                    if (c1 > rl) sacc[n8][1] = -1e30f;
                    if (c0 > rh) sacc[n8][2] = -1e30f;
                    if (c1 > rh) sacc[n8][3] = -1e30f;
                }
            }

            // online softmax
            float mx0 = -1e30f, mx1 = -1e30f;
#pragma unroll
            for (int n8 = 0; n8 < 8; n8++) {
                mx0 = fmaxf(mx0, fmaxf(sacc[n8][0], sacc[n8][1]));
                mx1 = fmaxf(mx1, fmaxf(sacc[n8][2], sacc[n8][3]));
            }
            mx0 = fmaxf(mx0, __shfl_xor_sync(0xffffffffu, mx0, 1));
            mx0 = fmaxf(mx0, __shfl_xor_sync(0xffffffffu, mx0, 2));
            mx1 = fmaxf(mx1, __shfl_xor_sync(0xffffffffu, mx1, 1));
            mx1 = fmaxf(mx1, __shfl_xor_sync(0xffffffffu, mx1, 2));

            float mn0 = fmaxf(m0, mx0), mn1 = fmaxf(m1, mx1);
            float al0 = __expf(m0 - mn0), al1 = __expf(m1 - mn1);
            m0 = mn0; m1 = mn1;

            float s0 = 0.f, s1 = 0.f;
#pragma unroll
            for (int n8 = 0; n8 < 8; n8++) {
                float p0 = __expf(sacc[n8][0] - m0);
                float p1 = __expf(sacc[n8][1] - m0);
                float p2 = __expf(sacc[n8][2] - m1);
                float p3 = __expf(sacc[n8][3] - m1);
                sacc[n8][0] = p0; sacc[n8][1] = p1; sacc[n8][2] = p2; sacc[n8][3] = p3;
                s0 += p0 + p1; s1 += p2 + p3;
            }
            s0 += __shfl_xor_sync(0xffffffffu, s0, 1);
            s0 += __shfl_xor_sync(0xffffffffu, s0, 2);
            s1 += __shfl_xor_sync(0xffffffffu, s1, 1);
            s1 += __shfl_xor_sync(0xffffffffu, s1, 2);
            l0 = l0 * al0 + s0;
            l1 = l1 * al1 + s1;

#pragma unroll
            for (int i = 0; i < 16; i++) {
                o[i][0] *= al0; o[i][1] *= al0;
                o[i][2] *= al1; o[i][3] *= al1;
            }

            // P -> bf16 fragments (hi/lo)
            uint32_t ph[4][4], pl[4][4];
#pragma unroll
            for (int kk = 0; kk < 4; kk++) {
                split2(sacc[2 * kk][0],     sacc[2 * kk][1],     ph[kk][0], pl[kk][0]);
                split2(sacc[2 * kk][2],     sacc[2 * kk][3],     ph[kk][1], pl[kk][1]);
                split2(sacc[2 * kk + 1][0], sacc[2 * kk + 1][1], ph[kk][2], pl[kk][2]);
                split2(sacc[2 * kk + 1][2], sacc[2 * kk + 1][3], ph[kk][3], pl[kk][3]);
            }

            CPA_WAIT(0);        // V(kt) arrived
            __syncthreads();    // all warps done reading A (K)

            // prefetch K(kt+1) into A while computing PV from B
            if (kt < qt) load_kv(Kh, Kl, sA, kt + 1);

            // O += P V  (PhVh + PlVh + PhVl)
#pragma unroll
            for (int ng = 0; ng < 8; ng++) {
#pragma unroll
                for (int kk = 0; kk < 4; kk++) {
                    uint32_t vfh[4], vfl[4];
                    int rr = kk * 16 + (lane & 15);
                    uint32_t ad = swz256(rr, ng * 2 + (lane >> 4));
                    ldm4t(vfh, sB + ad);
                    ldm4t(vfl, sB + AT_TILE + ad);
#pragma unroll
                    for (int hf = 0; hf < 2; hf++) {
                        int nt = ng * 2 + hf;
                        uint32_t b0 = vfh[hf * 2], b1 = vfh[hf * 2 + 1];
                        mma16816(o[nt], ph[kk], b0, b1);
                        mma16816(o[nt], pl[kk], b0, b1);
                        mma16816(o[nt], ph[kk], vfl[hf * 2], vfl[hf * 2 + 1]);
                    }
                }
            }

            CPA_WAIT(0);        // K(kt+1) arrived
            __syncthreads();    // all warps done reading B (V)
        }

        // epilogue: normalize, write bf16 hi/lo
        float inv0 = 1.f / l0, inv1 = 1.f / l1;
        __nv_bfloat16* Obh = OAh + (size_t)(b * SEQ + q0) * QW + h * HD;
        __nv_bfloat16* Obl = OAl + (size_t)(b * SEQ + q0) * QW + h * HD;
#pragma unroll
        for (int nt = 0; nt < 16; nt++) {
            int col = nt * 8 + tig * 2;
            uint32_t hh0, ll0, hh1, ll1;
            split2(o[nt][0] * inv0, o[nt][1] * inv0, hh0, ll0);
            split2(o[nt][2] * inv1, o[nt][3] * inv1, hh1, ll1);
            *(uint32_t*)(Obh + (size_t)rl * QW + col) = hh0;
            *(uint32_t*)(Obl + (size_t)rl * QW + col) = ll0;
            *(uint32_t*)(Obh + (size_t)rh * QW + col) = hh1;
            *(uint32_t*)(Obl + (size_t)rh * QW + col) = ll1;
        }
    }
}

// ---------------------------------------------------------------------------
// Launcher
// ---------------------------------------------------------------------------
extern "C" void kernel_launch(void* const* d_in, const int* in_sizes, int n_in,
                              void* d_out, int out_size)
{
    const float* x    = (const float*)d_in[0];
    const float* q_w  = (const float*)d_in[2];
    const float* k_w  = (const float*)d_in[3];
    const float* v_w  = (const float*)d_in[4];
    const float* o_w  = (const float*)d_in[5];
    const float* sinp = (const float*)d_in[6];
    const float* cosp = (const float*)d_in[7];
    float* out = (float*)d_out;

    __nv_bfloat16 *xh, *xl, *qwh, *qwl, *kvwh, *kvwl, *owh, *owl;
    cudaGetSymbolAddress((void**)&xh, g_xh);
    cudaGetSymbolAddress((void**)&xl, g_xl);
    cudaGetSymbolAddress((void**)&qwh, g_qwh);
    cudaGetSymbolAddress((void**)&qwl, g_qwl);
    cudaGetSymbolAddress((void**)&kvwh, g_kvwh);
    cudaGetSymbolAddress((void**)&kvwl, g_kvwl);
    cudaGetSymbolAddress((void**)&owh, g_owh);
    cudaGetSymbolAddress((void**)&owl, g_owl);
    __nv_bfloat16 *Qh, *Ql, *Kh, *Kl, *Vh, *Vl, *Ah, *Al;
    cudaGetSymbolAddress((void**)&Qh, g_Qh);
    cudaGetSymbolAddress((void**)&Ql, g_Ql);
    cudaGetSymbolAddress((void**)&Kh, g_Kh);
    cudaGetSymbolAddress((void**)&Kl, g_Kl);
    cudaGetSymbolAddress((void**)&Vh, g_Vh);
    cudaGetSymbolAddress((void**)&Vl, g_Vl);
    cudaGetSymbolAddress((void**)&Ah, g_Ah);
    cudaGetSymbolAddress((void**)&Al, g_Al);

    // 1) fused split of all fp32 operands
    split_all<<<(N4_ALL + 255) / 256, 256>>>(x, q_w, k_w, v_w, o_w,
                                             xh, xl, qwh, qwl, kvwh, kvwl, owh, owl);

    cudaFuncSetAttribute(hmma_gemm_pre<0>, cudaFuncAttributeMaxDynamicSharedMemorySize, GEMM_SMEM);
    cudaFuncSetAttribute(hmma_gemm_pre<1>, cudaFuncAttributeMaxDynamicSharedMemorySize, GEMM_SMEM);
    cudaFuncSetAttribute(hmma_gemm_pre<2>, cudaFuncAttributeMaxDynamicSharedMemorySize, GEMM_SMEM);

    // 2) Q projection + fused RoPE/split
    hmma_gemm_pre<1><<<dim3(QW / 128, MTOT / 128), 256, GEMM_SMEM>>>(
        xh, xl, qwh, qwl, nullptr, Qh, Ql, nullptr, nullptr, sinp, cosp, MTOT, QW, HID);
    // 3) KV projection + fused RoPE(K)/split
    hmma_gemm_pre<2><<<dim3(KVW2 / 128, MTOT / 128), 256, GEMM_SMEM>>>(
        xh, xl, kvwh, kvwl, nullptr, Kh, Kl, Vh, Vl, sinp, cosp, MTOT, KVW2, HID);

    // 4) flash attention (captured by ncu)
    cudaFuncSetAttribute(flash_attn_mma, cudaFuncAttributeMaxDynamicSharedMemorySize, AT_SMEM);
    flash_attn_mma<<<dim3(NQT / 2, NH, 2), 128, AT_SMEM>>>(Qh, Ql, Kh, Kl, Vh, Vl, Ah, Al);

    // 5) output projection (fp32 out)
    hmma_gemm_pre<0><<<dim3(HID / 128, MTOT / 128), 256, GEMM_SMEM>>>(
        Ah, Al, owh, owl, out, nullptr, nullptr, nullptr, nullptr, nullptr, nullptr, MTOT, HID, HID);
}

// round 8
// speedup vs baseline: 2.7783x; 1.0173x over previous
#include <cuda_runtime.h>
#include <cuda_bf16.h>
#include <math.h>
#include <stdint.h>

// Problem constants
#define MTOT 4096      // B*S
#define SEQ  2048
#define HID  2048
#define NH   16
#define NKV  4
#define HD   128
#define QW   2048      // NH*HD
#define KVW  512       // NKV*HD
#define W3   3072      // fused Q|K|V weight width

// Scratch (allocation-free rule: __device__ globals)
__device__ __nv_bfloat16 g_xh[(size_t)MTOT * HID];
__device__ __nv_bfloat16 g_xl[(size_t)MTOT * HID];
__device__ __nv_bfloat16 g_wh[(size_t)W3 * HID];     // q|k|v weights fused
__device__ __nv_bfloat16 g_wl[(size_t)W3 * HID];
__device__ __nv_bfloat16 g_owh[(size_t)HID * QW];
__device__ __nv_bfloat16 g_owl[(size_t)HID * QW];
__device__ __nv_bfloat16 g_Qh[(size_t)MTOT * QW];
__device__ __nv_bfloat16 g_Ql[(size_t)MTOT * QW];
__device__ __nv_bfloat16 g_Kh[(size_t)MTOT * KVW];
__device__ __nv_bfloat16 g_Kl[(size_t)MTOT * KVW];
__device__ __nv_bfloat16 g_Vh[(size_t)MTOT * KVW];
__device__ __nv_bfloat16 g_Vl[(size_t)MTOT * KVW];
__device__ __nv_bfloat16 g_Ah[(size_t)MTOT * QW];
__device__ __nv_bfloat16 g_Al[(size_t)MTOT * QW];

// ---------------------------------------------------------------------------
// helpers
// ---------------------------------------------------------------------------
__device__ __forceinline__ void mma16816(float* c, const uint32_t* a, uint32_t b0, uint32_t b1) {
    asm volatile(
        "mma.sync.aligned.m16n8k16.row.col.f32.bf16.bf16.f32 "
        "{%0,%1,%2,%3}, {%4,%5,%6,%7}, {%8,%9}, {%0,%1,%2,%3};"
        : "+f"(c[0]), "+f"(c[1]), "+f"(c[2]), "+f"(c[3])
        : "r"(a[0]), "r"(a[1]), "r"(a[2]), "r"(a[3]), "r"(b0), "r"(b1));
}
__device__ __forceinline__ void ldm4(uint32_t* r, uint32_t a) {
    asm volatile("ldmatrix.sync.aligned.m8n8.x4.shared.b16 {%0,%1,%2,%3}, [%4];"
                 : "=r"(r[0]), "=r"(r[1]), "=r"(r[2]), "=r"(r[3]) : "r"(a));
}
__device__ __forceinline__ void ldm4t(uint32_t* r, uint32_t a) {
    asm volatile("ldmatrix.sync.aligned.m8n8.x4.trans.shared.b16 {%0,%1,%2,%3}, [%4];"
                 : "=r"(r[0]), "=r"(r[1]), "=r"(r[2]), "=r"(r[3]) : "r"(a));
}
__device__ __forceinline__ uint32_t smem_u32(const void* p) {
    uint32_t a;
    asm("{ .reg .u64 tmp; cvta.to.shared.u64 tmp, %1; cvt.u32.u64 %0, tmp; }"
        : "=r"(a) : "l"(p));
    return a;
}
__device__ __forceinline__ void cpa16(uint32_t dst, const void* src) {
    asm volatile("cp.async.cg.shared.global [%0], [%1], 16;" :: "r"(dst), "l"(src));
}
#define CPA_COMMIT() asm volatile("cp.async.commit_group;" ::: "memory")
#define CPA_WAIT(n)  asm volatile("cp.async.wait_group %0;" :: "n"(n) : "memory")

__device__ __forceinline__ void split2(float a, float b, uint32_t& h, uint32_t& l) {
    __nv_bfloat162 hh = __floats2bfloat162_rn(a, b);
    float ra = a - __bfloat162float(hh.x);
    float rb = b - __bfloat162float(hh.y);
    __nv_bfloat162 ll = __floats2bfloat162_rn(ra, rb);
    h = *(uint32_t*)&hh;
    l = *(uint32_t*)&ll;
}

// ---------------------------------------------------------------------------
// One fused split kernel: x, q_w, k_w, v_w -> (xh/xl, wh/wl fused), o_w -> owh/owl
// ---------------------------------------------------------------------------
#define N4_X   (MTOT * HID / 4)
#define N4_QW  (QW * HID / 4)
#define N4_KW  (KVW * HID / 4)
#define N4_ALL (N4_X + N4_QW + 2 * N4_KW + N4_QW)

__global__ void split_all(const float* __restrict__ x, const float* __restrict__ qw,
                          const float* __restrict__ kw, const float* __restrict__ vw,
                          const float* __restrict__ ow,
                          __nv_bfloat16* __restrict__ xh, __nv_bfloat16* __restrict__ xl,
                          __nv_bfloat16* __restrict__ wh, __nv_bfloat16* __restrict__ wl,
                          __nv_bfloat16* __restrict__ owh, __nv_bfloat16* __restrict__ owl)
{
    int i = blockIdx.x * blockDim.x + threadIdx.x;
    if (i >= N4_ALL) return;
    const float* src;
    __nv_bfloat16 *dh, *dl;
    int j = i;
    if (j < N4_X)                  { src = x;  dh = xh; dl = xl; }
    else if ((j -= N4_X) < N4_QW)  { src = qw; dh = wh; dl = wl; }
    else if ((j -= N4_QW) < N4_KW) { src = kw; dh = wh + (size_t)QW * HID; dl = wl + (size_t)QW * HID; }
    else if ((j -= N4_KW) < N4_KW) { src = vw; dh = wh + (size_t)(QW + KVW) * HID; dl = wl + (size_t)(QW + KVW) * HID; }
    else                           { j -= N4_KW; src = ow; dh = owh; dl = owl; }
    float4 v = ((const float4*)src)[j];
    uint32_t h0, l0, h1, l1;
    split2(v.x, v.y, h0, l0);
    split2(v.z, v.w, h1, l1);
    ((uint2*)dh)[j] = make_uint2(h0, h1);
    ((uint2*)dl)[j] = make_uint2(l0, l1);
}

// ---------------------------------------------------------------------------
// NT GEMM on pre-split bf16 operands, 3-term split, term-major MMA issue.
// MODE 0: fp32 C out.  MODE 1: fused QKV epilogue (rope Q/K, split -> bf16).
// ---------------------------------------------------------------------------
#define GROW  80
#define GT    (128 * GROW)            // 10240 B
#define STG_B (4 * GT)                // 40960 B
#define GEMM_SMEM (2 * STG_B)         // 81920 B

template<int MODE>
__global__ __launch_bounds__(256)
void hmma_gemm_pre(const __nv_bfloat16* __restrict__ Ah, const __nv_bfloat16* __restrict__ Al,
                   const __nv_bfloat16* __restrict__ Bh, const __nv_bfloat16* __restrict__ Bl,
                   float* __restrict__ C,
                   __nv_bfloat16* __restrict__ Qoh, __nv_bfloat16* __restrict__ Qol,
                   __nv_bfloat16* __restrict__ Koh, __nv_bfloat16* __restrict__ Kol,
                   __nv_bfloat16* __restrict__ Voh, __nv_bfloat16* __restrict__ Vol,
                   const float* __restrict__ sinp, const float* __restrict__ cosp,
                   int M, int N, int K)
{
    extern __shared__ __align__(128) char smem[];
    const uint32_t sb = smem_u32(smem);

    const int t    = threadIdx.x;
    const int warp = t >> 5;
    const int lane = t & 31;
    const int wm   = warp >> 2;
    const int wn   = warp & 3;
    const int bm   = blockIdx.y * 128;
    const int bn   = blockIdx.x * 128;

    const int r0c = t >> 2, ch0 = t & 3;
    const int r1c = r0c + 64;
    const __nv_bfloat16* srcA[2] = { Ah, Al };
    const __nv_bfloat16* srcB[2] = { Bh, Bl };

    float acc[4][4][4];
#pragma unroll
    for (int mi = 0; mi < 4; mi++)
#pragma unroll
        for (int ni = 0; ni < 4; ni++)
#pragma unroll
            for (int r = 0; r < 4; r++) acc[mi][ni][r] = 0.f;

    const int S = K / 32;

    auto issue = [&](int s, int buf) {
        const int k0 = s * 32;
        const uint32_t stg = sb + (uint32_t)buf * STG_B;
#pragma unroll
        for (int hl = 0; hl < 2; hl++) {
            uint32_t dA = stg + hl * GT;
            cpa16(dA + r0c * GROW + ch0 * 16, srcA[hl] + (size_t)(bm + r0c) * K + k0 + ch0 * 8);
            cpa16(dA + r1c * GROW + ch0 * 16, srcA[hl] + (size_t)(bm + r1c) * K + k0 + ch0 * 8);
            uint32_t dB = stg + (2 + hl) * GT;
            cpa16(dB + r0c * GROW + ch0 * 16, srcB[hl] + (size_t)(bn + r0c) * K + k0 + ch0 * 8);
            cpa16(dB + r1c * GROW + ch0 * 16, srcB[hl] + (size_t)(bn + r1c) * K + k0 + ch0 * 8);
        }
        CPA_COMMIT();
    };

    issue(0, 0);

    for (int s = 0; s < S; s++) {
        const int buf = s & 1;
        if (s + 1 < S) { issue(s + 1, buf ^ 1); CPA_WAIT(1); }
        else           { CPA_WAIT(0); }
        __syncthreads();

        const uint32_t smAh = sb + (uint32_t)buf * STG_B;
        const uint32_t smAl = smAh + GT;
        const uint32_t smBh = smAh + 2 * GT;
        const uint32_t smBl = smAh + 3 * GT;

#pragma unroll
        for (int kk = 0; kk < 2; kk++) {
            const int chb = kk * 2;
            uint32_t bh[2][4], bl[2][4];
#pragma unroll
            for (int ng = 0; ng < 2; ng++) {
                int rr = wn * 32 + ng * 16 + (lane & 15);
                uint32_t ad = rr * GROW + (chb + (lane >> 4)) * 16;
                ldm4(bh[ng], smBh + ad);
                ldm4(bl[ng], smBl + ad);
            }
#pragma unroll
            for (int mt = 0; mt < 4; mt++) {
                uint32_t ah[4], al[4];
                int rr = wm * 64 + mt * 16 + (lane & 15);
                uint32_t ad = rr * GROW + (chb + (lane >> 4)) * 16;
                ldm4(ah, smAh + ad);
                ldm4(al, smAl + ad);
                // term-major: same-acc chains 4 MMAs apart
#pragma unroll
                for (int n8 = 0; n8 < 4; n8++) {
                    int ng = n8 >> 1, hf = n8 & 1;
                    mma16816(acc[mt][n8], ah, bh[ng][hf], bh[ng][hf + 2]);
                }
#pragma unroll
                for (int n8 = 0; n8 < 4; n8++) {
                    int ng = n8 >> 1, hf = n8 & 1;
                    mma16816(acc[mt][n8], al, bh[ng][hf], bh[ng][hf + 2]);
                }
#pragma unroll
                for (int n8 = 0; n8 < 4; n8++) {
                    int ng = n8 >> 1, hf = n8 & 1;
                    mma16816(acc[mt][n8], ah, bl[ng][hf], bl[ng][hf + 2]);
                }
            }
        }
        __syncthreads();
    }

    const int g   = lane >> 2;
    const int tig = lane & 3;

    if (MODE == 0) {
#pragma unroll
        for (int mt = 0; mt < 4; mt++)
#pragma unroll
            for (int n8 = 0; n8 < 4; n8++) {
                int row = bm + wm * 64 + mt * 16 + g;
                int col = bn + wn * 32 + n8 * 8 + tig * 2;
                *(float2*)(C + (size_t)row * N + col) = make_float2(acc[mt][n8][0], acc[mt][n8][1]);
                *(float2*)(C + (size_t)(row + 8) * N + col) = make_float2(acc[mt][n8][2], acc[mt][n8][3]);
            }
        return;
    }

    // MODE 1: stage acc -> smem, rope(optional) + bf16 split -> bf16 hi/lo out
    float* stg = (float*)smem;   // [128][132]
#pragma unroll
    for (int mt = 0; mt < 4; mt++)
#pragma unroll
        for (int n8 = 0; n8 < 4; n8++) {
            int row = wm * 64 + mt * 16 + g;
            int col = wn * 32 + n8 * 8 + tig * 2;
            stg[row * 132 + col]     = acc[mt][n8][0];
            stg[row * 132 + col + 1] = acc[mt][n8][1];
            stg[(row + 8) * 132 + col]     = acc[mt][n8][2];
            stg[(row + 8) * 132 + col + 1] = acc[mt][n8][3];
        }
    __syncthreads();

    {
        const int r    = t >> 1;
        const int half = t & 1;
        const int gm   = bm + r;
        const int spos = gm & (SEQ - 1);
        const int pb   = half * 32;

        bool rot;
        __nv_bfloat16 *dh, *dl;
        int bx = blockIdx.x;
        if (bx < 16) {
            rot = true;
            dh = Qoh + (size_t)gm * QW + bx * 128;
            dl = Qol + (size_t)gm * QW + bx * 128;
        } else if (bx < 20) {
            rot = true;
            dh = Koh + (size_t)gm * KVW + (bx - 16) * 128;
            dl = Kol + (size_t)gm * KVW + (bx - 16) * 128;
        } else {
            rot = false;
            dh = Voh + (size_t)gm * KVW + (bx - 20) * 128;
            dl = Vol + (size_t)gm * KVW + (bx - 20) * 128;
        }

        uint32_t h0[16], l0[16], h1[16], l1[16];
#pragma unroll
        for (int j = 0; j < 16; j++) {
            int pi = pb + j * 2;
            float x0a = stg[r * 132 + pi],      x0b = stg[r * 132 + pi + 1];
            float x1a = stg[r * 132 + pi + 64], x1b = stg[r * 132 + pi + 65];
            float y0a, y0b, y1a, y1b;
            if (rot) {
                float ca = cosp[(size_t)spos * HD + pi],  cb = cosp[(size_t)spos * HD + pi + 1];
                float sa = sinp[(size_t)spos * HD + pi],  sbv = sinp[(size_t)spos * HD + pi + 1];
                y0a = x0a * ca - x1a * sa;  y1a = x1a * ca + x0a * sa;
                y0b = x0b * cb - x1b * sbv; y1b = x1b * cb + x0b * sbv;
            } else {
                y0a = x0a; y0b = x0b; y1a = x1a; y1b = x1b;
            }
            split2(y0a, y0b, h0[j], l0[j]);
            split2(y1a, y1b, h1[j], l1[j]);
        }
#pragma unroll
        for (int w = 0; w < 4; w++) {
            *(uint4*)(dh + pb + w * 8)      = ((uint4*)h0)[w];
            *(uint4*)(dh + 64 + pb + w * 8) = ((uint4*)h1)[w];
            *(uint4*)(dl + pb + w * 8)      = ((uint4*)l0)[w];
            *(uint4*)(dl + 64 + pb + w * 8) = ((uint4*)l1)[w];
        }
    }
}

// ---------------------------------------------------------------------------
// Flash attention, bf16 mma.sync, cp.async K/V pipeline, causal pair-balanced.
// QK MMA issue is term-major (same-acc chains 8 apart).
// ---------------------------------------------------------------------------
#define AT_TILE 16384
#define AT_SMEM (6 * AT_TILE)               // 98304 B
#define NQT     (SEQ / 64)                  // 32

__device__ __forceinline__ uint32_t swz256(int r, int ch) {
    return (uint32_t)(r * 256 + (((ch ^ (r & 7)) & 15) << 4));
}

__global__ __launch_bounds__(128)
void flash_attn_mma(const __nv_bfloat16* __restrict__ Qh, const __nv_bfloat16* __restrict__ Ql,
                    const __nv_bfloat16* __restrict__ Kh, const __nv_bfloat16* __restrict__ Kl,
                    const __nv_bfloat16* __restrict__ Vh, const __nv_bfloat16* __restrict__ Vl,
                    __nv_bfloat16* __restrict__ OAh, __nv_bfloat16* __restrict__ OAl)
{
    extern __shared__ __align__(128) char smem[];
    const uint32_t sb  = smem_u32(smem);
    const uint32_t sQh = sb;
    const uint32_t sQl = sb + AT_TILE;
    const uint32_t sA  = sb + 2 * AT_TILE;   // K stage: {h, l}
    const uint32_t sB  = sb + 4 * AT_TILE;   // V stage: {h, l}

    const int h   = blockIdx.y;
    const int b   = blockIdx.z;
    const int kvh = h >> 2;
    const int t   = threadIdx.x;
    const int warp = t >> 5;
    const int lane = t & 31;
    const int g    = lane >> 2;
    const int tig  = lane & 3;

    const int rl = warp * 16 + g;
    const int rh = rl + 8;

    auto load_kv = [&](const __nv_bfloat16* srch, const __nv_bfloat16* srcl,
                       uint32_t dst, int kt) {
        const __nv_bfloat16* bh = srch + (size_t)(b * SEQ + kt * 64) * KVW + kvh * HD;
        const __nv_bfloat16* bl = srcl + (size_t)(b * SEQ + kt * 64) * KVW + kvh * HD;
#pragma unroll
        for (int i = 0; i < 8; i++) {
            int f = i * 128 + t;
            int r = f >> 4, ch = f & 15;
            cpa16(dst + swz256(r, ch),           bh + (size_t)r * KVW + ch * 8);
            cpa16(dst + AT_TILE + swz256(r, ch), bl + (size_t)r * KVW + ch * 8);
        }
        CPA_COMMIT();
    };

    for (int sel = 0; sel < 2; sel++) {
        const int qt = sel ? (NQT - 1 - blockIdx.x) : blockIdx.x;
        const int q0 = qt * 64;

        // Q tiles (cp.async)
        {
            const __nv_bfloat16* qbh = Qh + (size_t)(b * SEQ + q0) * QW + h * HD;
            const __nv_bfloat16* qbl = Ql + (size_t)(b * SEQ + q0) * QW + h * HD;
#pragma unroll
            for (int i = 0; i < 8; i++) {
                int f = i * 128 + t;
                int r = f >> 4, ch = f & 15;
                cpa16(sQh + swz256(r, ch), qbh + (size_t)r * QW + ch * 8);
                cpa16(sQl + swz256(r, ch), qbl + (size_t)r * QW + ch * 8);
            }
            CPA_COMMIT();
        }
        load_kv(Kh, Kl, sA, 0);
        CPA_WAIT(0);
        __syncthreads();

        float o[16][4];
        float m0 = -1e30f, m1 = -1e30f, l0 = 0.f, l1 = 0.f;
#pragma unroll
        for (int i = 0; i < 16; i++)
#pragma unroll
            for (int j = 0; j < 4; j++) o[i][j] = 0.f;

        for (int kt = 0; kt <= qt; kt++) {
            // prefetch V(kt) into B while computing QK from A
            load_kv(Vh, Vl, sB, kt);

            float sacc[8][4];
#pragma unroll
            for (int i = 0; i < 8; i++)
#pragma unroll
                for (int j = 0; j < 4; j++) sacc[i][j] = 0.f;

#pragma unroll
            for (int ks = 0; ks < 8; ks++) {
                uint32_t qfh[4], qfl[4];
                {
                    int rr = warp * 16 + (lane & 15);
                    uint32_t ad = swz256(rr, ks * 2 + (lane >> 4));
                    ldm4(qfh, sQh + ad);
                    ldm4(qfl, sQl + ad);
                }
                uint32_t kfh[4][4], kfl[4][4];
#pragma unroll
                for (int ng = 0; ng < 4; ng++) {
                    int rr = ng * 16 + (lane & 15);
                    uint32_t ad = swz256(rr, ks * 2 + (lane >> 4));
                    ldm4(kfh[ng], sA + ad);
                    ldm4(kfl[ng], sA + AT_TILE + ad);
                }
                // term-major: same-sacc chains 8 MMAs apart
#pragma unroll
                for (int n8 = 0; n8 < 8; n8++) {
                    int ng = n8 >> 1, hf = n8 & 1;
                    mma16816(sacc[n8], qfh, kfh[ng][hf], kfh[ng][hf + 2]);
                }
#pragma unroll
                for (int n8 = 0; n8 < 8; n8++) {
                    int ng = n8 >> 1, hf = n8 & 1;
                    mma16816(sacc[n8], qfl, kfh[ng][hf], kfh[ng][hf + 2]);
                }
#pragma unroll
                for (int n8 = 0; n8 < 8; n8++) {
                    int ng = n8 >> 1, hf = n8 & 1;
                    mma16816(sacc[n8], qfh, kfl[ng][hf], kfl[ng][hf + 2]);
                }
            }

            if (kt == qt) {
#pragma unroll
                for (int n8 = 0; n8 < 8; n8++) {
                    int c0 = n8 * 8 + tig * 2, c1 = c0 + 1;
                    if (c0 > rl) sacc[n8][0] = -1e30f;
                    if (c1 > rl) sacc[n8][1] = -1e30f;
                    if (c0 > rh) sacc[n8][2] = -1e30f;
                    if (c1 > rh) sacc[n8][3] = -1e30f;
                }
            }

            // online softmax
            float mx0 = -1e30f, mx1 = -1e30f;
#pragma unroll
            for (int n8 = 0; n8 < 8; n8++) {
                mx0 = fmaxf(mx0, fmaxf(sacc[n8][0], sacc[n8][1]));
                mx1 = fmaxf(mx1, fmaxf(sacc[n8][2], sacc[n8][3]));
            }
            mx0 = fmaxf(mx0, __shfl_xor_sync(0xffffffffu, mx0, 1));
            mx0 = fmaxf(mx0, __shfl_xor_sync(0xffffffffu, mx0, 2));
            mx1 = fmaxf(mx1, __shfl_xor_sync(0xffffffffu, mx1, 1));
            mx1 = fmaxf(mx1, __shfl_xor_sync(0xffffffffu, mx1, 2));

            float mn0 = fmaxf(m0, mx0), mn1 = fmaxf(m1, mx1);
            float al0 = __expf(m0 - mn0), al1 = __expf(m1 - mn1);
            m0 = mn0; m1 = mn1;

            float s0 = 0.f, s1 = 0.f;
#pragma unroll
            for (int n8 = 0; n8 < 8; n8++) {
                float p0 = __expf(sacc[n8][0] - m0);
                float p1 = __expf(sacc[n8][1] - m0);
                float p2 = __expf(sacc[n8][2] - m1);
                float p3 = __expf(sacc[n8][3] - m1);
                sacc[n8][0] = p0; sacc[n8][1] = p1; sacc[n8][2] = p2; sacc[n8][3] = p3;
                s0 += p0 + p1; s1 += p2 + p3;
            }
            s0 += __shfl_xor_sync(0xffffffffu, s0, 1);
            s0 += __shfl_xor_sync(0xffffffffu, s0, 2);
            s1 += __shfl_xor_sync(0xffffffffu, s1, 1);
            s1 += __shfl_xor_sync(0xffffffffu, s1, 2);
            l0 = l0 * al0 + s0;
            l1 = l1 * al1 + s1;

#pragma unroll
            for (int i = 0; i < 16; i++) {
                o[i][0] *= al0; o[i][1] *= al0;
                o[i][2] *= al1; o[i][3] *= al1;
            }

            // P -> bf16 fragments (hi/lo)
            uint32_t ph[4][4], pl[4][4];
#pragma unroll
            for (int kk = 0; kk < 4; kk++) {
                split2(sacc[2 * kk][0],     sacc[2 * kk][1],     ph[kk][0], pl[kk][0]);
                split2(sacc[2 * kk][2],     sacc[2 * kk][3],     ph[kk][1], pl[kk][1]);
                split2(sacc[2 * kk + 1][0], sacc[2 * kk + 1][1], ph[kk][2], pl[kk][2]);
                split2(sacc[2 * kk + 1][2], sacc[2 * kk + 1][3], ph[kk][3], pl[kk][3]);
            }

            CPA_WAIT(0);        // V(kt) arrived
            __syncthreads();    // all warps done reading A (K)

            if (kt < qt) load_kv(Kh, Kl, sA, kt + 1);

            // O += P V  (PhVh + PlVh + PhVl)
#pragma unroll
            for (int ng = 0; ng < 8; ng++) {
#pragma unroll
                for (int kk = 0; kk < 4; kk++) {
                    uint32_t vfh[4], vfl[4];
                    int rr = kk * 16 + (lane & 15);
                    uint32_t ad = swz256(rr, ng * 2 + (lane >> 4));
                    ldm4t(vfh, sB + ad);
                    ldm4t(vfl, sB + AT_TILE + ad);
#pragma unroll
                    for (int hf = 0; hf < 2; hf++) {
                        int nt = ng * 2 + hf;
                        uint32_t b0 = vfh[hf * 2], b1 = vfh[hf * 2 + 1];
                        mma16816(o[nt], ph[kk], b0, b1);
                        mma16816(o[nt], pl[kk], b0, b1);
                        mma16816(o[nt], ph[kk], vfl[hf * 2], vfl[hf * 2 + 1]);
                    }
                }
            }

            CPA_WAIT(0);        // K(kt+1) arrived
            __syncthreads();    // all warps done reading B (V)
        }

        // epilogue: normalize, write bf16 hi/lo
        float inv0 = 1.f / l0, inv1 = 1.f / l1;
        __nv_bfloat16* Obh = OAh + (size_t)(b * SEQ + q0) * QW + h * HD;
        __nv_bfloat16* Obl = OAl + (size_t)(b * SEQ + q0) * QW + h * HD;
#pragma unroll
        for (int nt = 0; nt < 16; nt++) {
            int col = nt * 8 + tig * 2;
            uint32_t hh0, ll0, hh1, ll1;
            split2(o[nt][0] * inv0, o[nt][1] * inv0, hh0, ll0);
            split2(o[nt][2] * inv1, o[nt][3] * inv1, hh1, ll1);
            *(uint32_t*)(Obh + (size_t)rl * QW + col) = hh0;
            *(uint32_t*)(Obl + (size_t)rl * QW + col) = ll0;
            *(uint32_t*)(Obh + (size_t)rh * QW + col) = hh1;
            *(uint32_t*)(Obl + (size_t)rh * QW + col) = ll1;
        }
    }
}

// ---------------------------------------------------------------------------
// Launcher
// ---------------------------------------------------------------------------
extern "C" void kernel_launch(void* const* d_in, const int* in_sizes, int n_in,
                              void* d_out, int out_size)
{
    const float* x    = (const float*)d_in[0];
    const float* q_w  = (const float*)d_in[2];
    const float* k_w  = (const float*)d_in[3];
    const float* v_w  = (const float*)d_in[4];
    const float* o_w  = (const float*)d_in[5];
    const float* sinp = (const float*)d_in[6];
    const float* cosp = (const float*)d_in[7];
    float* out = (float*)d_out;

    __nv_bfloat16 *xh, *xl, *wh, *wl, *owh, *owl;
    cudaGetSymbolAddress((void**)&xh, g_xh);
    cudaGetSymbolAddress((void**)&xl, g_xl);
    cudaGetSymbolAddress((void**)&wh, g_wh);
    cudaGetSymbolAddress((void**)&wl, g_wl);
    cudaGetSymbolAddress((void**)&owh, g_owh);
    cudaGetSymbolAddress((void**)&owl, g_owl);
    __nv_bfloat16 *Qh, *Ql, *Kh, *Kl, *Vh, *Vl, *Ah, *Al;
    cudaGetSymbolAddress((void**)&Qh, g_Qh);
    cudaGetSymbolAddress((void**)&Ql, g_Ql);
    cudaGetSymbolAddress((void**)&Kh, g_Kh);
    cudaGetSymbolAddress((void**)&Kl, g_Kl);
    cudaGetSymbolAddress((void**)&Vh, g_Vh);
    cudaGetSymbolAddress((void**)&Vl, g_Vl);
    cudaGetSymbolAddress((void**)&Ah, g_Ah);
    cudaGetSymbolAddress((void**)&Al, g_Al);

    // 1) fused split of all fp32 operands
    split_all<<<(N4_ALL + 255) / 256, 256>>>(x, q_w, k_w, v_w, o_w,
                                             xh, xl, wh, wl, owh, owl);

    cudaFuncSetAttribute(hmma_gemm_pre<0>, cudaFuncAttributeMaxDynamicSharedMemorySize, GEMM_SMEM);
    cudaFuncSetAttribute(hmma_gemm_pre<1>, cudaFuncAttributeMaxDynamicSharedMemorySize, GEMM_SMEM);

    // 2) fused QKV projection + rope/split epilogue
    hmma_gemm_pre<1><<<dim3(W3 / 128, MTOT / 128), 256, GEMM_SMEM>>>(
        xh, xl, wh, wl, nullptr, Qh, Ql, Kh, Kl, Vh, Vl, sinp, cosp, MTOT, W3, HID);

    // 3) flash attention
    cudaFuncSetAttribute(flash_attn_mma, cudaFuncAttributeMaxDynamicSharedMemorySize, AT_SMEM);
    flash_attn_mma<<<dim3(NQT / 2, NH, 2), 128, AT_SMEM>>>(Qh, Ql, Kh, Kl, Vh, Vl, Ah, Al);

    // 4) output projection (fp32 out)
    hmma_gemm_pre<0><<<dim3(HID / 128, MTOT / 128), 256, GEMM_SMEM>>>(
        Ah, Al, owh, owl, out, nullptr, nullptr, nullptr, nullptr, nullptr, nullptr,
        nullptr, nullptr, MTOT, HID, HID);
}

// round 9
// speedup vs baseline: 2.8001x; 1.0078x over previous
#include <cuda_runtime.h>
#include <cuda_bf16.h>
#include <math.h>
#include <stdint.h>

// Problem constants
#define MTOT 4096      // B*S
#define SEQ  2048
#define HID  2048
#define NH   16
#define NKV  4
#define HD   128
#define QW   2048      // NH*HD
#define KVW  512       // NKV*HD
#define W3   3072      // fused Q|K|V weight width

// Scratch (allocation-free rule: __device__ globals)
__device__ __nv_bfloat16 g_xh[(size_t)MTOT * HID];
__device__ __nv_bfloat16 g_xl[(size_t)MTOT * HID];
__device__ __nv_bfloat16 g_wh[(size_t)W3 * HID];     // q|k|v weights fused
__device__ __nv_bfloat16 g_wl[(size_t)W3 * HID];
__device__ __nv_bfloat16 g_owh[(size_t)HID * QW];
__device__ __nv_bfloat16 g_owl[(size_t)HID * QW];
__device__ __nv_bfloat16 g_Qh[(size_t)MTOT * QW];
__device__ __nv_bfloat16 g_Ql[(size_t)MTOT * QW];
__device__ __nv_bfloat16 g_Kh[(size_t)MTOT * KVW];
__device__ __nv_bfloat16 g_Kl[(size_t)MTOT * KVW];
__device__ __nv_bfloat16 g_Vh[(size_t)MTOT * KVW];
__device__ __nv_bfloat16 g_Vl[(size_t)MTOT * KVW];
__device__ __nv_bfloat16 g_Ah[(size_t)MTOT * QW];
__device__ __nv_bfloat16 g_Al[(size_t)MTOT * QW];

// ---------------------------------------------------------------------------
// helpers
// ---------------------------------------------------------------------------
__device__ __forceinline__ void mma16816(float* c, const uint32_t* a, uint32_t b0, uint32_t b1) {
    asm volatile(
        "mma.sync.aligned.m16n8k16.row.col.f32.bf16.bf16.f32 "
        "{%0,%1,%2,%3}, {%4,%5,%6,%7}, {%8,%9}, {%0,%1,%2,%3};"
        : "+f"(c[0]), "+f"(c[1]), "+f"(c[2]), "+f"(c[3])
        : "r"(a[0]), "r"(a[1]), "r"(a[2]), "r"(a[3]), "r"(b0), "r"(b1));
}
__device__ __forceinline__ void ldm4(uint32_t* r, uint32_t a) {
    asm volatile("ldmatrix.sync.aligned.m8n8.x4.shared.b16 {%0,%1,%2,%3}, [%4];"
                 : "=r"(r[0]), "=r"(r[1]), "=r"(r[2]), "=r"(r[3]) : "r"(a));
}
__device__ __forceinline__ void ldm4t(uint32_t* r, uint32_t a) {
    asm volatile("ldmatrix.sync.aligned.m8n8.x4.trans.shared.b16 {%0,%1,%2,%3}, [%4];"
                 : "=r"(r[0]), "=r"(r[1]), "=r"(r[2]), "=r"(r[3]) : "r"(a));
}
__device__ __forceinline__ uint32_t smem_u32(const void* p) {
    uint32_t a;
    asm("{ .reg .u64 tmp; cvta.to.shared.u64 tmp, %1; cvt.u32.u64 %0, tmp; }"
        : "=r"(a) : "l"(p));
    return a;
}
__device__ __forceinline__ void cpa16(uint32_t dst, const void* src) {
    asm volatile("cp.async.cg.shared.global [%0], [%1], 16;" :: "r"(dst), "l"(src));
}
#define CPA_COMMIT() asm volatile("cp.async.commit_group;" ::: "memory")
#define CPA_WAIT(n)  asm volatile("cp.async.wait_group %0;" :: "n"(n) : "memory")

__device__ __forceinline__ void split2(float a, float b, uint32_t& h, uint32_t& l) {
    __nv_bfloat162 hh = __floats2bfloat162_rn(a, b);
    float ra = a - __bfloat162float(hh.x);
    float rb = b - __bfloat162float(hh.y);
    __nv_bfloat162 ll = __floats2bfloat162_rn(ra, rb);
    h = *(uint32_t*)&hh;
    l = *(uint32_t*)&ll;
}

// ---------------------------------------------------------------------------
// One fused split kernel: x, q_w, k_w, v_w -> (xh/xl, wh/wl fused), o_w -> owh/owl
// ---------------------------------------------------------------------------
#define N4_X   (MTOT * HID / 4)
#define N4_QW  (QW * HID / 4)
#define N4_KW  (KVW * HID / 4)
#define N4_ALL (N4_X + N4_QW + 2 * N4_KW + N4_QW)

__global__ void split_all(const float* __restrict__ x, const float* __restrict__ qw,
                          const float* __restrict__ kw, const float* __restrict__ vw,
                          const float* __restrict__ ow,
                          __nv_bfloat16* __restrict__ xh, __nv_bfloat16* __restrict__ xl,
                          __nv_bfloat16* __restrict__ wh, __nv_bfloat16* __restrict__ wl,
                          __nv_bfloat16* __restrict__ owh, __nv_bfloat16* __restrict__ owl)
{
    int i = blockIdx.x * blockDim.x + threadIdx.x;
    if (i >= N4_ALL) return;
    const float* src;
    __nv_bfloat16 *dh, *dl;
    int j = i;
    if (j < N4_X)                  { src = x;  dh = xh; dl = xl; }
    else if ((j -= N4_X) < N4_QW)  { src = qw; dh = wh; dl = wl; }
    else if ((j -= N4_QW) < N4_KW) { src = kw; dh = wh + (size_t)QW * HID; dl = wl + (size_t)QW * HID; }
    else if ((j -= N4_KW) < N4_KW) { src = vw; dh = wh + (size_t)(QW + KVW) * HID; dl = wl + (size_t)(QW + KVW) * HID; }
    else                           { j -= N4_KW; src = ow; dh = owh; dl = owl; }
    float4 v = ((const float4*)src)[j];
    uint32_t h0, l0, h1, l1;
    split2(v.x, v.y, h0, l0);
    split2(v.z, v.w, h1, l1);
    ((uint2*)dh)[j] = make_uint2(h0, h1);
    ((uint2*)dl)[j] = make_uint2(l0, l1);
}

// ---------------------------------------------------------------------------
// NT GEMM on pre-split bf16 operands, 3-term split.
// 128 threads = 4 warps (2x2), warp tile 64x64, BM=BN=128, BK=32.
// MODE 0: fp32 C out.  MODE 1: fused QKV epilogue (rope Q/K, split -> bf16).
// ---------------------------------------------------------------------------
#define GROW  80
#define GT    (128 * GROW)            // 10240 B
#define STG_B (4 * GT)                // 40960 B
#define GEMM_SMEM (2 * STG_B)         // 81920 B

template<int MODE>
__global__ __launch_bounds__(128)
void hmma_gemm_pre(const __nv_bfloat16* __restrict__ Ah, const __nv_bfloat16* __restrict__ Al,
                   const __nv_bfloat16* __restrict__ Bh, const __nv_bfloat16* __restrict__ Bl,
                   float* __restrict__ C,
                   __nv_bfloat16* __restrict__ Qoh, __nv_bfloat16* __restrict__ Qol,
                   __nv_bfloat16* __restrict__ Koh, __nv_bfloat16* __restrict__ Kol,
                   __nv_bfloat16* __restrict__ Voh, __nv_bfloat16* __restrict__ Vol,
                   const float* __restrict__ sinp, const float* __restrict__ cosp,
                   int M, int N, int K)
{
    extern __shared__ __align__(128) char smem[];
    const uint32_t sb = smem_u32(smem);

    const int t    = threadIdx.x;
    const int warp = t >> 5;
    const int lane = t & 31;
    const int wm   = warp >> 1;        // 0..1 (M)
    const int wn   = warp & 1;         // 0..1 (N)
    const int bm   = blockIdx.y * 128;
    const int bn   = blockIdx.x * 128;

    const __nv_bfloat16* srcA[2] = { Ah, Al };
    const __nv_bfloat16* srcB[2] = { Bh, Bl };

    float acc[4][8][4];
#pragma unroll
    for (int mi = 0; mi < 4; mi++)
#pragma unroll
        for (int ni = 0; ni < 8; ni++)
#pragma unroll
            for (int r = 0; r < 4; r++) acc[mi][ni][r] = 0.f;

    const int S = K / 32;

    // 128 threads: per tile 512 chunks -> 4 per thread
    auto issue = [&](int s, int buf) {
        const int k0 = s * 32;
        const uint32_t stg = sb + (uint32_t)buf * STG_B;
#pragma unroll
        for (int i = 0; i < 4; i++) {
            int f = i * 128 + t;
            int r = f >> 2, ch = f & 3;
            uint32_t so = r * GROW + ch * 16;
            size_t  goA = (size_t)(bm + r) * K + k0 + ch * 8;
            size_t  goB = (size_t)(bn + r) * K + k0 + ch * 8;
            cpa16(stg + 0 * GT + so, srcA[0] + goA);
            cpa16(stg + 1 * GT + so, srcA[1] + goA);
            cpa16(stg + 2 * GT + so, srcB[0] + goB);
            cpa16(stg + 3 * GT + so, srcB[1] + goB);
        }
        CPA_COMMIT();
    };

    issue(0, 0);

    for (int s = 0; s < S; s++) {
        const int buf = s & 1;
        if (s + 1 < S) { issue(s + 1, buf ^ 1); CPA_WAIT(1); }
        else           { CPA_WAIT(0); }
        __syncthreads();

        const uint32_t smAh = sb + (uint32_t)buf * STG_B;
        const uint32_t smAl = smAh + GT;
        const uint32_t smBh = smAh + 2 * GT;
        const uint32_t smBl = smAh + 3 * GT;

#pragma unroll
        for (int kk = 0; kk < 2; kk++) {
            const int chb = kk * 2;
            uint32_t bh[4][4], bl[4][4];
#pragma unroll
            for (int ng = 0; ng < 4; ng++) {
                int rr = wn * 64 + ng * 16 + (lane & 15);
                uint32_t ad = rr * GROW + (chb + (lane >> 4)) * 16;
                ldm4(bh[ng], smBh + ad);
                ldm4(bl[ng], smBl + ad);
            }
#pragma unroll
            for (int mt = 0; mt < 4; mt++) {
                uint32_t ah[4], al[4];
                int rr = wm * 64 + mt * 16 + (lane & 15);
                uint32_t ad = rr * GROW + (chb + (lane >> 4)) * 16;
                ldm4(ah, smAh + ad);
                ldm4(al, smAl + ad);
                // term-major: same-acc chains 8 MMAs apart
#pragma unroll
                for (int n8 = 0; n8 < 8; n8++) {
                    int ng = n8 >> 1, hf = n8 & 1;
                    mma16816(acc[mt][n8], ah, bh[ng][hf], bh[ng][hf + 2]);
                }
#pragma unroll
                for (int n8 = 0; n8 < 8; n8++) {
                    int ng = n8 >> 1, hf = n8 & 1;
                    mma16816(acc[mt][n8], al, bh[ng][hf], bh[ng][hf + 2]);
                }
#pragma unroll
                for (int n8 = 0; n8 < 8; n8++) {
                    int ng = n8 >> 1, hf = n8 & 1;
                    mma16816(acc[mt][n8], ah, bl[ng][hf], bl[ng][hf + 2]);
                }
            }
        }
        __syncthreads();
    }

    const int g   = lane >> 2;
    const int tig = lane & 3;

    if (MODE == 0) {
#pragma unroll
        for (int mt = 0; mt < 4; mt++)
#pragma unroll
            for (int n8 = 0; n8 < 8; n8++) {
                int row = bm + wm * 64 + mt * 16 + g;
                int col = bn + wn * 64 + n8 * 8 + tig * 2;
                *(float2*)(C + (size_t)row * N + col) = make_float2(acc[mt][n8][0], acc[mt][n8][1]);
                *(float2*)(C + (size_t)(row + 8) * N + col) = make_float2(acc[mt][n8][2], acc[mt][n8][3]);
            }
        return;
    }

    // MODE 1: stage acc -> smem, rope(optional) + bf16 split -> bf16 hi/lo out
    float* stg = (float*)smem;   // [128][132]
#pragma unroll
    for (int mt = 0; mt < 4; mt++)
#pragma unroll
        for (int n8 = 0; n8 < 8; n8++) {
            int row = wm * 64 + mt * 16 + g;
            int col = wn * 64 + n8 * 8 + tig * 2;
            stg[row * 132 + col]     = acc[mt][n8][0];
            stg[row * 132 + col + 1] = acc[mt][n8][1];
            stg[(row + 8) * 132 + col]     = acc[mt][n8][2];
            stg[(row + 8) * 132 + col + 1] = acc[mt][n8][3];
        }
    __syncthreads();

    {
        const int r    = t;             // 128 threads, one row each
        const int gm   = bm + r;
        const int spos = gm & (SEQ - 1);

        bool rot;
        __nv_bfloat16 *dh, *dl;
        int bx = blockIdx.x;
        if (bx < 16) {
            rot = true;
            dh = Qoh + (size_t)gm * QW + bx * 128;
            dl = Qol + (size_t)gm * QW + bx * 128;
        } else if (bx < 20) {
            rot = true;
            dh = Koh + (size_t)gm * KVW + (bx - 16) * 128;
            dl = Kol + (size_t)gm * KVW + (bx - 16) * 128;
        } else {
            rot = false;
            dh = Voh + (size_t)gm * KVW + (bx - 20) * 128;
            dl = Vol + (size_t)gm * KVW + (bx - 20) * 128;
        }

#pragma unroll
        for (int half = 0; half < 2; half++) {
            const int pb = half * 32;
            uint32_t h0[16], l0[16], h1[16], l1[16];
#pragma unroll
            for (int j = 0; j < 16; j++) {
                int pi = pb + j * 2;
                float x0a = stg[r * 132 + pi],      x0b = stg[r * 132 + pi + 1];
                float x1a = stg[r * 132 + pi + 64], x1b = stg[r * 132 + pi + 65];
                float y0a, y0b, y1a, y1b;
                if (rot) {
                    float ca = cosp[(size_t)spos * HD + pi],  cb = cosp[(size_t)spos * HD + pi + 1];
                    float sa = sinp[(size_t)spos * HD + pi],  sbv = sinp[(size_t)spos * HD + pi + 1];
                    y0a = x0a * ca - x1a * sa;  y1a = x1a * ca + x0a * sa;
                    y0b = x0b * cb - x1b * sbv; y1b = x1b * cb + x0b * sbv;
                } else {
                    y0a = x0a; y0b = x0b; y1a = x1a; y1b = x1b;
                }
                split2(y0a, y0b, h0[j], l0[j]);
                split2(y1a, y1b, h1[j], l1[j]);
            }
#pragma unroll
            for (int w = 0; w < 4; w++) {
                *(uint4*)(dh + pb + w * 8)      = ((uint4*)h0)[w];
                *(uint4*)(dh + 64 + pb + w * 8) = ((uint4*)h1)[w];
                *(uint4*)(dl + pb + w * 8)      = ((uint4*)l0)[w];
                *(uint4*)(dl + 64 + pb + w * 8) = ((uint4*)l1)[w];
            }
        }
    }
}

// ---------------------------------------------------------------------------
// Flash attention, bf16 mma.sync, cp.async K/V pipeline, causal pair-balanced.
// ---------------------------------------------------------------------------
#define AT_TILE 16384
#define AT_SMEM (6 * AT_TILE)               // 98304 B
#define NQT     (SEQ / 64)                  // 32

__device__ __forceinline__ uint32_t swz256(int r, int ch) {
    return (uint32_t)(r * 256 + (((ch ^ (r & 7)) & 15) << 4));
}

__global__ __launch_bounds__(128)
void flash_attn_mma(const __nv_bfloat16* __restrict__ Qh, const __nv_bfloat16* __restrict__ Ql,
                    const __nv_bfloat16* __restrict__ Kh, const __nv_bfloat16* __restrict__ Kl,
                    const __nv_bfloat16* __restrict__ Vh, const __nv_bfloat16* __restrict__ Vl,
                    __nv_bfloat16* __restrict__ OAh, __nv_bfloat16* __restrict__ OAl)
{
    extern __shared__ __align__(128) char smem[];
    const uint32_t sb  = smem_u32(smem);
    const uint32_t sQh = sb;
    const uint32_t sQl = sb + AT_TILE;
    const uint32_t sA  = sb + 2 * AT_TILE;   // K stage: {h, l}
    const uint32_t sB  = sb + 4 * AT_TILE;   // V stage: {h, l}

    const int h   = blockIdx.y;
    const int b   = blockIdx.z;
    const int kvh = h >> 2;
    const int t   = threadIdx.x;
    const int warp = t >> 5;
    const int lane = t & 31;
    const int g    = lane >> 2;
    const int tig  = lane & 3;

    const int rl = warp * 16 + g;
    const int rh = rl + 8;

    auto load_kv = [&](const __nv_bfloat16* srch, const __nv_bfloat16* srcl,
                       uint32_t dst, int kt) {
        const __nv_bfloat16* bh = srch + (size_t)(b * SEQ + kt * 64) * KVW + kvh * HD;
        const __nv_bfloat16* bl = srcl + (size_t)(b * SEQ + kt * 64) * KVW + kvh * HD;
#pragma unroll
        for (int i = 0; i < 8; i++) {
            int f = i * 128 + t;
            int r = f >> 4, ch = f & 15;
            cpa16(dst + swz256(r, ch),           bh + (size_t)r * KVW + ch * 8);
            cpa16(dst + AT_TILE + swz256(r, ch), bl + (size_t)r * KVW + ch * 8);
        }
        CPA_COMMIT();
    };

    for (int sel = 0; sel < 2; sel++) {
        const int qt = sel ? (NQT - 1 - blockIdx.x) : blockIdx.x;
        const int q0 = qt * 64;

        // Q tiles (cp.async)
        {
            const __nv_bfloat16* qbh = Qh + (size_t)(b * SEQ + q0) * QW + h * HD;
            const __nv_bfloat16* qbl = Ql + (size_t)(b * SEQ + q0) * QW + h * HD;
#pragma unroll
            for (int i = 0; i < 8; i++) {
                int f = i * 128 + t;
                int r = f >> 4, ch = f & 15;
                cpa16(sQh + swz256(r, ch), qbh + (size_t)r * QW + ch * 8);
                cpa16(sQl + swz256(r, ch), qbl + (size_t)r * QW + ch * 8);
            }
            CPA_COMMIT();
        }
        load_kv(Kh, Kl, sA, 0);
        CPA_WAIT(0);
        __syncthreads();

        float o[16][4];
        float m0 = -1e30f, m1 = -1e30f, l0 = 0.f, l1 = 0.f;
#pragma unroll
        for (int i = 0; i < 16; i++)
#pragma unroll
            for (int j = 0; j < 4; j++) o[i][j] = 0.f;

        for (int kt = 0; kt <= qt; kt++) {
            load_kv(Vh, Vl, sB, kt);

            float sacc[8][4];
#pragma unroll
            for (int i = 0; i < 8; i++)
#pragma unroll
                for (int j = 0; j < 4; j++) sacc[i][j] = 0.f;

#pragma unroll
            for (int ks = 0; ks < 8; ks++) {
                uint32_t qfh[4], qfl[4];
                {
                    int rr = warp * 16 + (lane & 15);
                    uint32_t ad = swz256(rr, ks * 2 + (lane >> 4));
                    ldm4(qfh, sQh + ad);
                    ldm4(qfl, sQl + ad);
                }
                uint32_t kfh[4][4], kfl[4][4];
#pragma unroll
                for (int ng = 0; ng < 4; ng++) {
                    int rr = ng * 16 + (lane & 15);
                    uint32_t ad = swz256(rr, ks * 2 + (lane >> 4));
                    ldm4(kfh[ng], sA + ad);
                    ldm4(kfl[ng], sA + AT_TILE + ad);
                }
#pragma unroll
                for (int n8 = 0; n8 < 8; n8++) {
                    int ng = n8 >> 1, hf = n8 & 1;
                    mma16816(sacc[n8], qfh, kfh[ng][hf], kfh[ng][hf + 2]);
                }
#pragma unroll
                for (int n8 = 0; n8 < 8; n8++) {
                    int ng = n8 >> 1, hf = n8 & 1;
                    mma16816(sacc[n8], qfl, kfh[ng][hf], kfh[ng][hf + 2]);
                }
#pragma unroll
                for (int n8 = 0; n8 < 8; n8++) {
                    int ng = n8 >> 1, hf = n8 & 1;
                    mma16816(sacc[n8], qfh, kfl[ng][hf], kfl[ng][hf + 2]);
                }
            }

            if (kt == qt) {
#pragma unroll
                for (int n8 = 0; n8 < 8; n8++) {
                    int c0 = n8 * 8 + tig * 2, c1 = c0 + 1;
                    if (c0 > rl) sacc[n8][0] = -1e30f;
                    if (c1 > rl) sacc[n8][1] = -1e30f;
                    if (c0 > rh) sacc[n8][2] = -1e30f;
                    if (c1 > rh) sacc[n8][3] = -1e30f;
                }
            }

            float mx0 = -1e30f, mx1 = -1e30f;
#pragma unroll
            for (int n8 = 0; n8 < 8; n8++) {
                mx0 = fmaxf(mx0, fmaxf(sacc[n8][0], sacc[n8][1]));
                mx1 = fmaxf(mx1, fmaxf(sacc[n8][2], sacc[n8][3]));
            }
            mx0 = fmaxf(mx0, __shfl_xor_sync(0xffffffffu, mx0, 1));
            mx0 = fmaxf(mx0, __shfl_xor_sync(0xffffffffu, mx0, 2));
            mx1 = fmaxf(mx1, __shfl_xor_sync(0xffffffffu, mx1, 1));
            mx1 = fmaxf(mx1, __shfl_xor_sync(0xffffffffu, mx1, 2));

            float mn0 = fmaxf(m0, mx0), mn1 = fmaxf(m1, mx1);
            float al0 = __expf(m0 - mn0), al1 = __expf(m1 - mn1);
            m0 = mn0; m1 = mn1;

            float s0 = 0.f, s1 = 0.f;
#pragma unroll
            for (int n8 = 0; n8 < 8; n8++) {
                float p0 = __expf(sacc[n8][0] - m0);
                float p1 = __expf(sacc[n8][1] - m0);
                float p2 = __expf(sacc[n8][2] - m1);
                float p3 = __expf(sacc[n8][3] - m1);
                sacc[n8][0] = p0; sacc[n8][1] = p1; sacc[n8][2] = p2; sacc[n8][3] = p3;
                s0 += p0 + p1; s1 += p2 + p3;
            }
            s0 += __shfl_xor_sync(0xffffffffu, s0, 1);
            s0 += __shfl_xor_sync(0xffffffffu, s0, 2);
            s1 += __shfl_xor_sync(0xffffffffu, s1, 1);
            s1 += __shfl_xor_sync(0xffffffffu, s1, 2);
            l0 = l0 * al0 + s0;
            l1 = l1 * al1 + s1;

#pragma unroll
            for (int i = 0; i < 16; i++) {
                o[i][0] *= al0; o[i][1] *= al0;
                o[i][2] *= al1; o[i][3] *= al1;
            }

            uint32_t ph[4][4], pl[4][4];
#pragma unroll
            for (int kk = 0; kk < 4; kk++) {
                split2(sacc[2 * kk][0],     sacc[2 * kk][1],     ph[kk][0], pl[kk][0]);
                split2(sacc[2 * kk][2],     sacc[2 * kk][3],     ph[kk][1], pl[kk][1]);
                split2(sacc[2 * kk + 1][0], sacc[2 * kk + 1][1], ph[kk][2], pl[kk][2]);
                split2(sacc[2 * kk + 1][2], sacc[2 * kk + 1][3], ph[kk][3], pl[kk][3]);
            }

            CPA_WAIT(0);
            __syncthreads();

            if (kt < qt) load_kv(Kh, Kl, sA, kt + 1);

#pragma unroll
            for (int ng = 0; ng < 8; ng++) {
#pragma unroll
                for (int kk = 0; kk < 4; kk++) {
                    uint32_t vfh[4], vfl[4];
                    int rr = kk * 16 + (lane & 15);
                    uint32_t ad = swz256(rr, ng * 2 + (lane >> 4));
                    ldm4t(vfh, sB + ad);
                    ldm4t(vfl, sB + AT_TILE + ad);
#pragma unroll
                    for (int hf = 0; hf < 2; hf++) {
                        int nt = ng * 2 + hf;
                        uint32_t b0 = vfh[hf * 2], b1 = vfh[hf * 2 + 1];
                        mma16816(o[nt], ph[kk], b0, b1);
                        mma16816(o[nt], pl[kk], b0, b1);
                        mma16816(o[nt], ph[kk], vfl[hf * 2], vfl[hf * 2 + 1]);
                    }
                }
            }

            CPA_WAIT(0);
            __syncthreads();
        }

        float inv0 = 1.f / l0, inv1 = 1.f / l1;
        __nv_bfloat16* Obh = OAh + (size_t)(b * SEQ + q0) * QW + h * HD;
        __nv_bfloat16* Obl = OAl + (size_t)(b * SEQ + q0) * QW + h * HD;
#pragma unroll
        for (int nt = 0; nt < 16; nt++) {
            int col = nt * 8 + tig * 2;
            uint32_t hh0, ll0, hh1, ll1;
            split2(o[nt][0] * inv0, o[nt][1] * inv0, hh0, ll0);
            split2(o[nt][2] * inv1, o[nt][3] * inv1, hh1, ll1);
            *(uint32_t*)(Obh + (size_t)rl * QW + col) = hh0;
            *(uint32_t*)(Obl + (size_t)rl * QW + col) = ll0;
            *(uint32_t*)(Obh + (size_t)rh * QW + col) = hh1;
            *(uint32_t*)(Obl + (size_t)rh * QW + col) = ll1;
        }
    }
}

// ---------------------------------------------------------------------------
// Launcher
// ---------------------------------------------------------------------------
extern "C" void kernel_launch(void* const* d_in, const int* in_sizes, int n_in,
                              void* d_out, int out_size)
{
    const float* x    = (const float*)d_in[0];
    const float* q_w  = (const float*)d_in[2];
    const float* k_w  = (const float*)d_in[3];
    const float* v_w  = (const float*)d_in[4];
    const float* o_w  = (const float*)d_in[5];
    const float* sinp = (const float*)d_in[6];
    const float* cosp = (const float*)d_in[7];
    float* out = (float*)d_out;

    __nv_bfloat16 *xh, *xl, *wh, *wl, *owh, *owl;
    cudaGetSymbolAddress((void**)&xh, g_xh);
    cudaGetSymbolAddress((void**)&xl, g_xl);
    cudaGetSymbolAddress((void**)&wh, g_wh);
    cudaGetSymbolAddress((void**)&wl, g_wl);
    cudaGetSymbolAddress((void**)&owh, g_owh);
    cudaGetSymbolAddress((void**)&owl, g_owl);
    __nv_bfloat16 *Qh, *Ql, *Kh, *Kl, *Vh, *Vl, *Ah, *Al;
    cudaGetSymbolAddress((void**)&Qh, g_Qh);
    cudaGetSymbolAddress((void**)&Ql, g_Ql);
    cudaGetSymbolAddress((void**)&Kh, g_Kh);
    cudaGetSymbolAddress((void**)&Kl, g_Kl);
    cudaGetSymbolAddress((void**)&Vh, g_Vh);
    cudaGetSymbolAddress((void**)&Vl, g_Vl);
    cudaGetSymbolAddress((void**)&Ah, g_Ah);
    cudaGetSymbolAddress((void**)&Al, g_Al);

    // 1) fused split of all fp32 operands
    split_all<<<(N4_ALL + 255) / 256, 256>>>(x, q_w, k_w, v_w, o_w,
                                             xh, xl, wh, wl, owh, owl);

    cudaFuncSetAttribute(hmma_gemm_pre<0>, cudaFuncAttributeMaxDynamicSharedMemorySize, GEMM_SMEM);
    cudaFuncSetAttribute(hmma_gemm_pre<1>, cudaFuncAttributeMaxDynamicSharedMemorySize, GEMM_SMEM);

    // 2) fused QKV projection + rope/split epilogue
    hmma_gemm_pre<1><<<dim3(W3 / 128, MTOT / 128), 128, GEMM_SMEM>>>(
        xh, xl, wh, wl, nullptr, Qh, Ql, Kh, Kl, Vh, Vl, sinp, cosp, MTOT, W3, HID);

    // 3) flash attention
    cudaFuncSetAttribute(flash_attn_mma, cudaFuncAttributeMaxDynamicSharedMemorySize, AT_SMEM);
    flash_attn_mma<<<dim3(NQT / 2, NH, 2), 128, AT_SMEM>>>(Qh, Ql, Kh, Kl, Vh, Vl, Ah, Al);

    // 4) output projection (fp32 out)
    hmma_gemm_pre<0><<<dim3(HID / 128, MTOT / 128), 128, GEMM_SMEM>>>(
        Ah, Al, owh, owl, out, nullptr, nullptr, nullptr, nullptr, nullptr, nullptr,
        nullptr, nullptr, MTOT, HID, HID);
}

// round 10
// speedup vs baseline: 2.8392x; 1.0140x over previous
#include <cuda_runtime.h>
#include <cuda_bf16.h>
#include <math.h>
#include <stdint.h>

// Problem constants
#define MTOT 4096      // B*S
#define SEQ  2048
#define HID  2048
#define NH   16
#define NKV  4
#define HD   128
#define QW   2048      // NH*HD
#define KVW  512       // NKV*HD
#define W3   3072      // fused Q|K|V weight width

// Scratch (allocation-free rule: __device__ globals)
__device__ __nv_bfloat16 g_xh[(size_t)MTOT * HID];
__device__ __nv_bfloat16 g_xl[(size_t)MTOT * HID];
__device__ __nv_bfloat16 g_wh[(size_t)W3 * HID];     // q|k|v weights fused
__device__ __nv_bfloat16 g_wl[(size_t)W3 * HID];
__device__ __nv_bfloat16 g_owh[(size_t)HID * QW];
__device__ __nv_bfloat16 g_owl[(size_t)HID * QW];
__device__ __nv_bfloat16 g_Qh[(size_t)MTOT * QW];
__device__ __nv_bfloat16 g_Ql[(size_t)MTOT * QW];
__device__ __nv_bfloat16 g_Kh[(size_t)MTOT * KVW];
__device__ __nv_bfloat16 g_Kl[(size_t)MTOT * KVW];
__device__ __nv_bfloat16 g_Vh[(size_t)MTOT * KVW];
__device__ __nv_bfloat16 g_Vl[(size_t)MTOT * KVW];
__device__ __nv_bfloat16 g_Ah[(size_t)MTOT * QW];
__device__ __nv_bfloat16 g_Al[(size_t)MTOT * QW];

// ---------------------------------------------------------------------------
// helpers
// ---------------------------------------------------------------------------
__device__ __forceinline__ void mma16816(float* c, const uint32_t* a, uint32_t b0, uint32_t b1) {
    asm volatile(
        "mma.sync.aligned.m16n8k16.row.col.f32.bf16.bf16.f32 "
        "{%0,%1,%2,%3}, {%4,%5,%6,%7}, {%8,%9}, {%0,%1,%2,%3};"
        : "+f"(c[0]), "+f"(c[1]), "+f"(c[2]), "+f"(c[3])
        : "r"(a[0]), "r"(a[1]), "r"(a[2]), "r"(a[3]), "r"(b0), "r"(b1));
}
__device__ __forceinline__ void ldm4(uint32_t* r, uint32_t a) {
    asm volatile("ldmatrix.sync.aligned.m8n8.x4.shared.b16 {%0,%1,%2,%3}, [%4];"
                 : "=r"(r[0]), "=r"(r[1]), "=r"(r[2]), "=r"(r[3]) : "r"(a));
}
__device__ __forceinline__ void ldm4t(uint32_t* r, uint32_t a) {
    asm volatile("ldmatrix.sync.aligned.m8n8.x4.trans.shared.b16 {%0,%1,%2,%3}, [%4];"
                 : "=r"(r[0]), "=r"(r[1]), "=r"(r[2]), "=r"(r[3]) : "r"(a));
}
__device__ __forceinline__ uint32_t smem_u32(const void* p) {
    uint32_t a;
    asm("{ .reg .u64 tmp; cvta.to.shared.u64 tmp, %1; cvt.u32.u64 %0, tmp; }"
        : "=r"(a) : "l"(p));
    return a;
}
__device__ __forceinline__ void cpa16(uint32_t dst, const void* src) {
    asm volatile("cp.async.cg.shared.global [%0], [%1], 16;" :: "r"(dst), "l"(src));
}
#define CPA_COMMIT() asm volatile("cp.async.commit_group;" ::: "memory")
#define CPA_WAIT(n)  asm volatile("cp.async.wait_group %0;" :: "n"(n) : "memory")

__device__ __forceinline__ void split2(float a, float b, uint32_t& h, uint32_t& l) {
    __nv_bfloat162 hh = __floats2bfloat162_rn(a, b);
    float ra = a - __bfloat162float(hh.x);
    float rb = b - __bfloat162float(hh.y);
    __nv_bfloat162 ll = __floats2bfloat162_rn(ra, rb);
    h = *(uint32_t*)&hh;
    l = *(uint32_t*)&ll;
}

// ---------------------------------------------------------------------------
// One fused split kernel: x, q_w, k_w, v_w -> (xh/xl, wh/wl fused), o_w -> owh/owl
// ---------------------------------------------------------------------------
#define N4_X   (MTOT * HID / 4)
#define N4_QW  (QW * HID / 4)
#define N4_KW  (KVW * HID / 4)
#define N4_ALL (N4_X + N4_QW + 2 * N4_KW + N4_QW)

__global__ void split_all(const float* __restrict__ x, const float* __restrict__ qw,
                          const float* __restrict__ kw, const float* __restrict__ vw,
                          const float* __restrict__ ow,
                          __nv_bfloat16* __restrict__ xh, __nv_bfloat16* __restrict__ xl,
                          __nv_bfloat16* __restrict__ wh, __nv_bfloat16* __restrict__ wl,
                          __nv_bfloat16* __restrict__ owh, __nv_bfloat16* __restrict__ owl)
{
    int i = blockIdx.x * blockDim.x + threadIdx.x;
    if (i >= N4_ALL) return;
    const float* src;
    __nv_bfloat16 *dh, *dl;
    int j = i;
    if (j < N4_X)                  { src = x;  dh = xh; dl = xl; }
    else if ((j -= N4_X) < N4_QW)  { src = qw; dh = wh; dl = wl; }
    else if ((j -= N4_QW) < N4_KW) { src = kw; dh = wh + (size_t)QW * HID; dl = wl + (size_t)QW * HID; }
    else if ((j -= N4_KW) < N4_KW) { src = vw; dh = wh + (size_t)(QW + KVW) * HID; dl = wl + (size_t)(QW + KVW) * HID; }
    else                           { j -= N4_KW; src = ow; dh = owh; dl = owl; }
    float4 v = ((const float4*)src)[j];
    uint32_t h0, l0, h1, l1;
    split2(v.x, v.y, h0, l0);
    split2(v.z, v.w, h1, l1);
    ((uint2*)dh)[j] = make_uint2(h0, h1);
    ((uint2*)dl)[j] = make_uint2(l0, l1);
}

// ---------------------------------------------------------------------------
// NT GEMM on pre-split bf16 operands, 3-term split.
// 128 threads = 4 warps (2x2), warp tile 64x64, BM=BN=128, BK=32.
// Fragment-software-pipelined: ldmatrix for (kk,mt+1)/(kk+1) issued under
// the MMAs of (kk,mt). MMA order per accumulator unchanged (bit-identical).
// MODE 0: fp32 C out.  MODE 1: fused QKV epilogue (rope Q/K, split -> bf16).
// ---------------------------------------------------------------------------
#define GROW  80
#define GT    (128 * GROW)            // 10240 B
#define STG_B (4 * GT)                // 40960 B
#define GEMM_SMEM (2 * STG_B)         // 81920 B

template<int MODE>
__global__ __launch_bounds__(128)
void hmma_gemm_pre(const __nv_bfloat16* __restrict__ Ah, const __nv_bfloat16* __restrict__ Al,
                   const __nv_bfloat16* __restrict__ Bh, const __nv_bfloat16* __restrict__ Bl,
                   float* __restrict__ C,
                   __nv_bfloat16* __restrict__ Qoh, __nv_bfloat16* __restrict__ Qol,
                   __nv_bfloat16* __restrict__ Koh, __nv_bfloat16* __restrict__ Kol,
                   __nv_bfloat16* __restrict__ Voh, __nv_bfloat16* __restrict__ Vol,
                   const float* __restrict__ sinp, const float* __restrict__ cosp,
                   int M, int N, int K)
{
    extern __shared__ __align__(128) char smem[];
    const uint32_t sb = smem_u32(smem);

    const int t    = threadIdx.x;
    const int warp = t >> 5;
    const int lane = t & 31;
    const int wm   = warp >> 1;        // 0..1 (M)
    const int wn   = warp & 1;         // 0..1 (N)
    const int bm   = blockIdx.y * 128;
    const int bn   = blockIdx.x * 128;

    const __nv_bfloat16* srcA[2] = { Ah, Al };
    const __nv_bfloat16* srcB[2] = { Bh, Bl };

    float acc[4][8][4];
#pragma unroll
    for (int mi = 0; mi < 4; mi++)
#pragma unroll
        for (int ni = 0; ni < 8; ni++)
#pragma unroll
            for (int r = 0; r < 4; r++) acc[mi][ni][r] = 0.f;

    const int S = K / 32;

    // 128 threads: per tile 512 chunks -> 4 per thread
    auto issue = [&](int s, int buf) {
        const int k0 = s * 32;
        const uint32_t stg = sb + (uint32_t)buf * STG_B;
#pragma unroll
        for (int i = 0; i < 4; i++) {
            int f = i * 128 + t;
            int r = f >> 2, ch = f & 3;
            uint32_t so = r * GROW + ch * 16;
            size_t  goA = (size_t)(bm + r) * K + k0 + ch * 8;
            size_t  goB = (size_t)(bn + r) * K + k0 + ch * 8;
            cpa16(stg + 0 * GT + so, srcA[0] + goA);
            cpa16(stg + 1 * GT + so, srcA[1] + goA);
            cpa16(stg + 2 * GT + so, srcB[0] + goB);
            cpa16(stg + 3 * GT + so, srcB[1] + goB);
        }
        CPA_COMMIT();
    };

    issue(0, 0);

    // fragment buffers (software pipeline)
    uint32_t Bfh[2][4][4], Bfl[2][4][4];   // [kk][ng][4]
    uint32_t Afh[2][4], Afl[2][4];         // double buffer

    for (int s = 0; s < S; s++) {
        const int buf = s & 1;
        if (s + 1 < S) { issue(s + 1, buf ^ 1); CPA_WAIT(1); }
        else           { CPA_WAIT(0); }
        __syncthreads();

        const uint32_t smAh = sb + (uint32_t)buf * STG_B;
        const uint32_t smAl = smAh + GT;
        const uint32_t smBh = smAh + 2 * GT;
        const uint32_t smBl = smAh + 3 * GT;

        auto ldmB = [&](int kk) {
#pragma unroll
            for (int ng = 0; ng < 4; ng++) {
                int rr = wn * 64 + ng * 16 + (lane & 15);
                uint32_t ad = rr * GROW + (kk * 2 + (lane >> 4)) * 16;
                ldm4(Bfh[kk][ng], smBh + ad);
                ldm4(Bfl[kk][ng], smBl + ad);
            }
        };
        auto ldmA = [&](int kk, int mt, int slot) {
            int rr = wm * 64 + mt * 16 + (lane & 15);
            uint32_t ad = rr * GROW + (kk * 2 + (lane >> 4)) * 16;
            ldm4(Afh[slot], smAh + ad);
            ldm4(Afl[slot], smAl + ad);
        };

        ldmB(0);
        ldmA(0, 0, 0);

#pragma unroll
        for (int kk = 0; kk < 2; kk++) {
#pragma unroll
            for (int mt = 0; mt < 4; mt++) {
                const int slot = (kk * 4 + mt) & 1;
                const int nslot = slot ^ 1;
                // prefetch next step's fragments under this step's MMAs
                if (mt < 3)            ldmA(kk, mt + 1, nslot);
                else if (kk == 0)    { ldmB(1); ldmA(1, 0, nslot); }

                // term-major MMAs (order per accumulator unchanged)
#pragma unroll
                for (int n8 = 0; n8 < 8; n8++) {
                    int ng = n8 >> 1, hf = n8 & 1;
                    mma16816(acc[mt][n8], Afh[slot], Bfh[kk][ng][hf], Bfh[kk][ng][hf + 2]);
                }
#pragma unroll
                for (int n8 = 0; n8 < 8; n8++) {
                    int ng = n8 >> 1, hf = n8 & 1;
                    mma16816(acc[mt][n8], Afl[slot], Bfh[kk][ng][hf], Bfh[kk][ng][hf + 2]);
                }
#pragma unroll
                for (int n8 = 0; n8 < 8; n8++) {
                    int ng = n8 >> 1, hf = n8 & 1;
                    mma16816(acc[mt][n8], Afh[slot], Bfl[kk][ng][hf], Bfl[kk][ng][hf + 2]);
                }
            }
        }
        __syncthreads();
    }

    const int g   = lane >> 2;
    const int tig = lane & 3;

    if (MODE == 0) {
#pragma unroll
        for (int mt = 0; mt < 4; mt++)
#pragma unroll
            for (int n8 = 0; n8 < 8; n8++) {
                int row = bm + wm * 64 + mt * 16 + g;
                int col = bn + wn * 64 + n8 * 8 + tig * 2;
                *(float2*)(C + (size_t)row * N + col) = make_float2(acc[mt][n8][0], acc[mt][n8][1]);
                *(float2*)(C + (size_t)(row + 8) * N + col) = make_float2(acc[mt][n8][2], acc[mt][n8][3]);
            }
        return;
    }

    // MODE 1: stage acc -> smem, rope(optional) + bf16 split -> bf16 hi/lo out
    float* stg = (float*)smem;   // [128][132]
#pragma unroll
    for (int mt = 0; mt < 4; mt++)
#pragma unroll
        for (int n8 = 0; n8 < 8; n8++) {
            int row = wm * 64 + mt * 16 + g;
            int col = wn * 64 + n8 * 8 + tig * 2;
            stg[row * 132 + col]     = acc[mt][n8][0];
            stg[row * 132 + col + 1] = acc[mt][n8][1];
            stg[(row + 8) * 132 + col]     = acc[mt][n8][2];
            stg[(row + 8) * 132 + col + 1] = acc[mt][n8][3];
        }
    __syncthreads();

    {
        const int r    = t;             // 128 threads, one row each
        const int gm   = bm + r;
        const int spos = gm & (SEQ - 1);

        bool rot;
        __nv_bfloat16 *dh, *dl;
        int bx = blockIdx.x;
        if (bx < 16) {
            rot = true;
            dh = Qoh + (size_t)gm * QW + bx * 128;
            dl = Qol + (size_t)gm * QW + bx * 128;
        } else if (bx < 20) {
            rot = true;
            dh = Koh + (size_t)gm * KVW + (bx - 16) * 128;
            dl = Kol + (size_t)gm * KVW + (bx - 16) * 128;
        } else {
            rot = false;
            dh = Voh + (size_t)gm * KVW + (bx - 20) * 128;
            dl = Vol + (size_t)gm * KVW + (bx - 20) * 128;
        }

#pragma unroll
        for (int half = 0; half < 2; half++) {
            const int pb = half * 32;
            uint32_t h0[16], l0[16], h1[16], l1[16];
#pragma unroll
            for (int j = 0; j < 16; j++) {
                int pi = pb + j * 2;
                float x0a = stg[r * 132 + pi],      x0b = stg[r * 132 + pi + 1];
                float x1a = stg[r * 132 + pi + 64], x1b = stg[r * 132 + pi + 65];
                float y0a, y0b, y1a, y1b;
                if (rot) {
                    float ca = cosp[(size_t)spos * HD + pi],  cb = cosp[(size_t)spos * HD + pi + 1];
                    float sa = sinp[(size_t)spos * HD + pi],  sbv = sinp[(size_t)spos * HD + pi + 1];
                    y0a = x0a * ca - x1a * sa;  y1a = x1a * ca + x0a * sa;
                    y0b = x0b * cb - x1b * sbv; y1b = x1b * cb + x0b * sbv;
                } else {
                    y0a = x0a; y0b = x0b; y1a = x1a; y1b = x1b;
                }
                split2(y0a, y0b, h0[j], l0[j]);
                split2(y1a, y1b, h1[j], l1[j]);
            }
#pragma unroll
            for (int w = 0; w < 4; w++) {
                *(uint4*)(dh + pb + w * 8)      = ((uint4*)h0)[w];
                *(uint4*)(dh + 64 + pb + w * 8) = ((uint4*)h1)[w];
                *(uint4*)(dl + pb + w * 8)      = ((uint4*)l0)[w];
                *(uint4*)(dl + 64 + pb + w * 8) = ((uint4*)l1)[w];
            }
        }
    }
}

// ---------------------------------------------------------------------------
// Flash attention, bf16 mma.sync, cp.async K/V pipeline, causal pair-balanced.
// ---------------------------------------------------------------------------
#define AT_TILE 16384
#define AT_SMEM (6 * AT_TILE)               // 98304 B
#define NQT     (SEQ / 64)                  // 32

__device__ __forceinline__ uint32_t swz256(int r, int ch) {
    return (uint32_t)(r * 256 + (((ch ^ (r & 7)) & 15) << 4));
}

__global__ __launch_bounds__(128)
void flash_attn_mma(const __nv_bfloat16* __restrict__ Qh, const __nv_bfloat16* __restrict__ Ql,
                    const __nv_bfloat16* __restrict__ Kh, const __nv_bfloat16* __restrict__ Kl,
                    const __nv_bfloat16* __restrict__ Vh, const __nv_bfloat16* __restrict__ Vl,
                    __nv_bfloat16* __restrict__ OAh, __nv_bfloat16* __restrict__ OAl)
{
    extern __shared__ __align__(128) char smem[];
    const uint32_t sb  = smem_u32(smem);
    const uint32_t sQh = sb;
    const uint32_t sQl = sb + AT_TILE;
    const uint32_t sA  = sb + 2 * AT_TILE;   // K stage: {h, l}
    const uint32_t sB  = sb + 4 * AT_TILE;   // V stage: {h, l}

    const int h   = blockIdx.y;
    const int b   = blockIdx.z;
    const int kvh = h >> 2;
    const int t   = threadIdx.x;
    const int warp = t >> 5;
    const int lane = t & 31;
    const int g    = lane >> 2;
    const int tig  = lane & 3;

    const int rl = warp * 16 + g;
    const int rh = rl + 8;

    auto load_kv = [&](const __nv_bfloat16* srch, const __nv_bfloat16* srcl,
                       uint32_t dst, int kt) {
        const __nv_bfloat16* bh = srch + (size_t)(b * SEQ + kt * 64) * KVW + kvh * HD;
        const __nv_bfloat16* bl = srcl + (size_t)(b * SEQ + kt * 64) * KVW + kvh * HD;
#pragma unroll
        for (int i = 0; i < 8; i++) {
            int f = i * 128 + t;
            int r = f >> 4, ch = f & 15;
            cpa16(dst + swz256(r, ch),           bh + (size_t)r * KVW + ch * 8);
            cpa16(dst + AT_TILE + swz256(r, ch), bl + (size_t)r * KVW + ch * 8);
        }
        CPA_COMMIT();
    };

    for (int sel = 0; sel < 2; sel++) {
        const int qt = sel ? (NQT - 1 - blockIdx.x) : blockIdx.x;
        const int q0 = qt * 64;

        // Q tiles (cp.async)
        {
            const __nv_bfloat16* qbh = Qh + (size_t)(b * SEQ + q0) * QW + h * HD;
            const __nv_bfloat16* qbl = Ql + (size_t)(b * SEQ + q0) * QW + h * HD;
#pragma unroll
            for (int i = 0; i < 8; i++) {
                int f = i * 128 + t;
                int r = f >> 4, ch = f & 15;
                cpa16(sQh + swz256(r, ch), qbh + (size_t)r * QW + ch * 8);
                cpa16(sQl + swz256(r, ch), qbl + (size_t)r * QW + ch * 8);
            }
            CPA_COMMIT();
        }
        load_kv(Kh, Kl, sA, 0);
        CPA_WAIT(0);
        __syncthreads();

        float o[16][4];
        float m0 = -1e30f, m1 = -1e30f, l0 = 0.f, l1 = 0.f;
#pragma unroll
        for (int i = 0; i < 16; i++)
#pragma unroll
            for (int j = 0; j < 4; j++) o[i][j] = 0.f;

        for (int kt = 0; kt <= qt; kt++) {
            load_kv(Vh, Vl, sB, kt);

            float sacc[8][4];
#pragma unroll
            for (int i = 0; i < 8; i++)
#pragma unroll
                for (int j = 0; j < 4; j++) sacc[i][j] = 0.f;

#pragma unroll
            for (int ks = 0; ks < 8; ks++) {
                uint32_t qfh[4], qfl[4];
                {
                    int rr = warp * 16 + (lane & 15);
                    uint32_t ad = swz256(rr, ks * 2 + (lane >> 4));
                    ldm4(qfh, sQh + ad);
                    ldm4(qfl, sQl + ad);
                }
                uint32_t kfh[4][4], kfl[4][4];
#pragma unroll
                for (int ng = 0; ng < 4; ng++) {
                    int rr = ng * 16 + (lane & 15);
                    uint32_t ad = swz256(rr, ks * 2 + (lane >> 4));
                    ldm4(kfh[ng], sA + ad);
                    ldm4(kfl[ng], sA + AT_TILE + ad);
                }
#pragma unroll
                for (int n8 = 0; n8 < 8; n8++) {
                    int ng = n8 >> 1, hf = n8 & 1;
                    mma16816(sacc[n8], qfh, kfh[ng][hf], kfh[ng][hf + 2]);
                }
#pragma unroll
                for (int n8 = 0; n8 < 8; n8++) {
                    int ng = n8 >> 1, hf = n8 & 1;
                    mma16816(sacc[n8], qfl, kfh[ng][hf], kfh[ng][hf + 2]);
                }
#pragma unroll
                for (int n8 = 0; n8 < 8; n8++) {
                    int ng = n8 >> 1, hf = n8 & 1;
                    mma16816(sacc[n8], qfh, kfl[ng][hf], kfl[ng][hf + 2]);
                }
            }

            if (kt == qt) {
#pragma unroll
                for (int n8 = 0; n8 < 8; n8++) {
                    int c0 = n8 * 8 + tig * 2, c1 = c0 + 1;
                    if (c0 > rl) sacc[n8][0] = -1e30f;
                    if (c1 > rl) sacc[n8][1] = -1e30f;
                    if (c0 > rh) sacc[n8][2] = -1e30f;
                    if (c1 > rh) sacc[n8][3] = -1e30f;
                }
            }

            float mx0 = -1e30f, mx1 = -1e30f;
#pragma unroll
            for (int n8 = 0; n8 < 8; n8++) {
                mx0 = fmaxf(mx0, fmaxf(sacc[n8][0], sacc[n8][1]));
                mx1 = fmaxf(mx1, fmaxf(sacc[n8][2], sacc[n8][3]));
            }
            mx0 = fmaxf(mx0, __shfl_xor_sync(0xffffffffu, mx0, 1));
            mx0 = fmaxf(mx0, __shfl_xor_sync(0xffffffffu, mx0, 2));
            mx1 = fmaxf(mx1, __shfl_xor_sync(0xffffffffu, mx1, 1));
            mx1 = fmaxf(mx1, __shfl_xor_sync(0xffffffffu, mx1, 2));

            float mn0 = fmaxf(m0, mx0), mn1 = fmaxf(m1, mx1);
            float al0 = __expf(m0 - mn0), al1 = __expf(m1 - mn1);
            m0 = mn0; m1 = mn1;

            float s0 = 0.f, s1 = 0.f;
#pragma unroll
            for (int n8 = 0; n8 < 8; n8++) {
                float p0 = __expf(sacc[n8][0] - m0);
                float p1 = __expf(sacc[n8][1] - m0);
                float p2 = __expf(sacc[n8][2] - m1);
                float p3 = __expf(sacc[n8][3] - m1);
                sacc[n8][0] = p0; sacc[n8][1] = p1; sacc[n8][2] = p2; sacc[n8][3] = p3;
                s0 += p0 + p1; s1 += p2 + p3;
            }
            s0 += __shfl_xor_sync(0xffffffffu, s0, 1);
            s0 += __shfl_xor_sync(0xffffffffu, s0, 2);
            s1 += __shfl_xor_sync(0xffffffffu, s1, 1);
            s1 += __shfl_xor_sync(0xffffffffu, s1, 2);
            l0 = l0 * al0 + s0;
            l1 = l1 * al1 + s1;

#pragma unroll
            for (int i = 0; i < 16; i++) {
                o[i][0] *= al0; o[i][1] *= al0;
                o[i][2] *= al1; o[i][3] *= al1;
            }

            uint32_t ph[4][4], pl[4][4];
#pragma unroll
            for (int kk = 0; kk < 4; kk++) {
                split2(sacc[2 * kk][0],     sacc[2 * kk][1],     ph[kk][0], pl[kk][0]);
                split2(sacc[2 * kk][2],     sacc[2 * kk][3],     ph[kk][1], pl[kk][1]);
                split2(sacc[2 * kk + 1][0], sacc[2 * kk + 1][1], ph[kk][2], pl[kk][2]);
                split2(sacc[2 * kk + 1][2], sacc[2 * kk + 1][3], ph[kk][3], pl[kk][3]);
            }

            CPA_WAIT(0);
            __syncthreads();

            if (kt < qt) load_kv(Kh, Kl, sA, kt + 1);

#pragma unroll
            for (int ng = 0; ng < 8; ng++) {
#pragma unroll
                for (int kk = 0; kk < 4; kk++) {
                    uint32_t vfh[4], vfl[4];
                    int rr = kk * 16 + (lane & 15);
                    uint32_t ad = swz256(rr, ng * 2 + (lane >> 4));
                    ldm4t(vfh, sB + ad);
                    ldm4t(vfl, sB + AT_TILE + ad);
#pragma unroll
                    for (int hf = 0; hf < 2; hf++) {
                        int nt = ng * 2 + hf;
                        uint32_t b0 = vfh[hf * 2], b1 = vfh[hf * 2 + 1];
                        mma16816(o[nt], ph[kk], b0, b1);
                        mma16816(o[nt], pl[kk], b0, b1);
                        mma16816(o[nt], ph[kk], vfl[hf * 2], vfl[hf * 2 + 1]);
                    }
                }
            }

            CPA_WAIT(0);
            __syncthreads();
        }

        float inv0 = 1.f / l0, inv1 = 1.f / l1;
        __nv_bfloat16* Obh = OAh + (size_t)(b * SEQ + q0) * QW + h * HD;
        __nv_bfloat16* Obl = OAl + (size_t)(b * SEQ + q0) * QW + h * HD;
#pragma unroll
        for (int nt = 0; nt < 16; nt++) {
            int col = nt * 8 + tig * 2;
            uint32_t hh0, ll0, hh1, ll1;
            split2(o[nt][0] * inv0, o[nt][1] * inv0, hh0, ll0);
            split2(o[nt][2] * inv1, o[nt][3] * inv1, hh1, ll1);
            *(uint32_t*)(Obh + (size_t)rl * QW + col) = hh0;
            *(uint32_t*)(Obl + (size_t)rl * QW + col) = ll0;
            *(uint32_t*)(Obh + (size_t)rh * QW + col) = hh1;
            *(uint32_t*)(Obl + (size_t)rh * QW + col) = ll1;
        }
    }
}

// ---------------------------------------------------------------------------
// Launcher
// ---------------------------------------------------------------------------
extern "C" void kernel_launch(void* const* d_in, const int* in_sizes, int n_in,
                              void* d_out, int out_size)
{
    const float* x    = (const float*)d_in[0];
    const float* q_w  = (const float*)d_in[2];
    const float* k_w  = (const float*)d_in[3];
    const float* v_w  = (const float*)d_in[4];
    const float* o_w  = (const float*)d_in[5];
    const float* sinp = (const float*)d_in[6];
    const float* cosp = (const float*)d_in[7];
    float* out = (float*)d_out;

    __nv_bfloat16 *xh, *xl, *wh, *wl, *owh, *owl;
    cudaGetSymbolAddress((void**)&xh, g_xh);
    cudaGetSymbolAddress((void**)&xl, g_xl);
    cudaGetSymbolAddress((void**)&wh, g_wh);
    cudaGetSymbolAddress((void**)&wl, g_wl);
    cudaGetSymbolAddress((void**)&owh, g_owh);
    cudaGetSymbolAddress((void**)&owl, g_owl);
    __nv_bfloat16 *Qh, *Ql, *Kh, *Kl, *Vh, *Vl, *Ah, *Al;
    cudaGetSymbolAddress((void**)&Qh, g_Qh);
    cudaGetSymbolAddress((void**)&Ql, g_Ql);
    cudaGetSymbolAddress((void**)&Kh, g_Kh);
    cudaGetSymbolAddress((void**)&Kl, g_Kl);
    cudaGetSymbolAddress((void**)&Vh, g_Vh);
    cudaGetSymbolAddress((void**)&Vl, g_Vl);
    cudaGetSymbolAddress((void**)&Ah, g_Ah);
    cudaGetSymbolAddress((void**)&Al, g_Al);

    // 1) fused split of all fp32 operands
    split_all<<<(N4_ALL + 255) / 256, 256>>>(x, q_w, k_w, v_w, o_w,
                                             xh, xl, wh, wl, owh, owl);

    cudaFuncSetAttribute(hmma_gemm_pre<0>, cudaFuncAttributeMaxDynamicSharedMemorySize, GEMM_SMEM);
    cudaFuncSetAttribute(hmma_gemm_pre<1>, cudaFuncAttributeMaxDynamicSharedMemorySize, GEMM_SMEM);

    // 2) fused QKV projection + rope/split epilogue
    hmma_gemm_pre<1><<<dim3(W3 / 128, MTOT / 128), 128, GEMM_SMEM>>>(
        xh, xl, wh, wl, nullptr, Qh, Ql, Kh, Kl, Vh, Vl, sinp, cosp, MTOT, W3, HID);

    // 3) flash attention
    cudaFuncSetAttribute(flash_attn_mma, cudaFuncAttributeMaxDynamicSharedMemorySize, AT_SMEM);
    flash_attn_mma<<<dim3(NQT / 2, NH, 2), 128, AT_SMEM>>>(Qh, Ql, Kh, Kl, Vh, Vl, Ah, Al);

    // 4) output projection (fp32 out)
    hmma_gemm_pre<0><<<dim3(HID / 128, MTOT / 128), 128, GEMM_SMEM>>>(
        Ah, Al, owh, owl, out, nullptr, nullptr, nullptr, nullptr, nullptr, nullptr,
        nullptr, nullptr, MTOT, HID, HID);
}

// round 11
// speedup vs baseline: 3.3777x; 1.1897x over previous
#include <cuda_runtime.h>
#include <cuda_bf16.h>
#include <cuda_fp16.h>
#include <math.h>
#include <stdint.h>

// Problem constants
#define MTOT 4096      // B*S
#define SEQ  2048
#define HID  2048
#define NH   16
#define NKV  4
#define HD   128
#define QW   2048      // NH*HD
#define KVW  512       // NKV*HD
#define W3   3072      // fused Q|K|V weight width

// Scratch (allocation-free rule: __device__ globals)
__device__ __nv_bfloat16 g_xh[(size_t)MTOT * HID];
__device__ __nv_bfloat16 g_xl[(size_t)MTOT * HID];
__device__ __nv_bfloat16 g_wh[(size_t)W3 * HID];     // q|k|v weights fused (bf16 hi)
__device__ __nv_bfloat16 g_wl[(size_t)W3 * HID];
__device__ __half        g_owf[(size_t)HID * QW];    // o_w single fp16
__device__ __nv_bfloat16 g_Qh[(size_t)MTOT * QW];
__device__ __nv_bfloat16 g_Ql[(size_t)MTOT * QW];
__device__ __nv_bfloat16 g_Kh[(size_t)MTOT * KVW];
__device__ __nv_bfloat16 g_Kl[(size_t)MTOT * KVW];
__device__ __half        g_Vf[(size_t)MTOT * KVW];   // V single fp16
__device__ __half        g_Ah[(size_t)MTOT * QW];    // attn out fp16 hi
__device__ __half        g_Al[(size_t)MTOT * QW];    // attn out fp16 lo

// ---------------------------------------------------------------------------
// helpers
// ---------------------------------------------------------------------------
__device__ __forceinline__ void mma16816(float* c, const uint32_t* a, uint32_t b0, uint32_t b1) {
    asm volatile(
        "mma.sync.aligned.m16n8k16.row.col.f32.bf16.bf16.f32 "
        "{%0,%1,%2,%3}, {%4,%5,%6,%7}, {%8,%9}, {%0,%1,%2,%3};"
        : "+f"(c[0]), "+f"(c[1]), "+f"(c[2]), "+f"(c[3])
        : "r"(a[0]), "r"(a[1]), "r"(a[2]), "r"(a[3]), "r"(b0), "r"(b1));
}
__device__ __forceinline__ void mma16816f(float* c, const uint32_t* a, uint32_t b0, uint32_t b1) {
    asm volatile(
        "mma.sync.aligned.m16n8k16.row.col.f32.f16.f16.f32 "
        "{%0,%1,%2,%3}, {%4,%5,%6,%7}, {%8,%9}, {%0,%1,%2,%3};"
        : "+f"(c[0]), "+f"(c[1]), "+f"(c[2]), "+f"(c[3])
        : "r"(a[0]), "r"(a[1]), "r"(a[2]), "r"(a[3]), "r"(b0), "r"(b1));
}
__device__ __forceinline__ void ldm4(uint32_t* r, uint32_t a) {
    asm volatile("ldmatrix.sync.aligned.m8n8.x4.shared.b16 {%0,%1,%2,%3}, [%4];"
                 : "=r"(r[0]), "=r"(r[1]), "=r"(r[2]), "=r"(r[3]) : "r"(a));
}
__device__ __forceinline__ void ldm4t(uint32_t* r, uint32_t a) {
    asm volatile("ldmatrix.sync.aligned.m8n8.x4.trans.shared.b16 {%0,%1,%2,%3}, [%4];"
                 : "=r"(r[0]), "=r"(r[1]), "=r"(r[2]), "=r"(r[3]) : "r"(a));
}
__device__ __forceinline__ uint32_t smem_u32(const void* p) {
    uint32_t a;
    asm("{ .reg .u64 tmp; cvta.to.shared.u64 tmp, %1; cvt.u32.u64 %0, tmp; }"
        : "=r"(a) : "l"(p));
    return a;
}
__device__ __forceinline__ void cpa16(uint32_t dst, const void* src) {
    asm volatile("cp.async.cg.shared.global [%0], [%1], 16;" :: "r"(dst), "l"(src));
}
#define CPA_COMMIT() asm volatile("cp.async.commit_group;" ::: "memory")
#define CPA_WAIT(n)  asm volatile("cp.async.wait_group %0;" :: "n"(n) : "memory")

// bf16 split (hi/lo)
__device__ __forceinline__ void split2(float a, float b, uint32_t& h, uint32_t& l) {
    __nv_bfloat162 hh = __floats2bfloat162_rn(a, b);
    float ra = a - __bfloat162float(hh.x);
    float rb = b - __bfloat162float(hh.y);
    __nv_bfloat162 ll = __floats2bfloat162_rn(ra, rb);
    h = *(uint32_t*)&hh;
    l = *(uint32_t*)&ll;
}
// fp16 pack (single)
__device__ __forceinline__ uint32_t packh2(float a, float b) {
    __half2 h = __floats2half2_rn(a, b);
    return *(uint32_t*)&h;
}
// fp16 split (hi/lo)
__device__ __forceinline__ void splitf2(float a, float b, uint32_t& h, uint32_t& l) {
    __half2 hh = __floats2half2_rn(a, b);
    float ra = a - __half2float(hh.x);
    float rb = b - __half2float(hh.y);
    __half2 ll = __floats2half2_rn(ra, rb);
    h = *(uint32_t*)&hh;
    l = *(uint32_t*)&ll;
}

// ---------------------------------------------------------------------------
// Fused split kernel: x, q_w, k_w, v_w -> bf16 hi/lo; o_w -> single fp16
// ---------------------------------------------------------------------------
#define N4_X   (MTOT * HID / 4)
#define N4_QW  (QW * HID / 4)
#define N4_KW  (KVW * HID / 4)
#define N4_ALL (N4_X + N4_QW + 2 * N4_KW + N4_QW)

__global__ void split_all(const float* __restrict__ x, const float* __restrict__ qw,
                          const float* __restrict__ kw, const float* __restrict__ vw,
                          const float* __restrict__ ow,
                          __nv_bfloat16* __restrict__ xh, __nv_bfloat16* __restrict__ xl,
                          __nv_bfloat16* __restrict__ wh, __nv_bfloat16* __restrict__ wl,
                          __half* __restrict__ owf)
{
    int i = blockIdx.x * blockDim.x + threadIdx.x;
    if (i >= N4_ALL) return;
    const float* src;
    __nv_bfloat16 *dh, *dl;
    int j = i;
    bool is_ow = false;
    if (j < N4_X)                  { src = x;  dh = xh; dl = xl; }
    else if ((j -= N4_X) < N4_QW)  { src = qw; dh = wh; dl = wl; }
    else if ((j -= N4_QW) < N4_KW) { src = kw; dh = wh + (size_t)QW * HID; dl = wl + (size_t)QW * HID; }
    else if ((j -= N4_KW) < N4_KW) { src = vw; dh = wh + (size_t)(QW + KVW) * HID; dl = wl + (size_t)(QW + KVW) * HID; }
    else                           { j -= N4_KW; src = ow; is_ow = true; dh = nullptr; dl = nullptr; }
    float4 v = ((const float4*)src)[j];
    if (is_ow) {
        ((uint2*)owf)[j] = make_uint2(packh2(v.x, v.y), packh2(v.z, v.w));
    } else {
        uint32_t h0, l0, h1, l1;
        split2(v.x, v.y, h0, l0);
        split2(v.z, v.w, h1, l1);
        ((uint2*)dh)[j] = make_uint2(h0, h1);
        ((uint2*)dl)[j] = make_uint2(l0, l1);
    }
}

// ---------------------------------------------------------------------------
// Fused QKV GEMM (bf16 3-term) + epilogue: Q/K rope + bf16 split; V -> fp16.
// 128 threads = 4 warps (2x2), warp tile 64x64, BM=BN=128, BK=32.
// ---------------------------------------------------------------------------
#define GROW  80
#define GT    (128 * GROW)            // 10240 B
#define STG_B (4 * GT)                // 40960 B
#define GEMM_SMEM (2 * STG_B)         // 81920 B

__global__ __launch_bounds__(128)
void hmma_gemm_qkv(const __nv_bfloat16* __restrict__ Ah, const __nv_bfloat16* __restrict__ Al,
                   const __nv_bfloat16* __restrict__ Bh, const __nv_bfloat16* __restrict__ Bl,
                   __nv_bfloat16* __restrict__ Qoh, __nv_bfloat16* __restrict__ Qol,
                   __nv_bfloat16* __restrict__ Koh, __nv_bfloat16* __restrict__ Kol,
                   __half* __restrict__ Vof,
                   const float* __restrict__ sinp, const float* __restrict__ cosp,
                   int M, int N, int K)
{
    extern __shared__ __align__(128) char smem[];
    const uint32_t sb = smem_u32(smem);

    const int t    = threadIdx.x;
    const int warp = t >> 5;
    const int lane = t & 31;
    const int wm   = warp >> 1;
    const int wn   = warp & 1;
    const int bm   = blockIdx.y * 128;
    const int bn   = blockIdx.x * 128;

    const __nv_bfloat16* srcA[2] = { Ah, Al };
    const __nv_bfloat16* srcB[2] = { Bh, Bl };

    float acc[4][8][4];
#pragma unroll
    for (int mi = 0; mi < 4; mi++)
#pragma unroll
        for (int ni = 0; ni < 8; ni++)
#pragma unroll
            for (int r = 0; r < 4; r++) acc[mi][ni][r] = 0.f;

    const int S = K / 32;

    auto issue = [&](int s, int buf) {
        const int k0 = s * 32;
        const uint32_t stg = sb + (uint32_t)buf * STG_B;
#pragma unroll
        for (int i = 0; i < 4; i++) {
            int f = i * 128 + t;
            int r = f >> 2, ch = f & 3;
            uint32_t so = r * GROW + ch * 16;
            size_t  goA = (size_t)(bm + r) * K + k0 + ch * 8;
            size_t  goB = (size_t)(bn + r) * K + k0 + ch * 8;
            cpa16(stg + 0 * GT + so, srcA[0] + goA);
            cpa16(stg + 1 * GT + so, srcA[1] + goA);
            cpa16(stg + 2 * GT + so, srcB[0] + goB);
            cpa16(stg + 3 * GT + so, srcB[1] + goB);
        }
        CPA_COMMIT();
    };

    issue(0, 0);

    uint32_t Bfh[2][4][4], Bfl[2][4][4];
    uint32_t Afh[2][4], Afl[2][4];

    for (int s = 0; s < S; s++) {
        const int buf = s & 1;
        if (s + 1 < S) { issue(s + 1, buf ^ 1); CPA_WAIT(1); }
        else           { CPA_WAIT(0); }
        __syncthreads();

        const uint32_t smAh = sb + (uint32_t)buf * STG_B;
        const uint32_t smAl = smAh + GT;
        const uint32_t smBh = smAh + 2 * GT;
        const uint32_t smBl = smAh + 3 * GT;

        auto ldmB = [&](int kk) {
#pragma unroll
            for (int ng = 0; ng < 4; ng++) {
                int rr = wn * 64 + ng * 16 + (lane & 15);
                uint32_t ad = rr * GROW + (kk * 2 + (lane >> 4)) * 16;
                ldm4(Bfh[kk][ng], smBh + ad);
                ldm4(Bfl[kk][ng], smBl + ad);
            }
        };
        auto ldmA = [&](int kk, int mt, int slot) {
            int rr = wm * 64 + mt * 16 + (lane & 15);
            uint32_t ad = rr * GROW + (kk * 2 + (lane >> 4)) * 16;
            ldm4(Afh[slot], smAh + ad);
            ldm4(Afl[slot], smAl + ad);
        };

        ldmB(0);
        ldmA(0, 0, 0);

#pragma unroll
        for (int kk = 0; kk < 2; kk++) {
#pragma unroll
            for (int mt = 0; mt < 4; mt++) {
                const int slot = (kk * 4 + mt) & 1;
                const int nslot = slot ^ 1;
                if (mt < 3)            ldmA(kk, mt + 1, nslot);
                else if (kk == 0)    { ldmB(1); ldmA(1, 0, nslot); }

#pragma unroll
                for (int n8 = 0; n8 < 8; n8++) {
                    int ng = n8 >> 1, hf = n8 & 1;
                    mma16816(acc[mt][n8], Afh[slot], Bfh[kk][ng][hf], Bfh[kk][ng][hf + 2]);
                }
#pragma unroll
                for (int n8 = 0; n8 < 8; n8++) {
                    int ng = n8 >> 1, hf = n8 & 1;
                    mma16816(acc[mt][n8], Afl[slot], Bfh[kk][ng][hf], Bfh[kk][ng][hf + 2]);
                }
#pragma unroll
                for (int n8 = 0; n8 < 8; n8++) {
                    int ng = n8 >> 1, hf = n8 & 1;
                    mma16816(acc[mt][n8], Afh[slot], Bfl[kk][ng][hf], Bfl[kk][ng][hf + 2]);
                }
            }
        }
        __syncthreads();
    }

    const int g   = lane >> 2;
    const int tig = lane & 3;

    // stage acc -> smem
    float* stg = (float*)smem;   // [128][132]
#pragma unroll
    for (int mt = 0; mt < 4; mt++)
#pragma unroll
        for (int n8 = 0; n8 < 8; n8++) {
            int row = wm * 64 + mt * 16 + g;
            int col = wn * 64 + n8 * 8 + tig * 2;
            stg[row * 132 + col]     = acc[mt][n8][0];
            stg[row * 132 + col + 1] = acc[mt][n8][1];
            stg[(row + 8) * 132 + col]     = acc[mt][n8][2];
            stg[(row + 8) * 132 + col + 1] = acc[mt][n8][3];
        }
    __syncthreads();

    {
        const int r    = t;
        const int gm   = bm + r;
        const int spos = gm & (SEQ - 1);
        const int bx   = blockIdx.x;

        if (bx < 20) {
            // Q or K: rope + bf16 split
            bool isQ = bx < 16;
            __nv_bfloat16* dh = isQ ? (Qoh + (size_t)gm * QW + bx * 128)
                                    : (Koh + (size_t)gm * KVW + (bx - 16) * 128);
            __nv_bfloat16* dl = isQ ? (Qol + (size_t)gm * QW + bx * 128)
                                    : (Kol + (size_t)gm * KVW + (bx - 16) * 128);
#pragma unroll
            for (int half = 0; half < 2; half++) {
                const int pb = half * 32;
                uint32_t h0[16], l0[16], h1[16], l1[16];
#pragma unroll
                for (int j = 0; j < 16; j++) {
                    int pi = pb + j * 2;
                    float x0a = stg[r * 132 + pi],      x0b = stg[r * 132 + pi + 1];
                    float x1a = stg[r * 132 + pi + 64], x1b = stg[r * 132 + pi + 65];
                    float ca = cosp[(size_t)spos * HD + pi],  cb = cosp[(size_t)spos * HD + pi + 1];
                    float sa = sinp[(size_t)spos * HD + pi],  sbv = sinp[(size_t)spos * HD + pi + 1];
                    float y0a = x0a * ca - x1a * sa,  y1a = x1a * ca + x0a * sa;
                    float y0b = x0b * cb - x1b * sbv, y1b = x1b * cb + x0b * sbv;
                    split2(y0a, y0b, h0[j], l0[j]);
                    split2(y1a, y1b, h1[j], l1[j]);
                }
#pragma unroll
                for (int w = 0; w < 4; w++) {
                    *(uint4*)(dh + pb + w * 8)      = ((uint4*)h0)[w];
                    *(uint4*)(dh + 64 + pb + w * 8) = ((uint4*)h1)[w];
                    *(uint4*)(dl + pb + w * 8)      = ((uint4*)l0)[w];
                    *(uint4*)(dl + 64 + pb + w * 8) = ((uint4*)l1)[w];
                }
            }
        } else {
            // V: single fp16, no rope
            __half* dv = Vof + (size_t)gm * KVW + (bx - 20) * 128;
#pragma unroll
            for (int half = 0; half < 2; half++) {
                const int pb = half * 32;
                uint32_t h0[16], h1[16];
#pragma unroll
                for (int j = 0; j < 16; j++) {
                    int pi = pb + j * 2;
                    h0[j] = packh2(stg[r * 132 + pi],      stg[r * 132 + pi + 1]);
                    h1[j] = packh2(stg[r * 132 + pi + 64], stg[r * 132 + pi + 65]);
                }
#pragma unroll
                for (int w = 0; w < 4; w++) {
                    *(uint4*)(dv + pb + w * 8)      = ((uint4*)h0)[w];
                    *(uint4*)(dv + 64 + pb + w * 8) = ((uint4*)h1)[w];
                }
            }
        }
    }
}

// ---------------------------------------------------------------------------
// O-projection GEMM: A = fp16 hi/lo (2 terms), B = single fp16. fp32 out.
// 128 threads = 4 warps (2x2), warp tile 64x64, BM=BN=128, BK=32.
// ---------------------------------------------------------------------------
#define OSTG   (3 * GT)               // Ah, Al, Bf = 30720 B
#define OSMEM  (2 * OSTG)             // 61440 B

__global__ __launch_bounds__(128)
void hmma_gemm_o(const __half* __restrict__ Ah_, const __half* __restrict__ Al_,
                 const __half* __restrict__ Bf_, float* __restrict__ C,
                 int M, int N, int K)
{
    extern __shared__ __align__(128) char smem[];
    const uint32_t sb = smem_u32(smem);

    const int t    = threadIdx.x;
    const int warp = t >> 5;
    const int lane = t & 31;
    const int wm   = warp >> 1;
    const int wn   = warp & 1;
    const int bm   = blockIdx.y * 128;
    const int bn   = blockIdx.x * 128;

    float acc[4][8][4];
#pragma unroll
    for (int mi = 0; mi < 4; mi++)
#pragma unroll
        for (int ni = 0; ni < 8; ni++)
#pragma unroll
            for (int r = 0; r < 4; r++) acc[mi][ni][r] = 0.f;

    const int S = K / 32;

    auto issue = [&](int s, int buf) {
        const int k0 = s * 32;
        const uint32_t stg = sb + (uint32_t)buf * OSTG;
#pragma unroll
        for (int i = 0; i < 4; i++) {
            int f = i * 128 + t;
            int r = f >> 2, ch = f & 3;
            uint32_t so = r * GROW + ch * 16;
            size_t  goA = (size_t)(bm + r) * K + k0 + ch * 8;
            size_t  goB = (size_t)(bn + r) * K + k0 + ch * 8;
            cpa16(stg + 0 * GT + so, Ah_ + goA);
            cpa16(stg + 1 * GT + so, Al_ + goA);
            cpa16(stg + 2 * GT + so, Bf_ + goB);
        }
        CPA_COMMIT();
    };

    issue(0, 0);

    for (int s = 0; s < S; s++) {
        const int buf = s & 1;
        if (s + 1 < S) { issue(s + 1, buf ^ 1); CPA_WAIT(1); }
        else           { CPA_WAIT(0); }
        __syncthreads();

        const uint32_t smAh = sb + (uint32_t)buf * OSTG;
        const uint32_t smAl = smAh + GT;
        const uint32_t smBf = smAh + 2 * GT;

#pragma unroll
        for (int kk = 0; kk < 2; kk++) {
            uint32_t bfr[4][4];
#pragma unroll
            for (int ng = 0; ng < 4; ng++) {
                int rr = wn * 64 + ng * 16 + (lane & 15);
                uint32_t ad = rr * GROW + (kk * 2 + (lane >> 4)) * 16;
                ldm4(bfr[ng], smBf + ad);
            }
#pragma unroll
            for (int mt = 0; mt < 4; mt++) {
                uint32_t ah[4], al[4];
                int rr = wm * 64 + mt * 16 + (lane & 15);
                uint32_t ad = rr * GROW + (kk * 2 + (lane >> 4)) * 16;
                ldm4(ah, smAh + ad);
                ldm4(al, smAl + ad);
#pragma unroll
                for (int n8 = 0; n8 < 8; n8++) {
                    int ng = n8 >> 1, hf = n8 & 1;
                    mma16816f(acc[mt][n8], ah, bfr[ng][hf], bfr[ng][hf + 2]);
                }
#pragma unroll
                for (int n8 = 0; n8 < 8; n8++) {
                    int ng = n8 >> 1, hf = n8 & 1;
                    mma16816f(acc[mt][n8], al, bfr[ng][hf], bfr[ng][hf + 2]);
                }
            }
        }
        __syncthreads();
    }

    const int g   = lane >> 2;
    const int tig = lane & 3;
#pragma unroll
    for (int mt = 0; mt < 4; mt++)
#pragma unroll
        for (int n8 = 0; n8 < 8; n8++) {
            int row = bm + wm * 64 + mt * 16 + g;
            int col = bn + wn * 64 + n8 * 8 + tig * 2;
            *(float2*)(C + (size_t)row * N + col) = make_float2(acc[mt][n8][0], acc[mt][n8][1]);
            *(float2*)(C + (size_t)(row + 8) * N + col) = make_float2(acc[mt][n8][2], acc[mt][n8][3]);
        }
}

// ---------------------------------------------------------------------------
// Flash attention: QK bf16 3-term; PV single fp16 MMA; cp.async pipeline.
// smem: Qh,Ql (bf16) + K stage {h,l} + V stage (fp16 single) = 5 x 16KB.
// ---------------------------------------------------------------------------
#define AT_TILE 16384
#define AT_SMEM (5 * AT_TILE)               // 81920 B
#define NQT     (SEQ / 64)                  // 32

__device__ __forceinline__ uint32_t swz256(int r, int ch) {
    return (uint32_t)(r * 256 + (((ch ^ (r & 7)) & 15) << 4));
}

__global__ __launch_bounds__(128)
void flash_attn_mma(const __nv_bfloat16* __restrict__ Qh, const __nv_bfloat16* __restrict__ Ql,
                    const __nv_bfloat16* __restrict__ Kh, const __nv_bfloat16* __restrict__ Kl,
                    const __half* __restrict__ Vf,
                    __half* __restrict__ OAh, __half* __restrict__ OAl)
{
    extern __shared__ __align__(128) char smem[];
    const uint32_t sb  = smem_u32(smem);
    const uint32_t sQh = sb;
    const uint32_t sQl = sb + AT_TILE;
    const uint32_t sA  = sb + 2 * AT_TILE;   // K stage: {h, l}
    const uint32_t sBv = sb + 4 * AT_TILE;   // V stage: single fp16

    const int h   = blockIdx.y;
    const int b   = blockIdx.z;
    const int kvh = h >> 2;
    const int t   = threadIdx.x;
    const int warp = t >> 5;
    const int lane = t & 31;
    const int g    = lane >> 2;
    const int tig  = lane & 3;

    const int rl = warp * 16 + g;
    const int rh = rl + 8;

    auto load_k = [&](int kt) {
        const __nv_bfloat16* bh = Kh + (size_t)(b * SEQ + kt * 64) * KVW + kvh * HD;
        const __nv_bfloat16* bl = Kl + (size_t)(b * SEQ + kt * 64) * KVW + kvh * HD;
#pragma unroll
        for (int i = 0; i < 8; i++) {
            int f = i * 128 + t;
            int r = f >> 4, ch = f & 15;
            cpa16(sA + swz256(r, ch),           bh + (size_t)r * KVW + ch * 8);
            cpa16(sA + AT_TILE + swz256(r, ch), bl + (size_t)r * KVW + ch * 8);
        }
        CPA_COMMIT();
    };
    auto load_v = [&](int kt) {
        const __half* bv = Vf + (size_t)(b * SEQ + kt * 64) * KVW + kvh * HD;
#pragma unroll
        for (int i = 0; i < 8; i++) {
            int f = i * 128 + t;
            int r = f >> 4, ch = f & 15;
            cpa16(sBv + swz256(r, ch), bv + (size_t)r * KVW + ch * 8);
        }
        CPA_COMMIT();
    };

    for (int sel = 0; sel < 2; sel++) {
        const int qt = sel ? (NQT - 1 - blockIdx.x) : blockIdx.x;
        const int q0 = qt * 64;

        // Q tiles (cp.async)
        {
            const __nv_bfloat16* qbh = Qh + (size_t)(b * SEQ + q0) * QW + h * HD;
            const __nv_bfloat16* qbl = Ql + (size_t)(b * SEQ + q0) * QW + h * HD;
#pragma unroll
            for (int i = 0; i < 8; i++) {
                int f = i * 128 + t;
                int r = f >> 4, ch = f & 15;
                cpa16(sQh + swz256(r, ch), qbh + (size_t)r * QW + ch * 8);
                cpa16(sQl + swz256(r, ch), qbl + (size_t)r * QW + ch * 8);
            }
            CPA_COMMIT();
        }
        load_k(0);
        CPA_WAIT(0);
        __syncthreads();

        float o[16][4];
        float m0 = -1e30f, m1 = -1e30f, l0 = 0.f, l1 = 0.f;
#pragma unroll
        for (int i = 0; i < 16; i++)
#pragma unroll
            for (int j = 0; j < 4; j++) o[i][j] = 0.f;

        for (int kt = 0; kt <= qt; kt++) {
            load_v(kt);   // prefetch V under QK

            float sacc[8][4];
#pragma unroll
            for (int i = 0; i < 8; i++)
#pragma unroll
                for (int j = 0; j < 4; j++) sacc[i][j] = 0.f;

#pragma unroll
            for (int ks = 0; ks < 8; ks++) {
                uint32_t qfh[4], qfl[4];
                {
                    int rr = warp * 16 + (lane & 15);
                    uint32_t ad = swz256(rr, ks * 2 + (lane >> 4));
                    ldm4(qfh, sQh + ad);
                    ldm4(qfl, sQl + ad);
                }
                uint32_t kfh[4][4], kfl[4][4];
#pragma unroll
                for (int ng = 0; ng < 4; ng++) {
                    int rr = ng * 16 + (lane & 15);
                    uint32_t ad = swz256(rr, ks * 2 + (lane >> 4));
                    ldm4(kfh[ng], sA + ad);
                    ldm4(kfl[ng], sA + AT_TILE + ad);
                }
#pragma unroll
                for (int n8 = 0; n8 < 8; n8++) {
                    int ng = n8 >> 1, hf = n8 & 1;
                    mma16816(sacc[n8], qfh, kfh[ng][hf], kfh[ng][hf + 2]);
                }
#pragma unroll
                for (int n8 = 0; n8 < 8; n8++) {
                    int ng = n8 >> 1, hf = n8 & 1;
                    mma16816(sacc[n8], qfl, kfh[ng][hf], kfh[ng][hf + 2]);
                }
#pragma unroll
                for (int n8 = 0; n8 < 8; n8++) {
                    int ng = n8 >> 1, hf = n8 & 1;
                    mma16816(sacc[n8], qfh, kfl[ng][hf], kfl[ng][hf + 2]);
                }
            }

            if (kt == qt) {
#pragma unroll
                for (int n8 = 0; n8 < 8; n8++) {
                    int c0 = n8 * 8 + tig * 2, c1 = c0 + 1;
                    if (c0 > rl) sacc[n8][0] = -1e30f;
                    if (c1 > rl) sacc[n8][1] = -1e30f;
                    if (c0 > rh) sacc[n8][2] = -1e30f;
                    if (c1 > rh) sacc[n8][3] = -1e30f;
                }
            }

            float mx0 = -1e30f, mx1 = -1e30f;
#pragma unroll
            for (int n8 = 0; n8 < 8; n8++) {
                mx0 = fmaxf(mx0, fmaxf(sacc[n8][0], sacc[n8][1]));
                mx1 = fmaxf(mx1, fmaxf(sacc[n8][2], sacc[n8][3]));
            }
            mx0 = fmaxf(mx0, __shfl_xor_sync(0xffffffffu, mx0, 1));
            mx0 = fmaxf(mx0, __shfl_xor_sync(0xffffffffu, mx0, 2));
            mx1 = fmaxf(mx1, __shfl_xor_sync(0xffffffffu, mx1, 1));
            mx1 = fmaxf(mx1, __shfl_xor_sync(0xffffffffu, mx1, 2));

            float mn0 = fmaxf(m0, mx0), mn1 = fmaxf(m1, mx1);
            float al0 = __expf(m0 - mn0), al1 = __expf(m1 - mn1);
            m0 = mn0; m1 = mn1;

            float s0 = 0.f, s1 = 0.f;
#pragma unroll
            for (int n8 = 0; n8 < 8; n8++) {
                float p0 = __expf(sacc[n8][0] - m0);
                float p1 = __expf(sacc[n8][1] - m0);
                float p2 = __expf(sacc[n8][2] - m1);
                float p3 = __expf(sacc[n8][3] - m1);
                sacc[n8][0] = p0; sacc[n8][1] = p1; sacc[n8][2] = p2; sacc[n8][3] = p3;
                s0 += p0 + p1; s1 += p2 + p3;
            }
            s0 += __shfl_xor_sync(0xffffffffu, s0, 1);
            s0 += __shfl_xor_sync(0xffffffffu, s0, 2);
            s1 += __shfl_xor_sync(0xffffffffu, s1, 1);
            s1 += __shfl_xor_sync(0xffffffffu, s1, 2);
            l0 = l0 * al0 + s0;
            l1 = l1 * al1 + s1;

#pragma unroll
            for (int i = 0; i < 16; i++) {
                o[i][0] *= al0; o[i][1] *= al0;
                o[i][2] *= al1; o[i][3] *= al1;
            }

            // P -> single fp16 A-fragments
            uint32_t ph[4][4];
#pragma unroll
            for (int kk = 0; kk < 4; kk++) {
                ph[kk][0] = packh2(sacc[2 * kk][0],     sacc[2 * kk][1]);
                ph[kk][1] = packh2(sacc[2 * kk][2],     sacc[2 * kk][3]);
                ph[kk][2] = packh2(sacc[2 * kk + 1][0], sacc[2 * kk + 1][1]);
                ph[kk][3] = packh2(sacc[2 * kk + 1][2], sacc[2 * kk + 1][3]);
            }

            CPA_WAIT(0);        // V arrived
            __syncthreads();    // all warps done reading K

            if (kt < qt) load_k(kt + 1);   // prefetch next K under PV

            // O += P V  (single fp16 MMA)
#pragma unroll
            for (int ng = 0; ng < 8; ng++) {
#pragma unroll
                for (int kk = 0; kk < 4; kk++) {
                    uint32_t vf[4];
                    int rr = kk * 16 + (lane & 15);
                    uint32_t ad = swz256(rr, ng * 2 + (lane >> 4));
                    ldm4t(vf, sBv + ad);
#pragma unroll
                    for (int hf = 0; hf < 2; hf++) {
                        int nt = ng * 2 + hf;
                        mma16816f(o[nt], ph[kk], vf[hf * 2], vf[hf * 2 + 1]);
                    }
                }
            }

            CPA_WAIT(0);        // K(kt+1) arrived
            __syncthreads();    // all warps done reading V
        }

        // epilogue: normalize, split fp16 hi/lo
        float inv0 = 1.f / l0, inv1 = 1.f / l1;
        __half* Obh = OAh + (size_t)(b * SEQ + q0) * QW + h * HD;
        __half* Obl = OAl + (size_t)(b * SEQ + q0) * QW + h * HD;
#pragma unroll
        for (int nt = 0; nt < 16; nt++) {
            int col = nt * 8 + tig * 2;
            uint32_t hh0, ll0, hh1, ll1;
            splitf2(o[nt][0] * inv0, o[nt][1] * inv0, hh0, ll0);
            splitf2(o[nt][2] * inv1, o[nt][3] * inv1, hh1, ll1);
            *(uint32_t*)(Obh + (size_t)rl * QW + col) = hh0;
            *(uint32_t*)(Obl + (size_t)rl * QW + col) = ll0;
            *(uint32_t*)(Obh + (size_t)rh * QW + col) = hh1;
            *(uint32_t*)(Obl + (size_t)rh * QW + col) = ll1;
        }
    }
}

// ---------------------------------------------------------------------------
// Launcher
// ---------------------------------------------------------------------------
extern "C" void kernel_launch(void* const* d_in, const int* in_sizes, int n_in,
                              void* d_out, int out_size)
{
    const float* x    = (const float*)d_in[0];
    const float* q_w  = (const float*)d_in[2];
    const float* k_w  = (const float*)d_in[3];
    const float* v_w  = (const float*)d_in[4];
    const float* o_w  = (const float*)d_in[5];
    const float* sinp = (const float*)d_in[6];
    const float* cosp = (const float*)d_in[7];
    float* out = (float*)d_out;

    __nv_bfloat16 *xh, *xl, *wh, *wl;
    __half *owf, *Vfp, *Ahp, *Alp;
    cudaGetSymbolAddress((void**)&xh, g_xh);
    cudaGetSymbolAddress((void**)&xl, g_xl);
    cudaGetSymbolAddress((void**)&wh, g_wh);
    cudaGetSymbolAddress((void**)&wl, g_wl);
    cudaGetSymbolAddress((void**)&owf, g_owf);
    cudaGetSymbolAddress((void**)&Vfp, g_Vf);
    cudaGetSymbolAddress((void**)&Ahp, g_Ah);
    cudaGetSymbolAddress((void**)&Alp, g_Al);
    __nv_bfloat16 *Qh, *Ql, *Kh, *Kl;
    cudaGetSymbolAddress((void**)&Qh, g_Qh);
    cudaGetSymbolAddress((void**)&Ql, g_Ql);
    cudaGetSymbolAddress((void**)&Kh, g_Kh);
    cudaGetSymbolAddress((void**)&Kl, g_Kl);

    // 1) fused split of all fp32 operands
    split_all<<<(N4_ALL + 255) / 256, 256>>>(x, q_w, k_w, v_w, o_w,
                                             xh, xl, wh, wl, owf);

    cudaFuncSetAttribute(hmma_gemm_qkv, cudaFuncAttributeMaxDynamicSharedMemorySize, GEMM_SMEM);
    cudaFuncSetAttribute(hmma_gemm_o,   cudaFuncAttributeMaxDynamicSharedMemorySize, OSMEM);
    cudaFuncSetAttribute(flash_attn_mma, cudaFuncAttributeMaxDynamicSharedMemorySize, AT_SMEM);

    // 2) fused QKV projection + rope/split epilogue (V -> single fp16)
    hmma_gemm_qkv<<<dim3(W3 / 128, MTOT / 128), 128, GEMM_SMEM>>>(
        xh, xl, wh, wl, Qh, Ql, Kh, Kl, Vfp, sinp, cosp, MTOT, W3, HID);

    // 3) flash attention (PV single fp16 MMA)
    flash_attn_mma<<<dim3(NQT / 2, NH, 2), 128, AT_SMEM>>>(Qh, Ql, Kh, Kl, Vfp, Ahp, Alp);

    // 4) output projection (fp16 2-term)
    hmma_gemm_o<<<dim3(HID / 128, MTOT / 128), 128, OSMEM>>>(
        Ahp, Alp, owf, out, MTOT, HID, HID);
}

// round 12
// speedup vs baseline: 3.7831x; 1.1200x over previous
#include <cuda_runtime.h>
#include <cuda_bf16.h>
#include <cuda_fp16.h>
#include <math.h>
#include <stdint.h>

// Problem constants
#define MTOT 4096      // B*S
#define SEQ  2048
#define HID  2048
#define NH   16
#define NKV  4
#define HD   128
#define QW   2048      // NH*HD
#define KVW  512       // NKV*HD
#define W2   2560      // fused Q|K weight width (bf16 3-term path)

// Scratch (allocation-free rule: __device__ globals)
__device__ __nv_bfloat16 g_xh[(size_t)MTOT * HID];
__device__ __nv_bfloat16 g_xl[(size_t)MTOT * HID];
__device__ __half        g_xf[(size_t)MTOT * HID];   // x single fp16 (for V proj)
__device__ __nv_bfloat16 g_wh[(size_t)W2 * HID];     // q|k weights fused (bf16 hi)
__device__ __nv_bfloat16 g_wl[(size_t)W2 * HID];
__device__ __half        g_vwf[(size_t)KVW * HID];   // v_w single fp16
__device__ __half        g_owf[(size_t)HID * QW];    // o_w single fp16
__device__ __nv_bfloat16 g_Qh[(size_t)MTOT * QW];
__device__ __nv_bfloat16 g_Ql[(size_t)MTOT * QW];
__device__ __nv_bfloat16 g_Kh[(size_t)MTOT * KVW];
__device__ __nv_bfloat16 g_Kl[(size_t)MTOT * KVW];
__device__ __half        g_Vf[(size_t)MTOT * KVW];   // V single fp16
__device__ __half        g_Af[(size_t)MTOT * QW];    // attn out single fp16

// ---------------------------------------------------------------------------
// helpers
// ---------------------------------------------------------------------------
__device__ __forceinline__ void mma16816(float* c, const uint32_t* a, uint32_t b0, uint32_t b1) {
    asm volatile(
        "mma.sync.aligned.m16n8k16.row.col.f32.bf16.bf16.f32 "
        "{%0,%1,%2,%3}, {%4,%5,%6,%7}, {%8,%9}, {%0,%1,%2,%3};"
        : "+f"(c[0]), "+f"(c[1]), "+f"(c[2]), "+f"(c[3])
        : "r"(a[0]), "r"(a[1]), "r"(a[2]), "r"(a[3]), "r"(b0), "r"(b1));
}
__device__ __forceinline__ void mma16816f(float* c, const uint32_t* a, uint32_t b0, uint32_t b1) {
    asm volatile(
        "mma.sync.aligned.m16n8k16.row.col.f32.f16.f16.f32 "
        "{%0,%1,%2,%3}, {%4,%5,%6,%7}, {%8,%9}, {%0,%1,%2,%3};"
        : "+f"(c[0]), "+f"(c[1]), "+f"(c[2]), "+f"(c[3])
        : "r"(a[0]), "r"(a[1]), "r"(a[2]), "r"(a[3]), "r"(b0), "r"(b1));
}
__device__ __forceinline__ void ldm4(uint32_t* r, uint32_t a) {
    asm volatile("ldmatrix.sync.aligned.m8n8.x4.shared.b16 {%0,%1,%2,%3}, [%4];"
                 : "=r"(r[0]), "=r"(r[1]), "=r"(r[2]), "=r"(r[3]) : "r"(a));
}
__device__ __forceinline__ void ldm4t(uint32_t* r, uint32_t a) {
    asm volatile("ldmatrix.sync.aligned.m8n8.x4.trans.shared.b16 {%0,%1,%2,%3}, [%4];"
                 : "=r"(r[0]), "=r"(r[1]), "=r"(r[2]), "=r"(r[3]) : "r"(a));
}
__device__ __forceinline__ uint32_t smem_u32(const void* p) {
    uint32_t a;
    asm("{ .reg .u64 tmp; cvta.to.shared.u64 tmp, %1; cvt.u32.u64 %0, tmp; }"
        : "=r"(a) : "l"(p));
    return a;
}
__device__ __forceinline__ void cpa16(uint32_t dst, const void* src) {
    asm volatile("cp.async.cg.shared.global [%0], [%1], 16;" :: "r"(dst), "l"(src));
}
#define CPA_COMMIT() asm volatile("cp.async.commit_group;" ::: "memory")
#define CPA_WAIT(n)  asm volatile("cp.async.wait_group %0;" :: "n"(n) : "memory")

__device__ __forceinline__ void split2(float a, float b, uint32_t& h, uint32_t& l) {
    __nv_bfloat162 hh = __floats2bfloat162_rn(a, b);
    float ra = a - __bfloat162float(hh.x);
    float rb = b - __bfloat162float(hh.y);
    __nv_bfloat162 ll = __floats2bfloat162_rn(ra, rb);
    h = *(uint32_t*)&hh;
    l = *(uint32_t*)&ll;
}
__device__ __forceinline__ uint32_t packh2(float a, float b) {
    __half2 h = __floats2half2_rn(a, b);
    return *(uint32_t*)&h;
}

// ---------------------------------------------------------------------------
// Fused split kernel:
//   x   -> xh/xl (bf16) + xf (fp16)
//   q_w,k_w -> wh/wl (bf16, fused rows 0..2559)
//   v_w -> vwf (fp16), o_w -> owf (fp16)
// ---------------------------------------------------------------------------
#define N4_X   (MTOT * HID / 4)
#define N4_QW  (QW * HID / 4)
#define N4_KW  (KVW * HID / 4)
#define N4_ALL (N4_X + N4_QW + 2 * N4_KW + N4_QW)

__global__ void split_all(const float* __restrict__ x, const float* __restrict__ qw,
                          const float* __restrict__ kw, const float* __restrict__ vw,
                          const float* __restrict__ ow,
                          __nv_bfloat16* __restrict__ xh, __nv_bfloat16* __restrict__ xl,
                          __half* __restrict__ xf,
                          __nv_bfloat16* __restrict__ wh, __nv_bfloat16* __restrict__ wl,
                          __half* __restrict__ vwf, __half* __restrict__ owf)
{
    int i = blockIdx.x * blockDim.x + threadIdx.x;
    if (i >= N4_ALL) return;
    int j = i;
    if (j < N4_X) {
        float4 v = ((const float4*)x)[j];
        uint32_t h0, l0, h1, l1;
        split2(v.x, v.y, h0, l0);
        split2(v.z, v.w, h1, l1);
        ((uint2*)xh)[j] = make_uint2(h0, h1);
        ((uint2*)xl)[j] = make_uint2(l0, l1);
        ((uint2*)xf)[j] = make_uint2(packh2(v.x, v.y), packh2(v.z, v.w));
        return;
    }
    j -= N4_X;
    if (j < N4_QW) {
        float4 v = ((const float4*)qw)[j];
        uint32_t h0, l0, h1, l1;
        split2(v.x, v.y, h0, l0);
        split2(v.z, v.w, h1, l1);
        ((uint2*)wh)[j] = make_uint2(h0, h1);
        ((uint2*)wl)[j] = make_uint2(l0, l1);
        return;
    }
    j -= N4_QW;
    if (j < N4_KW) {
        float4 v = ((const float4*)kw)[j];
        uint32_t h0, l0, h1, l1;
        split2(v.x, v.y, h0, l0);
        split2(v.z, v.w, h1, l1);
        size_t off = (size_t)QW * HID / 4;
        ((uint2*)wh)[off + j] = make_uint2(h0, h1);
        ((uint2*)wl)[off + j] = make_uint2(l0, l1);
        return;
    }
    j -= N4_KW;
    if (j < N4_KW) {
        float4 v = ((const float4*)vw)[j];
        ((uint2*)vwf)[j] = make_uint2(packh2(v.x, v.y), packh2(v.z, v.w));
        return;
    }
    j -= N4_KW;
    {
        float4 v = ((const float4*)ow)[j];
        ((uint2*)owf)[j] = make_uint2(packh2(v.x, v.y), packh2(v.z, v.w));
    }
}

// ---------------------------------------------------------------------------
// QK GEMM (bf16 3-term) + rope/split epilogue. N = 2560 (Q 16 heads | K 4).
// 128 threads = 4 warps (2x2), warp tile 64x64, BM=BN=128, BK=32.
// ---------------------------------------------------------------------------
#define GROW  80
#define GT    (128 * GROW)            // 10240 B
#define STG_B (4 * GT)                // 40960 B
#define GEMM_SMEM (2 * STG_B)         // 81920 B

__global__ __launch_bounds__(128)
void hmma_gemm_qk(const __nv_bfloat16* __restrict__ Ah, const __nv_bfloat16* __restrict__ Al,
                  const __nv_bfloat16* __restrict__ Bh, const __nv_bfloat16* __restrict__ Bl,
                  __nv_bfloat16* __restrict__ Qoh, __nv_bfloat16* __restrict__ Qol,
                  __nv_bfloat16* __restrict__ Koh, __nv_bfloat16* __restrict__ Kol,
                  const float* __restrict__ sinp, const float* __restrict__ cosp,
                  int M, int N, int K)
{
    extern __shared__ __align__(128) char smem[];
    const uint32_t sb = smem_u32(smem);

    const int t    = threadIdx.x;
    const int warp = t >> 5;
    const int lane = t & 31;
    const int wm   = warp >> 1;
    const int wn   = warp & 1;
    const int bm   = blockIdx.y * 128;
    const int bn   = blockIdx.x * 128;

    const __nv_bfloat16* srcA[2] = { Ah, Al };
    const __nv_bfloat16* srcB[2] = { Bh, Bl };

    float acc[4][8][4];
#pragma unroll
    for (int mi = 0; mi < 4; mi++)
#pragma unroll
        for (int ni = 0; ni < 8; ni++)
#pragma unroll
            for (int r = 0; r < 4; r++) acc[mi][ni][r] = 0.f;

    const int S = K / 32;

    auto issue = [&](int s, int buf) {
        const int k0 = s * 32;
        const uint32_t stg = sb + (uint32_t)buf * STG_B;
#pragma unroll
        for (int i = 0; i < 4; i++) {
            int f = i * 128 + t;
            int r = f >> 2, ch = f & 3;
            uint32_t so = r * GROW + ch * 16;
            size_t  goA = (size_t)(bm + r) * K + k0 + ch * 8;
            size_t  goB = (size_t)(bn + r) * K + k0 + ch * 8;
            cpa16(stg + 0 * GT + so, srcA[0] + goA);
            cpa16(stg + 1 * GT + so, srcA[1] + goA);
            cpa16(stg + 2 * GT + so, srcB[0] + goB);
            cpa16(stg + 3 * GT + so, srcB[1] + goB);
        }
        CPA_COMMIT();
    };

    issue(0, 0);

    uint32_t Bfh[2][4][4], Bfl[2][4][4];
    uint32_t Afh[2][4], Afl[2][4];

    for (int s = 0; s < S; s++) {
        const int buf = s & 1;
        if (s + 1 < S) { issue(s + 1, buf ^ 1); CPA_WAIT(1); }
        else           { CPA_WAIT(0); }
        __syncthreads();

        const uint32_t smAh = sb + (uint32_t)buf * STG_B;
        const uint32_t smAl = smAh + GT;
        const uint32_t smBh = smAh + 2 * GT;
        const uint32_t smBl = smAh + 3 * GT;

        auto ldmB = [&](int kk) {
#pragma unroll
            for (int ng = 0; ng < 4; ng++) {
                int rr = wn * 64 + ng * 16 + (lane & 15);
                uint32_t ad = rr * GROW + (kk * 2 + (lane >> 4)) * 16;
                ldm4(Bfh[kk][ng], smBh + ad);
                ldm4(Bfl[kk][ng], smBl + ad);
            }
        };
        auto ldmA = [&](int kk, int mt, int slot) {
            int rr = wm * 64 + mt * 16 + (lane & 15);
            uint32_t ad = rr * GROW + (kk * 2 + (lane >> 4)) * 16;
            ldm4(Afh[slot], smAh + ad);
            ldm4(Afl[slot], smAl + ad);
        };

        ldmB(0);
        ldmA(0, 0, 0);

#pragma unroll
        for (int kk = 0; kk < 2; kk++) {
#pragma unroll
            for (int mt = 0; mt < 4; mt++) {
                const int slot = (kk * 4 + mt) & 1;
                const int nslot = slot ^ 1;
                if (mt < 3)            ldmA(kk, mt + 1, nslot);
                else if (kk == 0)    { ldmB(1); ldmA(1, 0, nslot); }

#pragma unroll
                for (int n8 = 0; n8 < 8; n8++) {
                    int ng = n8 >> 1, hf = n8 & 1;
                    mma16816(acc[mt][n8], Afh[slot], Bfh[kk][ng][hf], Bfh[kk][ng][hf + 2]);
                }
#pragma unroll
                for (int n8 = 0; n8 < 8; n8++) {
                    int ng = n8 >> 1, hf = n8 & 1;
                    mma16816(acc[mt][n8], Afl[slot], Bfh[kk][ng][hf], Bfh[kk][ng][hf + 2]);
                }
#pragma unroll
                for (int n8 = 0; n8 < 8; n8++) {
                    int ng = n8 >> 1, hf = n8 & 1;
                    mma16816(acc[mt][n8], Afh[slot], Bfl[kk][ng][hf], Bfl[kk][ng][hf + 2]);
                }
            }
        }
        __syncthreads();
    }

    const int g   = lane >> 2;
    const int tig = lane & 3;

    // stage acc -> smem, rope + bf16 split -> out
    float* stg = (float*)smem;   // [128][132]
#pragma unroll
    for (int mt = 0; mt < 4; mt++)
#pragma unroll
        for (int n8 = 0; n8 < 8; n8++) {
            int row = wm * 64 + mt * 16 + g;
            int col = wn * 64 + n8 * 8 + tig * 2;
            stg[row * 132 + col]     = acc[mt][n8][0];
            stg[row * 132 + col + 1] = acc[mt][n8][1];
            stg[(row + 8) * 132 + col]     = acc[mt][n8][2];
            stg[(row + 8) * 132 + col + 1] = acc[mt][n8][3];
        }
    __syncthreads();

    {
        const int r    = t;
        const int gm   = bm + r;
        const int spos = gm & (SEQ - 1);
        const int bx   = blockIdx.x;

        bool isQ = bx < 16;
        __nv_bfloat16* dh = isQ ? (Qoh + (size_t)gm * QW + bx * 128)
                                : (Koh + (size_t)gm * KVW + (bx - 16) * 128);
        __nv_bfloat16* dl = isQ ? (Qol + (size_t)gm * QW + bx * 128)
                                : (Kol + (size_t)gm * KVW + (bx - 16) * 128);
#pragma unroll
        for (int half = 0; half < 2; half++) {
            const int pb = half * 32;
            uint32_t h0[16], l0[16], h1[16], l1[16];
#pragma unroll
            for (int j = 0; j < 16; j++) {
                int pi = pb + j * 2;
                float x0a = stg[r * 132 + pi],      x0b = stg[r * 132 + pi + 1];
                float x1a = stg[r * 132 + pi + 64], x1b = stg[r * 132 + pi + 65];
                float ca = cosp[(size_t)spos * HD + pi],  cb = cosp[(size_t)spos * HD + pi + 1];
                float sa = sinp[(size_t)spos * HD + pi],  sbv = sinp[(size_t)spos * HD + pi + 1];
                float y0a = x0a * ca - x1a * sa,  y1a = x1a * ca + x0a * sa;
                float y0b = x0b * cb - x1b * sbv, y1b = x1b * cb + x0b * sbv;
                split2(y0a, y0b, h0[j], l0[j]);
                split2(y1a, y1b, h1[j], l1[j]);
            }
#pragma unroll
            for (int w = 0; w < 4; w++) {
                *(uint4*)(dh + pb + w * 8)      = ((uint4*)h0)[w];
                *(uint4*)(dh + 64 + pb + w * 8) = ((uint4*)h1)[w];
                *(uint4*)(dl + pb + w * 8)      = ((uint4*)l0)[w];
                *(uint4*)(dl + 64 + pb + w * 8) = ((uint4*)l1)[w];
            }
        }
    }
}

// ---------------------------------------------------------------------------
// 1-term fp16 GEMM (A, B single fp16). OUTF16=1 -> fp16 out (V proj),
// OUTF16=0 -> fp32 out (O proj). 128 threads, warp tile 64x64.
// ---------------------------------------------------------------------------
#define OST   (2 * GT)               // A, B per stage = 20480 B
#define OSMEM (2 * OST)              // 40960 B

template<int OUTF16>
__global__ __launch_bounds__(128)
void hmma_gemm_1t(const __half* __restrict__ A_, const __half* __restrict__ B_,
                  void* __restrict__ Cv, int M, int N, int K)
{
    extern __shared__ __align__(128) char smem[];
    const uint32_t sb = smem_u32(smem);

    const int t    = threadIdx.x;
    const int warp = t >> 5;
    const int lane = t & 31;
    const int wm   = warp >> 1;
    const int wn   = warp & 1;
    const int bm   = blockIdx.y * 128;
    const int bn   = blockIdx.x * 128;

    float acc[4][8][4];
#pragma unroll
    for (int mi = 0; mi < 4; mi++)
#pragma unroll
        for (int ni = 0; ni < 8; ni++)
#pragma unroll
            for (int r = 0; r < 4; r++) acc[mi][ni][r] = 0.f;

    const int S = K / 32;

    auto issue = [&](int s, int buf) {
        const int k0 = s * 32;
        const uint32_t stg = sb + (uint32_t)buf * OST;
#pragma unroll
        for (int i = 0; i < 4; i++) {
            int f = i * 128 + t;
            int r = f >> 2, ch = f & 3;
            uint32_t so = r * GROW + ch * 16;
            cpa16(stg + 0 * GT + so, A_ + (size_t)(bm + r) * K + k0 + ch * 8);
            cpa16(stg + 1 * GT + so, B_ + (size_t)(bn + r) * K + k0 + ch * 8);
        }
        CPA_COMMIT();
    };

    issue(0, 0);

    for (int s = 0; s < S; s++) {
        const int buf = s & 1;
        if (s + 1 < S) { issue(s + 1, buf ^ 1); CPA_WAIT(1); }
        else           { CPA_WAIT(0); }
        __syncthreads();

        const uint32_t smA = sb + (uint32_t)buf * OST;
        const uint32_t smB = smA + GT;

#pragma unroll
        for (int kk = 0; kk < 2; kk++) {
            uint32_t bfr[4][4];
#pragma unroll
            for (int ng = 0; ng < 4; ng++) {
                int rr = wn * 64 + ng * 16 + (lane & 15);
                uint32_t ad = rr * GROW + (kk * 2 + (lane >> 4)) * 16;
                ldm4(bfr[ng], smB + ad);
            }
#pragma unroll
            for (int mt = 0; mt < 4; mt++) {
                uint32_t af[4];
                int rr = wm * 64 + mt * 16 + (lane & 15);
                uint32_t ad = rr * GROW + (kk * 2 + (lane >> 4)) * 16;
                ldm4(af, smA + ad);
#pragma unroll
                for (int n8 = 0; n8 < 8; n8++) {
                    int ng = n8 >> 1, hf = n8 & 1;
                    mma16816f(acc[mt][n8], af, bfr[ng][hf], bfr[ng][hf + 2]);
                }
            }
        }
        __syncthreads();
    }

    const int g   = lane >> 2;
    const int tig = lane & 3;
    if (OUTF16) {
        __half* C = (__half*)Cv;
#pragma unroll
        for (int mt = 0; mt < 4; mt++)
#pragma unroll
            for (int n8 = 0; n8 < 8; n8++) {
                int row = bm + wm * 64 + mt * 16 + g;
                int col = bn + wn * 64 + n8 * 8 + tig * 2;
                *(uint32_t*)(C + (size_t)row * N + col) = packh2(acc[mt][n8][0], acc[mt][n8][1]);
                *(uint32_t*)(C + (size_t)(row + 8) * N + col) = packh2(acc[mt][n8][2], acc[mt][n8][3]);
            }
    } else {
        float* C = (float*)Cv;
#pragma unroll
        for (int mt = 0; mt < 4; mt++)
#pragma unroll
            for (int n8 = 0; n8 < 8; n8++) {
                int row = bm + wm * 64 + mt * 16 + g;
                int col = bn + wn * 64 + n8 * 8 + tig * 2;
                *(float2*)(C + (size_t)row * N + col) = make_float2(acc[mt][n8][0], acc[mt][n8][1]);
                *(float2*)(C + (size_t)(row + 8) * N + col) = make_float2(acc[mt][n8][2], acc[mt][n8][3]);
            }
    }
}

// ---------------------------------------------------------------------------
// Flash attention: QK bf16 3-term; PV single fp16 MMA; single-fp16 output.
// ---------------------------------------------------------------------------
#define AT_TILE 16384
#define AT_SMEM (5 * AT_TILE)               // 81920 B
#define NQT     (SEQ / 64)                  // 32

__device__ __forceinline__ uint32_t swz256(int r, int ch) {
    return (uint32_t)(r * 256 + (((ch ^ (r & 7)) & 15) << 4));
}

__global__ __launch_bounds__(128)
void flash_attn_mma(const __nv_bfloat16* __restrict__ Qh, const __nv_bfloat16* __restrict__ Ql,
                    const __nv_bfloat16* __restrict__ Kh, const __nv_bfloat16* __restrict__ Kl,
                    const __half* __restrict__ Vf, __half* __restrict__ OAf)
{
    extern __shared__ __align__(128) char smem[];
    const uint32_t sb  = smem_u32(smem);
    const uint32_t sQh = sb;
    const uint32_t sQl = sb + AT_TILE;
    const uint32_t sA  = sb + 2 * AT_TILE;   // K stage: {h, l}
    const uint32_t sBv = sb + 4 * AT_TILE;   // V stage: single fp16

    const int h   = blockIdx.y;
    const int b   = blockIdx.z;
    const int kvh = h >> 2;
    const int t   = threadIdx.x;
    const int warp = t >> 5;
    const int lane = t & 31;
    const int g    = lane >> 2;
    const int tig  = lane & 3;

    const int rl = warp * 16 + g;
    const int rh = rl + 8;

    auto load_k = [&](int kt) {
        const __nv_bfloat16* bh = Kh + (size_t)(b * SEQ + kt * 64) * KVW + kvh * HD;
        const __nv_bfloat16* bl = Kl + (size_t)(b * SEQ + kt * 64) * KVW + kvh * HD;
#pragma unroll
        for (int i = 0; i < 8; i++) {
            int f = i * 128 + t;
            int r = f >> 4, ch = f & 15;
            cpa16(sA + swz256(r, ch),           bh + (size_t)r * KVW + ch * 8);
            cpa16(sA + AT_TILE + swz256(r, ch), bl + (size_t)r * KVW + ch * 8);
        }
        CPA_COMMIT();
    };
    auto load_v = [&](int kt) {
        const __half* bv = Vf + (size_t)(b * SEQ + kt * 64) * KVW + kvh * HD;
#pragma unroll
        for (int i = 0; i < 8; i++) {
            int f = i * 128 + t;
            int r = f >> 4, ch = f & 15;
            cpa16(sBv + swz256(r, ch), bv + (size_t)r * KVW + ch * 8);
        }
        CPA_COMMIT();
    };

    for (int sel = 0; sel < 2; sel++) {
        const int qt = sel ? (NQT - 1 - blockIdx.x) : blockIdx.x;
        const int q0 = qt * 64;

        {
            const __nv_bfloat16* qbh = Qh + (size_t)(b * SEQ + q0) * QW + h * HD;
            const __nv_bfloat16* qbl = Ql + (size_t)(b * SEQ + q0) * QW + h * HD;
#pragma unroll
            for (int i = 0; i < 8; i++) {
                int f = i * 128 + t;
                int r = f >> 4, ch = f & 15;
                cpa16(sQh + swz256(r, ch), qbh + (size_t)r * QW + ch * 8);
                cpa16(sQl + swz256(r, ch), qbl + (size_t)r * QW + ch * 8);
            }
            CPA_COMMIT();
        }
        load_k(0);
        CPA_WAIT(0);
        __syncthreads();

        float o[16][4];
        float m0 = -1e30f, m1 = -1e30f, l0 = 0.f, l1 = 0.f;
#pragma unroll
        for (int i = 0; i < 16; i++)
#pragma unroll
            for (int j = 0; j < 4; j++) o[i][j] = 0.f;

        for (int kt = 0; kt <= qt; kt++) {
            load_v(kt);

            float sacc[8][4];
#pragma unroll
            for (int i = 0; i < 8; i++)
#pragma unroll
                for (int j = 0; j < 4; j++) sacc[i][j] = 0.f;

#pragma unroll
            for (int ks = 0; ks < 8; ks++) {
                uint32_t qfh[4], qfl[4];
                {
                    int rr = warp * 16 + (lane & 15);
                    uint32_t ad = swz256(rr, ks * 2 + (lane >> 4));
                    ldm4(qfh, sQh + ad);
                    ldm4(qfl, sQl + ad);
                }
                uint32_t kfh[4][4], kfl[4][4];
#pragma unroll
                for (int ng = 0; ng < 4; ng++) {
                    int rr = ng * 16 + (lane & 15);
                    uint32_t ad = swz256(rr, ks * 2 + (lane >> 4));
                    ldm4(kfh[ng], sA + ad);
                    ldm4(kfl[ng], sA + AT_TILE + ad);
                }
#pragma unroll
                for (int n8 = 0; n8 < 8; n8++) {
                    int ng = n8 >> 1, hf = n8 & 1;
                    mma16816(sacc[n8], qfh, kfh[ng][hf], kfh[ng][hf + 2]);
                }
#pragma unroll
                for (int n8 = 0; n8 < 8; n8++) {
                    int ng = n8 >> 1, hf = n8 & 1;
                    mma16816(sacc[n8], qfl, kfh[ng][hf], kfh[ng][hf + 2]);
                }
#pragma unroll
                for (int n8 = 0; n8 < 8; n8++) {
                    int ng = n8 >> 1, hf = n8 & 1;
                    mma16816(sacc[n8], qfh, kfl[ng][hf], kfl[ng][hf + 2]);
                }
            }

            if (kt == qt) {
#pragma unroll
                for (int n8 = 0; n8 < 8; n8++) {
                    int c0 = n8 * 8 + tig * 2, c1 = c0 + 1;
                    if (c0 > rl) sacc[n8][0] = -1e30f;
                    if (c1 > rl) sacc[n8][1] = -1e30f;
                    if (c0 > rh) sacc[n8][2] = -1e30f;
                    if (c1 > rh) sacc[n8][3] = -1e30f;
                }
            }

            float mx0 = -1e30f, mx1 = -1e30f;
#pragma unroll
            for (int n8 = 0; n8 < 8; n8++) {
                mx0 = fmaxf(mx0, fmaxf(sacc[n8][0], sacc[n8][1]));
                mx1 = fmaxf(mx1, fmaxf(sacc[n8][2], sacc[n8][3]));
            }
            mx0 = fmaxf(mx0, __shfl_xor_sync(0xffffffffu, mx0, 1));
            mx0 = fmaxf(mx0, __shfl_xor_sync(0xffffffffu, mx0, 2));
            mx1 = fmaxf(mx1, __shfl_xor_sync(0xffffffffu, mx1, 1));
            mx1 = fmaxf(mx1, __shfl_xor_sync(0xffffffffu, mx1, 2));

            float mn0 = fmaxf(m0, mx0), mn1 = fmaxf(m1, mx1);
            float al0 = __expf(m0 - mn0), al1 = __expf(m1 - mn1);
            m0 = mn0; m1 = mn1;

            float s0 = 0.f, s1 = 0.f;
#pragma unroll
            for (int n8 = 0; n8 < 8; n8++) {
                float p0 = __expf(sacc[n8][0] - m0);
                float p1 = __expf(sacc[n8][1] - m0);
                float p2 = __expf(sacc[n8][2] - m1);
                float p3 = __expf(sacc[n8][3] - m1);
                sacc[n8][0] = p0; sacc[n8][1] = p1; sacc[n8][2] = p2; sacc[n8][3] = p3;
                s0 += p0 + p1; s1 += p2 + p3;
            }
            s0 += __shfl_xor_sync(0xffffffffu, s0, 1);
            s0 += __shfl_xor_sync(0xffffffffu, s0, 2);
            s1 += __shfl_xor_sync(0xffffffffu, s1, 1);
            s1 += __shfl_xor_sync(0xffffffffu, s1, 2);
            l0 = l0 * al0 + s0;
            l1 = l1 * al1 + s1;

#pragma unroll
            for (int i = 0; i < 16; i++) {
                o[i][0] *= al0; o[i][1] *= al0;
                o[i][2] *= al1; o[i][3] *= al1;
            }

            uint32_t ph[4][4];
#pragma unroll
            for (int kk = 0; kk < 4; kk++) {
                ph[kk][0] = packh2(sacc[2 * kk][0],     sacc[2 * kk][1]);
                ph[kk][1] = packh2(sacc[2 * kk][2],     sacc[2 * kk][3]);
                ph[kk][2] = packh2(sacc[2 * kk + 1][0], sacc[2 * kk + 1][1]);
                ph[kk][3] = packh2(sacc[2 * kk + 1][2], sacc[2 * kk + 1][3]);
            }

            CPA_WAIT(0);
            __syncthreads();

            if (kt < qt) load_k(kt + 1);

#pragma unroll
            for (int ng = 0; ng < 8; ng++) {
#pragma unroll
                for (int kk = 0; kk < 4; kk++) {
                    uint32_t vf[4];
                    int rr = kk * 16 + (lane & 15);
                    uint32_t ad = swz256(rr, ng * 2 + (lane >> 4));
                    ldm4t(vf, sBv + ad);
#pragma unroll
                    for (int hf = 0; hf < 2; hf++) {
                        int nt = ng * 2 + hf;
                        mma16816f(o[nt], ph[kk], vf[hf * 2], vf[hf * 2 + 1]);
                    }
                }
            }

            CPA_WAIT(0);
            __syncthreads();
        }

        // epilogue: normalize, single fp16 out
        float inv0 = 1.f / l0, inv1 = 1.f / l1;
        __half* Obf = OAf + (size_t)(b * SEQ + q0) * QW + h * HD;
#pragma unroll
        for (int nt = 0; nt < 16; nt++) {
            int col = nt * 8 + tig * 2;
            *(uint32_t*)(Obf + (size_t)rl * QW + col) = packh2(o[nt][0] * inv0, o[nt][1] * inv0);
            *(uint32_t*)(Obf + (size_t)rh * QW + col) = packh2(o[nt][2] * inv1, o[nt][3] * inv1);
        }
    }
}

// ---------------------------------------------------------------------------
// Launcher
// ---------------------------------------------------------------------------
extern "C" void kernel_launch(void* const* d_in, const int* in_sizes, int n_in,
                              void* d_out, int out_size)
{
    const float* x    = (const float*)d_in[0];
    const float* q_w  = (const float*)d_in[2];
    const float* k_w  = (const float*)d_in[3];
    const float* v_w  = (const float*)d_in[4];
    const float* o_w  = (const float*)d_in[5];
    const float* sinp = (const float*)d_in[6];
    const float* cosp = (const float*)d_in[7];
    float* out = (float*)d_out;

    __nv_bfloat16 *xh, *xl, *wh, *wl, *Qh, *Ql, *Kh, *Kl;
    __half *xf, *vwf, *owf, *Vfp, *Afp;
    cudaGetSymbolAddress((void**)&xh, g_xh);
    cudaGetSymbolAddress((void**)&xl, g_xl);
    cudaGetSymbolAddress((void**)&xf, g_xf);
    cudaGetSymbolAddress((void**)&wh, g_wh);
    cudaGetSymbolAddress((void**)&wl, g_wl);
    cudaGetSymbolAddress((void**)&vwf, g_vwf);
    cudaGetSymbolAddress((void**)&owf, g_owf);
    cudaGetSymbolAddress((void**)&Qh, g_Qh);
    cudaGetSymbolAddress((void**)&Ql, g_Ql);
    cudaGetSymbolAddress((void**)&Kh, g_Kh);
    cudaGetSymbolAddress((void**)&Kl, g_Kl);
    cudaGetSymbolAddress((void**)&Vfp, g_Vf);
    cudaGetSymbolAddress((void**)&Afp, g_Af);

    // 1) fused split of all fp32 operands
    split_all<<<(N4_ALL + 255) / 256, 256>>>(x, q_w, k_w, v_w, o_w,
                                             xh, xl, xf, wh, wl, vwf, owf);

    cudaFuncSetAttribute(hmma_gemm_qk, cudaFuncAttributeMaxDynamicSharedMemorySize, GEMM_SMEM);
    cudaFuncSetAttribute(hmma_gemm_1t<0>, cudaFuncAttributeMaxDynamicSharedMemorySize, OSMEM);
    cudaFuncSetAttribute(hmma_gemm_1t<1>, cudaFuncAttributeMaxDynamicSharedMemorySize, OSMEM);
    cudaFuncSetAttribute(flash_attn_mma, cudaFuncAttributeMaxDynamicSharedMemorySize, AT_SMEM);

    // 2) QK projection (bf16 3-term) + rope/split epilogue
    hmma_gemm_qk<<<dim3(W2 / 128, MTOT / 128), 128, GEMM_SMEM>>>(
        xh, xl, wh, wl, Qh, Ql, Kh, Kl, sinp, cosp, MTOT, W2, HID);

    // 3) V projection (1-term fp16, fp16 out)
    hmma_gemm_1t<1><<<dim3(KVW / 128, MTOT / 128), 128, OSMEM>>>(
        xf, vwf, Vfp, MTOT, KVW, HID);

    // 4) flash attention
    flash_attn_mma<<<dim3(NQT / 2, NH, 2), 128, AT_SMEM>>>(Qh, Ql, Kh, Kl, Vfp, Afp);

    // 5) output projection (1-term fp16, fp32 out)
    hmma_gemm_1t<0><<<dim3(HID / 128, MTOT / 128), 128, OSMEM>>>(
        Afp, owf, out, MTOT, HID, HID);
}

// round 13
// speedup vs baseline: 3.7853x; 1.0006x over previous
#include <cuda_runtime.h>
#include <cuda_bf16.h>
#include <cuda_fp16.h>
#include <math.h>
#include <stdint.h>

// Problem constants
#define MTOT 4096      // B*S
#define SEQ  2048
#define HID  2048
#define NH   16
#define NKV  4
#define HD   128
#define QW   2048      // NH*HD
#define KVW  512       // NKV*HD
#define W2   2560      // fused Q|K weight width (bf16 3-term path)

// Scratch (allocation-free rule: __device__ globals)
__device__ __nv_bfloat16 g_xh[(size_t)MTOT * HID];
__device__ __nv_bfloat16 g_xl[(size_t)MTOT * HID];
__device__ __half        g_xf[(size_t)MTOT * HID];   // x single fp16 (for V proj)
__device__ __nv_bfloat16 g_wh[(size_t)W2 * HID];     // q|k weights fused (bf16 hi)
__device__ __nv_bfloat16 g_wl[(size_t)W2 * HID];
__device__ __half        g_vwf[(size_t)KVW * HID];   // v_w single fp16
__device__ __half        g_owf[(size_t)HID * QW];    // o_w single fp16
__device__ __nv_bfloat16 g_Qh[(size_t)MTOT * QW];
__device__ __nv_bfloat16 g_Ql[(size_t)MTOT * QW];
__device__ __nv_bfloat16 g_Kh[(size_t)MTOT * KVW];
__device__ __nv_bfloat16 g_Kl[(size_t)MTOT * KVW];
__device__ __half        g_Vf[(size_t)MTOT * KVW];   // V single fp16
__device__ __half        g_Af[(size_t)MTOT * QW];    // attn out single fp16

// ---------------------------------------------------------------------------
// helpers
// ---------------------------------------------------------------------------
__device__ __forceinline__ void mma16816(float* c, const uint32_t* a, uint32_t b0, uint32_t b1) {
    asm volatile(
        "mma.sync.aligned.m16n8k16.row.col.f32.bf16.bf16.f32 "
        "{%0,%1,%2,%3}, {%4,%5,%6,%7}, {%8,%9}, {%0,%1,%2,%3};"
        : "+f"(c[0]), "+f"(c[1]), "+f"(c[2]), "+f"(c[3])
        : "r"(a[0]), "r"(a[1]), "r"(a[2]), "r"(a[3]), "r"(b0), "r"(b1));
}
__device__ __forceinline__ void mma16816f(float* c, const uint32_t* a, uint32_t b0, uint32_t b1) {
    asm volatile(
        "mma.sync.aligned.m16n8k16.row.col.f32.f16.f16.f32 "
        "{%0,%1,%2,%3}, {%4,%5,%6,%7}, {%8,%9}, {%0,%1,%2,%3};"
        : "+f"(c[0]), "+f"(c[1]), "+f"(c[2]), "+f"(c[3])
        : "r"(a[0]), "r"(a[1]), "r"(a[2]), "r"(a[3]), "r"(b0), "r"(b1));
}
__device__ __forceinline__ void ldm4(uint32_t* r, uint32_t a) {
    asm volatile("ldmatrix.sync.aligned.m8n8.x4.shared.b16 {%0,%1,%2,%3}, [%4];"
                 : "=r"(r[0]), "=r"(r[1]), "=r"(r[2]), "=r"(r[3]) : "r"(a));
}
__device__ __forceinline__ void ldm4t(uint32_t* r, uint32_t a) {
    asm volatile("ldmatrix.sync.aligned.m8n8.x4.trans.shared.b16 {%0,%1,%2,%3}, [%4];"
                 : "=r"(r[0]), "=r"(r[1]), "=r"(r[2]), "=r"(r[3]) : "r"(a));
}
__device__ __forceinline__ uint32_t smem_u32(const void* p) {
    uint32_t a;
    asm("{ .reg .u64 tmp; cvta.to.shared.u64 tmp, %1; cvt.u32.u64 %0, tmp; }"
        : "=r"(a) : "l"(p));
    return a;
}
__device__ __forceinline__ void cpa16(uint32_t dst, const void* src) {
    asm volatile("cp.async.cg.shared.global [%0], [%1], 16;" :: "r"(dst), "l"(src));
}
#define CPA_COMMIT() asm volatile("cp.async.commit_group;" ::: "memory")
#define CPA_WAIT(n)  asm volatile("cp.async.wait_group %0;" :: "n"(n) : "memory")

__device__ __forceinline__ void split2(float a, float b, uint32_t& h, uint32_t& l) {
    __nv_bfloat162 hh = __floats2bfloat162_rn(a, b);
    float ra = a - __bfloat162float(hh.x);
    float rb = b - __bfloat162float(hh.y);
    __nv_bfloat162 ll = __floats2bfloat162_rn(ra, rb);
    h = *(uint32_t*)&hh;
    l = *(uint32_t*)&ll;
}
__device__ __forceinline__ uint32_t packh2(float a, float b) {
    __half2 h = __floats2half2_rn(a, b);
    return *(uint32_t*)&h;
}

// ---------------------------------------------------------------------------
// Fused split kernel
// ---------------------------------------------------------------------------
#define N4_X   (MTOT * HID / 4)
#define N4_QW  (QW * HID / 4)
#define N4_KW  (KVW * HID / 4)
#define N4_ALL (N4_X + N4_QW + 2 * N4_KW + N4_QW)

__global__ void split_all(const float* __restrict__ x, const float* __restrict__ qw,
                          const float* __restrict__ kw, const float* __restrict__ vw,
                          const float* __restrict__ ow,
                          __nv_bfloat16* __restrict__ xh, __nv_bfloat16* __restrict__ xl,
                          __half* __restrict__ xf,
                          __nv_bfloat16* __restrict__ wh, __nv_bfloat16* __restrict__ wl,
                          __half* __restrict__ vwf, __half* __restrict__ owf)
{
    int i = blockIdx.x * blockDim.x + threadIdx.x;
    if (i >= N4_ALL) return;
    int j = i;
    if (j < N4_X) {
        float4 v = ((const float4*)x)[j];
        uint32_t h0, l0, h1, l1;
        split2(v.x, v.y, h0, l0);
        split2(v.z, v.w, h1, l1);
        ((uint2*)xh)[j] = make_uint2(h0, h1);
        ((uint2*)xl)[j] = make_uint2(l0, l1);
        ((uint2*)xf)[j] = make_uint2(packh2(v.x, v.y), packh2(v.z, v.w));
        return;
    }
    j -= N4_X;
    if (j < N4_QW) {
        float4 v = ((const float4*)qw)[j];
        uint32_t h0, l0, h1, l1;
        split2(v.x, v.y, h0, l0);
        split2(v.z, v.w, h1, l1);
        ((uint2*)wh)[j] = make_uint2(h0, h1);
        ((uint2*)wl)[j] = make_uint2(l0, l1);
        return;
    }
    j -= N4_QW;
    if (j < N4_KW) {
        float4 v = ((const float4*)kw)[j];
        uint32_t h0, l0, h1, l1;
        split2(v.x, v.y, h0, l0);
        split2(v.z, v.w, h1, l1);
        size_t off = (size_t)QW * HID / 4;
        ((uint2*)wh)[off + j] = make_uint2(h0, h1);
        ((uint2*)wl)[off + j] = make_uint2(l0, l1);
        return;
    }
    j -= N4_KW;
    if (j < N4_KW) {
        float4 v = ((const float4*)vw)[j];
        ((uint2*)vwf)[j] = make_uint2(packh2(v.x, v.y), packh2(v.z, v.w));
        return;
    }
    j -= N4_KW;
    {
        float4 v = ((const float4*)ow)[j];
        ((uint2*)owf)[j] = make_uint2(packh2(v.x, v.y), packh2(v.z, v.w));
    }
}

// ---------------------------------------------------------------------------
// QK GEMM (bf16 3-term) + rope/split epilogue. N = 2560.
// SINGLE-stage smem (40KB) + __launch_bounds__(128,3): 3 CTAs/SM cover load
// latency cross-CTA instead of intra-CTA double buffering.
// Per-accumulator MMA order unchanged (t1=hh, t2=lh, t3=hl) -> bit-identical.
// ---------------------------------------------------------------------------
#define GROW  80
#define GT    (128 * GROW)            // 10240 B
#define QK_SMEM (4 * GT)              // 40960 B, single stage

__global__ __launch_bounds__(128, 3)
void hmma_gemm_qk(const __nv_bfloat16* __restrict__ Ah, const __nv_bfloat16* __restrict__ Al,
                  const __nv_bfloat16* __restrict__ Bh, const __nv_bfloat16* __restrict__ Bl,
                  __nv_bfloat16* __restrict__ Qoh, __nv_bfloat16* __restrict__ Qol,
                  __nv_bfloat16* __restrict__ Koh, __nv_bfloat16* __restrict__ Kol,
                  const float* __restrict__ sinp, const float* __restrict__ cosp,
                  int M, int N, int K)
{
    extern __shared__ __align__(128) char smem[];
    const uint32_t sb = smem_u32(smem);

    const int t    = threadIdx.x;
    const int warp = t >> 5;
    const int lane = t & 31;
    const int wm   = warp >> 1;
    const int wn   = warp & 1;
    const int bm   = blockIdx.y * 128;
    const int bn   = blockIdx.x * 128;

    float acc[4][8][4];
#pragma unroll
    for (int mi = 0; mi < 4; mi++)
#pragma unroll
        for (int ni = 0; ni < 8; ni++)
#pragma unroll
            for (int r = 0; r < 4; r++) acc[mi][ni][r] = 0.f;

    const int S = K / 32;
    const uint32_t smAh = sb, smAl = sb + GT, smBh = sb + 2 * GT, smBl = sb + 3 * GT;

    for (int s = 0; s < S; s++) {
        const int k0 = s * 32;
#pragma unroll
        for (int i = 0; i < 4; i++) {
            int f = i * 128 + t;
            int r = f >> 2, ch = f & 3;
            uint32_t so = r * GROW + ch * 16;
            size_t  goA = (size_t)(bm + r) * K + k0 + ch * 8;
            size_t  goB = (size_t)(bn + r) * K + k0 + ch * 8;
            cpa16(smAh + so, Ah + goA);
            cpa16(smAl + so, Al + goA);
            cpa16(smBh + so, Bh + goB);
            cpa16(smBl + so, Bl + goB);
        }
        CPA_COMMIT();
        CPA_WAIT(0);
        __syncthreads();

#pragma unroll
        for (int kk = 0; kk < 2; kk++) {
            // phase 1: terms hh + lh
            {
                uint32_t bh[4][4];
#pragma unroll
                for (int ng = 0; ng < 4; ng++) {
                    int rr = wn * 64 + ng * 16 + (lane & 15);
                    ldm4(bh[ng], smBh + rr * GROW + (kk * 2 + (lane >> 4)) * 16);
                }
#pragma unroll
                for (int mt = 0; mt < 4; mt++) {
                    uint32_t ah[4], al[4];
                    int rr = wm * 64 + mt * 16 + (lane & 15);
                    uint32_t ad = rr * GROW + (kk * 2 + (lane >> 4)) * 16;
                    ldm4(ah, smAh + ad);
                    ldm4(al, smAl + ad);
#pragma unroll
                    for (int n8 = 0; n8 < 8; n8++) {
                        int ng = n8 >> 1, hf = n8 & 1;
                        mma16816(acc[mt][n8], ah, bh[ng][hf], bh[ng][hf + 2]);
                    }
#pragma unroll
                    for (int n8 = 0; n8 < 8; n8++) {
                        int ng = n8 >> 1, hf = n8 & 1;
                        mma16816(acc[mt][n8], al, bh[ng][hf], bh[ng][hf + 2]);
                    }
                }
            }
            // phase 2: term hl
            {
                uint32_t bl[4][4];
#pragma unroll
                for (int ng = 0; ng < 4; ng++) {
                    int rr = wn * 64 + ng * 16 + (lane & 15);
                    ldm4(bl[ng], smBl + rr * GROW + (kk * 2 + (lane >> 4)) * 16);
                }
#pragma unroll
                for (int mt = 0; mt < 4; mt++) {
                    uint32_t ah[4];
                    int rr = wm * 64 + mt * 16 + (lane & 15);
                    ldm4(ah, smAh + rr * GROW + (kk * 2 + (lane >> 4)) * 16);
#pragma unroll
                    for (int n8 = 0; n8 < 8; n8++) {
                        int ng = n8 >> 1, hf = n8 & 1;
                        mma16816(acc[mt][n8], ah, bl[ng][hf], bl[ng][hf + 2]);
                    }
                }
            }
        }
        __syncthreads();
    }

    // Epilogue: two passes of 64 rows through smem staging (fits 40KB)
    const int g   = lane >> 2;
    const int tig = lane & 3;
    float* stg = (float*)smem;   // [64][132] = 33792 B
    const int bx = blockIdx.x;

#pragma unroll 1
    for (int p = 0; p < 2; p++) {
        if (wm == p) {
#pragma unroll
            for (int mt = 0; mt < 4; mt++)
#pragma unroll
                for (int n8 = 0; n8 < 8; n8++) {
                    int row = mt * 16 + g;
                    int col = wn * 64 + n8 * 8 + tig * 2;
                    stg[row * 132 + col]     = acc[mt][n8][0];
                    stg[row * 132 + col + 1] = acc[mt][n8][1];
                    stg[(row + 8) * 132 + col]     = acc[mt][n8][2];
                    stg[(row + 8) * 132 + col + 1] = acc[mt][n8][3];
                }
        }
        __syncthreads();
        {
            const int r2   = t >> 1;
            const int half = t & 1;
            const int gm   = bm + p * 64 + r2;
            const int spos = gm & (SEQ - 1);
            const int pb   = half * 32;

            bool isQ = bx < 16;
            __nv_bfloat16* dh = isQ ? (Qoh + (size_t)gm * QW + bx * 128)
                                    : (Koh + (size_t)gm * KVW + (bx - 16) * 128);
            __nv_bfloat16* dl = isQ ? (Qol + (size_t)gm * QW + bx * 128)
                                    : (Kol + (size_t)gm * KVW + (bx - 16) * 128);

            uint32_t h0[16], l0[16], h1[16], l1[16];
#pragma unroll
            for (int j = 0; j < 16; j++) {
                int pi = pb + j * 2;
                float x0a = stg[r2 * 132 + pi],      x0b = stg[r2 * 132 + pi + 1];
                float x1a = stg[r2 * 132 + pi + 64], x1b = stg[r2 * 132 + pi + 65];
                float ca = cosp[(size_t)spos * HD + pi],  cb = cosp[(size_t)spos * HD + pi + 1];
                float sa = sinp[(size_t)spos * HD + pi],  sbv = sinp[(size_t)spos * HD + pi + 1];
                float y0a = x0a * ca - x1a * sa,  y1a = x1a * ca + x0a * sa;
                float y0b = x0b * cb - x1b * sbv, y1b = x1b * cb + x0b * sbv;
                split2(y0a, y0b, h0[j], l0[j]);
                split2(y1a, y1b, h1[j], l1[j]);
            }
#pragma unroll
            for (int w = 0; w < 4; w++) {
                *(uint4*)(dh + pb + w * 8)      = ((uint4*)h0)[w];
                *(uint4*)(dh + 64 + pb + w * 8) = ((uint4*)h1)[w];
                *(uint4*)(dl + pb + w * 8)      = ((uint4*)l0)[w];
                *(uint4*)(dl + 64 + pb + w * 8) = ((uint4*)l1)[w];
            }
        }
        __syncthreads();
    }
}

// ---------------------------------------------------------------------------
// 1-term fp16 GEMM. OUTF16=1 -> fp16 out (V proj), 0 -> fp32 out (O proj).
// Double-buffered, __launch_bounds__(128,3).
// ---------------------------------------------------------------------------
#define OST   (2 * GT)               // 20480 B per stage
#define OSMEM (2 * OST)              // 40960 B

template<int OUTF16>
__global__ __launch_bounds__(128, 3)
void hmma_gemm_1t(const __half* __restrict__ A_, const __half* __restrict__ B_,
                  void* __restrict__ Cv, int M, int N, int K)
{
    extern __shared__ __align__(128) char smem[];
    const uint32_t sb = smem_u32(smem);

    const int t    = threadIdx.x;
    const int warp = t >> 5;
    const int lane = t & 31;
    const int wm   = warp >> 1;
    const int wn   = warp & 1;
    const int bm   = blockIdx.y * 128;
    const int bn   = blockIdx.x * 128;

    float acc[4][8][4];
#pragma unroll
    for (int mi = 0; mi < 4; mi++)
#pragma unroll
        for (int ni = 0; ni < 8; ni++)
#pragma unroll
            for (int r = 0; r < 4; r++) acc[mi][ni][r] = 0.f;

    const int S = K / 32;

    auto issue = [&](int s, int buf) {
        const int k0 = s * 32;
        const uint32_t stg = sb + (uint32_t)buf * OST;
#pragma unroll
        for (int i = 0; i < 4; i++) {
            int f = i * 128 + t;
            int r = f >> 2, ch = f & 3;
            uint32_t so = r * GROW + ch * 16;
            cpa16(stg + 0 * GT + so, A_ + (size_t)(bm + r) * K + k0 + ch * 8);
            cpa16(stg + 1 * GT + so, B_ + (size_t)(bn + r) * K + k0 + ch * 8);
        }
        CPA_COMMIT();
    };

    issue(0, 0);

    for (int s = 0; s < S; s++) {
        const int buf = s & 1;
        if (s + 1 < S) { issue(s + 1, buf ^ 1); CPA_WAIT(1); }
        else           { CPA_WAIT(0); }
        __syncthreads();

        const uint32_t smA = sb + (uint32_t)buf * OST;
        const uint32_t smB = smA + GT;

#pragma unroll
        for (int kk = 0; kk < 2; kk++) {
            uint32_t bfr[4][4];
#pragma unroll
            for (int ng = 0; ng < 4; ng++) {
                int rr = wn * 64 + ng * 16 + (lane & 15);
                uint32_t ad = rr * GROW + (kk * 2 + (lane >> 4)) * 16;
                ldm4(bfr[ng], smB + ad);
            }
#pragma unroll
            for (int mt = 0; mt < 4; mt++) {
                uint32_t af[4];
                int rr = wm * 64 + mt * 16 + (lane & 15);
                uint32_t ad = rr * GROW + (kk * 2 + (lane >> 4)) * 16;
                ldm4(af, smA + ad);
#pragma unroll
                for (int n8 = 0; n8 < 8; n8++) {
                    int ng = n8 >> 1, hf = n8 & 1;
                    mma16816f(acc[mt][n8], af, bfr[ng][hf], bfr[ng][hf + 2]);
                }
            }
        }
        __syncthreads();
    }

    const int g   = lane >> 2;
    const int tig = lane & 3;
    if (OUTF16) {
        __half* C = (__half*)Cv;
#pragma unroll
        for (int mt = 0; mt < 4; mt++)
#pragma unroll
            for (int n8 = 0; n8 < 8; n8++) {
                int row = bm + wm * 64 + mt * 16 + g;
                int col = bn + wn * 64 + n8 * 8 + tig * 2;
                *(uint32_t*)(C + (size_t)row * N + col) = packh2(acc[mt][n8][0], acc[mt][n8][1]);
                *(uint32_t*)(C + (size_t)(row + 8) * N + col) = packh2(acc[mt][n8][2], acc[mt][n8][3]);
            }
    } else {
        float* C = (float*)Cv;
#pragma unroll
        for (int mt = 0; mt < 4; mt++)
#pragma unroll
            for (int n8 = 0; n8 < 8; n8++) {
                int row = bm + wm * 64 + mt * 16 + g;
                int col = bn + wn * 64 + n8 * 8 + tig * 2;
                *(float2*)(C + (size_t)row * N + col) = make_float2(acc[mt][n8][0], acc[mt][n8][1]);
                *(float2*)(C + (size_t)(row + 8) * N + col) = make_float2(acc[mt][n8][2], acc[mt][n8][3]);
            }
    }
}

// ---------------------------------------------------------------------------
// Flash attention: QK bf16 3-term; PV single fp16 MMA; single-fp16 output.
// ---------------------------------------------------------------------------
#define AT_TILE 16384
#define AT_SMEM (5 * AT_TILE)               // 81920 B
#define NQT     (SEQ / 64)                  // 32

__device__ __forceinline__ uint32_t swz256(int r, int ch) {
    return (uint32_t)(r * 256 + (((ch ^ (r & 7)) & 15) << 4));
}

__global__ __launch_bounds__(128)
void flash_attn_mma(const __nv_bfloat16* __restrict__ Qh, const __nv_bfloat16* __restrict__ Ql,
                    const __nv_bfloat16* __restrict__ Kh, const __nv_bfloat16* __restrict__ Kl,
                    const __half* __restrict__ Vf, __half* __restrict__ OAf)
{
    extern __shared__ __align__(128) char smem[];
    const uint32_t sb  = smem_u32(smem);
    const uint32_t sQh = sb;
    const uint32_t sQl = sb + AT_TILE;
    const uint32_t sA  = sb + 2 * AT_TILE;   // K stage: {h, l}
    const uint32_t sBv = sb + 4 * AT_TILE;   // V stage: single fp16

    const int h   = blockIdx.y;
    const int b   = blockIdx.z;
    const int kvh = h >> 2;
    const int t   = threadIdx.x;
    const int warp = t >> 5;
    const int lane = t & 31;
    const int g    = lane >> 2;
    const int tig  = lane & 3;

    const int rl = warp * 16 + g;
    const int rh = rl + 8;

    auto load_k = [&](int kt) {
        const __nv_bfloat16* bh = Kh + (size_t)(b * SEQ + kt * 64) * KVW + kvh * HD;
        const __nv_bfloat16* bl = Kl + (size_t)(b * SEQ + kt * 64) * KVW + kvh * HD;
#pragma unroll
        for (int i = 0; i < 8; i++) {
            int f = i * 128 + t;
            int r = f >> 4, ch = f & 15;
            cpa16(sA + swz256(r, ch),           bh + (size_t)r * KVW + ch * 8);
            cpa16(sA + AT_TILE + swz256(r, ch), bl + (size_t)r * KVW + ch * 8);
        }
        CPA_COMMIT();
    };
    auto load_v = [&](int kt) {
        const __half* bv = Vf + (size_t)(b * SEQ + kt * 64) * KVW + kvh * HD;
#pragma unroll
        for (int i = 0; i < 8; i++) {
            int f = i * 128 + t;
            int r = f >> 4, ch = f & 15;
            cpa16(sBv + swz256(r, ch), bv + (size_t)r * KVW + ch * 8);
        }
        CPA_COMMIT();
    };

    for (int sel = 0; sel < 2; sel++) {
        const int qt = sel ? (NQT - 1 - blockIdx.x) : blockIdx.x;
        const int q0 = qt * 64;

        {
            const __nv_bfloat16* qbh = Qh + (size_t)(b * SEQ + q0) * QW + h * HD;
            const __nv_bfloat16* qbl = Ql + (size_t)(b * SEQ + q0) * QW + h * HD;
#pragma unroll
            for (int i = 0; i < 8; i++) {
                int f = i * 128 + t;
                int r = f >> 4, ch = f & 15;
                cpa16(sQh + swz256(r, ch), qbh + (size_t)r * QW + ch * 8);
                cpa16(sQl + swz256(r, ch), qbl + (size_t)r * QW + ch * 8);
            }
            CPA_COMMIT();
        }
        load_k(0);
        CPA_WAIT(0);
        __syncthreads();

        float o[16][4];
        float m0 = -1e30f, m1 = -1e30f, l0 = 0.f, l1 = 0.f;
#pragma unroll
        for (int i = 0; i < 16; i++)
#pragma unroll
            for (int j = 0; j < 4; j++) o[i][j] = 0.f;

        for (int kt = 0; kt <= qt; kt++) {
            load_v(kt);

            float sacc[8][4];
#pragma unroll
            for (int i = 0; i < 8; i++)
#pragma unroll
                for (int j = 0; j < 4; j++) sacc[i][j] = 0.f;

#pragma unroll
            for (int ks = 0; ks < 8; ks++) {
                uint32_t qfh[4], qfl[4];
                {
                    int rr = warp * 16 + (lane & 15);
                    uint32_t ad = swz256(rr, ks * 2 + (lane >> 4));
                    ldm4(qfh, sQh + ad);
                    ldm4(qfl, sQl + ad);
                }
                uint32_t kfh[4][4], kfl[4][4];
#pragma unroll
                for (int ng = 0; ng < 4; ng++) {
                    int rr = ng * 16 + (lane & 15);
                    uint32_t ad = swz256(rr, ks * 2 + (lane >> 4));
                    ldm4(kfh[ng], sA + ad);
                    ldm4(kfl[ng], sA + AT_TILE + ad);
                }
#pragma unroll
                for (int n8 = 0; n8 < 8; n8++) {
                    int ng = n8 >> 1, hf = n8 & 1;
                    mma16816(sacc[n8], qfh, kfh[ng][hf], kfh[ng][hf + 2]);
                }
#pragma unroll
                for (int n8 = 0; n8 < 8; n8++) {
                    int ng = n8 >> 1, hf = n8 & 1;
                    mma16816(sacc[n8], qfl, kfh[ng][hf], kfh[ng][hf + 2]);
                }
#pragma unroll
                for (int n8 = 0; n8 < 8; n8++) {
                    int ng = n8 >> 1, hf = n8 & 1;
                    mma16816(sacc[n8], qfh, kfl[ng][hf], kfl[ng][hf + 2]);
                }
            }

            if (kt == qt) {
#pragma unroll
                for (int n8 = 0; n8 < 8; n8++) {
                    int c0 = n8 * 8 + tig * 2, c1 = c0 + 1;
                    if (c0 > rl) sacc[n8][0] = -1e30f;
                    if (c1 > rl) sacc[n8][1] = -1e30f;
                    if (c0 > rh) sacc[n8][2] = -1e30f;
                    if (c1 > rh) sacc[n8][3] = -1e30f;
                }
            }

            float mx0 = -1e30f, mx1 = -1e30f;
#pragma unroll
            for (int n8 = 0; n8 < 8; n8++) {
                mx0 = fmaxf(mx0, fmaxf(sacc[n8][0], sacc[n8][1]));
                mx1 = fmaxf(mx1, fmaxf(sacc[n8][2], sacc[n8][3]));
            }
            mx0 = fmaxf(mx0, __shfl_xor_sync(0xffffffffu, mx0, 1));
            mx0 = fmaxf(mx0, __shfl_xor_sync(0xffffffffu, mx0, 2));
            mx1 = fmaxf(mx1, __shfl_xor_sync(0xffffffffu, mx1, 1));
            mx1 = fmaxf(mx1, __shfl_xor_sync(0xffffffffu, mx1, 2));

            float mn0 = fmaxf(m0, mx0), mn1 = fmaxf(m1, mx1);
            float al0 = __expf(m0 - mn0), al1 = __expf(m1 - mn1);
            m0 = mn0; m1 = mn1;

            float s0 = 0.f, s1 = 0.f;
#pragma unroll
            for (int n8 = 0; n8 < 8; n8++) {
                float p0 = __expf(sacc[n8][0] - m0);
                float p1 = __expf(sacc[n8][1] - m0);
                float p2 = __expf(sacc[n8][2] - m1);
                float p3 = __expf(sacc[n8][3] - m1);
                sacc[n8][0] = p0; sacc[n8][1] = p1; sacc[n8][2] = p2; sacc[n8][3] = p3;
                s0 += p0 + p1; s1 += p2 + p3;
            }
            s0 += __shfl_xor_sync(0xffffffffu, s0, 1);
            s0 += __shfl_xor_sync(0xffffffffu, s0, 2);
            s1 += __shfl_xor_sync(0xffffffffu, s1, 1);
            s1 += __shfl_xor_sync(0xffffffffu, s1, 2);
            l0 = l0 * al0 + s0;
            l1 = l1 * al1 + s1;

#pragma unroll
            for (int i = 0; i < 16; i++) {
                o[i][0] *= al0; o[i][1] *= al0;
                o[i][2] *= al1; o[i][3] *= al1;
            }

            uint32_t ph[4][4];
#pragma unroll
            for (int kk = 0; kk < 4; kk++) {
                ph[kk][0] = packh2(sacc[2 * kk][0],     sacc[2 * kk][1]);
                ph[kk][1] = packh2(sacc[2 * kk][2],     sacc[2 * kk][3]);
                ph[kk][2] = packh2(sacc[2 * kk + 1][0], sacc[2 * kk + 1][1]);
                ph[kk][3] = packh2(sacc[2 * kk + 1][2], sacc[2 * kk + 1][3]);
            }

            CPA_WAIT(0);
            __syncthreads();

            if (kt < qt) load_k(kt + 1);

#pragma unroll
            for (int ng = 0; ng < 8; ng++) {
#pragma unroll
                for (int kk = 0; kk < 4; kk++) {
                    uint32_t vf[4];
                    int rr = kk * 16 + (lane & 15);
                    uint32_t ad = swz256(rr, ng * 2 + (lane >> 4));
                    ldm4t(vf, sBv + ad);
#pragma unroll
                    for (int hf = 0; hf < 2; hf++) {
                        int nt = ng * 2 + hf;
                        mma16816f(o[nt], ph[kk], vf[hf * 2], vf[hf * 2 + 1]);
                    }
                }
            }

            CPA_WAIT(0);
            __syncthreads();
        }

        float inv0 = 1.f / l0, inv1 = 1.f / l1;
        __half* Obf = OAf + (size_t)(b * SEQ + q0) * QW + h * HD;
#pragma unroll
        for (int nt = 0; nt < 16; nt++) {
            int col = nt * 8 + tig * 2;
            *(uint32_t*)(Obf + (size_t)rl * QW + col) = packh2(o[nt][0] * inv0, o[nt][1] * inv0);
            *(uint32_t*)(Obf + (size_t)rh * QW + col) = packh2(o[nt][2] * inv1, o[nt][3] * inv1);
        }
    }
}

// ---------------------------------------------------------------------------
// Launcher — forked-capture streams: V-proj overlaps QK-proj.
// ---------------------------------------------------------------------------
extern "C" void kernel_launch(void* const* d_in, const int* in_sizes, int n_in,
                              void* d_out, int out_size)
{
    const float* x    = (const float*)d_in[0];
    const float* q_w  = (const float*)d_in[2];
    const float* k_w  = (const float*)d_in[3];
    const float* v_w  = (const float*)d_in[4];
    const float* o_w  = (const float*)d_in[5];
    const float* sinp = (const float*)d_in[6];
    const float* cosp = (const float*)d_in[7];
    float* out = (float*)d_out;

    __nv_bfloat16 *xh, *xl, *wh, *wl, *Qh, *Ql, *Kh, *Kl;
    __half *xf, *vwf, *owf, *Vfp, *Afp;
    cudaGetSymbolAddress((void**)&xh, g_xh);
    cudaGetSymbolAddress((void**)&xl, g_xl);
    cudaGetSymbolAddress((void**)&xf, g_xf);
    cudaGetSymbolAddress((void**)&wh, g_wh);
    cudaGetSymbolAddress((void**)&wl, g_wl);
    cudaGetSymbolAddress((void**)&vwf, g_vwf);
    cudaGetSymbolAddress((void**)&owf, g_owf);
    cudaGetSymbolAddress((void**)&Qh, g_Qh);
    cudaGetSymbolAddress((void**)&Ql, g_Ql);
    cudaGetSymbolAddress((void**)&Kh, g_Kh);
    cudaGetSymbolAddress((void**)&Kl, g_Kl);
    cudaGetSymbolAddress((void**)&Vfp, g_Vf);
    cudaGetSymbolAddress((void**)&Afp, g_Af);

    cudaFuncSetAttribute(hmma_gemm_qk, cudaFuncAttributeMaxDynamicSharedMemorySize, QK_SMEM);
    cudaFuncSetAttribute(hmma_gemm_1t<0>, cudaFuncAttributeMaxDynamicSharedMemorySize, OSMEM);
    cudaFuncSetAttribute(hmma_gemm_1t<1>, cudaFuncAttributeMaxDynamicSharedMemorySize, OSMEM);
    cudaFuncSetAttribute(flash_attn_mma, cudaFuncAttributeMaxDynamicSharedMemorySize, AT_SMEM);

    // fork/join resources (host-side objects; created per call, not destroyed
    // to stay safe inside graph capture — no device memory involved)
    cudaStream_t s2;
    cudaEvent_t e1, e2;
    cudaStreamCreateWithFlags(&s2, cudaStreamNonBlocking);
    cudaEventCreateWithFlags(&e1, cudaEventDisableTiming);
    cudaEventCreateWithFlags(&e2, cudaEventDisableTiming);

    // 1) fused split of all fp32 operands (main stream)
    split_all<<<(N4_ALL + 255) / 256, 256>>>(x, q_w, k_w, v_w, o_w,
                                             xh, xl, xf, wh, wl, vwf, owf);
    cudaEventRecord(e1, 0);
    cudaStreamWaitEvent(s2, e1, 0);

    // 2) QK projection (bf16 3-term) on main stream
    hmma_gemm_qk<<<dim3(W2 / 128, MTOT / 128), 128, QK_SMEM>>>(
        xh, xl, wh, wl, Qh, Ql, Kh, Kl, sinp, cosp, MTOT, W2, HID);

    // 3) V projection (1-term fp16) concurrently on s2
    hmma_gemm_1t<1><<<dim3(KVW / 128, MTOT / 128), 128, OSMEM, s2>>>(
        xf, vwf, Vfp, MTOT, KVW, HID);
    cudaEventRecord(e2, s2);
    cudaStreamWaitEvent(0, e2, 0);

    // 4) flash attention (joined)
    flash_attn_mma<<<dim3(NQT / 2, NH, 2), 128, AT_SMEM>>>(Qh, Ql, Kh, Kl, Vfp, Afp);

    // 5) output projection (1-term fp16, fp32 out)
    hmma_gemm_1t<0><<<dim3(HID / 128, MTOT / 128), 128, OSMEM>>>(
        Afp, owf, out, MTOT, HID, HID);
}

// round 14
// speedup vs baseline: 4.1840x; 1.1053x over previous
#include <cuda_runtime.h>
#include <cuda_bf16.h>
#include <cuda_fp16.h>
#include <math.h>
#include <stdint.h>

// Problem constants
#define MTOT 4096      // B*S
#define SEQ  2048
#define HID  2048
#define NH   16
#define NKV  4
#define HD   128
#define QW   2048      // NH*HD
#define KVW  512       // NKV*HD
#define W2   2560      // fused Q|K weight width (bf16 3-term path)

// Scratch (allocation-free rule: __device__ globals)
__device__ __nv_bfloat16 g_xh[(size_t)MTOT * HID];
__device__ __nv_bfloat16 g_xl[(size_t)MTOT * HID];
__device__ __half        g_xf[(size_t)MTOT * HID];
__device__ __nv_bfloat16 g_wh[(size_t)W2 * HID];
__device__ __nv_bfloat16 g_wl[(size_t)W2 * HID];
__device__ __half        g_vwf[(size_t)KVW * HID];
__device__ __half        g_owf[(size_t)HID * QW];
__device__ __nv_bfloat16 g_Qh[(size_t)MTOT * QW];
__device__ __nv_bfloat16 g_Ql[(size_t)MTOT * QW];
__device__ __nv_bfloat16 g_Kh[(size_t)MTOT * KVW];
__device__ __nv_bfloat16 g_Kl[(size_t)MTOT * KVW];
__device__ __half        g_Vf[(size_t)MTOT * KVW];
__device__ __half        g_Af[(size_t)MTOT * QW];

// ---------------------------------------------------------------------------
// helpers
// ---------------------------------------------------------------------------
__device__ __forceinline__ void mma16816(float* c, const uint32_t* a, uint32_t b0, uint32_t b1) {
    asm volatile(
        "mma.sync.aligned.m16n8k16.row.col.f32.bf16.bf16.f32 "
        "{%0,%1,%2,%3}, {%4,%5,%6,%7}, {%8,%9}, {%0,%1,%2,%3};"
        : "+f"(c[0]), "+f"(c[1]), "+f"(c[2]), "+f"(c[3])
        : "r"(a[0]), "r"(a[1]), "r"(a[2]), "r"(a[3]), "r"(b0), "r"(b1));
}
__device__ __forceinline__ void mma16816f(float* c, const uint32_t* a, uint32_t b0, uint32_t b1) {
    asm volatile(
        "mma.sync.aligned.m16n8k16.row.col.f32.f16.f16.f32 "
        "{%0,%1,%2,%3}, {%4,%5,%6,%7}, {%8,%9}, {%0,%1,%2,%3};"
        : "+f"(c[0]), "+f"(c[1]), "+f"(c[2]), "+f"(c[3])
        : "r"(a[0]), "r"(a[1]), "r"(a[2]), "r"(a[3]), "r"(b0), "r"(b1));
}
__device__ __forceinline__ void ldm4(uint32_t* r, uint32_t a) {
    asm volatile("ldmatrix.sync.aligned.m8n8.x4.shared.b16 {%0,%1,%2,%3}, [%4];"
                 : "=r"(r[0]), "=r"(r[1]), "=r"(r[2]), "=r"(r[3]) : "r"(a));
}
__device__ __forceinline__ void ldm4t(uint32_t* r, uint32_t a) {
    asm volatile("ldmatrix.sync.aligned.m8n8.x4.trans.shared.b16 {%0,%1,%2,%3}, [%4];"
                 : "=r"(r[0]), "=r"(r[1]), "=r"(r[2]), "=r"(r[3]) : "r"(a));
}
__device__ __forceinline__ uint32_t smem_u32(const void* p) {
    uint32_t a;
    asm("{ .reg .u64 tmp; cvta.to.shared.u64 tmp, %1; cvt.u32.u64 %0, tmp; }"
        : "=r"(a) : "l"(p));
    return a;
}
__device__ __forceinline__ void cpa16(uint32_t dst, const void* src) {
    asm volatile("cp.async.cg.shared.global [%0], [%1], 16;" :: "r"(dst), "l"(src));
}
#define CPA_COMMIT() asm volatile("cp.async.commit_group;" ::: "memory")
#define CPA_WAIT(n)  asm volatile("cp.async.wait_group %0;" :: "n"(n) : "memory")

__device__ __forceinline__ void split2(float a, float b, uint32_t& h, uint32_t& l) {
    __nv_bfloat162 hh = __floats2bfloat162_rn(a, b);
    float ra = a - __bfloat162float(hh.x);
    float rb = b - __bfloat162float(hh.y);
    __nv_bfloat162 ll = __floats2bfloat162_rn(ra, rb);
    h = *(uint32_t*)&hh;
    l = *(uint32_t*)&ll;
}
__device__ __forceinline__ uint32_t packh2(float a, float b) {
    __half2 h = __floats2half2_rn(a, b);
    return *(uint32_t*)&h;
}

// ---------------------------------------------------------------------------
// Fused split kernel
// ---------------------------------------------------------------------------
#define N4_X   (MTOT * HID / 4)
#define N4_QW  (QW * HID / 4)
#define N4_KW  (KVW * HID / 4)
#define N4_ALL (N4_X + N4_QW + 2 * N4_KW + N4_QW)

__global__ void split_all(const float* __restrict__ x, const float* __restrict__ qw,
                          const float* __restrict__ kw, const float* __restrict__ vw,
                          const float* __restrict__ ow,
                          __nv_bfloat16* __restrict__ xh, __nv_bfloat16* __restrict__ xl,
                          __half* __restrict__ xf,
                          __nv_bfloat16* __restrict__ wh, __nv_bfloat16* __restrict__ wl,
                          __half* __restrict__ vwf, __half* __restrict__ owf)
{
    int i = blockIdx.x * blockDim.x + threadIdx.x;
    if (i >= N4_ALL) return;
    int j = i;
    if (j < N4_X) {
        float4 v = ((const float4*)x)[j];
        uint32_t h0, l0, h1, l1;
        split2(v.x, v.y, h0, l0);
        split2(v.z, v.w, h1, l1);
        ((uint2*)xh)[j] = make_uint2(h0, h1);
        ((uint2*)xl)[j] = make_uint2(l0, l1);
        ((uint2*)xf)[j] = make_uint2(packh2(v.x, v.y), packh2(v.z, v.w));
        return;
    }
    j -= N4_X;
    if (j < N4_QW) {
        float4 v = ((const float4*)qw)[j];
        uint32_t h0, l0, h1, l1;
        split2(v.x, v.y, h0, l0);
        split2(v.z, v.w, h1, l1);
        ((uint2*)wh)[j] = make_uint2(h0, h1);
        ((uint2*)wl)[j] = make_uint2(l0, l1);
        return;
    }
    j -= N4_QW;
    if (j < N4_KW) {
        float4 v = ((const float4*)kw)[j];
        uint32_t h0, l0, h1, l1;
        split2(v.x, v.y, h0, l0);
        split2(v.z, v.w, h1, l1);
        size_t off = (size_t)QW * HID / 4;
        ((uint2*)wh)[off + j] = make_uint2(h0, h1);
        ((uint2*)wl)[off + j] = make_uint2(l0, l1);
        return;
    }
    j -= N4_KW;
    if (j < N4_KW) {
        float4 v = ((const float4*)vw)[j];
        ((uint2*)vwf)[j] = make_uint2(packh2(v.x, v.y), packh2(v.z, v.w));
        return;
    }
    j -= N4_KW;
    {
        float4 v = ((const float4*)ow)[j];
        ((uint2*)owf)[j] = make_uint2(packh2(v.x, v.y), packh2(v.z, v.w));
    }
}

// ---------------------------------------------------------------------------
// QK GEMM (bf16 3-term) + rope/split epilogue. BM=64, BN=128 -> 1280 CTAs.
// Single-stage smem, 3 CTAs/SM. Warp tile 32x64.
// Per-accumulator MMA order unchanged -> bit-identical to previous rounds.
// ---------------------------------------------------------------------------
#define GROW  80
#define GTA   (64 * GROW)             // 5120 B  (A tile, 64 rows)
#define GTB   (128 * GROW)            // 10240 B (B tile, 128 rows)
#define QK_SMEM 33792                 // max(tiles 30720, epilogue 64*132*4)

__global__ __launch_bounds__(128, 3)
void hmma_gemm_qk(const __nv_bfloat16* __restrict__ Ah, const __nv_bfloat16* __restrict__ Al,
                  const __nv_bfloat16* __restrict__ Bh, const __nv_bfloat16* __restrict__ Bl,
                  __nv_bfloat16* __restrict__ Qoh, __nv_bfloat16* __restrict__ Qol,
                  __nv_bfloat16* __restrict__ Koh, __nv_bfloat16* __restrict__ Kol,
                  const float* __restrict__ sinp, const float* __restrict__ cosp,
                  int M, int N, int K)
{
    extern __shared__ __align__(128) char smem[];
    const uint32_t sb = smem_u32(smem);

    const int t    = threadIdx.x;
    const int warp = t >> 5;
    const int lane = t & 31;
    const int wm   = warp >> 1;        // 0..1 -> 32-row halves
    const int wn   = warp & 1;         // 0..1 -> 64-col halves
    const int bm   = blockIdx.y * 64;
    const int bn   = blockIdx.x * 128;

    float acc[2][8][4];
#pragma unroll
    for (int mi = 0; mi < 2; mi++)
#pragma unroll
        for (int ni = 0; ni < 8; ni++)
#pragma unroll
            for (int r = 0; r < 4; r++) acc[mi][ni][r] = 0.f;

    const int S = K / 32;
    const uint32_t smAh = sb, smAl = sb + GTA, smBh = sb + 2 * GTA, smBl = sb + 2 * GTA + GTB;

    for (int s = 0; s < S; s++) {
        const int k0 = s * 32;
        // A: 64 rows x 4 chunks = 256 -> 2/thread (hi+lo)
#pragma unroll
        for (int i = 0; i < 2; i++) {
            int f = i * 128 + t;
            int r = f >> 2, ch = f & 3;
            uint32_t so = r * GROW + ch * 16;
            size_t  go = (size_t)(bm + r) * K + k0 + ch * 8;
            cpa16(smAh + so, Ah + go);
            cpa16(smAl + so, Al + go);
        }
        // B: 128 rows x 4 chunks = 512 -> 4/thread (hi+lo)
#pragma unroll
        for (int i = 0; i < 4; i++) {
            int f = i * 128 + t;
            int r = f >> 2, ch = f & 3;
            uint32_t so = r * GROW + ch * 16;
            size_t  go = (size_t)(bn + r) * K + k0 + ch * 8;
            cpa16(smBh + so, Bh + go);
            cpa16(smBl + so, Bl + go);
        }
        CPA_COMMIT();
        CPA_WAIT(0);
        __syncthreads();

#pragma unroll
        for (int kk = 0; kk < 2; kk++) {
            // phase 1: terms hh + lh
            {
                uint32_t bh[4][4];
#pragma unroll
                for (int ng = 0; ng < 4; ng++) {
                    int rr = wn * 64 + ng * 16 + (lane & 15);
                    ldm4(bh[ng], smBh + rr * GROW + (kk * 2 + (lane >> 4)) * 16);
                }
#pragma unroll
                for (int mt = 0; mt < 2; mt++) {
                    uint32_t ah[4], al[4];
                    int rr = wm * 32 + mt * 16 + (lane & 15);
                    uint32_t ad = rr * GROW + (kk * 2 + (lane >> 4)) * 16;
                    ldm4(ah, smAh + ad);
                    ldm4(al, smAl + ad);
#pragma unroll
                    for (int n8 = 0; n8 < 8; n8++) {
                        int ng = n8 >> 1, hf = n8 & 1;
                        mma16816(acc[mt][n8], ah, bh[ng][hf], bh[ng][hf + 2]);
                    }
#pragma unroll
                    for (int n8 = 0; n8 < 8; n8++) {
                        int ng = n8 >> 1, hf = n8 & 1;
                        mma16816(acc[mt][n8], al, bh[ng][hf], bh[ng][hf + 2]);
                    }
                }
            }
            // phase 2: term hl
            {
                uint32_t bl[4][4];
#pragma unroll
                for (int ng = 0; ng < 4; ng++) {
                    int rr = wn * 64 + ng * 16 + (lane & 15);
                    ldm4(bl[ng], smBl + rr * GROW + (kk * 2 + (lane >> 4)) * 16);
                }
#pragma unroll
                for (int mt = 0; mt < 2; mt++) {
                    uint32_t ah[4];
                    int rr = wm * 32 + mt * 16 + (lane & 15);
                    ldm4(ah, smAh + rr * GROW + (kk * 2 + (lane >> 4)) * 16);
#pragma unroll
                    for (int n8 = 0; n8 < 8; n8++) {
                        int ng = n8 >> 1, hf = n8 & 1;
                        mma16816(acc[mt][n8], ah, bl[ng][hf], bl[ng][hf + 2]);
                    }
                }
            }
        }
        __syncthreads();
    }

    // Epilogue: stage all 64 rows, rope + bf16 split
    const int g   = lane >> 2;
    const int tig = lane & 3;
    float* stg = (float*)smem;   // [64][132]
    const int bx = blockIdx.x;

#pragma unroll
    for (int mt = 0; mt < 2; mt++)
#pragma unroll
        for (int n8 = 0; n8 < 8; n8++) {
            int row = wm * 32 + mt * 16 + g;
            int col = wn * 64 + n8 * 8 + tig * 2;
            stg[row * 132 + col]     = acc[mt][n8][0];
            stg[row * 132 + col + 1] = acc[mt][n8][1];
            stg[(row + 8) * 132 + col]     = acc[mt][n8][2];
            stg[(row + 8) * 132 + col + 1] = acc[mt][n8][3];
        }
    __syncthreads();

    {
        const int r2   = t >> 1;
        const int half = t & 1;
        const int gm   = bm + r2;
        const int spos = gm & (SEQ - 1);
        const int pb   = half * 32;

        bool isQ = bx < 16;
        __nv_bfloat16* dh = isQ ? (Qoh + (size_t)gm * QW + bx * 128)
                                : (Koh + (size_t)gm * KVW + (bx - 16) * 128);
        __nv_bfloat16* dl = isQ ? (Qol + (size_t)gm * QW + bx * 128)
                                : (Kol + (size_t)gm * KVW + (bx - 16) * 128);

        uint32_t h0[16], l0[16], h1[16], l1[16];
#pragma unroll
        for (int j = 0; j < 16; j++) {
            int pi = pb + j * 2;
            float x0a = stg[r2 * 132 + pi],      x0b = stg[r2 * 132 + pi + 1];
            float x1a = stg[r2 * 132 + pi + 64], x1b = stg[r2 * 132 + pi + 65];
            float ca = cosp[(size_t)spos * HD + pi],  cb = cosp[(size_t)spos * HD + pi + 1];
            float sa = sinp[(size_t)spos * HD + pi],  sbv = sinp[(size_t)spos * HD + pi + 1];
            float y0a = x0a * ca - x1a * sa,  y1a = x1a * ca + x0a * sa;
            float y0b = x0b * cb - x1b * sbv, y1b = x1b * cb + x0b * sbv;
            split2(y0a, y0b, h0[j], l0[j]);
            split2(y1a, y1b, h1[j], l1[j]);
        }
#pragma unroll
        for (int w = 0; w < 4; w++) {
            *(uint4*)(dh + pb + w * 8)      = ((uint4*)h0)[w];
            *(uint4*)(dh + 64 + pb + w * 8) = ((uint4*)h1)[w];
            *(uint4*)(dl + pb + w * 8)      = ((uint4*)l0)[w];
            *(uint4*)(dl + 64 + pb + w * 8) = ((uint4*)l1)[w];
        }
    }
}

// ---------------------------------------------------------------------------
// 1-term fp16 GEMM, BM=64, BN=128. OUTF16=1 -> fp16 out, 0 -> fp32 out.
// 2-stage pipeline, 3 CTAs/SM.
// ---------------------------------------------------------------------------
#define OST   (GTA + GTB)            // 15360 B per stage
#define OSMEM (2 * OST)              // 30720 B

template<int OUTF16>
__global__ __launch_bounds__(128, 3)
void hmma_gemm_1t(const __half* __restrict__ A_, const __half* __restrict__ B_,
                  void* __restrict__ Cv, int M, int N, int K)
{
    extern __shared__ __align__(128) char smem[];
    const uint32_t sb = smem_u32(smem);

    const int t    = threadIdx.x;
    const int warp = t >> 5;
    const int lane = t & 31;
    const int wm   = warp >> 1;
    const int wn   = warp & 1;
    const int bm   = blockIdx.y * 64;
    const int bn   = blockIdx.x * 128;

    float acc[2][8][4];
#pragma unroll
    for (int mi = 0; mi < 2; mi++)
#pragma unroll
        for (int ni = 0; ni < 8; ni++)
#pragma unroll
            for (int r = 0; r < 4; r++) acc[mi][ni][r] = 0.f;

    const int S = K / 32;

    auto issue = [&](int s, int buf) {
        const int k0 = s * 32;
        const uint32_t stg = sb + (uint32_t)buf * OST;
#pragma unroll
        for (int i = 0; i < 2; i++) {
            int f = i * 128 + t;
            int r = f >> 2, ch = f & 3;
            cpa16(stg + r * GROW + ch * 16, A_ + (size_t)(bm + r) * K + k0 + ch * 8);
        }
#pragma unroll
        for (int i = 0; i < 4; i++) {
            int f = i * 128 + t;
            int r = f >> 2, ch = f & 3;
            cpa16(stg + GTA + r * GROW + ch * 16, B_ + (size_t)(bn + r) * K + k0 + ch * 8);
        }
        CPA_COMMIT();
    };

    issue(0, 0);

    for (int s = 0; s < S; s++) {
        const int buf = s & 1;
        if (s + 1 < S) { issue(s + 1, buf ^ 1); CPA_WAIT(1); }
        else           { CPA_WAIT(0); }
        __syncthreads();

        const uint32_t smA = sb + (uint32_t)buf * OST;
        const uint32_t smB = smA + GTA;

#pragma unroll
        for (int kk = 0; kk < 2; kk++) {
            uint32_t bfr[4][4];
#pragma unroll
            for (int ng = 0; ng < 4; ng++) {
                int rr = wn * 64 + ng * 16 + (lane & 15);
                uint32_t ad = rr * GROW + (kk * 2 + (lane >> 4)) * 16;
                ldm4(bfr[ng], smB + ad);
            }
#pragma unroll
            for (int mt = 0; mt < 2; mt++) {
                uint32_t af[4];
                int rr = wm * 32 + mt * 16 + (lane & 15);
                uint32_t ad = rr * GROW + (kk * 2 + (lane >> 4)) * 16;
                ldm4(af, smA + ad);
#pragma unroll
                for (int n8 = 0; n8 < 8; n8++) {
                    int ng = n8 >> 1, hf = n8 & 1;
                    mma16816f(acc[mt][n8], af, bfr[ng][hf], bfr[ng][hf + 2]);
                }
            }
        }
        __syncthreads();
    }

    const int g   = lane >> 2;
    const int tig = lane & 3;
    if (OUTF16) {
        __half* C = (__half*)Cv;
#pragma unroll
        for (int mt = 0; mt < 2; mt++)
#pragma unroll
            for (int n8 = 0; n8 < 8; n8++) {
                int row = bm + wm * 32 + mt * 16 + g;
                int col = bn + wn * 64 + n8 * 8 + tig * 2;
                *(uint32_t*)(C + (size_t)row * N + col) = packh2(acc[mt][n8][0], acc[mt][n8][1]);
                *(uint32_t*)(C + (size_t)(row + 8) * N + col) = packh2(acc[mt][n8][2], acc[mt][n8][3]);
            }
    } else {
        float* C = (float*)Cv;
#pragma unroll
        for (int mt = 0; mt < 2; mt++)
#pragma unroll
            for (int n8 = 0; n8 < 8; n8++) {
                int row = bm + wm * 32 + mt * 16 + g;
                int col = bn + wn * 64 + n8 * 8 + tig * 2;
                *(float2*)(C + (size_t)row * N + col) = make_float2(acc[mt][n8][0], acc[mt][n8][1]);
                *(float2*)(C + (size_t)(row + 8) * N + col) = make_float2(acc[mt][n8][2], acc[mt][n8][3]);
            }
    }
}

// ---------------------------------------------------------------------------
// Flash attention: QK bf16 3-term; PV single fp16 MMA; single-fp16 output.
// ---------------------------------------------------------------------------
#define AT_TILE 16384
#define AT_SMEM (5 * AT_TILE)               // 81920 B
#define NQT     (SEQ / 64)                  // 32

__device__ __forceinline__ uint32_t swz256(int r, int ch) {
    return (uint32_t)(r * 256 + (((ch ^ (r & 7)) & 15) << 4));
}

__global__ __launch_bounds__(128)
void flash_attn_mma(const __nv_bfloat16* __restrict__ Qh, const __nv_bfloat16* __restrict__ Ql,
                    const __nv_bfloat16* __restrict__ Kh, const __nv_bfloat16* __restrict__ Kl,
                    const __half* __restrict__ Vf, __half* __restrict__ OAf)
{
    extern __shared__ __align__(128) char smem[];
    const uint32_t sb  = smem_u32(smem);
    const uint32_t sQh = sb;
    const uint32_t sQl = sb + AT_TILE;
    const uint32_t sA  = sb + 2 * AT_TILE;
    const uint32_t sBv = sb + 4 * AT_TILE;

    const int h   = blockIdx.y;
    const int b   = blockIdx.z;
    const int kvh = h >> 2;
    const int t   = threadIdx.x;
    const int warp = t >> 5;
    const int lane = t & 31;
    const int g    = lane >> 2;
    const int tig  = lane & 3;

    const int rl = warp * 16 + g;
    const int rh = rl + 8;

    auto load_k = [&](int kt) {
        const __nv_bfloat16* bh = Kh + (size_t)(b * SEQ + kt * 64) * KVW + kvh * HD;
        const __nv_bfloat16* bl = Kl + (size_t)(b * SEQ + kt * 64) * KVW + kvh * HD;
#pragma unroll
        for (int i = 0; i < 8; i++) {
            int f = i * 128 + t;
            int r = f >> 4, ch = f & 15;
            cpa16(sA + swz256(r, ch),           bh + (size_t)r * KVW + ch * 8);
            cpa16(sA + AT_TILE + swz256(r, ch), bl + (size_t)r * KVW + ch * 8);
        }
        CPA_COMMIT();
    };
    auto load_v = [&](int kt) {
        const __half* bv = Vf + (size_t)(b * SEQ + kt * 64) * KVW + kvh * HD;
#pragma unroll
        for (int i = 0; i < 8; i++) {
            int f = i * 128 + t;
            int r = f >> 4, ch = f & 15;
            cpa16(sBv + swz256(r, ch), bv + (size_t)r * KVW + ch * 8);
        }
        CPA_COMMIT();
    };

    for (int sel = 0; sel < 2; sel++) {
        const int qt = sel ? (NQT - 1 - blockIdx.x) : blockIdx.x;
        const int q0 = qt * 64;

        {
            const __nv_bfloat16* qbh = Qh + (size_t)(b * SEQ + q0) * QW + h * HD;
            const __nv_bfloat16* qbl = Ql + (size_t)(b * SEQ + q0) * QW + h * HD;
#pragma unroll
            for (int i = 0; i < 8; i++) {
                int f = i * 128 + t;
                int r = f >> 4, ch = f & 15;
                cpa16(sQh + swz256(r, ch), qbh + (size_t)r * QW + ch * 8);
                cpa16(sQl + swz256(r, ch), qbl + (size_t)r * QW + ch * 8);
            }
            CPA_COMMIT();
        }
        load_k(0);
        CPA_WAIT(0);
        __syncthreads();

        float o[16][4];
        float m0 = -1e30f, m1 = -1e30f, l0 = 0.f, l1 = 0.f;
#pragma unroll
        for (int i = 0; i < 16; i++)
#pragma unroll
            for (int j = 0; j < 4; j++) o[i][j] = 0.f;

        for (int kt = 0; kt <= qt; kt++) {
            load_v(kt);

            float sacc[8][4];
#pragma unroll
            for (int i = 0; i < 8; i++)
#pragma unroll
                for (int j = 0; j < 4; j++) sacc[i][j] = 0.f;

#pragma unroll
            for (int ks = 0; ks < 8; ks++) {
                uint32_t qfh[4], qfl[4];
                {
                    int rr = warp * 16 + (lane & 15);
                    uint32_t ad = swz256(rr, ks * 2 + (lane >> 4));
                    ldm4(qfh, sQh + ad);
                    ldm4(qfl, sQl + ad);
                }
                uint32_t kfh[4][4], kfl[4][4];
#pragma unroll
                for (int ng = 0; ng < 4; ng++) {
                    int rr = ng * 16 + (lane & 15);
                    uint32_t ad = swz256(rr, ks * 2 + (lane >> 4));
                    ldm4(kfh[ng], sA + ad);
                    ldm4(kfl[ng], sA + AT_TILE + ad);
                }
#pragma unroll
                for (int n8 = 0; n8 < 8; n8++) {
                    int ng = n8 >> 1, hf = n8 & 1;
                    mma16816(sacc[n8], qfh, kfh[ng][hf], kfh[ng][hf + 2]);
                }
#pragma unroll
                for (int n8 = 0; n8 < 8; n8++) {
                    int ng = n8 >> 1, hf = n8 & 1;
                    mma16816(sacc[n8], qfl, kfh[ng][hf], kfh[ng][hf + 2]);
                }
#pragma unroll
                for (int n8 = 0; n8 < 8; n8++) {
                    int ng = n8 >> 1, hf = n8 & 1;
                    mma16816(sacc[n8], qfh, kfl[ng][hf], kfl[ng][hf + 2]);
                }
            }

            if (kt == qt) {
#pragma unroll
                for (int n8 = 0; n8 < 8; n8++) {
                    int c0 = n8 * 8 + tig * 2, c1 = c0 + 1;
                    if (c0 > rl) sacc[n8][0] = -1e30f;
                    if (c1 > rl) sacc[n8][1] = -1e30f;
                    if (c0 > rh) sacc[n8][2] = -1e30f;
                    if (c1 > rh) sacc[n8][3] = -1e30f;
                }
            }

            float mx0 = -1e30f, mx1 = -1e30f;
#pragma unroll
            for (int n8 = 0; n8 < 8; n8++) {
                mx0 = fmaxf(mx0, fmaxf(sacc[n8][0], sacc[n8][1]));
                mx1 = fmaxf(mx1, fmaxf(sacc[n8][2], sacc[n8][3]));
            }
            mx0 = fmaxf(mx0, __shfl_xor_sync(0xffffffffu, mx0, 1));
            mx0 = fmaxf(mx0, __shfl_xor_sync(0xffffffffu, mx0, 2));
            mx1 = fmaxf(mx1, __shfl_xor_sync(0xffffffffu, mx1, 1));
            mx1 = fmaxf(mx1, __shfl_xor_sync(0xffffffffu, mx1, 2));

            float mn0 = fmaxf(m0, mx0), mn1 = fmaxf(m1, mx1);
            float al0 = __expf(m0 - mn0), al1 = __expf(m1 - mn1);
            m0 = mn0; m1 = mn1;

            float s0 = 0.f, s1 = 0.f;
#pragma unroll
            for (int n8 = 0; n8 < 8; n8++) {
                float p0 = __expf(sacc[n8][0] - m0);
                float p1 = __expf(sacc[n8][1] - m0);
                float p2 = __expf(sacc[n8][2] - m1);
                float p3 = __expf(sacc[n8][3] - m1);
                sacc[n8][0] = p0; sacc[n8][1] = p1; sacc[n8][2] = p2; sacc[n8][3] = p3;
                s0 += p0 + p1; s1 += p2 + p3;
            }
            s0 += __shfl_xor_sync(0xffffffffu, s0, 1);
            s0 += __shfl_xor_sync(0xffffffffu, s0, 2);
            s1 += __shfl_xor_sync(0xffffffffu, s1, 1);
            s1 += __shfl_xor_sync(0xffffffffu, s1, 2);
            l0 = l0 * al0 + s0;
            l1 = l1 * al1 + s1;

#pragma unroll
            for (int i = 0; i < 16; i++) {
                o[i][0] *= al0; o[i][1] *= al0;
                o[i][2] *= al1; o[i][3] *= al1;
            }

            uint32_t ph[4][4];
#pragma unroll
            for (int kk = 0; kk < 4; kk++) {
                ph[kk][0] = packh2(sacc[2 * kk][0],     sacc[2 * kk][1]);
                ph[kk][1] = packh2(sacc[2 * kk][2],     sacc[2 * kk][3]);
                ph[kk][2] = packh2(sacc[2 * kk + 1][0], sacc[2 * kk + 1][1]);
                ph[kk][3] = packh2(sacc[2 * kk + 1][2], sacc[2 * kk + 1][3]);
            }

            CPA_WAIT(0);
            __syncthreads();

            if (kt < qt) load_k(kt + 1);

#pragma unroll
            for (int ng = 0; ng < 8; ng++) {
#pragma unroll
                for (int kk = 0; kk < 4; kk++) {
                    uint32_t vf[4];
                    int rr = kk * 16 + (lane & 15);
                    uint32_t ad = swz256(rr, ng * 2 + (lane >> 4));
                    ldm4t(vf, sBv + ad);
#pragma unroll
                    for (int hf = 0; hf < 2; hf++) {
                        int nt = ng * 2 + hf;
                        mma16816f(o[nt], ph[kk], vf[hf * 2], vf[hf * 2 + 1]);
                    }
                }
            }

            CPA_WAIT(0);
            __syncthreads();
        }

        float inv0 = 1.f / l0, inv1 = 1.f / l1;
        __half* Obf = OAf + (size_t)(b * SEQ + q0) * QW + h * HD;
#pragma unroll
        for (int nt = 0; nt < 16; nt++) {
            int col = nt * 8 + tig * 2;
            *(uint32_t*)(Obf + (size_t)rl * QW + col) = packh2(o[nt][0] * inv0, o[nt][1] * inv0);
            *(uint32_t*)(Obf + (size_t)rh * QW + col) = packh2(o[nt][2] * inv1, o[nt][3] * inv1);
        }
    }
}

// ---------------------------------------------------------------------------
// Launcher — forked-capture streams: V-proj overlaps QK-proj.
// ---------------------------------------------------------------------------
extern "C" void kernel_launch(void* const* d_in, const int* in_sizes, int n_in,
                              void* d_out, int out_size)
{
    const float* x    = (const float*)d_in[0];
    const float* q_w  = (const float*)d_in[2];
    const float* k_w  = (const float*)d_in[3];
    const float* v_w  = (const float*)d_in[4];
    const float* o_w  = (const float*)d_in[5];
    const float* sinp = (const float*)d_in[6];
    const float* cosp = (const float*)d_in[7];
    float* out = (float*)d_out;

    __nv_bfloat16 *xh, *xl, *wh, *wl, *Qh, *Ql, *Kh, *Kl;
    __half *xf, *vwf, *owf, *Vfp, *Afp;
    cudaGetSymbolAddress((void**)&xh, g_xh);
    cudaGetSymbolAddress((void**)&xl, g_xl);
    cudaGetSymbolAddress((void**)&xf, g_xf);
    cudaGetSymbolAddress((void**)&wh, g_wh);
    cudaGetSymbolAddress((void**)&wl, g_wl);
    cudaGetSymbolAddress((void**)&vwf, g_vwf);
    cudaGetSymbolAddress((void**)&owf, g_owf);
    cudaGetSymbolAddress((void**)&Qh, g_Qh);
    cudaGetSymbolAddress((void**)&Ql, g_Ql);
    cudaGetSymbolAddress((void**)&Kh, g_Kh);
    cudaGetSymbolAddress((void**)&Kl, g_Kl);
    cudaGetSymbolAddress((void**)&Vfp, g_Vf);
    cudaGetSymbolAddress((void**)&Afp, g_Af);

    cudaFuncSetAttribute(hmma_gemm_qk, cudaFuncAttributeMaxDynamicSharedMemorySize, QK_SMEM);
    cudaFuncSetAttribute(hmma_gemm_1t<0>, cudaFuncAttributeMaxDynamicSharedMemorySize, OSMEM);
    cudaFuncSetAttribute(hmma_gemm_1t<1>, cudaFuncAttributeMaxDynamicSharedMemorySize, OSMEM);
    cudaFuncSetAttribute(flash_attn_mma, cudaFuncAttributeMaxDynamicSharedMemorySize, AT_SMEM);

    cudaStream_t s2;
    cudaEvent_t e1, e2;
    cudaStreamCreateWithFlags(&s2, cudaStreamNonBlocking);
    cudaEventCreateWithFlags(&e1, cudaEventDisableTiming);
    cudaEventCreateWithFlags(&e2, cudaEventDisableTiming);

    // 1) fused split of all fp32 operands
    split_all<<<(N4_ALL + 255) / 256, 256>>>(x, q_w, k_w, v_w, o_w,
                                             xh, xl, xf, wh, wl, vwf, owf);
    cudaEventRecord(e1, 0);
    cudaStreamWaitEvent(s2, e1, 0);

    // 2) QK projection (bf16 3-term), BM=64 balanced grid
    hmma_gemm_qk<<<dim3(W2 / 128, MTOT / 64), 128, QK_SMEM>>>(
        xh, xl, wh, wl, Qh, Ql, Kh, Kl, sinp, cosp, MTOT, W2, HID);

    // 3) V projection (1-term fp16) concurrently on s2
    hmma_gemm_1t<1><<<dim3(KVW / 128, MTOT / 64), 128, OSMEM, s2>>>(
        xf, vwf, Vfp, MTOT, KVW, HID);
    cudaEventRecord(e2, s2);
    cudaStreamWaitEvent(0, e2, 0);

    // 4) flash attention (joined)
    flash_attn_mma<<<dim3(NQT / 2, NH, 2), 128, AT_SMEM>>>(Qh, Ql, Kh, Kl, Vfp, Afp);

    // 5) output projection (1-term fp16, fp32 out), BM=64 balanced grid
    hmma_gemm_1t<0><<<dim3(HID / 128, MTOT / 64), 128, OSMEM>>>(
        Afp, owf, out, MTOT, HID, HID);
}

// round 15
// speedup vs baseline: 4.4014x; 1.0520x over previous
#include <cuda_runtime.h>
#include <cuda_bf16.h>
#include <cuda_fp16.h>
#include <math.h>
#include <stdint.h>

// Problem constants
#define MTOT 4096      // B*S
#define SEQ  2048
#define HID  2048
#define NH   16
#define NKV  4
#define HD   128
#define QW   2048      // NH*HD
#define KVW  512       // NKV*HD
#define W2   2560      // fused Q|K weight width (bf16 3-term path)

// Scratch (allocation-free rule: __device__ globals)
__device__ __nv_bfloat16 g_xh[(size_t)MTOT * HID];
__device__ __nv_bfloat16 g_xl[(size_t)MTOT * HID];
__device__ __half        g_xf[(size_t)MTOT * HID];
__device__ __nv_bfloat16 g_wh[(size_t)W2 * HID];
__device__ __nv_bfloat16 g_wl[(size_t)W2 * HID];
__device__ __half        g_vwf[(size_t)KVW * HID];
__device__ __half        g_owf[(size_t)HID * QW];
__device__ __nv_bfloat16 g_Qh[(size_t)MTOT * QW];
__device__ __nv_bfloat16 g_Ql[(size_t)MTOT * QW];
__device__ __nv_bfloat16 g_Kh[(size_t)MTOT * KVW];
__device__ __nv_bfloat16 g_Kl[(size_t)MTOT * KVW];
__device__ __half        g_Vf[(size_t)MTOT * KVW];
__device__ __half        g_Af[(size_t)MTOT * QW];

// ---------------------------------------------------------------------------
// helpers
// ---------------------------------------------------------------------------
__device__ __forceinline__ void mma16816(float* c, const uint32_t* a, uint32_t b0, uint32_t b1) {
    asm volatile(
        "mma.sync.aligned.m16n8k16.row.col.f32.bf16.bf16.f32 "
        "{%0,%1,%2,%3}, {%4,%5,%6,%7}, {%8,%9}, {%0,%1,%2,%3};"
        : "+f"(c[0]), "+f"(c[1]), "+f"(c[2]), "+f"(c[3])
        : "r"(a[0]), "r"(a[1]), "r"(a[2]), "r"(a[3]), "r"(b0), "r"(b1));
}
__device__ __forceinline__ void mma16816f(float* c, const uint32_t* a, uint32_t b0, uint32_t b1) {
    asm volatile(
        "mma.sync.aligned.m16n8k16.row.col.f32.f16.f16.f32 "
        "{%0,%1,%2,%3}, {%4,%5,%6,%7}, {%8,%9}, {%0,%1,%2,%3};"
        : "+f"(c[0]), "+f"(c[1]), "+f"(c[2]), "+f"(c[3])
        : "r"(a[0]), "r"(a[1]), "r"(a[2]), "r"(a[3]), "r"(b0), "r"(b1));
}
__device__ __forceinline__ void ldm4(uint32_t* r, uint32_t a) {
    asm volatile("ldmatrix.sync.aligned.m8n8.x4.shared.b16 {%0,%1,%2,%3}, [%4];"
                 : "=r"(r[0]), "=r"(r[1]), "=r"(r[2]), "=r"(r[3]) : "r"(a));
}
__device__ __forceinline__ void ldm4t(uint32_t* r, uint32_t a) {
    asm volatile("ldmatrix.sync.aligned.m8n8.x4.trans.shared.b16 {%0,%1,%2,%3}, [%4];"
                 : "=r"(r[0]), "=r"(r[1]), "=r"(r[2]), "=r"(r[3]) : "r"(a));
}
__device__ __forceinline__ uint32_t smem_u32(const void* p) {
    uint32_t a;
    asm("{ .reg .u64 tmp; cvta.to.shared.u64 tmp, %1; cvt.u32.u64 %0, tmp; }"
        : "=r"(a) : "l"(p));
    return a;
}
__device__ __forceinline__ void cpa16(uint32_t dst, const void* src) {
    asm volatile("cp.async.cg.shared.global [%0], [%1], 16;" :: "r"(dst), "l"(src));
}
#define CPA_COMMIT() asm volatile("cp.async.commit_group;" ::: "memory")
#define CPA_WAIT(n)  asm volatile("cp.async.wait_group %0;" :: "n"(n) : "memory")

__device__ __forceinline__ void split2(float a, float b, uint32_t& h, uint32_t& l) {
    __nv_bfloat162 hh = __floats2bfloat162_rn(a, b);
    float ra = a - __bfloat162float(hh.x);
    float rb = b - __bfloat162float(hh.y);
    __nv_bfloat162 ll = __floats2bfloat162_rn(ra, rb);
    h = *(uint32_t*)&hh;
    l = *(uint32_t*)&ll;
}
__device__ __forceinline__ uint32_t packh2(float a, float b) {
    __half2 h = __floats2half2_rn(a, b);
    return *(uint32_t*)&h;
}

// ---------------------------------------------------------------------------
// Fused split kernel
// ---------------------------------------------------------------------------
#define N4_X   (MTOT * HID / 4)
#define N4_QW  (QW * HID / 4)
#define N4_KW  (KVW * HID / 4)
#define N4_ALL (N4_X + N4_QW + 2 * N4_KW + N4_QW)

__global__ void split_all(const float* __restrict__ x, const float* __restrict__ qw,
                          const float* __restrict__ kw, const float* __restrict__ vw,
                          const float* __restrict__ ow,
                          __nv_bfloat16* __restrict__ xh, __nv_bfloat16* __restrict__ xl,
                          __half* __restrict__ xf,
                          __nv_bfloat16* __restrict__ wh, __nv_bfloat16* __restrict__ wl,
                          __half* __restrict__ vwf, __half* __restrict__ owf)
{
    int i = blockIdx.x * blockDim.x + threadIdx.x;
    if (i >= N4_ALL) return;
    int j = i;
    if (j < N4_X) {
        float4 v = ((const float4*)x)[j];
        uint32_t h0, l0, h1, l1;
        split2(v.x, v.y, h0, l0);
        split2(v.z, v.w, h1, l1);
        ((uint2*)xh)[j] = make_uint2(h0, h1);
        ((uint2*)xl)[j] = make_uint2(l0, l1);
        ((uint2*)xf)[j] = make_uint2(packh2(v.x, v.y), packh2(v.z, v.w));
        return;
    }
    j -= N4_X;
    if (j < N4_QW) {
        float4 v = ((const float4*)qw)[j];
        uint32_t h0, l0, h1, l1;
        split2(v.x, v.y, h0, l0);
        split2(v.z, v.w, h1, l1);
        ((uint2*)wh)[j] = make_uint2(h0, h1);
        ((uint2*)wl)[j] = make_uint2(l0, l1);
        return;
    }
    j -= N4_QW;
    if (j < N4_KW) {
        float4 v = ((const float4*)kw)[j];
        uint32_t h0, l0, h1, l1;
        split2(v.x, v.y, h0, l0);
        split2(v.z, v.w, h1, l1);
        size_t off = (size_t)QW * HID / 4;
        ((uint2*)wh)[off + j] = make_uint2(h0, h1);
        ((uint2*)wl)[off + j] = make_uint2(l0, l1);
        return;
    }
    j -= N4_KW;
    if (j < N4_KW) {
        float4 v = ((const float4*)vw)[j];
        ((uint2*)vwf)[j] = make_uint2(packh2(v.x, v.y), packh2(v.z, v.w));
        return;
    }
    j -= N4_KW;
    {
        float4 v = ((const float4*)ow)[j];
        ((uint2*)owf)[j] = make_uint2(packh2(v.x, v.y), packh2(v.z, v.w));
    }
}

// ---------------------------------------------------------------------------
// QK GEMM (bf16 3-term) + rope/split epilogue. BM=64, BN=128 -> 1280 CTAs.
// 2-stage cp.async double buffer AND 3 CTAs/SM (stage 30720B, total 61440B).
// Per-accumulator MMA order unchanged -> bit-identical.
// ---------------------------------------------------------------------------
#define GROW  80
#define GTA   (64 * GROW)             // 5120 B  (A tile, 64 rows)
#define GTB   (128 * GROW)            // 10240 B (B tile, 128 rows)
#define QK_STG (2 * GTA + 2 * GTB)    // 30720 B per stage
#define QK_SMEM (2 * QK_STG)          // 61440 B

__global__ __launch_bounds__(128, 3)
void hmma_gemm_qk(const __nv_bfloat16* __restrict__ Ah, const __nv_bfloat16* __restrict__ Al,
                  const __nv_bfloat16* __restrict__ Bh, const __nv_bfloat16* __restrict__ Bl,
                  __nv_bfloat16* __restrict__ Qoh, __nv_bfloat16* __restrict__ Qol,
                  __nv_bfloat16* __restrict__ Koh, __nv_bfloat16* __restrict__ Kol,
                  const float* __restrict__ sinp, const float* __restrict__ cosp,
                  int M, int N, int K)
{
    extern __shared__ __align__(128) char smem[];
    const uint32_t sb = smem_u32(smem);

    const int t    = threadIdx.x;
    const int warp = t >> 5;
    const int lane = t & 31;
    const int wm   = warp >> 1;
    const int wn   = warp & 1;
    const int bm   = blockIdx.y * 64;
    const int bn   = blockIdx.x * 128;

    float acc[2][8][4];
#pragma unroll
    for (int mi = 0; mi < 2; mi++)
#pragma unroll
        for (int ni = 0; ni < 8; ni++)
#pragma unroll
            for (int r = 0; r < 4; r++) acc[mi][ni][r] = 0.f;

    const int S = K / 32;

    auto issue = [&](int s, int buf) {
        const int k0 = s * 32;
        const uint32_t stg = sb + (uint32_t)buf * QK_STG;
#pragma unroll
        for (int i = 0; i < 2; i++) {
            int f = i * 128 + t;
            int r = f >> 2, ch = f & 3;
            uint32_t so = r * GROW + ch * 16;
            size_t  go = (size_t)(bm + r) * K + k0 + ch * 8;
            cpa16(stg + so, Ah + go);
            cpa16(stg + GTA + so, Al + go);
        }
#pragma unroll
        for (int i = 0; i < 4; i++) {
            int f = i * 128 + t;
            int r = f >> 2, ch = f & 3;
            uint32_t so = r * GROW + ch * 16;
            size_t  go = (size_t)(bn + r) * K + k0 + ch * 8;
            cpa16(stg + 2 * GTA + so, Bh + go);
            cpa16(stg + 2 * GTA + GTB + so, Bl + go);
        }
        CPA_COMMIT();
    };

    issue(0, 0);

    for (int s = 0; s < S; s++) {
        const int buf = s & 1;
        if (s + 1 < S) { issue(s + 1, buf ^ 1); CPA_WAIT(1); }
        else           { CPA_WAIT(0); }
        __syncthreads();

        const uint32_t smAh = sb + (uint32_t)buf * QK_STG;
        const uint32_t smAl = smAh + GTA;
        const uint32_t smBh = smAh + 2 * GTA;
        const uint32_t smBl = smAh + 2 * GTA + GTB;

#pragma unroll
        for (int kk = 0; kk < 2; kk++) {
            // phase 1: terms hh + lh
            {
                uint32_t bh[4][4];
#pragma unroll
                for (int ng = 0; ng < 4; ng++) {
                    int rr = wn * 64 + ng * 16 + (lane & 15);
                    ldm4(bh[ng], smBh + rr * GROW + (kk * 2 + (lane >> 4)) * 16);
                }
#pragma unroll
                for (int mt = 0; mt < 2; mt++) {
                    uint32_t ah[4], al[4];
                    int rr = wm * 32 + mt * 16 + (lane & 15);
                    uint32_t ad = rr * GROW + (kk * 2 + (lane >> 4)) * 16;
                    ldm4(ah, smAh + ad);
                    ldm4(al, smAl + ad);
#pragma unroll
                    for (int n8 = 0; n8 < 8; n8++) {
                        int ng = n8 >> 1, hf = n8 & 1;
                        mma16816(acc[mt][n8], ah, bh[ng][hf], bh[ng][hf + 2]);
                    }
#pragma unroll
                    for (int n8 = 0; n8 < 8; n8++) {
                        int ng = n8 >> 1, hf = n8 & 1;
                        mma16816(acc[mt][n8], al, bh[ng][hf], bh[ng][hf + 2]);
                    }
                }
            }
            // phase 2: term hl
            {
                uint32_t bl[4][4];
#pragma unroll
                for (int ng = 0; ng < 4; ng++) {
                    int rr = wn * 64 + ng * 16 + (lane & 15);
                    ldm4(bl[ng], smBl + rr * GROW + (kk * 2 + (lane >> 4)) * 16);
                }
#pragma unroll
                for (int mt = 0; mt < 2; mt++) {
                    uint32_t ah[4];
                    int rr = wm * 32 + mt * 16 + (lane & 15);
                    ldm4(ah, smAh + rr * GROW + (kk * 2 + (lane >> 4)) * 16);
#pragma unroll
                    for (int n8 = 0; n8 < 8; n8++) {
                        int ng = n8 >> 1, hf = n8 & 1;
                        mma16816(acc[mt][n8], ah, bl[ng][hf], bl[ng][hf + 2]);
                    }
                }
            }
        }
        __syncthreads();
    }

    // Epilogue: stage 64 rows, rope + bf16 split
    const int g   = lane >> 2;
    const int tig = lane & 3;
    float* stg = (float*)smem;   // [64][132] = 33792 B
    const int bx = blockIdx.x;

#pragma unroll
    for (int mt = 0; mt < 2; mt++)
#pragma unroll
        for (int n8 = 0; n8 < 8; n8++) {
            int row = wm * 32 + mt * 16 + g;
            int col = wn * 64 + n8 * 8 + tig * 2;
            stg[row * 132 + col]     = acc[mt][n8][0];
            stg[row * 132 + col + 1] = acc[mt][n8][1];
            stg[(row + 8) * 132 + col]     = acc[mt][n8][2];
            stg[(row + 8) * 132 + col + 1] = acc[mt][n8][3];
        }
    __syncthreads();

    {
        const int r2   = t >> 1;
        const int half = t & 1;
        const int gm   = bm + r2;
        const int spos = gm & (SEQ - 1);
        const int pb   = half * 32;

        bool isQ = bx < 16;
        __nv_bfloat16* dh = isQ ? (Qoh + (size_t)gm * QW + bx * 128)
                                : (Koh + (size_t)gm * KVW + (bx - 16) * 128);
        __nv_bfloat16* dl = isQ ? (Qol + (size_t)gm * QW + bx * 128)
                                : (Kol + (size_t)gm * KVW + (bx - 16) * 128);

        uint32_t h0[16], l0[16], h1[16], l1[16];
#pragma unroll
        for (int j = 0; j < 16; j++) {
            int pi = pb + j * 2;
            float x0a = stg[r2 * 132 + pi],      x0b = stg[r2 * 132 + pi + 1];
            float x1a = stg[r2 * 132 + pi + 64], x1b = stg[r2 * 132 + pi + 65];
            float ca = cosp[(size_t)spos * HD + pi],  cb = cosp[(size_t)spos * HD + pi + 1];
            float sa = sinp[(size_t)spos * HD + pi],  sbv = sinp[(size_t)spos * HD + pi + 1];
            float y0a = x0a * ca - x1a * sa,  y1a = x1a * ca + x0a * sa;
            float y0b = x0b * cb - x1b * sbv, y1b = x1b * cb + x0b * sbv;
            split2(y0a, y0b, h0[j], l0[j]);
            split2(y1a, y1b, h1[j], l1[j]);
        }
#pragma unroll
        for (int w = 0; w < 4; w++) {
            *(uint4*)(dh + pb + w * 8)      = ((uint4*)h0)[w];
            *(uint4*)(dh + 64 + pb + w * 8) = ((uint4*)h1)[w];
            *(uint4*)(dl + pb + w * 8)      = ((uint4*)l0)[w];
            *(uint4*)(dl + 64 + pb + w * 8) = ((uint4*)l1)[w];
        }
    }
}

// ---------------------------------------------------------------------------
// 1-term fp16 GEMM, BM=64, BN=128. OUTF16=1 -> fp16 out, 0 -> fp32 out.
// ---------------------------------------------------------------------------
#define OST   (GTA + GTB)            // 15360 B per stage
#define OSMEM (2 * OST)              // 30720 B

template<int OUTF16>
__global__ __launch_bounds__(128, 3)
void hmma_gemm_1t(const __half* __restrict__ A_, const __half* __restrict__ B_,
                  void* __restrict__ Cv, int M, int N, int K)
{
    extern __shared__ __align__(128) char smem[];
    const uint32_t sb = smem_u32(smem);

    const int t    = threadIdx.x;
    const int warp = t >> 5;
    const int lane = t & 31;
    const int wm   = warp >> 1;
    const int wn   = warp & 1;
    const int bm   = blockIdx.y * 64;
    const int bn   = blockIdx.x * 128;

    float acc[2][8][4];
#pragma unroll
    for (int mi = 0; mi < 2; mi++)
#pragma unroll
        for (int ni = 0; ni < 8; ni++)
#pragma unroll
            for (int r = 0; r < 4; r++) acc[mi][ni][r] = 0.f;

    const int S = K / 32;

    auto issue = [&](int s, int buf) {
        const int k0 = s * 32;
        const uint32_t stg = sb + (uint32_t)buf * OST;
#pragma unroll
        for (int i = 0; i < 2; i++) {
            int f = i * 128 + t;
            int r = f >> 2, ch = f & 3;
            cpa16(stg + r * GROW + ch * 16, A_ + (size_t)(bm + r) * K + k0 + ch * 8);
        }
#pragma unroll
        for (int i = 0; i < 4; i++) {
            int f = i * 128 + t;
            int r = f >> 2, ch = f & 3;
            cpa16(stg + GTA + r * GROW + ch * 16, B_ + (size_t)(bn + r) * K + k0 + ch * 8);
        }
        CPA_COMMIT();
    };

    issue(0, 0);

    for (int s = 0; s < S; s++) {
        const int buf = s & 1;
        if (s + 1 < S) { issue(s + 1, buf ^ 1); CPA_WAIT(1); }
        else           { CPA_WAIT(0); }
        __syncthreads();

        const uint32_t smA = sb + (uint32_t)buf * OST;
        const uint32_t smB = smA + GTA;

#pragma unroll
        for (int kk = 0; kk < 2; kk++) {
            uint32_t bfr[4][4];
#pragma unroll
            for (int ng = 0; ng < 4; ng++) {
                int rr = wn * 64 + ng * 16 + (lane & 15);
                uint32_t ad = rr * GROW + (kk * 2 + (lane >> 4)) * 16;
                ldm4(bfr[ng], smB + ad);
            }
#pragma unroll
            for (int mt = 0; mt < 2; mt++) {
                uint32_t af[4];
                int rr = wm * 32 + mt * 16 + (lane & 15);
                uint32_t ad = rr * GROW + (kk * 2 + (lane >> 4)) * 16;
                ldm4(af, smA + ad);
#pragma unroll
                for (int n8 = 0; n8 < 8; n8++) {
                    int ng = n8 >> 1, hf = n8 & 1;
                    mma16816f(acc[mt][n8], af, bfr[ng][hf], bfr[ng][hf + 2]);
                }
            }
        }
        __syncthreads();
    }

    const int g   = lane >> 2;
    const int tig = lane & 3;
    if (OUTF16) {
        __half* C = (__half*)Cv;
#pragma unroll
        for (int mt = 0; mt < 2; mt++)
#pragma unroll
            for (int n8 = 0; n8 < 8; n8++) {
                int row = bm + wm * 32 + mt * 16 + g;
                int col = bn + wn * 64 + n8 * 8 + tig * 2;
                *(uint32_t*)(C + (size_t)row * N + col) = packh2(acc[mt][n8][0], acc[mt][n8][1]);
                *(uint32_t*)(C + (size_t)(row + 8) * N + col) = packh2(acc[mt][n8][2], acc[mt][n8][3]);
            }
    } else {
        float* C = (float*)Cv;
#pragma unroll
        for (int mt = 0; mt < 2; mt++)
#pragma unroll
            for (int n8 = 0; n8 < 8; n8++) {
                int row = bm + wm * 32 + mt * 16 + g;
                int col = bn + wn * 64 + n8 * 8 + tig * 2;
                *(float2*)(C + (size_t)row * N + col) = make_float2(acc[mt][n8][0], acc[mt][n8][1]);
                *(float2*)(C + (size_t)(row + 8) * N + col) = make_float2(acc[mt][n8][2], acc[mt][n8][3]);
            }
    }
}

// ---------------------------------------------------------------------------
// Flash attention: one qt per CTA, LPT (descending-work) bid->qt mapping.
// QK bf16 3-term; PV single fp16 MMA; single-fp16 output.
// ---------------------------------------------------------------------------
#define AT_TILE 16384
#define AT_SMEM (5 * AT_TILE)               // 81920 B
#define NQT     (SEQ / 64)                  // 32

__device__ __forceinline__ uint32_t swz256(int r, int ch) {
    return (uint32_t)(r * 256 + (((ch ^ (r & 7)) & 15) << 4));
}

__global__ __launch_bounds__(128)
void flash_attn_mma(const __nv_bfloat16* __restrict__ Qh, const __nv_bfloat16* __restrict__ Ql,
                    const __nv_bfloat16* __restrict__ Kh, const __nv_bfloat16* __restrict__ Kl,
                    const __half* __restrict__ Vf, __half* __restrict__ OAf)
{
    extern __shared__ __align__(128) char smem[];
    const uint32_t sb  = smem_u32(smem);
    const uint32_t sQh = sb;
    const uint32_t sQl = sb + AT_TILE;
    const uint32_t sA  = sb + 2 * AT_TILE;
    const uint32_t sBv = sb + 4 * AT_TILE;

    // LPT mapping: biggest qt first
    const int bid = blockIdx.x;
    const int qt  = (NQT - 1) - (bid >> 5);
    const int hb  = bid & 31;
    const int h   = hb >> 1;
    const int b   = hb & 1;
    const int kvh = h >> 2;
    const int q0  = qt * 64;

    const int t    = threadIdx.x;
    const int warp = t >> 5;
    const int lane = t & 31;
    const int g    = lane >> 2;
    const int tig  = lane & 3;

    const int rl = warp * 16 + g;
    const int rh = rl + 8;

    auto load_k = [&](int kt) {
        const __nv_bfloat16* bh = Kh + (size_t)(b * SEQ + kt * 64) * KVW + kvh * HD;
        const __nv_bfloat16* bl = Kl + (size_t)(b * SEQ + kt * 64) * KVW + kvh * HD;
#pragma unroll
        for (int i = 0; i < 8; i++) {
            int f = i * 128 + t;
            int r = f >> 4, ch = f & 15;
            cpa16(sA + swz256(r, ch),           bh + (size_t)r * KVW + ch * 8);
            cpa16(sA + AT_TILE + swz256(r, ch), bl + (size_t)r * KVW + ch * 8);
        }
        CPA_COMMIT();
    };
    auto load_v = [&](int kt) {
        const __half* bv = Vf + (size_t)(b * SEQ + kt * 64) * KVW + kvh * HD;
#pragma unroll
        for (int i = 0; i < 8; i++) {
            int f = i * 128 + t;
            int r = f >> 4, ch = f & 15;
            cpa16(sBv + swz256(r, ch), bv + (size_t)r * KVW + ch * 8);
        }
        CPA_COMMIT();
    };

    {
        const __nv_bfloat16* qbh = Qh + (size_t)(b * SEQ + q0) * QW + h * HD;
        const __nv_bfloat16* qbl = Ql + (size_t)(b * SEQ + q0) * QW + h * HD;
#pragma unroll
        for (int i = 0; i < 8; i++) {
            int f = i * 128 + t;
            int r = f >> 4, ch = f & 15;
            cpa16(sQh + swz256(r, ch), qbh + (size_t)r * QW + ch * 8);
            cpa16(sQl + swz256(r, ch), qbl + (size_t)r * QW + ch * 8);
        }
        CPA_COMMIT();
    }
    load_k(0);
    CPA_WAIT(0);
    __syncthreads();

    float o[16][4];
    float m0 = -1e30f, m1 = -1e30f, l0 = 0.f, l1 = 0.f;
#pragma unroll
    for (int i = 0; i < 16; i++)
#pragma unroll
        for (int j = 0; j < 4; j++) o[i][j] = 0.f;

    for (int kt = 0; kt <= qt; kt++) {
        load_v(kt);

        float sacc[8][4];
#pragma unroll
        for (int i = 0; i < 8; i++)
#pragma unroll
            for (int j = 0; j < 4; j++) sacc[i][j] = 0.f;

#pragma unroll
        for (int ks = 0; ks < 8; ks++) {
            uint32_t qfh[4], qfl[4];
            {
                int rr = warp * 16 + (lane & 15);
                uint32_t ad = swz256(rr, ks * 2 + (lane >> 4));
                ldm4(qfh, sQh + ad);
                ldm4(qfl, sQl + ad);
            }
            uint32_t kfh[4][4], kfl[4][4];
#pragma unroll
            for (int ng = 0; ng < 4; ng++) {
                int rr = ng * 16 + (lane & 15);
                uint32_t ad = swz256(rr, ks * 2 + (lane >> 4));
                ldm4(kfh[ng], sA + ad);
                ldm4(kfl[ng], sA + AT_TILE + ad);
            }
#pragma unroll
            for (int n8 = 0; n8 < 8; n8++) {
                int ng = n8 >> 1, hf = n8 & 1;
                mma16816(sacc[n8], qfh, kfh[ng][hf], kfh[ng][hf + 2]);
            }
#pragma unroll
            for (int n8 = 0; n8 < 8; n8++) {
                int ng = n8 >> 1, hf = n8 & 1;
                mma16816(sacc[n8], qfl, kfh[ng][hf], kfh[ng][hf + 2]);
            }
#pragma unroll
            for (int n8 = 0; n8 < 8; n8++) {
                int ng = n8 >> 1, hf = n8 & 1;
                mma16816(sacc[n8], qfh, kfl[ng][hf], kfl[ng][hf + 2]);
            }
        }

        if (kt == qt) {
#pragma unroll
            for (int n8 = 0; n8 < 8; n8++) {
                int c0 = n8 * 8 + tig * 2, c1 = c0 + 1;
                if (c0 > rl) sacc[n8][0] = -1e30f;
                if (c1 > rl) sacc[n8][1] = -1e30f;
                if (c0 > rh) sacc[n8][2] = -1e30f;
                if (c1 > rh) sacc[n8][3] = -1e30f;
            }
        }

        float mx0 = -1e30f, mx1 = -1e30f;
#pragma unroll
        for (int n8 = 0; n8 < 8; n8++) {
            mx0 = fmaxf(mx0, fmaxf(sacc[n8][0], sacc[n8][1]));
            mx1 = fmaxf(mx1, fmaxf(sacc[n8][2], sacc[n8][3]));
        }
        mx0 = fmaxf(mx0, __shfl_xor_sync(0xffffffffu, mx0, 1));
        mx0 = fmaxf(mx0, __shfl_xor_sync(0xffffffffu, mx0, 2));
        mx1 = fmaxf(mx1, __shfl_xor_sync(0xffffffffu, mx1, 1));
        mx1 = fmaxf(mx1, __shfl_xor_sync(0xffffffffu, mx1, 2));

        float mn0 = fmaxf(m0, mx0), mn1 = fmaxf(m1, mx1);
        float al0 = __expf(m0 - mn0), al1 = __expf(m1 - mn1);
        m0 = mn0; m1 = mn1;

        float s0 = 0.f, s1 = 0.f;
#pragma unroll
        for (int n8 = 0; n8 < 8; n8++) {
            float p0 = __expf(sacc[n8][0] - m0);
            float p1 = __expf(sacc[n8][1] - m0);
            float p2 = __expf(sacc[n8][2] - m1);
            float p3 = __expf(sacc[n8][3] - m1);
            sacc[n8][0] = p0; sacc[n8][1] = p1; sacc[n8][2] = p2; sacc[n8][3] = p3;
            s0 += p0 + p1; s1 += p2 + p3;
        }
        s0 += __shfl_xor_sync(0xffffffffu, s0, 1);
        s0 += __shfl_xor_sync(0xffffffffu, s0, 2);
        s1 += __shfl_xor_sync(0xffffffffu, s1, 1);
        s1 += __shfl_xor_sync(0xffffffffu, s1, 2);
        l0 = l0 * al0 + s0;
        l1 = l1 * al1 + s1;

#pragma unroll
        for (int i = 0; i < 16; i++) {
            o[i][0] *= al0; o[i][1] *= al0;
            o[i][2] *= al1; o[i][3] *= al1;
        }

        uint32_t ph[4][4];
#pragma unroll
        for (int kk = 0; kk < 4; kk++) {
            ph[kk][0] = packh2(sacc[2 * kk][0],     sacc[2 * kk][1]);
            ph[kk][1] = packh2(sacc[2 * kk][2],     sacc[2 * kk][3]);
            ph[kk][2] = packh2(sacc[2 * kk + 1][0], sacc[2 * kk + 1][1]);
            ph[kk][3] = packh2(sacc[2 * kk + 1][2], sacc[2 * kk + 1][3]);
        }

        CPA_WAIT(0);
        __syncthreads();

        if (kt < qt) load_k(kt + 1);

#pragma unroll
        for (int ng = 0; ng < 8; ng++) {
#pragma unroll
            for (int kk = 0; kk < 4; kk++) {
                uint32_t vf[4];
                int rr = kk * 16 + (lane & 15);
                uint32_t ad = swz256(rr, ng * 2 + (lane >> 4));
                ldm4t(vf, sBv + ad);
#pragma unroll
                for (int hf = 0; hf < 2; hf++) {
                    int nt = ng * 2 + hf;
                    mma16816f(o[nt], ph[kk], vf[hf * 2], vf[hf * 2 + 1]);
                }
            }
        }

        CPA_WAIT(0);
        __syncthreads();
    }

    float inv0 = 1.f / l0, inv1 = 1.f / l1;
    __half* Obf = OAf + (size_t)(b * SEQ + q0) * QW + h * HD;
#pragma unroll
    for (int nt = 0; nt < 16; nt++) {
        int col = nt * 8 + tig * 2;
        *(uint32_t*)(Obf + (size_t)rl * QW + col) = packh2(o[nt][0] * inv0, o[nt][1] * inv0);
        *(uint32_t*)(Obf + (size_t)rh * QW + col) = packh2(o[nt][2] * inv1, o[nt][3] * inv1);
    }
}

// ---------------------------------------------------------------------------
// Launcher — forked-capture streams: V-proj overlaps QK-proj.
// ---------------------------------------------------------------------------
extern "C" void kernel_launch(void* const* d_in, const int* in_sizes, int n_in,
                              void* d_out, int out_size)
{
    const float* x    = (const float*)d_in[0];
    const float* q_w  = (const float*)d_in[2];
    const float* k_w  = (const float*)d_in[3];
    const float* v_w  = (const float*)d_in[4];
    const float* o_w  = (const float*)d_in[5];
    const float* sinp = (const float*)d_in[6];
    const float* cosp = (const float*)d_in[7];
    float* out = (float*)d_out;

    __nv_bfloat16 *xh, *xl, *wh, *wl, *Qh, *Ql, *Kh, *Kl;
    __half *xf, *vwf, *owf, *Vfp, *Afp;
    cudaGetSymbolAddress((void**)&xh, g_xh);
    cudaGetSymbolAddress((void**)&xl, g_xl);
    cudaGetSymbolAddress((void**)&xf, g_xf);
    cudaGetSymbolAddress((void**)&wh, g_wh);
    cudaGetSymbolAddress((void**)&wl, g_wl);
    cudaGetSymbolAddress((void**)&vwf, g_vwf);
    cudaGetSymbolAddress((void**)&owf, g_owf);
    cudaGetSymbolAddress((void**)&Qh, g_Qh);
    cudaGetSymbolAddress((void**)&Ql, g_Ql);
    cudaGetSymbolAddress((void**)&Kh, g_Kh);
    cudaGetSymbolAddress((void**)&Kl, g_Kl);
    cudaGetSymbolAddress((void**)&Vfp, g_Vf);
    cudaGetSymbolAddress((void**)&Afp, g_Af);

    cudaFuncSetAttribute(hmma_gemm_qk, cudaFuncAttributeMaxDynamicSharedMemorySize, QK_SMEM);
    cudaFuncSetAttribute(hmma_gemm_1t<0>, cudaFuncAttributeMaxDynamicSharedMemorySize, OSMEM);
    cudaFuncSetAttribute(hmma_gemm_1t<1>, cudaFuncAttributeMaxDynamicSharedMemorySize, OSMEM);
    cudaFuncSetAttribute(flash_attn_mma, cudaFuncAttributeMaxDynamicSharedMemorySize, AT_SMEM);

    cudaStream_t s2;
    cudaEvent_t e1, e2;
    cudaStreamCreateWithFlags(&s2, cudaStreamNonBlocking);
    cudaEventCreateWithFlags(&e1, cudaEventDisableTiming);
    cudaEventCreateWithFlags(&e2, cudaEventDisableTiming);

    // 1) fused split of all fp32 operands
    split_all<<<(N4_ALL + 255) / 256, 256>>>(x, q_w, k_w, v_w, o_w,
                                             xh, xl, xf, wh, wl, vwf, owf);
    cudaEventRecord(e1, 0);
    cudaStreamWaitEvent(s2, e1, 0);

    // 2) QK projection (bf16 3-term), BM=64, 2-stage, 3 CTA/SM
    hmma_gemm_qk<<<dim3(W2 / 128, MTOT / 64), 128, QK_SMEM>>>(
        xh, xl, wh, wl, Qh, Ql, Kh, Kl, sinp, cosp, MTOT, W2, HID);

    // 3) V projection (1-term fp16) concurrently on s2
    hmma_gemm_1t<1><<<dim3(KVW / 128, MTOT / 64), 128, OSMEM, s2>>>(
        xf, vwf, Vfp, MTOT, KVW, HID);
    cudaEventRecord(e2, s2);
    cudaStreamWaitEvent(0, e2, 0);

    // 4) flash attention — 1024 CTAs, LPT descending-work order
    flash_attn_mma<<<dim3(NQT * 32), 128, AT_SMEM>>>(Qh, Ql, Kh, Kl, Vfp, Afp);

    // 5) output projection (1-term fp16, fp32 out)
    hmma_gemm_1t<0><<<dim3(HID / 128, MTOT / 64), 128, OSMEM>>>(
        Afp, owf, out, MTOT, HID, HID);
}

// round 16
// speedup vs baseline: 4.4041x; 1.0006x over previous
#include <cuda_runtime.h>
#include <cuda_bf16.h>
#include <cuda_fp16.h>
#include <math.h>
#include <stdint.h>

// Problem constants
#define MTOT 4096      // B*S
#define SEQ  2048
#define HID  2048
#define NH   16
#define NKV  4
#define HD   128
#define QW   2048      // NH*HD
#define KVW  512       // NKV*HD
#define W2   2560      // fused Q|K weight width (bf16 3-term path)

// Scratch (allocation-free rule: __device__ globals)
__device__ __nv_bfloat16 g_xh[(size_t)MTOT * HID];
__device__ __nv_bfloat16 g_xl[(size_t)MTOT * HID];
__device__ __half        g_xf[(size_t)MTOT * HID];
__device__ __nv_bfloat16 g_wh[(size_t)W2 * HID];
__device__ __nv_bfloat16 g_wl[(size_t)W2 * HID];
__device__ __half        g_vwf[(size_t)KVW * HID];
__device__ __half        g_owf[(size_t)HID * QW];
__device__ __nv_bfloat16 g_Qh[(size_t)MTOT * QW];
__device__ __nv_bfloat16 g_Ql[(size_t)MTOT * QW];
__device__ __nv_bfloat16 g_Kh[(size_t)MTOT * KVW];
__device__ __nv_bfloat16 g_Kl[(size_t)MTOT * KVW];
__device__ __half        g_Vf[(size_t)MTOT * KVW];
__device__ __half        g_Af[(size_t)MTOT * QW];

// ---------------------------------------------------------------------------
// helpers
// ---------------------------------------------------------------------------
__device__ __forceinline__ void mma16816(float* c, const uint32_t* a, uint32_t b0, uint32_t b1) {
    asm volatile(
        "mma.sync.aligned.m16n8k16.row.col.f32.bf16.bf16.f32 "
        "{%0,%1,%2,%3}, {%4,%5,%6,%7}, {%8,%9}, {%0,%1,%2,%3};"
        : "+f"(c[0]), "+f"(c[1]), "+f"(c[2]), "+f"(c[3])
        : "r"(a[0]), "r"(a[1]), "r"(a[2]), "r"(a[3]), "r"(b0), "r"(b1));
}
__device__ __forceinline__ void mma16816f(float* c, const uint32_t* a, uint32_t b0, uint32_t b1) {
    asm volatile(
        "mma.sync.aligned.m16n8k16.row.col.f32.f16.f16.f32 "
        "{%0,%1,%2,%3}, {%4,%5,%6,%7}, {%8,%9}, {%0,%1,%2,%3};"
        : "+f"(c[0]), "+f"(c[1]), "+f"(c[2]), "+f"(c[3])
        : "r"(a[0]), "r"(a[1]), "r"(a[2]), "r"(a[3]), "r"(b0), "r"(b1));
}
__device__ __forceinline__ void ldm4(uint32_t* r, uint32_t a) {
    asm volatile("ldmatrix.sync.aligned.m8n8.x4.shared.b16 {%0,%1,%2,%3}, [%4];"
                 : "=r"(r[0]), "=r"(r[1]), "=r"(r[2]), "=r"(r[3]) : "r"(a));
}
__device__ __forceinline__ void ldm4t(uint32_t* r, uint32_t a) {
    asm volatile("ldmatrix.sync.aligned.m8n8.x4.trans.shared.b16 {%0,%1,%2,%3}, [%4];"
                 : "=r"(r[0]), "=r"(r[1]), "=r"(r[2]), "=r"(r[3]) : "r"(a));
}
__device__ __forceinline__ uint32_t smem_u32(const void* p) {
    uint32_t a;
    asm("{ .reg .u64 tmp; cvta.to.shared.u64 tmp, %1; cvt.u32.u64 %0, tmp; }"
        : "=r"(a) : "l"(p));
    return a;
}
__device__ __forceinline__ void cpa16(uint32_t dst, const void* src) {
    asm volatile("cp.async.cg.shared.global [%0], [%1], 16;" :: "r"(dst), "l"(src));
}
#define CPA_COMMIT() asm volatile("cp.async.commit_group;" ::: "memory")
#define CPA_WAIT(n)  asm volatile("cp.async.wait_group %0;" :: "n"(n) : "memory")

__device__ __forceinline__ void split2(float a, float b, uint32_t& h, uint32_t& l) {
    __nv_bfloat162 hh = __floats2bfloat162_rn(a, b);
    float ra = a - __bfloat162float(hh.x);
    float rb = b - __bfloat162float(hh.y);
    __nv_bfloat162 ll = __floats2bfloat162_rn(ra, rb);
    h = *(uint32_t*)&hh;
    l = *(uint32_t*)&ll;
}
__device__ __forceinline__ uint32_t packh2(float a, float b) {
    __half2 h = __floats2half2_rn(a, b);
    return *(uint32_t*)&h;
}

// ---------------------------------------------------------------------------
// Fused split kernel
// ---------------------------------------------------------------------------
#define N4_X   (MTOT * HID / 4)
#define N4_QW  (QW * HID / 4)
#define N4_KW  (KVW * HID / 4)
#define N4_ALL (N4_X + N4_QW + 2 * N4_KW + N4_QW)

__global__ void split_all(const float* __restrict__ x, const float* __restrict__ qw,
                          const float* __restrict__ kw, const float* __restrict__ vw,
                          const float* __restrict__ ow,
                          __nv_bfloat16* __restrict__ xh, __nv_bfloat16* __restrict__ xl,
                          __half* __restrict__ xf,
                          __nv_bfloat16* __restrict__ wh, __nv_bfloat16* __restrict__ wl,
                          __half* __restrict__ vwf, __half* __restrict__ owf)
{
    int i = blockIdx.x * blockDim.x + threadIdx.x;
    if (i >= N4_ALL) return;
    int j = i;
    if (j < N4_X) {
        float4 v = ((const float4*)x)[j];
        uint32_t h0, l0, h1, l1;
        split2(v.x, v.y, h0, l0);
        split2(v.z, v.w, h1, l1);
        ((uint2*)xh)[j] = make_uint2(h0, h1);
        ((uint2*)xl)[j] = make_uint2(l0, l1);
        ((uint2*)xf)[j] = make_uint2(packh2(v.x, v.y), packh2(v.z, v.w));
        return;
    }
    j -= N4_X;
    if (j < N4_QW) {
        float4 v = ((const float4*)qw)[j];
        uint32_t h0, l0, h1, l1;
        split2(v.x, v.y, h0, l0);
        split2(v.z, v.w, h1, l1);
        ((uint2*)wh)[j] = make_uint2(h0, h1);
        ((uint2*)wl)[j] = make_uint2(l0, l1);
        return;
    }
    j -= N4_QW;
    if (j < N4_KW) {
        float4 v = ((const float4*)kw)[j];
        uint32_t h0, l0, h1, l1;
        split2(v.x, v.y, h0, l0);
        split2(v.z, v.w, h1, l1);
        size_t off = (size_t)QW * HID / 4;
        ((uint2*)wh)[off + j] = make_uint2(h0, h1);
        ((uint2*)wl)[off + j] = make_uint2(l0, l1);
        return;
    }
    j -= N4_KW;
    if (j < N4_KW) {
        float4 v = ((const float4*)vw)[j];
        ((uint2*)vwf)[j] = make_uint2(packh2(v.x, v.y), packh2(v.z, v.w));
        return;
    }
    j -= N4_KW;
    {
        float4 v = ((const float4*)ow)[j];
        ((uint2*)owf)[j] = make_uint2(packh2(v.x, v.y), packh2(v.z, v.w));
    }
}

// ---------------------------------------------------------------------------
// QK GEMM (bf16 3-term) + rope/split epilogue. BM=64, BN=128 -> 1280 CTAs.
// 2-stage cp.async double buffer AND 3 CTAs/SM (stage 30720B, total 61440B).
// Per-accumulator MMA order unchanged -> bit-identical.
// ---------------------------------------------------------------------------
#define GROW  80
#define GTA   (64 * GROW)             // 5120 B  (A tile, 64 rows)
#define GTB   (128 * GROW)            // 10240 B (B tile, 128 rows)
#define QK_STG (2 * GTA + 2 * GTB)    // 30720 B per stage
#define QK_SMEM (2 * QK_STG)          // 61440 B

__global__ __launch_bounds__(128, 3)
void hmma_gemm_qk(const __nv_bfloat16* __restrict__ Ah, const __nv_bfloat16* __restrict__ Al,
                  const __nv_bfloat16* __restrict__ Bh, const __nv_bfloat16* __restrict__ Bl,
                  __nv_bfloat16* __restrict__ Qoh, __nv_bfloat16* __restrict__ Qol,
                  __nv_bfloat16* __restrict__ Koh, __nv_bfloat16* __restrict__ Kol,
                  const float* __restrict__ sinp, const float* __restrict__ cosp,
                  int M, int N, int K)
{
    extern __shared__ __align__(128) char smem[];
    const uint32_t sb = smem_u32(smem);

    const int t    = threadIdx.x;
    const int warp = t >> 5;
    const int lane = t & 31;
    const int wm   = warp >> 1;
    const int wn   = warp & 1;
    const int bm   = blockIdx.y * 64;
    const int bn   = blockIdx.x * 128;

    float acc[2][8][4];
#pragma unroll
    for (int mi = 0; mi < 2; mi++)
#pragma unroll
        for (int ni = 0; ni < 8; ni++)
#pragma unroll
            for (int r = 0; r < 4; r++) acc[mi][ni][r] = 0.f;

    const int S = K / 32;

    auto issue = [&](int s, int buf) {
        const int k0 = s * 32;
        const uint32_t stg = sb + (uint32_t)buf * QK_STG;
#pragma unroll
        for (int i = 0; i < 2; i++) {
            int f = i * 128 + t;
            int r = f >> 2, ch = f & 3;
            uint32_t so = r * GROW + ch * 16;
            size_t  go = (size_t)(bm + r) * K + k0 + ch * 8;
            cpa16(stg + so, Ah + go);
            cpa16(stg + GTA + so, Al + go);
        }
#pragma unroll
        for (int i = 0; i < 4; i++) {
            int f = i * 128 + t;
            int r = f >> 2, ch = f & 3;
            uint32_t so = r * GROW + ch * 16;
            size_t  go = (size_t)(bn + r) * K + k0 + ch * 8;
            cpa16(stg + 2 * GTA + so, Bh + go);
            cpa16(stg + 2 * GTA + GTB + so, Bl + go);
        }
        CPA_COMMIT();
    };

    issue(0, 0);

    for (int s = 0; s < S; s++) {
        const int buf = s & 1;
        if (s + 1 < S) { issue(s + 1, buf ^ 1); CPA_WAIT(1); }
        else           { CPA_WAIT(0); }
        __syncthreads();

        const uint32_t smAh = sb + (uint32_t)buf * QK_STG;
        const uint32_t smAl = smAh + GTA;
        const uint32_t smBh = smAh + 2 * GTA;
        const uint32_t smBl = smAh + 2 * GTA + GTB;

#pragma unroll
        for (int kk = 0; kk < 2; kk++) {
            // phase 1: terms hh + lh
            {
                uint32_t bh[4][4];
#pragma unroll
                for (int ng = 0; ng < 4; ng++) {
                    int rr = wn * 64 + ng * 16 + (lane & 15);
                    ldm4(bh[ng], smBh + rr * GROW + (kk * 2 + (lane >> 4)) * 16);
                }
#pragma unroll
                for (int mt = 0; mt < 2; mt++) {
                    uint32_t ah[4], al[4];
                    int rr = wm * 32 + mt * 16 + (lane & 15);
                    uint32_t ad = rr * GROW + (kk * 2 + (lane >> 4)) * 16;
                    ldm4(ah, smAh + ad);
                    ldm4(al, smAl + ad);
#pragma unroll
                    for (int n8 = 0; n8 < 8; n8++) {
                        int ng = n8 >> 1, hf = n8 & 1;
                        mma16816(acc[mt][n8], ah, bh[ng][hf], bh[ng][hf + 2]);
                    }
#pragma unroll
                    for (int n8 = 0; n8 < 8; n8++) {
                        int ng = n8 >> 1, hf = n8 & 1;
                        mma16816(acc[mt][n8], al, bh[ng][hf], bh[ng][hf + 2]);
                    }
                }
            }
            // phase 2: term hl
            {
                uint32_t bl[4][4];
#pragma unroll
                for (int ng = 0; ng < 4; ng++) {
                    int rr = wn * 64 + ng * 16 + (lane & 15);
                    ldm4(bl[ng], smBl + rr * GROW + (kk * 2 + (lane >> 4)) * 16);
                }
#pragma unroll
                for (int mt = 0; mt < 2; mt++) {
                    uint32_t ah[4];
                    int rr = wm * 32 + mt * 16 + (lane & 15);
                    ldm4(ah, smAh + rr * GROW + (kk * 2 + (lane >> 4)) * 16);
#pragma unroll
                    for (int n8 = 0; n8 < 8; n8++) {
                        int ng = n8 >> 1, hf = n8 & 1;
                        mma16816(acc[mt][n8], ah, bl[ng][hf], bl[ng][hf + 2]);
                    }
                }
            }
        }
        __syncthreads();
    }

    // Epilogue: stage 64 rows, rope + bf16 split
    const int g   = lane >> 2;
    const int tig = lane & 3;
    float* stg = (float*)smem;   // [64][132] = 33792 B
    const int bx = blockIdx.x;

#pragma unroll
    for (int mt = 0; mt < 2; mt++)
#pragma unroll
        for (int n8 = 0; n8 < 8; n8++) {
            int row = wm * 32 + mt * 16 + g;
            int col = wn * 64 + n8 * 8 + tig * 2;
            stg[row * 132 + col]     = acc[mt][n8][0];
            stg[row * 132 + col + 1] = acc[mt][n8][1];
            stg[(row + 8) * 132 + col]     = acc[mt][n8][2];
            stg[(row + 8) * 132 + col + 1] = acc[mt][n8][3];
        }
    __syncthreads();

    {
        const int r2   = t >> 1;
        const int half = t & 1;
        const int gm   = bm + r2;
        const int spos = gm & (SEQ - 1);
        const int pb   = half * 32;

        bool isQ = bx < 16;
        __nv_bfloat16* dh = isQ ? (Qoh + (size_t)gm * QW + bx * 128)
                                : (Koh + (size_t)gm * KVW + (bx - 16) * 128);
        __nv_bfloat16* dl = isQ ? (Qol + (size_t)gm * QW + bx * 128)
                                : (Kol + (size_t)gm * KVW + (bx - 16) * 128);

        uint32_t h0[16], l0[16], h1[16], l1[16];
#pragma unroll
        for (int j = 0; j < 16; j++) {
            int pi = pb + j * 2;
            float x0a = stg[r2 * 132 + pi],      x0b = stg[r2 * 132 + pi + 1];
            float x1a = stg[r2 * 132 + pi + 64], x1b = stg[r2 * 132 + pi + 65];
            float ca = cosp[(size_t)spos * HD + pi],  cb = cosp[(size_t)spos * HD + pi + 1];
            float sa = sinp[(size_t)spos * HD + pi],  sbv = sinp[(size_t)spos * HD + pi + 1];
            float y0a = x0a * ca - x1a * sa,  y1a = x1a * ca + x0a * sa;
            float y0b = x0b * cb - x1b * sbv, y1b = x1b * cb + x0b * sbv;
            split2(y0a, y0b, h0[j], l0[j]);
            split2(y1a, y1b, h1[j], l1[j]);
        }
#pragma unroll
        for (int w = 0; w < 4; w++) {
            *(uint4*)(dh + pb + w * 8)      = ((uint4*)h0)[w];
            *(uint4*)(dh + 64 + pb + w * 8) = ((uint4*)h1)[w];
            *(uint4*)(dl + pb + w * 8)      = ((uint4*)l0)[w];
            *(uint4*)(dl + 64 + pb + w * 8) = ((uint4*)l1)[w];
        }
    }
}

// ---------------------------------------------------------------------------
// 1-term fp16 GEMM, BM=64, BN=128. OUTF16=1 -> fp16 out, 0 -> fp32 out.
// ---------------------------------------------------------------------------
#define OST   (GTA + GTB)            // 15360 B per stage
#define OSMEM (2 * OST)              // 30720 B

template<int OUTF16>
__global__ __launch_bounds__(128, 3)
void hmma_gemm_1t(const __half* __restrict__ A_, const __half* __restrict__ B_,
                  void* __restrict__ Cv, int M, int N, int K)
{
    extern __shared__ __align__(128) char smem[];
    const uint32_t sb = smem_u32(smem);

    const int t    = threadIdx.x;
    const int warp = t >> 5;
    const int lane = t & 31;
    const int wm   = warp >> 1;
    const int wn   = warp & 1;
    const int bm   = blockIdx.y * 64;
    const int bn   = blockIdx.x * 128;

    float acc[2][8][4];
#pragma unroll
    for (int mi = 0; mi < 2; mi++)
#pragma unroll
        for (int ni = 0; ni < 8; ni++)
#pragma unroll
            for (int r = 0; r < 4; r++) acc[mi][ni][r] = 0.f;

    const int S = K / 32;

    auto issue = [&](int s, int buf) {
        const int k0 = s * 32;
        const uint32_t stg = sb + (uint32_t)buf * OST;
#pragma unroll
        for (int i = 0; i < 2; i++) {
            int f = i * 128 + t;
            int r = f >> 2, ch = f & 3;
            cpa16(stg + r * GROW + ch * 16, A_ + (size_t)(bm + r) * K + k0 + ch * 8);
        }
#pragma unroll
        for (int i = 0; i < 4; i++) {
            int f = i * 128 + t;
            int r = f >> 2, ch = f & 3;
            cpa16(stg + GTA + r * GROW + ch * 16, B_ + (size_t)(bn + r) * K + k0 + ch * 8);
        }
        CPA_COMMIT();
    };

    issue(0, 0);

    for (int s = 0; s < S; s++) {
        const int buf = s & 1;
        if (s + 1 < S) { issue(s + 1, buf ^ 1); CPA_WAIT(1); }
        else           { CPA_WAIT(0); }
        __syncthreads();

        const uint32_t smA = sb + (uint32_t)buf * OST;
        const uint32_t smB = smA + GTA;

#pragma unroll
        for (int kk = 0; kk < 2; kk++) {
            uint32_t bfr[4][4];
#pragma unroll
            for (int ng = 0; ng < 4; ng++) {
                int rr = wn * 64 + ng * 16 + (lane & 15);
                uint32_t ad = rr * GROW + (kk * 2 + (lane >> 4)) * 16;
                ldm4(bfr[ng], smB + ad);
            }
#pragma unroll
            for (int mt = 0; mt < 2; mt++) {
                uint32_t af[4];
                int rr = wm * 32 + mt * 16 + (lane & 15);
                uint32_t ad = rr * GROW + (kk * 2 + (lane >> 4)) * 16;
                ldm4(af, smA + ad);
#pragma unroll
                for (int n8 = 0; n8 < 8; n8++) {
                    int ng = n8 >> 1, hf = n8 & 1;
                    mma16816f(acc[mt][n8], af, bfr[ng][hf], bfr[ng][hf + 2]);
                }
            }
        }
        __syncthreads();
    }

    const int g   = lane >> 2;
    const int tig = lane & 3;
    if (OUTF16) {
        __half* C = (__half*)Cv;
#pragma unroll
        for (int mt = 0; mt < 2; mt++)
#pragma unroll
            for (int n8 = 0; n8 < 8; n8++) {
                int row = bm + wm * 32 + mt * 16 + g;
                int col = bn + wn * 64 + n8 * 8 + tig * 2;
                *(uint32_t*)(C + (size_t)row * N + col) = packh2(acc[mt][n8][0], acc[mt][n8][1]);
                *(uint32_t*)(C + (size_t)(row + 8) * N + col) = packh2(acc[mt][n8][2], acc[mt][n8][3]);
            }
    } else {
        float* C = (float*)Cv;
#pragma unroll
        for (int mt = 0; mt < 2; mt++)
#pragma unroll
            for (int n8 = 0; n8 < 8; n8++) {
                int row = bm + wm * 32 + mt * 16 + g;
                int col = bn + wn * 64 + n8 * 8 + tig * 2;
                *(float2*)(C + (size_t)row * N + col) = make_float2(acc[mt][n8][0], acc[mt][n8][1]);
                *(float2*)(C + (size_t)(row + 8) * N + col) = make_float2(acc[mt][n8][2], acc[mt][n8][3]);
            }
    }
}

// ---------------------------------------------------------------------------
// Flash attention: one qt per CTA, LPT (descending-work) bid->qt mapping.
// QK bf16 3-term; PV single fp16 MMA; single-fp16 output.
// ---------------------------------------------------------------------------
#define AT_TILE 16384
#define AT_SMEM (5 * AT_TILE)               // 81920 B
#define NQT     (SEQ / 64)                  // 32

__device__ __forceinline__ uint32_t swz256(int r, int ch) {
    return (uint32_t)(r * 256 + (((ch ^ (r & 7)) & 15) << 4));
}

__global__ __launch_bounds__(128)
void flash_attn_mma(const __nv_bfloat16* __restrict__ Qh, const __nv_bfloat16* __restrict__ Ql,
                    const __nv_bfloat16* __restrict__ Kh, const __nv_bfloat16* __restrict__ Kl,
                    const __half* __restrict__ Vf, __half* __restrict__ OAf)
{
    extern __shared__ __align__(128) char smem[];
    const uint32_t sb  = smem_u32(smem);
    const uint32_t sQh = sb;
    const uint32_t sQl = sb + AT_TILE;
    const uint32_t sA  = sb + 2 * AT_TILE;
    const uint32_t sBv = sb + 4 * AT_TILE;

    // LPT mapping: biggest qt first
    const int bid = blockIdx.x;
    const int qt  = (NQT - 1) - (bid >> 5);
    const int hb  = bid & 31;
    const int h   = hb >> 1;
    const int b   = hb & 1;
    const int kvh = h >> 2;
    const int q0  = qt * 64;

    const int t    = threadIdx.x;
    const int warp = t >> 5;
    const int lane = t & 31;
    const int g    = lane >> 2;
    const int tig  = lane & 3;

    const int rl = warp * 16 + g;
    const int rh = rl + 8;

    auto load_k = [&](int kt) {
        const __nv_bfloat16* bh = Kh + (size_t)(b * SEQ + kt * 64) * KVW + kvh * HD;
        const __nv_bfloat16* bl = Kl + (size_t)(b * SEQ + kt * 64) * KVW + kvh * HD;
#pragma unroll
        for (int i = 0; i < 8; i++) {
            int f = i * 128 + t;
            int r = f >> 4, ch = f & 15;
            cpa16(sA + swz256(r, ch),           bh + (size_t)r * KVW + ch * 8);
            cpa16(sA + AT_TILE + swz256(r, ch), bl + (size_t)r * KVW + ch * 8);
        }
        CPA_COMMIT();
    };
    auto load_v = [&](int kt) {
        const __half* bv = Vf + (size_t)(b * SEQ + kt * 64) * KVW + kvh * HD;
#pragma unroll
        for (int i = 0; i < 8; i++) {
            int f = i * 128 + t;
            int r = f >> 4, ch = f & 15;
            cpa16(sBv + swz256(r, ch), bv + (size_t)r * KVW + ch * 8);
        }
        CPA_COMMIT();
    };

    {
        const __nv_bfloat16* qbh = Qh + (size_t)(b * SEQ + q0) * QW + h * HD;
        const __nv_bfloat16* qbl = Ql + (size_t)(b * SEQ + q0) * QW + h * HD;
#pragma unroll
        for (int i = 0; i < 8; i++) {
            int f = i * 128 + t;
            int r = f >> 4, ch = f & 15;
            cpa16(sQh + swz256(r, ch), qbh + (size_t)r * QW + ch * 8);
            cpa16(sQl + swz256(r, ch), qbl + (size_t)r * QW + ch * 8);
        }
        CPA_COMMIT();
    }
    load_k(0);
    CPA_WAIT(0);
    __syncthreads();

    float o[16][4];
    float m0 = -1e30f, m1 = -1e30f, l0 = 0.f, l1 = 0.f;
#pragma unroll
    for (int i = 0; i < 16; i++)
#pragma unroll
        for (int j = 0; j < 4; j++) o[i][j] = 0.f;

    for (int kt = 0; kt <= qt; kt++) {
        load_v(kt);

        float sacc[8][4];
#pragma unroll
        for (int i = 0; i < 8; i++)
#pragma unroll
            for (int j = 0; j < 4; j++) sacc[i][j] = 0.f;

#pragma unroll
        for (int ks = 0; ks < 8; ks++) {
            uint32_t qfh[4], qfl[4];
            {
                int rr = warp * 16 + (lane & 15);
                uint32_t ad = swz256(rr, ks * 2 + (lane >> 4));
                ldm4(qfh, sQh + ad);
                ldm4(qfl, sQl + ad);
            }
            uint32_t kfh[4][4], kfl[4][4];
#pragma unroll
            for (int ng = 0; ng < 4; ng++) {
                int rr = ng * 16 + (lane & 15);
                uint32_t ad = swz256(rr, ks * 2 + (lane >> 4));
                ldm4(kfh[ng], sA + ad);
                ldm4(kfl[ng], sA + AT_TILE + ad);
            }
#pragma unroll
            for (int n8 = 0; n8 < 8; n8++) {
                int ng = n8 >> 1, hf = n8 & 1;
                mma16816(sacc[n8], qfh, kfh[ng][hf], kfh[ng][hf + 2]);
            }
#pragma unroll
            for (int n8 = 0; n8 < 8; n8++) {
                int ng = n8 >> 1, hf = n8 & 1;
                mma16816(sacc[n8], qfl, kfh[ng][hf], kfh[ng][hf + 2]);
            }
#pragma unroll
            for (int n8 = 0; n8 < 8; n8++) {
                int ng = n8 >> 1, hf = n8 & 1;
                mma16816(sacc[n8], qfh, kfl[ng][hf], kfl[ng][hf + 2]);
            }
        }

        if (kt == qt) {
#pragma unroll
            for (int n8 = 0; n8 < 8; n8++) {
                int c0 = n8 * 8 + tig * 2, c1 = c0 + 1;
                if (c0 > rl) sacc[n8][0] = -1e30f;
                if (c1 > rl) sacc[n8][1] = -1e30f;
                if (c0 > rh) sacc[n8][2] = -1e30f;
                if (c1 > rh) sacc[n8][3] = -1e30f;
            }
        }

        float mx0 = -1e30f, mx1 = -1e30f;
#pragma unroll
        for (int n8 = 0; n8 < 8; n8++) {
            mx0 = fmaxf(mx0, fmaxf(sacc[n8][0], sacc[n8][1]));
            mx1 = fmaxf(mx1, fmaxf(sacc[n8][2], sacc[n8][3]));
        }
        mx0 = fmaxf(mx0, __shfl_xor_sync(0xffffffffu, mx0, 1));
        mx0 = fmaxf(mx0, __shfl_xor_sync(0xffffffffu, mx0, 2));
        mx1 = fmaxf(mx1, __shfl_xor_sync(0xffffffffu, mx1, 1));
        mx1 = fmaxf(mx1, __shfl_xor_sync(0xffffffffu, mx1, 2));

        float mn0 = fmaxf(m0, mx0), mn1 = fmaxf(m1, mx1);
        float al0 = __expf(m0 - mn0), al1 = __expf(m1 - mn1);
        m0 = mn0; m1 = mn1;

        float s0 = 0.f, s1 = 0.f;
#pragma unroll
        for (int n8 = 0; n8 < 8; n8++) {
            float p0 = __expf(sacc[n8][0] - m0);
            float p1 = __expf(sacc[n8][1] - m0);
            float p2 = __expf(sacc[n8][2] - m1);
            float p3 = __expf(sacc[n8][3] - m1);
            sacc[n8][0] = p0; sacc[n8][1] = p1; sacc[n8][2] = p2; sacc[n8][3] = p3;
            s0 += p0 + p1; s1 += p2 + p3;
        }
        s0 += __shfl_xor_sync(0xffffffffu, s0, 1);
        s0 += __shfl_xor_sync(0xffffffffu, s0, 2);
        s1 += __shfl_xor_sync(0xffffffffu, s1, 1);
        s1 += __shfl_xor_sync(0xffffffffu, s1, 2);
        l0 = l0 * al0 + s0;
        l1 = l1 * al1 + s1;

#pragma unroll
        for (int i = 0; i < 16; i++) {
            o[i][0] *= al0; o[i][1] *= al0;
            o[i][2] *= al1; o[i][3] *= al1;
        }

        uint32_t ph[4][4];
#pragma unroll
        for (int kk = 0; kk < 4; kk++) {
            ph[kk][0] = packh2(sacc[2 * kk][0],     sacc[2 * kk][1]);
            ph[kk][1] = packh2(sacc[2 * kk][2],     sacc[2 * kk][3]);
            ph[kk][2] = packh2(sacc[2 * kk + 1][0], sacc[2 * kk + 1][1]);
            ph[kk][3] = packh2(sacc[2 * kk + 1][2], sacc[2 * kk + 1][3]);
        }

        CPA_WAIT(0);
        __syncthreads();

        if (kt < qt) load_k(kt + 1);

#pragma unroll
        for (int ng = 0; ng < 8; ng++) {
#pragma unroll
            for (int kk = 0; kk < 4; kk++) {
                uint32_t vf[4];
                int rr = kk * 16 + (lane & 15);
                uint32_t ad = swz256(rr, ng * 2 + (lane >> 4));
                ldm4t(vf, sBv + ad);
#pragma unroll
                for (int hf = 0; hf < 2; hf++) {
                    int nt = ng * 2 + hf;
                    mma16816f(o[nt], ph[kk], vf[hf * 2], vf[hf * 2 + 1]);
                }
            }
        }

        CPA_WAIT(0);
        __syncthreads();
    }

    float inv0 = 1.f / l0, inv1 = 1.f / l1;
    __half* Obf = OAf + (size_t)(b * SEQ + q0) * QW + h * HD;
#pragma unroll
    for (int nt = 0; nt < 16; nt++) {
        int col = nt * 8 + tig * 2;
        *(uint32_t*)(Obf + (size_t)rl * QW + col) = packh2(o[nt][0] * inv0, o[nt][1] * inv0);
        *(uint32_t*)(Obf + (size_t)rh * QW + col) = packh2(o[nt][2] * inv1, o[nt][3] * inv1);
    }
}

// ---------------------------------------------------------------------------
// Launcher — forked-capture streams: V-proj overlaps QK-proj.
// ---------------------------------------------------------------------------
extern "C" void kernel_launch(void* const* d_in, const int* in_sizes, int n_in,
                              void* d_out, int out_size)
{
    const float* x    = (const float*)d_in[0];
    const float* q_w  = (const float*)d_in[2];
    const float* k_w  = (const float*)d_in[3];
    const float* v_w  = (const float*)d_in[4];
    const float* o_w  = (const float*)d_in[5];
    const float* sinp = (const float*)d_in[6];
    const float* cosp = (const float*)d_in[7];
    float* out = (float*)d_out;

    __nv_bfloat16 *xh, *xl, *wh, *wl, *Qh, *Ql, *Kh, *Kl;
    __half *xf, *vwf, *owf, *Vfp, *Afp;
    cudaGetSymbolAddress((void**)&xh, g_xh);
    cudaGetSymbolAddress((void**)&xl, g_xl);
    cudaGetSymbolAddress((void**)&xf, g_xf);
    cudaGetSymbolAddress((void**)&wh, g_wh);
    cudaGetSymbolAddress((void**)&wl, g_wl);
    cudaGetSymbolAddress((void**)&vwf, g_vwf);
    cudaGetSymbolAddress((void**)&owf, g_owf);
    cudaGetSymbolAddress((void**)&Qh, g_Qh);
    cudaGetSymbolAddress((void**)&Ql, g_Ql);
    cudaGetSymbolAddress((void**)&Kh, g_Kh);
    cudaGetSymbolAddress((void**)&Kl, g_Kl);
    cudaGetSymbolAddress((void**)&Vfp, g_Vf);
    cudaGetSymbolAddress((void**)&Afp, g_Af);

    cudaFuncSetAttribute(hmma_gemm_qk, cudaFuncAttributeMaxDynamicSharedMemorySize, QK_SMEM);
    cudaFuncSetAttribute(hmma_gemm_1t<0>, cudaFuncAttributeMaxDynamicSharedMemorySize, OSMEM);
    cudaFuncSetAttribute(hmma_gemm_1t<1>, cudaFuncAttributeMaxDynamicSharedMemorySize, OSMEM);
    cudaFuncSetAttribute(flash_attn_mma, cudaFuncAttributeMaxDynamicSharedMemorySize, AT_SMEM);

    cudaStream_t s2;
    cudaEvent_t e1, e2;
    cudaStreamCreateWithFlags(&s2, cudaStreamNonBlocking);
    cudaEventCreateWithFlags(&e1, cudaEventDisableTiming);
    cudaEventCreateWithFlags(&e2, cudaEventDisableTiming);

    // 1) fused split of all fp32 operands
    split_all<<<(N4_ALL + 255) / 256, 256>>>(x, q_w, k_w, v_w, o_w,
                                             xh, xl, xf, wh, wl, vwf, owf);
    cudaEventRecord(e1, 0);
    cudaStreamWaitEvent(s2, e1, 0);

    // 2) QK projection (bf16 3-term), BM=64, 2-stage, 3 CTA/SM
    hmma_gemm_qk<<<dim3(W2 / 128, MTOT / 64), 128, QK_SMEM>>>(
        xh, xl, wh, wl, Qh, Ql, Kh, Kl, sinp, cosp, MTOT, W2, HID);

    // 3) V projection (1-term fp16) concurrently on s2
    hmma_gemm_1t<1><<<dim3(KVW / 128, MTOT / 64), 128, OSMEM, s2>>>(
        xf, vwf, Vfp, MTOT, KVW, HID);
    cudaEventRecord(e2, s2);
    cudaStreamWaitEvent(0, e2, 0);

    // 4) flash attention — 1024 CTAs, LPT descending-work order
    flash_attn_mma<<<dim3(NQT * 32), 128, AT_SMEM>>>(Qh, Ql, Kh, Kl, Vfp, Afp);

    // 5) output projection (1-term fp16, fp32 out)
    hmma_gemm_1t<0><<<dim3(HID / 128, MTOT / 64), 128, OSMEM>>>(
        Afp, owf, out, MTOT, HID, HID);
}